// round 5
// baseline (speedup 1.0000x reference)
#include <cuda_runtime.h>
#include <math.h>
#include <stdint.h>

#define B_   8
#define N1_  4096
#define N2_  4096
#define C_   512
#define P_   256
#define H_   8
#define HD_  64
#define MLP_ 2048
#define M_   (B_*N1_)

typedef unsigned short u16;

// ---------------- device scratch ----------------
__device__ float g_q [B_*N1_*C_];
__device__ float g_k [B_*N2_*C_];     // k, later xa
__device__ float g_v [B_*N2_*C_];     // v, later xn
__device__ float g_kp[B_*H_*HD_*P_];
__device__ float g_vp[B_*H_*HD_*P_];
// bf16-split activations
__device__ u16 g_x1h[M_*C_], g_x1l[M_*C_];
__device__ u16 g_x2h[M_*C_], g_x2l[M_*C_];
__device__ u16 g_xnh[M_*C_], g_xnl[M_*C_];
__device__ u16 g_hh [M_*MLP_], g_hl [M_*MLP_];
// transposed + bf16-split weights: Wt[n][k]
__device__ u16 g_wq_hi [C_*C_],   g_wq_lo [C_*C_];
__device__ u16 g_wkv_hi[2*C_*C_], g_wkv_lo[2*C_*C_];
__device__ u16 g_w1_hi [MLP_*C_], g_w1_lo [MLP_*C_];
__device__ u16 g_w2_hi [C_*MLP_], g_w2_lo [C_*MLP_];

// ======================= helpers =======================
__device__ __forceinline__ uint32_t smem_u32(const void* p) {
    uint32_t a;
    asm("{ .reg .u64 t; cvta.to.shared.u64 t, %1; cvt.u32.u64 %0, t; }"
        : "=r"(a) : "l"(p));
    return a;
}
#define SWZ(b) ((b) ^ (((b) >> 3) & 0x70))
#define CPA16(dst, src) asm volatile( \
    "cp.async.cg.shared.global [%0], [%1], 16;" :: "r"(dst), "l"(src))
#define CPA_COMMIT() asm volatile("cp.async.commit_group;" ::: "memory")
#define CPA_WAIT1()  asm volatile("cp.async.wait_group 1;" ::: "memory")

__device__ __forceinline__ void ldsm_x4(uint32_t& r0, uint32_t& r1,
                                        uint32_t& r2, uint32_t& r3, uint32_t a) {
    asm volatile("ldmatrix.sync.aligned.m8n8.x4.shared.b16 {%0,%1,%2,%3}, [%4];"
                 : "=r"(r0), "=r"(r1), "=r"(r2), "=r"(r3) : "r"(a));
}
__device__ __forceinline__ void mma_bf16(float* c, uint32_t a0, uint32_t a1,
                                         uint32_t a2, uint32_t a3,
                                         uint32_t b0, uint32_t b1) {
    asm volatile(
        "mma.sync.aligned.m16n8k16.row.col.f32.bf16.bf16.f32 "
        "{%0,%1,%2,%3}, {%4,%5,%6,%7}, {%8,%9}, {%0,%1,%2,%3};"
        : "+f"(c[0]), "+f"(c[1]), "+f"(c[2]), "+f"(c[3])
        : "r"(a0), "r"(a1), "r"(a2), "r"(a3), "r"(b0), "r"(b1));
}
__device__ __forceinline__ void bsplit(float a, uint32_t& hi, uint32_t& lo) {
    uint32_t u = __float_as_uint(a);
    uint32_t hr = (u + 0x7fffu + ((u >> 16) & 1u)) & 0xffff0000u;
    hi = hr >> 16;
    float l = a - __uint_as_float(hr);
    uint32_t ul = __float_as_uint(l);
    lo = (ul + 0x7fffu + ((ul >> 16) & 1u)) >> 16;
}

// =======================================================================
// Weight transpose + bf16 split: W[K][N] fp32 -> Wt_hi/lo[N][K] bf16
// =======================================================================
__global__ __launch_bounds__(256)
void wsplit_k(const float* __restrict__ W, u16* __restrict__ hi,
              u16* __restrict__ lo, int K, int N)
{
    __shared__ float tile[32][33];
    const int n0 = blockIdx.x * 32, k0 = blockIdx.y * 32;
    const int tx = threadIdx.x & 31, ty = threadIdx.x >> 5;
#pragma unroll
    for (int r = 0; r < 4; r++)
        tile[ty + 8 * r][tx] = W[(size_t)(k0 + ty + 8 * r) * N + n0 + tx];
    __syncthreads();
#pragma unroll
    for (int r = 0; r < 4; r++) {
        const int n = n0 + ty + 8 * r, k = k0 + tx;
        uint32_t h, l;
        bsplit(tile[tx][ty + 8 * r], h, l);
        hi[(size_t)n * K + k] = (u16)h;
        lo[(size_t)n * K + k] = (u16)l;
    }
}

// =======================================================================
// Activation bf16 split: A fp32 [n] -> hi/lo bf16 [n] (same layout)
// =======================================================================
__global__ __launch_bounds__(256)
void asplit_k(const float* __restrict__ A, u16* __restrict__ hi,
              u16* __restrict__ lo)
{
    const size_t i4 = ((size_t)blockIdx.x * 256 + threadIdx.x) * 4;
    float4 f = *(const float4*)(A + i4);
    uint32_t h0, l0, h1, l1, h2, l2, h3, l3;
    bsplit(f.x, h0, l0); bsplit(f.y, h1, l1);
    bsplit(f.z, h2, l2); bsplit(f.w, h3, l3);
    *(uint2*)(hi + i4) = make_uint2(h0 | (h1 << 16), h2 | (h3 << 16));
    *(uint2*)(lo + i4) = make_uint2(l0 | (l1 << 16), l2 | (l3 << 16));
}

// =======================================================================
// bf16x3 HMMA GEMM via mma.sync: D[128m x 128n] per CTA.
// A pre-split bf16 [M][K]; B pre-split bf16 [N][K].
// 3-stage cp.async pipeline. 256 threads, 8 warps (2m x 4n), warp tile 64x32.
// EPI 0: out=acc+bias+pos_q         (fp32)
// EPI 1: split k (+pos_k) / v      (fp32)
// EPI 2: gelu -> bf16 hi/lo split  (u16 out/out2)
// EPI 3: out=acc+bias+extra        (fp32)
// =======================================================================
#define TG_SMEM (3 * 65536)

template<int EPI>
__global__ __launch_bounds__(256, 1)
void tgemm(const u16* __restrict__ Ahi, const u16* __restrict__ Alo,
           const u16* __restrict__ Bhi, const u16* __restrict__ Blo,
           const float* __restrict__ bias, const float* __restrict__ extra,
           void* __restrict__ out, void* __restrict__ out2,
           int M, int N, int K)
{
    extern __shared__ __align__(1024) char sm_raw[];
    const uint32_t sb = smem_u32(sm_raw);
    const int tid = threadIdx.x;
    const int wid = tid >> 5, lane = tid & 31;
    const int bm = blockIdx.y * 128, bn = blockIdx.x * 128;
    const int wm = (wid & 1) * 64, wn = (wid >> 1) * 32;
    const int nck = K >> 6;

    float acc[4][4][4];
#pragma unroll
    for (int i = 0; i < 4; i++)
#pragma unroll
        for (int j = 0; j < 4; j++)
#pragma unroll
            for (int r = 0; r < 4; r++) acc[i][j][r] = 0.0f;

    // ldmatrix lane-address components
    const int a_row = ((lane >> 3) & 1) * 8 + (lane & 7);
    const int a_col = (lane >> 4) * 8;
    const int b_row = (lane >> 4) * 8 + (lane & 7);
    const int b_col = ((lane >> 3) & 1) * 8;

    auto load_stage = [&](int ck, int stage) {
        if (ck < nck) {
            const int k0 = ck * 64;
            const uint32_t sbase = sb + stage * 65536;
#pragma unroll
            for (int i = 0; i < 4; i++) {
                const int id = tid + i * 256;
                const int row = id >> 3, c16 = id & 7;
                const uint32_t dsw = SWZ((uint32_t)(row * 128 + c16 * 16));
                const size_t asrc = (size_t)(bm + row) * K + k0 + c16 * 8;
                const size_t bsrc = (size_t)(bn + row) * K + k0 + c16 * 8;
                CPA16(sbase + dsw,         Ahi + asrc);
                CPA16(sbase + 16384 + dsw, Alo + asrc);
                CPA16(sbase + 32768 + dsw, Bhi + bsrc);
                CPA16(sbase + 49152 + dsw, Blo + bsrc);
            }
        }
        CPA_COMMIT();
    };

    load_stage(0, 0);
    load_stage(1, 1);

    for (int ck = 0; ck < nck; ck++) {
        CPA_WAIT1();
        __syncthreads();
        load_stage(ck + 2, (ck + 2) % 3);

        const uint32_t base = sb + (ck % 3) * 65536;
#pragma unroll
        for (int ks = 0; ks < 4; ks++) {
            const int kk = ks * 16;
            uint32_t ah[4][4], al[4][4], bh[2][4], bl[2][4];
#pragma unroll
            for (int mf = 0; mf < 4; mf++) {
                const uint32_t ao = SWZ((uint32_t)((wm + mf * 16 + a_row) * 128 +
                                                   (kk + a_col) * 2));
                ldsm_x4(ah[mf][0], ah[mf][1], ah[mf][2], ah[mf][3], base + ao);
                ldsm_x4(al[mf][0], al[mf][1], al[mf][2], al[mf][3],
                        base + 16384 + ao);
            }
#pragma unroll
            for (int p = 0; p < 2; p++) {
                const uint32_t bo = SWZ((uint32_t)((wn + p * 16 + b_row) * 128 +
                                                   (kk + b_col) * 2));
                ldsm_x4(bh[p][0], bh[p][1], bh[p][2], bh[p][3], base + 32768 + bo);
                ldsm_x4(bl[p][0], bl[p][1], bl[p][2], bl[p][3], base + 49152 + bo);
            }
#pragma unroll
            for (int mf = 0; mf < 4; mf++)
#pragma unroll
                for (int p = 0; p < 2; p++)
#pragma unroll
                    for (int s = 0; s < 2; s++) {
                        float* c = acc[mf][p * 2 + s];
                        mma_bf16(c, ah[mf][0], ah[mf][1], ah[mf][2], ah[mf][3],
                                 bh[p][s * 2], bh[p][s * 2 + 1]);
                        mma_bf16(c, al[mf][0], al[mf][1], al[mf][2], al[mf][3],
                                 bh[p][s * 2], bh[p][s * 2 + 1]);
                        mma_bf16(c, ah[mf][0], ah[mf][1], ah[mf][2], ah[mf][3],
                                 bl[p][s * 2], bl[p][s * 2 + 1]);
                    }
        }
    }

    // ---- epilogue ----
    const int l4 = lane >> 2, l2 = (lane & 3) * 2;
#pragma unroll
    for (int mf = 0; mf < 4; mf++)
#pragma unroll
        for (int nf = 0; nf < 4; nf++) {
            const int col = bn + wn + nf * 8 + l2;
            const float bia0 = bias[col], bia1 = bias[col + 1];
#pragma unroll
            for (int half = 0; half < 2; half++) {
                const int m = bm + wm + mf * 16 + l4 + half * 8;
                float v0 = acc[mf][nf][half * 2]     + bia0;
                float v1 = acc[mf][nf][half * 2 + 1] + bia1;
                if (EPI == 0) {
                    v0 += extra[(size_t)(m & (N1_ - 1)) * C_ + col];
                    v1 += extra[(size_t)(m & (N1_ - 1)) * C_ + col + 1];
                    *(float2*)((float*)out + (size_t)m * N + col) = make_float2(v0, v1);
                } else if (EPI == 1) {
                    if (col < C_) {
                        v0 += extra[(size_t)(m & (N2_ - 1)) * C_ + col];
                        v1 += extra[(size_t)(m & (N2_ - 1)) * C_ + col + 1];
                        *(float2*)((float*)out + (size_t)m * C_ + col) = make_float2(v0, v1);
                    } else {
                        *(float2*)((float*)out2 + (size_t)m * C_ + col - C_) = make_float2(v0, v1);
                    }
                } else if (EPI == 2) {
                    v0 = 0.5f * v0 * (1.0f + erff(v0 * 0.70710678118654752f));
                    v1 = 0.5f * v1 * (1.0f + erff(v1 * 0.70710678118654752f));
                    uint32_t h0, l0, h1, l1;
                    bsplit(v0, h0, l0); bsplit(v1, h1, l1);
                    *(uint32_t*)((u16*)out  + (size_t)m * N + col) = h0 | (h1 << 16);
                    *(uint32_t*)((u16*)out2 + (size_t)m * N + col) = l0 | (l1 << 16);
                } else {
                    v0 += extra[(size_t)m * N + col];
                    v1 += extra[(size_t)m * N + col + 1];
                    *(float2*)((float*)out + (size_t)m * N + col) = make_float2(v0, v1);
                }
            }
        }
}

// =======================================================================
// kp[b,h,d,p] = sum_n k[b,n,h*64+d] * Wp[n,p] + bp[p]  (fp32)
// =======================================================================
__global__ __launch_bounds__(256, 4)
void kvp_k(const float* __restrict__ kin, const float* __restrict__ vin,
           const float* __restrict__ Wp, const float* __restrict__ bp,
           float* __restrict__ kp, float* __restrict__ vp)
{
    __shared__ float At[32][64];
    __shared__ float Bt[32][64];
    const int p0 = blockIdx.x * 64;
    const int bh = blockIdx.y;
    const int b = bh >> 3, h = bh & 7;
    const float* __restrict__ src = blockIdx.z ? vin : kin;
    float* __restrict__ dst = blockIdx.z ? vp : kp;
    const int tid = threadIdx.x;
    const int tx = tid & 15, ty = tid >> 4;

    float acc[4][4];
#pragma unroll
    for (int i = 0; i < 4; i++)
#pragma unroll
        for (int j = 0; j < 4; j++) acc[i][j] = 0.0f;

    for (int n0 = 0; n0 < N2_; n0 += 32) {
#pragma unroll
        for (int i = 0; i < 8; i++) {
            const int idx = tid + i * 256;
            const int nl = idx >> 6, dd = idx & 63;
            At[nl][dd] = src[((size_t)(b * N2_ + n0 + nl)) * C_ + h * 64 + dd];
            Bt[nl][dd] = Wp[(size_t)(n0 + nl) * P_ + p0 + dd];
        }
        __syncthreads();
#pragma unroll
        for (int kk = 0; kk < 32; kk++) {
            float ar[4], br[4];
#pragma unroll
            for (int i = 0; i < 4; i++) ar[i] = At[kk][ty * 4 + i];
#pragma unroll
            for (int j = 0; j < 4; j++) br[j] = Bt[kk][tx * 4 + j];
#pragma unroll
            for (int i = 0; i < 4; i++)
#pragma unroll
                for (int j = 0; j < 4; j++)
                    acc[i][j] = fmaf(ar[i], br[j], acc[i][j]);
        }
        __syncthreads();
    }
#pragma unroll
    for (int i = 0; i < 4; i++)
#pragma unroll
        for (int j = 0; j < 4; j++) {
            const int d = ty * 4 + i, p = p0 + tx * 4 + j;
            dst[((size_t)bh * 64 + d) * P_ + p] = acc[i][j] + bp[p];
        }
}

// =======================================================================
// Fused attention (fp32)
// =======================================================================
#define ATT_SMEM_FLOATS (64*256 + 256*68 + 64*68 + 64*257)
#define ATT_SMEM_BYTES  (ATT_SMEM_FLOATS * 4)

__global__ __launch_bounds__(256)
void attn_k(const float* __restrict__ temp, float* __restrict__ xa)
{
    extern __shared__ float sm[];
    float* Ks  = sm;
    float* VsT = Ks  + 64 * 256;
    float* QsT = VsT + 256 * 68;
    float* Ss  = QsT + 64 * 68;

    const int bh = blockIdx.x;
    const int b = bh >> 3, h = bh & 7;
    const int q0 = blockIdx.y * 64;
    const int tid = threadIdx.x;

#pragma unroll 4
    for (int i = 0; i < 64; i++) {
        const int idx = tid + i * 256;
        Ks[idx] = g_kp[(size_t)bh * (HD_ * P_) + idx];
    }
#pragma unroll 4
    for (int i = 0; i < 64; i++) {
        const int idx = tid + i * 256;
        const int d = idx >> 8, p = idx & 255;
        VsT[p * 68 + d] = g_vp[(size_t)bh * (HD_ * P_) + idx];
    }
#pragma unroll 4
    for (int i = 0; i < 16; i++) {
        const int idx = tid + i * 256;
        const int r = idx >> 6, d = idx & 63;
        QsT[d * 68 + r] = g_q[((size_t)(b * N1_ + q0 + r)) * C_ + h * 64 + d];
    }
    __syncthreads();

    const float tscale = temp[h];

    {
        const int tx = tid & 31, ty = tid >> 5;
        float acc[8][8];
#pragma unroll
        for (int i = 0; i < 8; i++)
#pragma unroll
            for (int j = 0; j < 8; j++) acc[i][j] = 0.0f;
#pragma unroll 4
        for (int d = 0; d < 64; d++) {
            float ar[8], br[8];
            *(float4*)(ar)     = *(const float4*)&QsT[d * 68 + ty * 8];
            *(float4*)(ar + 4) = *(const float4*)&QsT[d * 68 + ty * 8 + 4];
            *(float4*)(br)     = *(const float4*)&Ks[d * 256 + tx * 8];
            *(float4*)(br + 4) = *(const float4*)&Ks[d * 256 + tx * 8 + 4];
#pragma unroll
            for (int i = 0; i < 8; i++)
#pragma unroll
                for (int j = 0; j < 8; j++)
                    acc[i][j] = fmaf(ar[i], br[j], acc[i][j]);
        }
#pragma unroll
        for (int i = 0; i < 8; i++)
#pragma unroll
            for (int j = 0; j < 8; j++)
                Ss[(ty * 8 + i) * 257 + tx * 8 + j] = acc[i][j] * tscale;
    }
    __syncthreads();

    {
        const int r = tid >> 2, seg = tid & 3;
        float* row = Ss + r * 257 + seg * 64;
        float mx = -1e30f;
#pragma unroll 8
        for (int j = 0; j < 64; j++) mx = fmaxf(mx, row[j]);
        mx = fmaxf(mx, __shfl_xor_sync(0xffffffffu, mx, 1));
        mx = fmaxf(mx, __shfl_xor_sync(0xffffffffu, mx, 2));
        float s = 0.0f;
#pragma unroll 8
        for (int j = 0; j < 64; j++) {
            const float e = __expf(row[j] - mx);
            row[j] = e;
            s += e;
        }
        s += __shfl_xor_sync(0xffffffffu, s, 1);
        s += __shfl_xor_sync(0xffffffffu, s, 2);
        const float inv = 1.0f / s;
#pragma unroll 8
        for (int j = 0; j < 64; j++) row[j] *= inv;
    }
    __syncthreads();

    {
        const int tx = tid & 15, ty = tid >> 4;
        float acc[4][4];
#pragma unroll
        for (int i = 0; i < 4; i++)
#pragma unroll
            for (int j = 0; j < 4; j++) acc[i][j] = 0.0f;
#pragma unroll 4
        for (int p = 0; p < 256; p++) {
            float ar[4], br[4];
#pragma unroll
            for (int i = 0; i < 4; i++) ar[i] = Ss[(tx * 4 + i) * 257 + p];
            *(float4*)br = *(const float4*)&VsT[p * 68 + ty * 4];
#pragma unroll
            for (int i = 0; i < 4; i++)
#pragma unroll
                for (int j = 0; j < 4; j++)
                    acc[i][j] = fmaf(ar[i], br[j], acc[i][j]);
        }
        const size_t base = (size_t)b * (N1_ * C_) + (size_t)h * N1_ + q0 + tx * 4;
#pragma unroll
        for (int j = 0; j < 4; j++) {
            float4 o = make_float4(acc[0][j], acc[1][j], acc[2][j], acc[3][j]);
            *(float4*)&xa[base + (size_t)(ty * 4 + j) * (H_ * N1_)] = o;
        }
    }
}

// =======================================================================
// Row-wise L2 norm over C=512; optional bf16 split side-output.
// =======================================================================
__global__ __launch_bounds__(256)
void l2n_k(const float* __restrict__ a, const float* __restrict__ bb,
           float* __restrict__ out, u16* __restrict__ oh, u16* __restrict__ ol)
{
    const int row = blockIdx.x * 8 + (threadIdx.x >> 5);
    const int lane = threadIdx.x & 31;
    const float4* pa = (const float4*)(a + (size_t)row * C_);
    const float4* pb = bb ? (const float4*)(bb + (size_t)row * C_) : nullptr;
    float4 v[4];
    float ss = 0.0f;
#pragma unroll
    for (int i = 0; i < 4; i++) {
        float4 t = pa[lane + 32 * i];
        if (pb) {
            float4 u = pb[lane + 32 * i];
            t.x += u.x; t.y += u.y; t.z += u.z; t.w += u.w;
        }
        v[i] = t;
        ss += t.x * t.x + t.y * t.y + t.z * t.z + t.w * t.w;
    }
#pragma unroll
    for (int o = 16; o > 0; o >>= 1) ss += __shfl_xor_sync(0xffffffffu, ss, o);
    const float inv = 1.0f / fmaxf(sqrtf(ss), 1e-12f);
    float4* po = (float4*)(out + (size_t)row * C_);
#pragma unroll
    for (int i = 0; i < 4; i++) {
        v[i].x *= inv; v[i].y *= inv; v[i].z *= inv; v[i].w *= inv;
        po[lane + 32 * i] = v[i];
        if (oh) {
            uint32_t h0, l0, h1, l1, h2, l2, h3, l3;
            bsplit(v[i].x, h0, l0); bsplit(v[i].y, h1, l1);
            bsplit(v[i].z, h2, l2); bsplit(v[i].w, h3, l3);
            const size_t off = (size_t)row * C_ + (lane + 32 * i) * 4;
            *(uint2*)(oh + off) = make_uint2(h0 | (h1 << 16), h2 | (h3 << 16));
            *(uint2*)(ol + off) = make_uint2(l0 | (l1 << 16), l2 | (l3 << 16));
        }
    }
}

// =======================================================================
extern "C" void kernel_launch(void* const* d_in, const int* in_sizes, int n_in,
                              void* d_out, int out_size)
{
    const float* x1    = (const float*)d_in[0];
    const float* x2    = (const float*)d_in[1];
    const float* Wq    = (const float*)d_in[2];
    const float* bq    = (const float*)d_in[3];
    const float* Wkv   = (const float*)d_in[4];
    const float* bkv   = (const float*)d_in[5];
    const float* Wp    = (const float*)d_in[6];
    const float* bp    = (const float*)d_in[7];
    const float* pos_q = (const float*)d_in[8];
    const float* pos_k = (const float*)d_in[9];
    const float* temp  = (const float*)d_in[10];
    const float* W1    = (const float*)d_in[11];
    const float* b1    = (const float*)d_in[12];
    const float* W2    = (const float*)d_in[13];
    const float* b2    = (const float*)d_in[14];

    float *q, *k, *v, *kp, *vp;
    u16 *x1h, *x1l, *x2h, *x2l, *xnh, *xnl, *hh, *hl;
    u16 *wqh, *wql, *wkvh, *wkvl, *w1h, *w1l, *w2h, *w2l;
    cudaGetSymbolAddress((void**)&q,  g_q);
    cudaGetSymbolAddress((void**)&k,  g_k);
    cudaGetSymbolAddress((void**)&v,  g_v);
    cudaGetSymbolAddress((void**)&kp, g_kp);
    cudaGetSymbolAddress((void**)&vp, g_vp);
    cudaGetSymbolAddress((void**)&x1h, g_x1h); cudaGetSymbolAddress((void**)&x1l, g_x1l);
    cudaGetSymbolAddress((void**)&x2h, g_x2h); cudaGetSymbolAddress((void**)&x2l, g_x2l);
    cudaGetSymbolAddress((void**)&xnh, g_xnh); cudaGetSymbolAddress((void**)&xnl, g_xnl);
    cudaGetSymbolAddress((void**)&hh,  g_hh);  cudaGetSymbolAddress((void**)&hl,  g_hl);
    cudaGetSymbolAddress((void**)&wqh,  g_wq_hi);  cudaGetSymbolAddress((void**)&wql,  g_wq_lo);
    cudaGetSymbolAddress((void**)&wkvh, g_wkv_hi); cudaGetSymbolAddress((void**)&wkvl, g_wkv_lo);
    cudaGetSymbolAddress((void**)&w1h,  g_w1_hi);  cudaGetSymbolAddress((void**)&w1l,  g_w1_lo);
    cudaGetSymbolAddress((void**)&w2h,  g_w2_hi);  cudaGetSymbolAddress((void**)&w2l,  g_w2_lo);
    float* xa = k;   // reuse: k dead after kvp_k
    float* xn = v;   // reuse: v dead after kvp_k

    cudaFuncSetAttribute(attn_k, cudaFuncAttributeMaxDynamicSharedMemorySize, ATT_SMEM_BYTES);
    cudaFuncSetAttribute(tgemm<0>, cudaFuncAttributeMaxDynamicSharedMemorySize, TG_SMEM);
    cudaFuncSetAttribute(tgemm<1>, cudaFuncAttributeMaxDynamicSharedMemorySize, TG_SMEM);
    cudaFuncSetAttribute(tgemm<2>, cudaFuncAttributeMaxDynamicSharedMemorySize, TG_SMEM);
    cudaFuncSetAttribute(tgemm<3>, cudaFuncAttributeMaxDynamicSharedMemorySize, TG_SMEM);

    // 0) splits: weights (transpose) + input activations
    wsplit_k<<<dim3(C_ / 32, C_ / 32), 256>>>(Wq, wqh, wql, C_, C_);
    wsplit_k<<<dim3(2 * C_ / 32, C_ / 32), 256>>>(Wkv, wkvh, wkvl, C_, 2 * C_);
    wsplit_k<<<dim3(MLP_ / 32, C_ / 32), 256>>>(W1, w1h, w1l, C_, MLP_);
    wsplit_k<<<dim3(C_ / 32, MLP_ / 32), 256>>>(W2, w2h, w2l, MLP_, C_);
    asplit_k<<<(M_ * C_) / 1024, 256>>>(x1, x1h, x1l);
    asplit_k<<<(M_ * C_) / 1024, 256>>>(x2, x2h, x2l);

    // 1) q = x1 @ Wq + bq + pos_q
    tgemm<0><<<dim3(C_ / 128, M_ / 128), 256, TG_SMEM>>>(
        x1h, x1l, wqh, wql, bq, pos_q, q, nullptr, M_, C_, C_);
    // 2) kv = x2 @ Wkv + bkv ; k += pos_k ; split k/v
    tgemm<1><<<dim3(2 * C_ / 128, M_ / 128), 256, TG_SMEM>>>(
        x2h, x2l, wkvh, wkvl, bkv, pos_k, k, v, M_, 2 * C_, C_);
    // 3) kp/vp
    kvp_k<<<dim3(P_ / 64, B_ * H_, 2), 256>>>(k, v, Wp, bp, kp, vp);
    // 4) fused attention
    attn_k<<<dim3(B_ * H_, N1_ / 64), 256, ATT_SMEM_BYTES>>>(temp, xa);
    // 5) xn = l2norm(attn_out + q), plus bf16 split for MLP1
    l2n_k<<<M_ / 8, 256>>>(xa, q, xn, xnh, xnl);
    // 6) h = gelu(xn @ W1 + b1) -> bf16 split directly
    tgemm<2><<<dim3(MLP_ / 128, M_ / 128), 256, TG_SMEM>>>(
        xnh, xnl, w1h, w1l, b1, nullptr, hh, hl, M_, MLP_, C_);
    // 7) pre = h @ W2 + b2 + xn
    tgemm<3><<<dim3(C_ / 128, M_ / 128), 256, TG_SMEM>>>(
        hh, hl, w2h, w2l, b2, xn, xa, nullptr, M_, C_, MLP_);
    // 8) out = l2norm(pre)
    l2n_k<<<M_ / 8, 256>>>(xa, nullptr, (float*)d_out, nullptr, nullptr);
}

// round 6
// speedup vs baseline: 1.9048x; 1.9048x over previous
#include <cuda_runtime.h>
#include <math.h>
#include <stdint.h>

#define B_   8
#define N1_  4096
#define N2_  4096
#define C_   512
#define P_   256
#define H_   8
#define HD_  64
#define MLP_ 2048
#define M_   (B_*N1_)

typedef unsigned short u16;

__device__ float g_q [M_*C_];
__device__ float g_k [M_*C_];     // k, later xa
__device__ float g_v [M_*C_];     // v, later xn
__device__ u16 g_qh [M_*C_],  g_ql [M_*C_];
__device__ u16 g_x1h[M_*C_],  g_x1l[M_*C_];
__device__ u16 g_x2h[M_*C_],  g_x2l[M_*C_];
__device__ u16 g_xnh[M_*C_],  g_xnl[M_*C_];
__device__ u16 g_hh [M_*MLP_], g_hl [M_*MLP_];
__device__ u16 g_kpth[B_*H_*P_*HD_], g_kptl[B_*H_*P_*HD_];  // kp^T [bh][p][d]
__device__ u16 g_vph [B_*H_*HD_*P_], g_vpl [B_*H_*HD_*P_];  // vp   [bh][d][p]
__device__ u16 g_wq_hi [C_*C_],   g_wq_lo [C_*C_];
__device__ u16 g_wkv_hi[2*C_*C_], g_wkv_lo[2*C_*C_];
__device__ u16 g_w1_hi [MLP_*C_], g_w1_lo [MLP_*C_];
__device__ u16 g_w2_hi [C_*MLP_], g_w2_lo [C_*MLP_];

__device__ __forceinline__ uint32_t smem_u32(const void* p) {
    uint32_t a;
    asm("{ .reg .u64 t; cvta.to.shared.u64 t, %1; cvt.u32.u64 %0, t; }" : "=r"(a) : "l"(p));
    return a;
}
#define SWZ(b) ((b) ^ (((b) >> 3) & 0x70))
#define CPA16(dst, src) asm volatile("cp.async.cg.shared.global [%0], [%1], 16;" :: "r"(dst), "l"(src))
#define CPA_COMMIT() asm volatile("cp.async.commit_group;" ::: "memory")
#define CPA_WAIT1()  asm volatile("cp.async.wait_group 1;" ::: "memory")
#define CPA_WAIT0()  asm volatile("cp.async.wait_group 0;" ::: "memory")

__device__ __forceinline__ void ldsm4(uint32_t* r, uint32_t a) {
    asm volatile("ldmatrix.sync.aligned.m8n8.x4.shared.b16 {%0,%1,%2,%3}, [%4];"
                 : "=r"(r[0]), "=r"(r[1]), "=r"(r[2]), "=r"(r[3]) : "r"(a));
}
__device__ __forceinline__ void mma_bf16(float* c, const uint32_t* a, uint32_t b0, uint32_t b1) {
    asm volatile("mma.sync.aligned.m16n8k16.row.col.f32.bf16.bf16.f32 "
        "{%0,%1,%2,%3}, {%4,%5,%6,%7}, {%8,%9}, {%0,%1,%2,%3};"
        : "+f"(c[0]), "+f"(c[1]), "+f"(c[2]), "+f"(c[3])
        : "r"(a[0]), "r"(a[1]), "r"(a[2]), "r"(a[3]), "r"(b0), "r"(b1));
}
__device__ __forceinline__ void bsplit(float a, uint32_t& hi, uint32_t& lo) {
    uint32_t u = __float_as_uint(a);
    uint32_t hr = (u + 0x7fffu + ((u >> 16) & 1u)) & 0xffff0000u;
    hi = hr >> 16;
    float l = a - __uint_as_float(hr);
    uint32_t ul = __float_as_uint(l);
    lo = (ul + 0x7fffu + ((ul >> 16) & 1u)) >> 16;
}
__device__ __forceinline__ void bsplit2(float a, float b, uint32_t& hi, uint32_t& lo) {
    uint32_t h0, l0, h1, l1;
    bsplit(a, h0, l0); bsplit(b, h1, l1);
    hi = h0 | (h1 << 16); lo = l0 | (l1 << 16);
}

// ---- weight transpose + split: W[K][N] -> Wt[N][K] hi/lo ----
__global__ __launch_bounds__(256)
void wsplit_k(const float* __restrict__ W, u16* __restrict__ hi, u16* __restrict__ lo, int K, int N)
{
    __shared__ float tile[32][33];
    const int n0 = blockIdx.x * 32, k0 = blockIdx.y * 32;
    const int tx = threadIdx.x & 31, ty = threadIdx.x >> 5;
#pragma unroll
    for (int r = 0; r < 4; r++)
        tile[ty + 8 * r][tx] = W[(size_t)(k0 + ty + 8 * r) * N + n0 + tx];
    __syncthreads();
#pragma unroll
    for (int r = 0; r < 4; r++) {
        const int n = n0 + ty + 8 * r, k = k0 + tx;
        uint32_t h, l;
        bsplit(tile[tx][ty + 8 * r], h, l);
        hi[(size_t)n * K + k] = (u16)h;
        lo[(size_t)n * K + k] = (u16)l;
    }
}

__global__ __launch_bounds__(256)
void asplit_k(const float* __restrict__ A, u16* __restrict__ hi, u16* __restrict__ lo)
{
    const size_t i4 = ((size_t)blockIdx.x * 256 + threadIdx.x) * 4;
    float4 f = *(const float4*)(A + i4);
    uint32_t a, b, c, d;
    bsplit2(f.x, f.y, a, c); bsplit2(f.z, f.w, b, d);
    *(uint2*)(hi + i4) = make_uint2(a, b);
    *(uint2*)(lo + i4) = make_uint2(c, d);
}

// ---- bf16x3 HMMA GEMM, 128x128 tile, 3-stage cp.async ----
#define TG_SMEM (3 * 65536)
template<int EPI>
__global__ __launch_bounds__(256, 1)
void tgemm(const u16* __restrict__ Ahi, const u16* __restrict__ Alo,
           const u16* __restrict__ Bhi, const u16* __restrict__ Blo,
           const float* __restrict__ bias, const float* __restrict__ extra,
           void* __restrict__ out, void* __restrict__ out2, int M, int N, int K)
{
    extern __shared__ __align__(1024) char sm_raw[];
    const uint32_t sb = smem_u32(sm_raw);
    const int tid = threadIdx.x, wid = tid >> 5, lane = tid & 31;
    const int bm = blockIdx.y * 128, bn = blockIdx.x * 128;
    const int wm = (wid & 1) * 64, wn = (wid >> 1) * 32;
    const int nck = K >> 6;

    float acc[4][4][4];
#pragma unroll
    for (int i = 0; i < 4; i++)
#pragma unroll
        for (int j = 0; j < 4; j++)
#pragma unroll
            for (int r = 0; r < 4; r++) acc[i][j][r] = 0.0f;

    const int a_row = ((lane >> 3) & 1) * 8 + (lane & 7);
    const int a_col = (lane >> 4) * 8;
    const int b_row = (lane >> 4) * 8 + (lane & 7);
    const int b_col = ((lane >> 3) & 1) * 8;

    auto load_stage = [&](int ck, int stage) {
        if (ck < nck) {
            const int k0 = ck * 64;
            const uint32_t sbase = sb + stage * 65536;
#pragma unroll
            for (int i = 0; i < 4; i++) {
                const int id = tid + i * 256;
                const int row = id >> 3, c16 = id & 7;
                const uint32_t dsw = SWZ((uint32_t)(row * 128 + c16 * 16));
                const size_t asrc = (size_t)(bm + row) * K + k0 + c16 * 8;
                const size_t bsrc = (size_t)(bn + row) * K + k0 + c16 * 8;
                CPA16(sbase + dsw,         Ahi + asrc);
                CPA16(sbase + 16384 + dsw, Alo + asrc);
                CPA16(sbase + 32768 + dsw, Bhi + bsrc);
                CPA16(sbase + 49152 + dsw, Blo + bsrc);
            }
        }
        CPA_COMMIT();
    };

    load_stage(0, 0);
    load_stage(1, 1);

    for (int ck = 0; ck < nck; ck++) {
        CPA_WAIT1();
        __syncthreads();
        load_stage(ck + 2, (ck + 2) % 3);
        const uint32_t base = sb + (ck % 3) * 65536;
#pragma unroll
        for (int ks = 0; ks < 4; ks++) {
            const int kk = ks * 16;
            uint32_t ah[4][4], al[4][4], bh[2][4], bl[2][4];
#pragma unroll
            for (int mf = 0; mf < 4; mf++) {
                const uint32_t ao = SWZ((uint32_t)((wm + mf * 16 + a_row) * 128 + (kk + a_col) * 2));
                ldsm4(ah[mf], base + ao);
                ldsm4(al[mf], base + 16384 + ao);
            }
#pragma unroll
            for (int p = 0; p < 2; p++) {
                const uint32_t bo = SWZ((uint32_t)((wn + p * 16 + b_row) * 128 + (kk + b_col) * 2));
                ldsm4(bh[p], base + 32768 + bo);
                ldsm4(bl[p], base + 49152 + bo);
            }
#pragma unroll
            for (int mf = 0; mf < 4; mf++)
#pragma unroll
                for (int p = 0; p < 2; p++)
#pragma unroll
                    for (int s = 0; s < 2; s++) {
                        float* c = acc[mf][p * 2 + s];
                        mma_bf16(c, ah[mf], bh[p][s * 2], bh[p][s * 2 + 1]);
                        mma_bf16(c, al[mf], bh[p][s * 2], bh[p][s * 2 + 1]);
                        mma_bf16(c, ah[mf], bl[p][s * 2], bl[p][s * 2 + 1]);
                    }
        }
    }

    const int l4 = lane >> 2, l2 = (lane & 3) * 2;
#pragma unroll
    for (int mf = 0; mf < 4; mf++)
#pragma unroll
        for (int nf = 0; nf < 4; nf++) {
            const int col = bn + wn + nf * 8 + l2;
            const float bia0 = bias[col], bia1 = bias[col + 1];
#pragma unroll
            for (int half = 0; half < 2; half++) {
                const int m = bm + wm + mf * 16 + l4 + half * 8;
                float v0 = acc[mf][nf][half * 2]     + bia0;
                float v1 = acc[mf][nf][half * 2 + 1] + bia1;
                if (EPI == 0) {
                    v0 += extra[(size_t)(m & (N1_ - 1)) * C_ + col];
                    v1 += extra[(size_t)(m & (N1_ - 1)) * C_ + col + 1];
                    *(float2*)((float*)out + (size_t)m * N + col) = make_float2(v0, v1);
                    uint32_t hi, lo;
                    bsplit2(v0, v1, hi, lo);
                    *(uint32_t*)(g_qh + (size_t)m * N + col) = hi;
                    *(uint32_t*)(g_ql + (size_t)m * N + col) = lo;
                } else if (EPI == 1) {
                    if (col < C_) {
                        v0 += extra[(size_t)(m & (N2_ - 1)) * C_ + col];
                        v1 += extra[(size_t)(m & (N2_ - 1)) * C_ + col + 1];
                        *(float2*)((float*)out + (size_t)m * C_ + col) = make_float2(v0, v1);
                    } else {
                        *(float2*)((float*)out2 + (size_t)m * C_ + col - C_) = make_float2(v0, v1);
                    }
                } else if (EPI == 2) {
                    v0 = 0.5f * v0 * (1.0f + erff(v0 * 0.70710678118654752f));
                    v1 = 0.5f * v1 * (1.0f + erff(v1 * 0.70710678118654752f));
                    uint32_t hi, lo;
                    bsplit2(v0, v1, hi, lo);
                    *(uint32_t*)((u16*)out  + (size_t)m * N + col) = hi;
                    *(uint32_t*)((u16*)out2 + (size_t)m * N + col) = lo;
                } else {
                    v0 += extra[(size_t)m * N + col];
                    v1 += extra[(size_t)m * N + col + 1];
                    *(float2*)((float*)out + (size_t)m * N + col) = make_float2(v0, v1);
                }
            }
        }
}

// ---- kvp (fp32 math) -> bf16-split kp^T[p][d] and vp[d][p] ----
__global__ __launch_bounds__(256, 4)
void kvp_k(const float* __restrict__ kin, const float* __restrict__ vin,
           const float* __restrict__ Wp, const float* __restrict__ bp)
{
    __shared__ float At[32][64];
    __shared__ float Bt[32][64];
    const int p0 = blockIdx.x * 64;
    const int bh = blockIdx.y;
    const int b = bh >> 3, h = bh & 7;
    const int mode = blockIdx.z;
    const float* __restrict__ src = mode ? vin : kin;
    const int tid = threadIdx.x, tx = tid & 15, ty = tid >> 4;

    float acc[4][4];
#pragma unroll
    for (int i = 0; i < 4; i++)
#pragma unroll
        for (int j = 0; j < 4; j++) acc[i][j] = 0.0f;

    for (int n0 = 0; n0 < N2_; n0 += 32) {
#pragma unroll
        for (int i = 0; i < 8; i++) {
            const int idx = tid + i * 256;
            const int nl = idx >> 6, dd = idx & 63;
            At[nl][dd] = src[((size_t)(b * N2_ + n0 + nl)) * C_ + h * 64 + dd];
            Bt[nl][dd] = Wp[(size_t)(n0 + nl) * P_ + p0 + dd];
        }
        __syncthreads();
#pragma unroll
        for (int kk = 0; kk < 32; kk++) {
            float ar[4], br[4];
#pragma unroll
            for (int i = 0; i < 4; i++) ar[i] = At[kk][ty * 4 + i];
#pragma unroll
            for (int j = 0; j < 4; j++) br[j] = Bt[kk][tx * 4 + j];
#pragma unroll
            for (int i = 0; i < 4; i++)
#pragma unroll
                for (int j = 0; j < 4; j++)
                    acc[i][j] = fmaf(ar[i], br[j], acc[i][j]);
        }
        __syncthreads();
    }
    if (mode == 0) {
        // kpt[p][d0..d0+3], d contiguous over i
#pragma unroll
        for (int j = 0; j < 4; j++) {
            const int p = p0 + tx * 4 + j;
            const float bv = bp[p];
            uint32_t h0, l0, h1, l1;
            bsplit2(acc[0][j] + bv, acc[1][j] + bv, h0, l0);
            bsplit2(acc[2][j] + bv, acc[3][j] + bv, h1, l1);
            const size_t o = ((size_t)bh * P_ + p) * HD_ + ty * 4;
            *(uint2*)(g_kpth + o) = make_uint2(h0, h1);
            *(uint2*)(g_kptl + o) = make_uint2(l0, l1);
        }
    } else {
        // vp[d][p0..p0+3], p contiguous over j
#pragma unroll
        for (int i = 0; i < 4; i++) {
            const int d = ty * 4 + i;
            const int p = p0 + tx * 4;
            uint32_t h0, l0, h1, l1;
            bsplit2(acc[i][0] + bp[p],     acc[i][1] + bp[p + 1], h0, l0);
            bsplit2(acc[i][2] + bp[p + 2], acc[i][3] + bp[p + 3], h1, l1);
            const size_t o = ((size_t)bh * HD_ + d) * P_ + p;
            *(uint2*)(g_vph + o) = make_uint2(h0, h1);
            *(uint2*)(g_vpl + o) = make_uint2(l0, l1);
        }
    }
}

// ---- attention via bf16x3 HMMA ----
#define A_QH   0
#define A_QL   8192
#define A_KH   16384
#define A_KL   49152
#define A_VH   81920
#define A_VL   114688
#define A_ST   147456
#define A_ZN   149504
#define ATT_SMEM (149504 + 4*64*66*4)

__global__ __launch_bounds__(256, 1)
void attn_mma(const float* __restrict__ temp, float* __restrict__ xa)
{
    extern __shared__ __align__(1024) char sm_raw[];
    const uint32_t sb = smem_u32(sm_raw);
    const int tid = threadIdx.x, wid = tid >> 5, lane = tid & 31;
    const int g = lane >> 2, t4 = lane & 3;
    const int bh = blockIdx.x, b = bh >> 3, h = bh & 7;
    const int q0 = blockIdx.y * 64;
    const int wm = (wid & 1) * 32, zn = wid >> 1, wn = zn * 64;

#pragma unroll
    for (int t = 0; t < 2; t++) {
        const int i = tid + t * 256;
        const int row = i >> 3, c16 = i & 7;
        const uint32_t dsw = SWZ((uint32_t)(row * 128 + c16 * 16));
        const size_t src = (size_t)(b * N1_ + q0 + row) * C_ + h * 64 + c16 * 8;
        CPA16(sb + A_QH + dsw, g_qh + src);
        CPA16(sb + A_QL + dsw, g_ql + src);
    }
#pragma unroll
    for (int t = 0; t < 8; t++) {
        const int i = tid + t * 256;
        const int row = i >> 3, c16 = i & 7;
        const uint32_t dsw = SWZ((uint32_t)(row * 128 + c16 * 16));
        const size_t src = (size_t)bh * (P_ * HD_) + row * 64 + c16 * 8;
        CPA16(sb + A_KH + dsw, g_kpth + src);
        CPA16(sb + A_KL + dsw, g_kptl + src);
    }
#pragma unroll
    for (int t = 0; t < 8; t++) {
        const int i = tid + t * 256;
        const int c16 = i & 7, d = (i >> 3) & 63, ch = i >> 9;
        const uint32_t dsw = (uint32_t)(ch * 8192) + SWZ((uint32_t)(d * 128 + c16 * 16));
        const size_t src = (size_t)bh * (HD_ * P_) + d * 256 + ch * 64 + c16 * 8;
        CPA16(sb + A_VH + dsw, g_vph + src);
        CPA16(sb + A_VL + dsw, g_vpl + src);
    }
    CPA_COMMIT();
    CPA_WAIT0();
    __syncthreads();

    const int a_row = ((lane >> 3) & 1) * 8 + (lane & 7);
    const int a_col = (lane >> 4) * 8;
    const int b_row = (lane >> 4) * 8 + (lane & 7);
    const int b_col = ((lane >> 3) & 1) * 8;

    // QK: S[32q(wm)][64p(wn)] per warp
    float acc[2][8][4];
#pragma unroll
    for (int i = 0; i < 2; i++)
#pragma unroll
        for (int j = 0; j < 8; j++)
#pragma unroll
            for (int r = 0; r < 4; r++) acc[i][j][r] = 0.0f;

#pragma unroll
    for (int ks = 0; ks < 4; ks++) {
        const int kk = ks * 16;
        uint32_t ah[2][4], al[2][4];
#pragma unroll
        for (int mf = 0; mf < 2; mf++) {
            const uint32_t ao = SWZ((uint32_t)((wm + mf * 16 + a_row) * 128 + (kk + a_col) * 2));
            ldsm4(ah[mf], sb + A_QH + ao);
            ldsm4(al[mf], sb + A_QL + ao);
        }
#pragma unroll
        for (int p = 0; p < 4; p++) {
            uint32_t bhr[4], blr[4];
            const uint32_t bo = SWZ((uint32_t)((wn + p * 16 + b_row) * 128 + (kk + b_col) * 2));
            ldsm4(bhr, sb + A_KH + bo);
            ldsm4(blr, sb + A_KL + bo);
#pragma unroll
            for (int mf = 0; mf < 2; mf++)
#pragma unroll
                for (int s = 0; s < 2; s++) {
                    float* c = acc[mf][p * 2 + s];
                    mma_bf16(c, ah[mf], bhr[s * 2], bhr[s * 2 + 1]);
                    mma_bf16(c, al[mf], bhr[s * 2], bhr[s * 2 + 1]);
                    mma_bf16(c, ah[mf], blr[s * 2], blr[s * 2 + 1]);
                }
        }
    }

    // softmax
    const float tscale = temp[h];
    float* smax = (float*)(sm_raw + A_ST);
    float* ssum = smax + 256;
#pragma unroll
    for (int mf = 0; mf < 2; mf++)
#pragma unroll
        for (int nf = 0; nf < 8; nf++)
#pragma unroll
            for (int r = 0; r < 4; r++) acc[mf][nf][r] *= tscale;

    float rmx[2][2] = {{-1e30f, -1e30f}, {-1e30f, -1e30f}};
#pragma unroll
    for (int mf = 0; mf < 2; mf++)
#pragma unroll
        for (int nf = 0; nf < 8; nf++) {
            rmx[mf][0] = fmaxf(rmx[mf][0], fmaxf(acc[mf][nf][0], acc[mf][nf][1]));
            rmx[mf][1] = fmaxf(rmx[mf][1], fmaxf(acc[mf][nf][2], acc[mf][nf][3]));
        }
#pragma unroll
    for (int mf = 0; mf < 2; mf++)
#pragma unroll
        for (int hf = 0; hf < 2; hf++) {
            rmx[mf][hf] = fmaxf(rmx[mf][hf], __shfl_xor_sync(~0u, rmx[mf][hf], 1));
            rmx[mf][hf] = fmaxf(rmx[mf][hf], __shfl_xor_sync(~0u, rmx[mf][hf], 2));
        }
    if (t4 == 0)
#pragma unroll
        for (int mf = 0; mf < 2; mf++)
#pragma unroll
            for (int hf = 0; hf < 2; hf++)
                smax[(wm + mf * 16 + hf * 8 + g) * 4 + zn] = rmx[mf][hf];
    __syncthreads();
    float gmx[2][2], rsm[2][2] = {{0, 0}, {0, 0}};
#pragma unroll
    for (int mf = 0; mf < 2; mf++)
#pragma unroll
        for (int hf = 0; hf < 2; hf++) {
            const int r = wm + mf * 16 + hf * 8 + g;
            gmx[mf][hf] = fmaxf(fmaxf(smax[r * 4], smax[r * 4 + 1]),
                                fmaxf(smax[r * 4 + 2], smax[r * 4 + 3]));
        }
#pragma unroll
    for (int mf = 0; mf < 2; mf++)
#pragma unroll
        for (int nf = 0; nf < 8; nf++)
#pragma unroll
            for (int r = 0; r < 4; r++) {
                const int hf = r >> 1;
                const float e = __expf(acc[mf][nf][r] - gmx[mf][hf]);
                acc[mf][nf][r] = e;
                rsm[mf][hf] += e;
            }
#pragma unroll
    for (int mf = 0; mf < 2; mf++)
#pragma unroll
        for (int hf = 0; hf < 2; hf++) {
            rsm[mf][hf] += __shfl_xor_sync(~0u, rsm[mf][hf], 1);
            rsm[mf][hf] += __shfl_xor_sync(~0u, rsm[mf][hf], 2);
        }
    if (t4 == 0)
#pragma unroll
        for (int mf = 0; mf < 2; mf++)
#pragma unroll
            for (int hf = 0; hf < 2; hf++)
                ssum[(wm + mf * 16 + hf * 8 + g) * 4 + zn] = rsm[mf][hf];
    __syncthreads();
#pragma unroll
    for (int mf = 0; mf < 2; mf++)
#pragma unroll
        for (int hf = 0; hf < 2; hf++) {
            const int r = wm + mf * 16 + hf * 8 + g;
            const float inv = 1.0f / (ssum[r * 4] + ssum[r * 4 + 1] + ssum[r * 4 + 2] + ssum[r * 4 + 3]);
#pragma unroll
            for (int nf = 0; nf < 8; nf++) {
                acc[mf][nf][hf * 2]     *= inv;
                acc[mf][nf][hf * 2 + 1] *= inv;
            }
        }

    // AV: P[32q][64p(zone)] @ vp[64d][p-slice]^T
    float acc2[2][8][4];
#pragma unroll
    for (int i = 0; i < 2; i++)
#pragma unroll
        for (int j = 0; j < 8; j++)
#pragma unroll
            for (int r = 0; r < 4; r++) acc2[i][j][r] = 0.0f;

#pragma unroll
    for (int kf = 0; kf < 4; kf++) {
        uint32_t pah[2][4], pal[2][4];
#pragma unroll
        for (int mf = 0; mf < 2; mf++) {
            bsplit2(acc[mf][2*kf][0],   acc[mf][2*kf][1],   pah[mf][0], pal[mf][0]);
            bsplit2(acc[mf][2*kf][2],   acc[mf][2*kf][3],   pah[mf][1], pal[mf][1]);
            bsplit2(acc[mf][2*kf+1][0], acc[mf][2*kf+1][1], pah[mf][2], pal[mf][2]);
            bsplit2(acc[mf][2*kf+1][2], acc[mf][2*kf+1][3], pah[mf][3], pal[mf][3]);
        }
#pragma unroll
        for (int df = 0; df < 4; df++) {
            uint32_t bhr[4], blr[4];
            const uint32_t bo = (uint32_t)(zn * 8192) +
                SWZ((uint32_t)((df * 16 + b_row) * 128 + (kf * 16 + b_col) * 2));
            ldsm4(bhr, sb + A_VH + bo);
            ldsm4(blr, sb + A_VL + bo);
#pragma unroll
            for (int mf = 0; mf < 2; mf++)
#pragma unroll
                for (int s = 0; s < 2; s++) {
                    float* c = acc2[mf][df * 2 + s];
                    mma_bf16(c, pah[mf], bhr[s * 2], bhr[s * 2 + 1]);
                    mma_bf16(c, pal[mf], bhr[s * 2], bhr[s * 2 + 1]);
                    mma_bf16(c, pah[mf], blr[s * 2], blr[s * 2 + 1]);
                }
        }
    }

    // zone partials + reduce + scatter
    float* zone = (float*)(sm_raw + A_ZN) + zn * (64 * 66);
#pragma unroll
    for (int mf = 0; mf < 2; mf++)
#pragma unroll
        for (int nf = 0; nf < 8; nf++)
#pragma unroll
            for (int hf = 0; hf < 2; hf++) {
                const int row = wm + mf * 16 + hf * 8 + g;
                const int dc = nf * 8 + t4 * 2;
                *(float2*)&zone[row * 66 + dc] =
                    make_float2(acc2[mf][nf][hf * 2], acc2[mf][nf][hf * 2 + 1]);
            }
    __syncthreads();

    const int tx = tid & 15, ty = tid >> 4;
    float* z0 = (float*)(sm_raw + A_ZN);
    const size_t base = (size_t)b * (N1_ * C_) + (size_t)h * N1_ + q0 + tx * 4;
#pragma unroll
    for (int j = 0; j < 4; j++) {
        const int d = ty * 4 + j;
        float o[4];
#pragma unroll
        for (int qi = 0; qi < 4; qi++) {
            const int idx = (tx * 4 + qi) * 66 + d;
            o[qi] = z0[idx] + z0[64*66 + idx] + z0[2*64*66 + idx] + z0[3*64*66 + idx];
        }
        *(float4*)&xa[base + (size_t)d * (H_ * N1_)] = make_float4(o[0], o[1], o[2], o[3]);
    }
}

// ---- L2 norm + optional bf16 split ----
__global__ __launch_bounds__(256)
void l2n_k(const float* __restrict__ a, const float* __restrict__ bb,
           float* __restrict__ out, u16* __restrict__ oh, u16* __restrict__ ol)
{
    const int row = blockIdx.x * 8 + (threadIdx.x >> 5);
    const int lane = threadIdx.x & 31;
    const float4* pa = (const float4*)(a + (size_t)row * C_);
    const float4* pb = bb ? (const float4*)(bb + (size_t)row * C_) : nullptr;
    float4 v[4];
    float ss = 0.0f;
#pragma unroll
    for (int i = 0; i < 4; i++) {
        float4 t = pa[lane + 32 * i];
        if (pb) {
            float4 u = pb[lane + 32 * i];
            t.x += u.x; t.y += u.y; t.z += u.z; t.w += u.w;
        }
        v[i] = t;
        ss += t.x * t.x + t.y * t.y + t.z * t.z + t.w * t.w;
    }
#pragma unroll
    for (int o = 16; o > 0; o >>= 1) ss += __shfl_xor_sync(~0u, ss, o);
    const float inv = 1.0f / fmaxf(sqrtf(ss), 1e-12f);
    float4* po = (float4*)(out + (size_t)row * C_);
#pragma unroll
    for (int i = 0; i < 4; i++) {
        v[i].x *= inv; v[i].y *= inv; v[i].z *= inv; v[i].w *= inv;
        po[lane + 32 * i] = v[i];
        if (oh) {
            uint32_t a0, b0, c0, d0;
            bsplit2(v[i].x, v[i].y, a0, c0); bsplit2(v[i].z, v[i].w, b0, d0);
            const size_t off = (size_t)row * C_ + (lane + 32 * i) * 4;
            *(uint2*)(oh + off) = make_uint2(a0, b0);
            *(uint2*)(ol + off) = make_uint2(c0, d0);
        }
    }
}

extern "C" void kernel_launch(void* const* d_in, const int* in_sizes, int n_in,
                              void* d_out, int out_size)
{
    const float* x1    = (const float*)d_in[0];
    const float* x2    = (const float*)d_in[1];
    const float* Wq    = (const float*)d_in[2];
    const float* bq    = (const float*)d_in[3];
    const float* Wkv   = (const float*)d_in[4];
    const float* bkv   = (const float*)d_in[5];
    const float* Wp    = (const float*)d_in[6];
    const float* bp    = (const float*)d_in[7];
    const float* pos_q = (const float*)d_in[8];
    const float* pos_k = (const float*)d_in[9];
    const float* temp  = (const float*)d_in[10];
    const float* W1    = (const float*)d_in[11];
    const float* b1    = (const float*)d_in[12];
    const float* W2    = (const float*)d_in[13];
    const float* b2    = (const float*)d_in[14];

    float *q, *k, *v;
    u16 *x1h, *x1l, *x2h, *x2l, *xnh, *xnl, *hh, *hl;
    u16 *wqh, *wql, *wkvh, *wkvl, *w1h, *w1l, *w2h, *w2l;
    cudaGetSymbolAddress((void**)&q, g_q);
    cudaGetSymbolAddress((void**)&k, g_k);
    cudaGetSymbolAddress((void**)&v, g_v);
    cudaGetSymbolAddress((void**)&x1h, g_x1h); cudaGetSymbolAddress((void**)&x1l, g_x1l);
    cudaGetSymbolAddress((void**)&x2h, g_x2h); cudaGetSymbolAddress((void**)&x2l, g_x2l);
    cudaGetSymbolAddress((void**)&xnh, g_xnh); cudaGetSymbolAddress((void**)&xnl, g_xnl);
    cudaGetSymbolAddress((void**)&hh, g_hh);   cudaGetSymbolAddress((void**)&hl, g_hl);
    cudaGetSymbolAddress((void**)&wqh, g_wq_hi);   cudaGetSymbolAddress((void**)&wql, g_wq_lo);
    cudaGetSymbolAddress((void**)&wkvh, g_wkv_hi); cudaGetSymbolAddress((void**)&wkvl, g_wkv_lo);
    cudaGetSymbolAddress((void**)&w1h, g_w1_hi);   cudaGetSymbolAddress((void**)&w1l, g_w1_lo);
    cudaGetSymbolAddress((void**)&w2h, g_w2_hi);   cudaGetSymbolAddress((void**)&w2l, g_w2_lo);
    float* xa = k;
    float* xn = v;

    cudaFuncSetAttribute(attn_mma, cudaFuncAttributeMaxDynamicSharedMemorySize, ATT_SMEM);
    cudaFuncSetAttribute(tgemm<0>, cudaFuncAttributeMaxDynamicSharedMemorySize, TG_SMEM);
    cudaFuncSetAttribute(tgemm<1>, cudaFuncAttributeMaxDynamicSharedMemorySize, TG_SMEM);
    cudaFuncSetAttribute(tgemm<2>, cudaFuncAttributeMaxDynamicSharedMemorySize, TG_SMEM);
    cudaFuncSetAttribute(tgemm<3>, cudaFuncAttributeMaxDynamicSharedMemorySize, TG_SMEM);

    wsplit_k<<<dim3(C_ / 32, C_ / 32), 256>>>(Wq, wqh, wql, C_, C_);
    wsplit_k<<<dim3(2 * C_ / 32, C_ / 32), 256>>>(Wkv, wkvh, wkvl, C_, 2 * C_);
    wsplit_k<<<dim3(MLP_ / 32, C_ / 32), 256>>>(W1, w1h, w1l, C_, MLP_);
    wsplit_k<<<dim3(C_ / 32, MLP_ / 32), 256>>>(W2, w2h, w2l, MLP_, C_);
    asplit_k<<<(M_ * C_) / 1024, 256>>>(x1, x1h, x1l);
    asplit_k<<<(M_ * C_) / 1024, 256>>>(x2, x2h, x2l);

    tgemm<0><<<dim3(C_ / 128, M_ / 128), 256, TG_SMEM>>>(
        x1h, x1l, wqh, wql, bq, pos_q, q, nullptr, M_, C_, C_);
    tgemm<1><<<dim3(2 * C_ / 128, M_ / 128), 256, TG_SMEM>>>(
        x2h, x2l, wkvh, wkvl, bkv, pos_k, k, v, M_, 2 * C_, C_);
    kvp_k<<<dim3(P_ / 64, B_ * H_, 2), 256>>>(k, v, Wp, bp);
    attn_mma<<<dim3(B_ * H_, N1_ / 64), 256, ATT_SMEM>>>(temp, xa);
    l2n_k<<<M_ / 8, 256>>>(xa, q, xn, xnh, xnl);
    tgemm<2><<<dim3(MLP_ / 128, M_ / 128), 256, TG_SMEM>>>(
        xnh, xnl, w1h, w1l, b1, nullptr, hh, hl, M_, MLP_, C_);
    tgemm<3><<<dim3(C_ / 128, M_ / 128), 256, TG_SMEM>>>(
        hh, hl, w2h, w2l, b2, xn, xa, nullptr, M_, C_, MLP_);
    l2n_k<<<M_ / 8, 256>>>(xa, nullptr, (float*)d_out, nullptr, nullptr);
}

// round 7
// speedup vs baseline: 2.1785x; 1.1437x over previous
#include <cuda_runtime.h>
#include <math.h>
#include <stdint.h>

#define B_   8
#define N1_  4096
#define N2_  4096
#define C_   512
#define P_   256
#define H_   8
#define HD_  64
#define MLP_ 2048
#define M_   (B_*N1_)

typedef unsigned short u16;

__device__ float g_q [M_*C_];
__device__ float g_k [M_*C_];     // k, later xa
__device__ float g_v [M_*C_];     // v, later xn
__device__ u16 g_qh [M_*C_],  g_ql [M_*C_];
__device__ u16 g_x1h[M_*C_],  g_x1l[M_*C_];
__device__ u16 g_x2h[M_*C_],  g_x2l[M_*C_];
__device__ u16 g_xnh[M_*C_],  g_xnl[M_*C_];
__device__ u16 g_hh [M_*MLP_], g_hl [M_*MLP_];
__device__ u16 g_kTh[B_*C_*N2_], g_kTl[B_*C_*N2_];          // kT [b][c][n]
__device__ u16 g_vTh[B_*C_*N2_], g_vTl[B_*C_*N2_];
__device__ u16 g_kpth[B_*H_*P_*HD_], g_kptl[B_*H_*P_*HD_];  // kp^T [bh][p][d]
__device__ u16 g_vph [B_*H_*HD_*P_], g_vpl [B_*H_*HD_*P_];  // vp   [bh][d][p]
__device__ u16 g_wq_hi [C_*C_],   g_wq_lo [C_*C_];
__device__ u16 g_wkv_hi[2*C_*C_], g_wkv_lo[2*C_*C_];
__device__ u16 g_w1_hi [MLP_*C_], g_w1_lo [MLP_*C_];
__device__ u16 g_w2_hi [C_*MLP_], g_w2_lo [C_*MLP_];
__device__ u16 g_wpth  [P_*N2_],  g_wptl  [P_*N2_];         // WpT [p][n]

__device__ __forceinline__ uint32_t smem_u32(const void* p) {
    uint32_t a;
    asm("{ .reg .u64 t; cvta.to.shared.u64 t, %1; cvt.u32.u64 %0, t; }" : "=r"(a) : "l"(p));
    return a;
}
#define SWZ(b) ((b) ^ (((b) >> 3) & 0x70))
#define CPA16(dst, src) asm volatile("cp.async.cg.shared.global [%0], [%1], 16;" :: "r"(dst), "l"(src))
#define CPA_COMMIT() asm volatile("cp.async.commit_group;" ::: "memory")
#define CPA_WAIT1()  asm volatile("cp.async.wait_group 1;" ::: "memory")
#define CPA_WAIT0()  asm volatile("cp.async.wait_group 0;" ::: "memory")

__device__ __forceinline__ void ldsm4(uint32_t* r, uint32_t a) {
    asm volatile("ldmatrix.sync.aligned.m8n8.x4.shared.b16 {%0,%1,%2,%3}, [%4];"
                 : "=r"(r[0]), "=r"(r[1]), "=r"(r[2]), "=r"(r[3]) : "r"(a));
}
__device__ __forceinline__ void mma_bf16(float* c, const uint32_t* a, uint32_t b0, uint32_t b1) {
    asm volatile("mma.sync.aligned.m16n8k16.row.col.f32.bf16.bf16.f32 "
        "{%0,%1,%2,%3}, {%4,%5,%6,%7}, {%8,%9}, {%0,%1,%2,%3};"
        : "+f"(c[0]), "+f"(c[1]), "+f"(c[2]), "+f"(c[3])
        : "r"(a[0]), "r"(a[1]), "r"(a[2]), "r"(a[3]), "r"(b0), "r"(b1));
}
__device__ __forceinline__ void bsplit(float a, uint32_t& hi, uint32_t& lo) {
    uint32_t u = __float_as_uint(a);
    uint32_t hr = (u + 0x7fffu + ((u >> 16) & 1u)) & 0xffff0000u;
    hi = hr >> 16;
    float l = a - __uint_as_float(hr);
    uint32_t ul = __float_as_uint(l);
    lo = (ul + 0x7fffu + ((ul >> 16) & 1u)) >> 16;
}
__device__ __forceinline__ void bsplit2(float a, float b, uint32_t& hi, uint32_t& lo) {
    uint32_t h0, l0, h1, l1;
    bsplit(a, h0, l0); bsplit(b, h1, l1);
    hi = h0 | (h1 << 16); lo = l0 | (l1 << 16);
}

// transpose+split: W[K][N] fp32 -> Wt[N][K] hi/lo bf16
__global__ __launch_bounds__(256)
void wsplit_k(const float* __restrict__ W, u16* __restrict__ hi, u16* __restrict__ lo, int K, int N)
{
    __shared__ float tile[32][33];
    const int n0 = blockIdx.x * 32, k0 = blockIdx.y * 32;
    const int tx = threadIdx.x & 31, ty = threadIdx.x >> 5;
#pragma unroll
    for (int r = 0; r < 4; r++)
        tile[ty + 8 * r][tx] = W[(size_t)(k0 + ty + 8 * r) * N + n0 + tx];
    __syncthreads();
#pragma unroll
    for (int r = 0; r < 4; r++) {
        const int n = n0 + ty + 8 * r, k = k0 + tx;
        uint32_t h, l;
        bsplit(tile[tx][ty + 8 * r], h, l);
        hi[(size_t)n * K + k] = (u16)h;
        lo[(size_t)n * K + k] = (u16)l;
    }
}

__global__ __launch_bounds__(256)
void asplit_k(const float* __restrict__ A, u16* __restrict__ hi, u16* __restrict__ lo)
{
    const size_t i4 = ((size_t)blockIdx.x * 256 + threadIdx.x) * 4;
    float4 f = *(const float4*)(A + i4);
    uint32_t a, b, c, d;
    bsplit2(f.x, f.y, a, c); bsplit2(f.z, f.w, b, d);
    *(uint2*)(hi + i4) = make_uint2(a, b);
    *(uint2*)(lo + i4) = make_uint2(c, d);
}

// ---- bf16x3 HMMA GEMM, 128x128 tile, 3-stage cp.async ----
#define TG_SMEM (3 * 65536)
template<int EPI>
__global__ __launch_bounds__(256, 1)
void tgemm(const u16* __restrict__ Ahi, const u16* __restrict__ Alo,
           const u16* __restrict__ Bhi, const u16* __restrict__ Blo,
           const float* __restrict__ bias, const float* __restrict__ extra,
           void* __restrict__ out, void* __restrict__ out2, int M, int N, int K)
{
    extern __shared__ __align__(1024) char sm_raw[];
    const uint32_t sb = smem_u32(sm_raw);
    const int tid = threadIdx.x, wid = tid >> 5, lane = tid & 31;
    const int bm = blockIdx.y * 128, bn = blockIdx.x * 128;
    const int wm = (wid & 1) * 64, wn = (wid >> 1) * 32;
    const int nck = K >> 6;

    float acc[4][4][4];
#pragma unroll
    for (int i = 0; i < 4; i++)
#pragma unroll
        for (int j = 0; j < 4; j++)
#pragma unroll
            for (int r = 0; r < 4; r++) acc[i][j][r] = 0.0f;

    const int a_row = ((lane >> 3) & 1) * 8 + (lane & 7);
    const int a_col = (lane >> 4) * 8;
    const int b_row = (lane >> 4) * 8 + (lane & 7);
    const int b_col = ((lane >> 3) & 1) * 8;

    auto load_stage = [&](int ck, int stage) {
        if (ck < nck) {
            const int k0 = ck * 64;
            const uint32_t sbase = sb + stage * 65536;
#pragma unroll
            for (int i = 0; i < 4; i++) {
                const int id = tid + i * 256;
                const int row = id >> 3, c16 = id & 7;
                const uint32_t dsw = SWZ((uint32_t)(row * 128 + c16 * 16));
                const size_t asrc = (size_t)(bm + row) * K + k0 + c16 * 8;
                const size_t bsrc = (size_t)(bn + row) * K + k0 + c16 * 8;
                CPA16(sbase + dsw,         Ahi + asrc);
                CPA16(sbase + 16384 + dsw, Alo + asrc);
                CPA16(sbase + 32768 + dsw, Bhi + bsrc);
                CPA16(sbase + 49152 + dsw, Blo + bsrc);
            }
        }
        CPA_COMMIT();
    };

    load_stage(0, 0);
    load_stage(1, 1);

    for (int ck = 0; ck < nck; ck++) {
        CPA_WAIT1();
        __syncthreads();
        load_stage(ck + 2, (ck + 2) % 3);
        const uint32_t base = sb + (ck % 3) * 65536;
#pragma unroll
        for (int ks = 0; ks < 4; ks++) {
            const int kk = ks * 16;
            uint32_t ah[4][4], al[4][4], bh[2][4], bl[2][4];
#pragma unroll
            for (int mf = 0; mf < 4; mf++) {
                const uint32_t ao = SWZ((uint32_t)((wm + mf * 16 + a_row) * 128 + (kk + a_col) * 2));
                ldsm4(ah[mf], base + ao);
                ldsm4(al[mf], base + 16384 + ao);
            }
#pragma unroll
            for (int p = 0; p < 2; p++) {
                const uint32_t bo = SWZ((uint32_t)((wn + p * 16 + b_row) * 128 + (kk + b_col) * 2));
                ldsm4(bh[p], base + 32768 + bo);
                ldsm4(bl[p], base + 49152 + bo);
            }
#pragma unroll
            for (int mf = 0; mf < 4; mf++)
#pragma unroll
                for (int p = 0; p < 2; p++)
#pragma unroll
                    for (int s = 0; s < 2; s++) {
                        float* c = acc[mf][p * 2 + s];
                        mma_bf16(c, ah[mf], bh[p][s * 2], bh[p][s * 2 + 1]);
                        mma_bf16(c, al[mf], bh[p][s * 2], bh[p][s * 2 + 1]);
                        mma_bf16(c, ah[mf], bl[p][s * 2], bl[p][s * 2 + 1]);
                    }
        }
    }

    const int l4 = lane >> 2, l2 = (lane & 3) * 2;
#pragma unroll
    for (int mf = 0; mf < 4; mf++)
#pragma unroll
        for (int nf = 0; nf < 4; nf++) {
            const int col = bn + wn + nf * 8 + l2;
            const float bia0 = bias[col], bia1 = bias[col + 1];
#pragma unroll
            for (int half = 0; half < 2; half++) {
                const int m = bm + wm + mf * 16 + l4 + half * 8;
                float v0 = acc[mf][nf][half * 2]     + bia0;
                float v1 = acc[mf][nf][half * 2 + 1] + bia1;
                if (EPI == 0) {
                    v0 += extra[(size_t)(m & (N1_ - 1)) * C_ + col];
                    v1 += extra[(size_t)(m & (N1_ - 1)) * C_ + col + 1];
                    *(float2*)((float*)out + (size_t)m * N + col) = make_float2(v0, v1);
                    uint32_t hi, lo;
                    bsplit2(v0, v1, hi, lo);
                    *(uint32_t*)(g_qh + (size_t)m * N + col) = hi;
                    *(uint32_t*)(g_ql + (size_t)m * N + col) = lo;
                } else if (EPI == 1) {
                    if (col < C_) {
                        v0 += extra[(size_t)(m & (N2_ - 1)) * C_ + col];
                        v1 += extra[(size_t)(m & (N2_ - 1)) * C_ + col + 1];
                        *(float2*)((float*)out + (size_t)m * C_ + col) = make_float2(v0, v1);
                    } else {
                        *(float2*)((float*)out2 + (size_t)m * C_ + col - C_) = make_float2(v0, v1);
                    }
                } else if (EPI == 2) {
                    v0 = 0.5f * v0 * (1.0f + erff(v0 * 0.70710678118654752f));
                    v1 = 0.5f * v1 * (1.0f + erff(v1 * 0.70710678118654752f));
                    uint32_t hi, lo;
                    bsplit2(v0, v1, hi, lo);
                    *(uint32_t*)((u16*)out  + (size_t)m * N + col) = hi;
                    *(uint32_t*)((u16*)out2 + (size_t)m * N + col) = lo;
                } else {
                    v0 += extra[(size_t)m * N + col];
                    v1 += extra[(size_t)m * N + col + 1];
                    *(float2*)((float*)out + (size_t)m * N + col) = make_float2(v0, v1);
                }
            }
        }
}

// ---- kvp via bf16x3 HMMA.  grid (64 bh, 2 mode).  K=4096 in 64-chunks. ----
// mode 0: kp^T[p][d] = WpT[256][n] x kT_slice[64][n]   (M=256, N=64)
// mode 1: vp[d][p]   = vT_slice[64][n] x WpT[256][n]   (M=64,  N=256)
#define KVP_STG  81920
#define KVP_SMEM (2 * KVP_STG)
__global__ __launch_bounds__(256, 1)
void kvp_mma(const float* __restrict__ bp)
{
    extern __shared__ __align__(1024) char sm_raw[];
    const uint32_t sb = smem_u32(sm_raw);
    const int tid = threadIdx.x, wid = tid >> 5, lane = tid & 31;
    const int g = lane >> 2, t4 = lane & 3;
    const int bh = blockIdx.x, b = bh >> 3, h = bh & 7;
    const int mode = blockIdx.y;
    const u16* __restrict__ Dh = mode ? g_vTh : g_kTh;
    const u16* __restrict__ Dl = mode ? g_vTl : g_kTl;

    const int a_row = ((lane >> 3) & 1) * 8 + (lane & 7);
    const int a_col = (lane >> 4) * 8;
    const int b_row = (lane >> 4) * 8 + (lane & 7);
    const int b_col = ((lane >> 3) & 1) * 8;

    auto load_stage = [&](int ck) {
        if (ck < 64) {
            const uint32_t base = sb + (ck & 1) * KVP_STG;
            const int k0 = ck * 64;
#pragma unroll
            for (int t = 0; t < 8; t++) {
                const int i = tid + t * 256;
                const int row = i >> 3, c16 = i & 7;
                const uint32_t dsw = SWZ((uint32_t)(row * 128 + c16 * 16));
                const size_t src = (size_t)row * N2_ + k0 + c16 * 8;
                CPA16(base + dsw,         g_wpth + src);
                CPA16(base + 32768 + dsw, g_wptl + src);
            }
#pragma unroll
            for (int t = 0; t < 2; t++) {
                const int i = tid + t * 256;
                const int row = i >> 3, c16 = i & 7;
                const uint32_t dsw = SWZ((uint32_t)(row * 128 + c16 * 16));
                const size_t src = ((size_t)b * C_ + h * 64 + row) * N2_ + k0 + c16 * 8;
                CPA16(base + 65536 + dsw, Dh + src);
                CPA16(base + 73728 + dsw, Dl + src);
            }
        }
        CPA_COMMIT();
    };

    load_stage(0);
    load_stage(1);

    if (mode == 0) {
        const int wm = (wid & 3) * 64, wn = (wid >> 2) * 32;
        float acc[4][4][4];
#pragma unroll
        for (int i = 0; i < 4; i++)
#pragma unroll
            for (int j = 0; j < 4; j++)
#pragma unroll
                for (int r = 0; r < 4; r++) acc[i][j][r] = 0.0f;

        for (int ck = 0; ck < 64; ck++) {
            CPA_WAIT1();
            __syncthreads();
            const uint32_t base = sb + (ck & 1) * KVP_STG;
#pragma unroll
            for (int ks = 0; ks < 4; ks++) {
                const int kk = ks * 16;
                uint32_t ah[4][4], al[4][4], bhr[2][4], blr[2][4];
#pragma unroll
                for (int mf = 0; mf < 4; mf++) {
                    const uint32_t ao = SWZ((uint32_t)((wm + mf * 16 + a_row) * 128 + (kk + a_col) * 2));
                    ldsm4(ah[mf], base + ao);
                    ldsm4(al[mf], base + 32768 + ao);
                }
#pragma unroll
                for (int p = 0; p < 2; p++) {
                    const uint32_t bo = SWZ((uint32_t)((wn + p * 16 + b_row) * 128 + (kk + b_col) * 2));
                    ldsm4(bhr[p], base + 65536 + bo);
                    ldsm4(blr[p], base + 73728 + bo);
                }
#pragma unroll
                for (int mf = 0; mf < 4; mf++)
#pragma unroll
                    for (int p = 0; p < 2; p++)
#pragma unroll
                        for (int s = 0; s < 2; s++) {
                            float* c = acc[mf][p * 2 + s];
                            mma_bf16(c, ah[mf], bhr[p][s * 2], bhr[p][s * 2 + 1]);
                            mma_bf16(c, al[mf], bhr[p][s * 2], bhr[p][s * 2 + 1]);
                            mma_bf16(c, ah[mf], blr[p][s * 2], blr[p][s * 2 + 1]);
                        }
            }
            __syncthreads();
            load_stage(ck + 2);
        }
#pragma unroll
        for (int mf = 0; mf < 4; mf++)
#pragma unroll
            for (int hf = 0; hf < 2; hf++) {
                const int p = wm + mf * 16 + hf * 8 + g;
                const float bv = bp[p];
#pragma unroll
                for (int nf = 0; nf < 4; nf++) {
                    const int d = wn + nf * 8 + t4 * 2;
                    uint32_t hi, lo;
                    bsplit2(acc[mf][nf][hf * 2] + bv, acc[mf][nf][hf * 2 + 1] + bv, hi, lo);
                    *(uint32_t*)(g_kpth + (size_t)bh * (P_ * HD_) + p * 64 + d) = hi;
                    *(uint32_t*)(g_kptl + (size_t)bh * (P_ * HD_) + p * 64 + d) = lo;
                }
            }
    } else {
        const int wm = (wid & 1) * 32, wn = (wid >> 1) * 64;
        float acc[2][8][4];
#pragma unroll
        for (int i = 0; i < 2; i++)
#pragma unroll
            for (int j = 0; j < 8; j++)
#pragma unroll
                for (int r = 0; r < 4; r++) acc[i][j][r] = 0.0f;

        for (int ck = 0; ck < 64; ck++) {
            CPA_WAIT1();
            __syncthreads();
            const uint32_t base = sb + (ck & 1) * KVP_STG;
#pragma unroll
            for (int ks = 0; ks < 4; ks++) {
                const int kk = ks * 16;
                uint32_t ah[2][4], al[2][4];
#pragma unroll
                for (int mf = 0; mf < 2; mf++) {
                    const uint32_t ao = SWZ((uint32_t)((wm + mf * 16 + a_row) * 128 + (kk + a_col) * 2));
                    ldsm4(ah[mf], base + 65536 + ao);
                    ldsm4(al[mf], base + 73728 + ao);
                }
#pragma unroll
                for (int p = 0; p < 4; p++) {
                    uint32_t bhr[4], blr[4];
                    const uint32_t bo = SWZ((uint32_t)((wn + p * 16 + b_row) * 128 + (kk + b_col) * 2));
                    ldsm4(bhr, base + bo);
                    ldsm4(blr, base + 32768 + bo);
#pragma unroll
                    for (int mf = 0; mf < 2; mf++)
#pragma unroll
                        for (int s = 0; s < 2; s++) {
                            float* c = acc[mf][p * 2 + s];
                            mma_bf16(c, ah[mf], bhr[s * 2], bhr[s * 2 + 1]);
                            mma_bf16(c, al[mf], bhr[s * 2], bhr[s * 2 + 1]);
                            mma_bf16(c, ah[mf], blr[s * 2], blr[s * 2 + 1]);
                        }
                }
            }
            __syncthreads();
            load_stage(ck + 2);
        }
#pragma unroll
        for (int mf = 0; mf < 2; mf++)
#pragma unroll
            for (int hf = 0; hf < 2; hf++) {
                const int d = wm + mf * 16 + hf * 8 + g;
#pragma unroll
                for (int nf = 0; nf < 8; nf++) {
                    const int p = wn + nf * 8 + t4 * 2;
                    uint32_t hi, lo;
                    bsplit2(acc[mf][nf][hf * 2] + bp[p], acc[mf][nf][hf * 2 + 1] + bp[p + 1], hi, lo);
                    *(uint32_t*)(g_vph + (size_t)bh * (HD_ * P_) + d * 256 + p) = hi;
                    *(uint32_t*)(g_vpl + (size_t)bh * (HD_ * P_) + d * 256 + p) = lo;
                }
            }
    }
}

// ---- attention via bf16x3 HMMA (validated R6) ----
#define A_QH   0
#define A_QL   8192
#define A_KH   16384
#define A_KL   49152
#define A_VH   81920
#define A_VL   114688
#define A_ST   147456
#define A_ZN   149504
#define ATT_SMEM (149504 + 4*64*66*4)

__global__ __launch_bounds__(256, 1)
void attn_mma(const float* __restrict__ temp, float* __restrict__ xa)
{
    extern __shared__ __align__(1024) char sm_raw[];
    const uint32_t sb = smem_u32(sm_raw);
    const int tid = threadIdx.x, wid = tid >> 5, lane = tid & 31;
    const int g = lane >> 2, t4 = lane & 3;
    const int bh = blockIdx.x, b = bh >> 3, h = bh & 7;
    const int q0 = blockIdx.y * 64;
    const int wm = (wid & 1) * 32, zn = wid >> 1, wn = zn * 64;

#pragma unroll
    for (int t = 0; t < 2; t++) {
        const int i = tid + t * 256;
        const int row = i >> 3, c16 = i & 7;
        const uint32_t dsw = SWZ((uint32_t)(row * 128 + c16 * 16));
        const size_t src = (size_t)(b * N1_ + q0 + row) * C_ + h * 64 + c16 * 8;
        CPA16(sb + A_QH + dsw, g_qh + src);
        CPA16(sb + A_QL + dsw, g_ql + src);
    }
#pragma unroll
    for (int t = 0; t < 8; t++) {
        const int i = tid + t * 256;
        const int row = i >> 3, c16 = i & 7;
        const uint32_t dsw = SWZ((uint32_t)(row * 128 + c16 * 16));
        const size_t src = (size_t)bh * (P_ * HD_) + row * 64 + c16 * 8;
        CPA16(sb + A_KH + dsw, g_kpth + src);
        CPA16(sb + A_KL + dsw, g_kptl + src);
    }
#pragma unroll
    for (int t = 0; t < 8; t++) {
        const int i = tid + t * 256;
        const int c16 = i & 7, d = (i >> 3) & 63, ch = i >> 9;
        const uint32_t dsw = (uint32_t)(ch * 8192) + SWZ((uint32_t)(d * 128 + c16 * 16));
        const size_t src = (size_t)bh * (HD_ * P_) + d * 256 + ch * 64 + c16 * 8;
        CPA16(sb + A_VH + dsw, g_vph + src);
        CPA16(sb + A_VL + dsw, g_vpl + src);
    }
    CPA_COMMIT();
    CPA_WAIT0();
    __syncthreads();

    const int a_row = ((lane >> 3) & 1) * 8 + (lane & 7);
    const int a_col = (lane >> 4) * 8;
    const int b_row = (lane >> 4) * 8 + (lane & 7);
    const int b_col = ((lane >> 3) & 1) * 8;

    float acc[2][8][4];
#pragma unroll
    for (int i = 0; i < 2; i++)
#pragma unroll
        for (int j = 0; j < 8; j++)
#pragma unroll
            for (int r = 0; r < 4; r++) acc[i][j][r] = 0.0f;

#pragma unroll
    for (int ks = 0; ks < 4; ks++) {
        const int kk = ks * 16;
        uint32_t ah[2][4], al[2][4];
#pragma unroll
        for (int mf = 0; mf < 2; mf++) {
            const uint32_t ao = SWZ((uint32_t)((wm + mf * 16 + a_row) * 128 + (kk + a_col) * 2));
            ldsm4(ah[mf], sb + A_QH + ao);
            ldsm4(al[mf], sb + A_QL + ao);
        }
#pragma unroll
        for (int p = 0; p < 4; p++) {
            uint32_t bhr[4], blr[4];
            const uint32_t bo = SWZ((uint32_t)((wn + p * 16 + b_row) * 128 + (kk + b_col) * 2));
            ldsm4(bhr, sb + A_KH + bo);
            ldsm4(blr, sb + A_KL + bo);
#pragma unroll
            for (int mf = 0; mf < 2; mf++)
#pragma unroll
                for (int s = 0; s < 2; s++) {
                    float* c = acc[mf][p * 2 + s];
                    mma_bf16(c, ah[mf], bhr[s * 2], bhr[s * 2 + 1]);
                    mma_bf16(c, al[mf], bhr[s * 2], bhr[s * 2 + 1]);
                    mma_bf16(c, ah[mf], blr[s * 2], blr[s * 2 + 1]);
                }
        }
    }

    const float tscale = temp[h];
    float* smax = (float*)(sm_raw + A_ST);
    float* ssum = smax + 256;
#pragma unroll
    for (int mf = 0; mf < 2; mf++)
#pragma unroll
        for (int nf = 0; nf < 8; nf++)
#pragma unroll
            for (int r = 0; r < 4; r++) acc[mf][nf][r] *= tscale;

    float rmx[2][2] = {{-1e30f, -1e30f}, {-1e30f, -1e30f}};
#pragma unroll
    for (int mf = 0; mf < 2; mf++)
#pragma unroll
        for (int nf = 0; nf < 8; nf++) {
            rmx[mf][0] = fmaxf(rmx[mf][0], fmaxf(acc[mf][nf][0], acc[mf][nf][1]));
            rmx[mf][1] = fmaxf(rmx[mf][1], fmaxf(acc[mf][nf][2], acc[mf][nf][3]));
        }
#pragma unroll
    for (int mf = 0; mf < 2; mf++)
#pragma unroll
        for (int hf = 0; hf < 2; hf++) {
            rmx[mf][hf] = fmaxf(rmx[mf][hf], __shfl_xor_sync(~0u, rmx[mf][hf], 1));
            rmx[mf][hf] = fmaxf(rmx[mf][hf], __shfl_xor_sync(~0u, rmx[mf][hf], 2));
        }
    if (t4 == 0)
#pragma unroll
        for (int mf = 0; mf < 2; mf++)
#pragma unroll
            for (int hf = 0; hf < 2; hf++)
                smax[(wm + mf * 16 + hf * 8 + g) * 4 + zn] = rmx[mf][hf];
    __syncthreads();
    float gmx[2][2], rsm[2][2] = {{0, 0}, {0, 0}};
#pragma unroll
    for (int mf = 0; mf < 2; mf++)
#pragma unroll
        for (int hf = 0; hf < 2; hf++) {
            const int r = wm + mf * 16 + hf * 8 + g;
            gmx[mf][hf] = fmaxf(fmaxf(smax[r * 4], smax[r * 4 + 1]),
                                fmaxf(smax[r * 4 + 2], smax[r * 4 + 3]));
        }
#pragma unroll
    for (int mf = 0; mf < 2; mf++)
#pragma unroll
        for (int nf = 0; nf < 8; nf++)
#pragma unroll
            for (int r = 0; r < 4; r++) {
                const int hf = r >> 1;
                const float e = __expf(acc[mf][nf][r] - gmx[mf][hf]);
                acc[mf][nf][r] = e;
                rsm[mf][hf] += e;
            }
#pragma unroll
    for (int mf = 0; mf < 2; mf++)
#pragma unroll
        for (int hf = 0; hf < 2; hf++) {
            rsm[mf][hf] += __shfl_xor_sync(~0u, rsm[mf][hf], 1);
            rsm[mf][hf] += __shfl_xor_sync(~0u, rsm[mf][hf], 2);
        }
    if (t4 == 0)
#pragma unroll
        for (int mf = 0; mf < 2; mf++)
#pragma unroll
            for (int hf = 0; hf < 2; hf++)
                ssum[(wm + mf * 16 + hf * 8 + g) * 4 + zn] = rsm[mf][hf];
    __syncthreads();
#pragma unroll
    for (int mf = 0; mf < 2; mf++)
#pragma unroll
        for (int hf = 0; hf < 2; hf++) {
            const int r = wm + mf * 16 + hf * 8 + g;
            const float inv = 1.0f / (ssum[r * 4] + ssum[r * 4 + 1] + ssum[r * 4 + 2] + ssum[r * 4 + 3]);
#pragma unroll
            for (int nf = 0; nf < 8; nf++) {
                acc[mf][nf][hf * 2]     *= inv;
                acc[mf][nf][hf * 2 + 1] *= inv;
            }
        }

    float acc2[2][8][4];
#pragma unroll
    for (int i = 0; i < 2; i++)
#pragma unroll
        for (int j = 0; j < 8; j++)
#pragma unroll
            for (int r = 0; r < 4; r++) acc2[i][j][r] = 0.0f;

#pragma unroll
    for (int kf = 0; kf < 4; kf++) {
        uint32_t pah[2][4], pal[2][4];
#pragma unroll
        for (int mf = 0; mf < 2; mf++) {
            bsplit2(acc[mf][2*kf][0],   acc[mf][2*kf][1],   pah[mf][0], pal[mf][0]);
            bsplit2(acc[mf][2*kf][2],   acc[mf][2*kf][3],   pah[mf][1], pal[mf][1]);
            bsplit2(acc[mf][2*kf+1][0], acc[mf][2*kf+1][1], pah[mf][2], pal[mf][2]);
            bsplit2(acc[mf][2*kf+1][2], acc[mf][2*kf+1][3], pah[mf][3], pal[mf][3]);
        }
#pragma unroll
        for (int df = 0; df < 4; df++) {
            uint32_t bhr[4], blr[4];
            const uint32_t bo = (uint32_t)(zn * 8192) +
                SWZ((uint32_t)((df * 16 + b_row) * 128 + (kf * 16 + b_col) * 2));
            ldsm4(bhr, sb + A_VH + bo);
            ldsm4(blr, sb + A_VL + bo);
#pragma unroll
            for (int mf = 0; mf < 2; mf++)
#pragma unroll
                for (int s = 0; s < 2; s++) {
                    float* c = acc2[mf][df * 2 + s];
                    mma_bf16(c, pah[mf], bhr[s * 2], bhr[s * 2 + 1]);
                    mma_bf16(c, pal[mf], bhr[s * 2], bhr[s * 2 + 1]);
                    mma_bf16(c, pah[mf], blr[s * 2], blr[s * 2 + 1]);
                }
        }
    }

    float* zone = (float*)(sm_raw + A_ZN) + zn * (64 * 66);
#pragma unroll
    for (int mf = 0; mf < 2; mf++)
#pragma unroll
        for (int nf = 0; nf < 8; nf++)
#pragma unroll
            for (int hf = 0; hf < 2; hf++) {
                const int row = wm + mf * 16 + hf * 8 + g;
                const int dc = nf * 8 + t4 * 2;
                *(float2*)&zone[row * 66 + dc] =
                    make_float2(acc2[mf][nf][hf * 2], acc2[mf][nf][hf * 2 + 1]);
            }
    __syncthreads();

    const int tx = tid & 15, ty = tid >> 4;
    float* z0 = (float*)(sm_raw + A_ZN);
    const size_t base = (size_t)b * (N1_ * C_) + (size_t)h * N1_ + q0 + tx * 4;
#pragma unroll
    for (int j = 0; j < 4; j++) {
        const int d = ty * 4 + j;
        float o[4];
#pragma unroll
        for (int qi = 0; qi < 4; qi++) {
            const int idx = (tx * 4 + qi) * 66 + d;
            o[qi] = z0[idx] + z0[64*66 + idx] + z0[2*64*66 + idx] + z0[3*64*66 + idx];
        }
        *(float4*)&xa[base + (size_t)d * (H_ * N1_)] = make_float4(o[0], o[1], o[2], o[3]);
    }
}

// ---- L2 norm + optional bf16 split ----
__global__ __launch_bounds__(256)
void l2n_k(const float* __restrict__ a, const float* __restrict__ bb,
           float* __restrict__ out, u16* __restrict__ oh, u16* __restrict__ ol)
{
    const int row = blockIdx.x * 8 + (threadIdx.x >> 5);
    const int lane = threadIdx.x & 31;
    const float4* pa = (const float4*)(a + (size_t)row * C_);
    const float4* pb = bb ? (const float4*)(bb + (size_t)row * C_) : nullptr;
    float4 v[4];
    float ss = 0.0f;
#pragma unroll
    for (int i = 0; i < 4; i++) {
        float4 t = pa[lane + 32 * i];
        if (pb) {
            float4 u = pb[lane + 32 * i];
            t.x += u.x; t.y += u.y; t.z += u.z; t.w += u.w;
        }
        v[i] = t;
        ss += t.x * t.x + t.y * t.y + t.z * t.z + t.w * t.w;
    }
#pragma unroll
    for (int o = 16; o > 0; o >>= 1) ss += __shfl_xor_sync(~0u, ss, o);
    const float inv = 1.0f / fmaxf(sqrtf(ss), 1e-12f);
    float4* po = (float4*)(out + (size_t)row * C_);
#pragma unroll
    for (int i = 0; i < 4; i++) {
        v[i].x *= inv; v[i].y *= inv; v[i].z *= inv; v[i].w *= inv;
        po[lane + 32 * i] = v[i];
        if (oh) {
            uint32_t a0, b0, c0, d0;
            bsplit2(v[i].x, v[i].y, a0, c0); bsplit2(v[i].z, v[i].w, b0, d0);
            const size_t off = (size_t)row * C_ + (lane + 32 * i) * 4;
            *(uint2*)(oh + off) = make_uint2(a0, b0);
            *(uint2*)(ol + off) = make_uint2(c0, d0);
        }
    }
}

extern "C" void kernel_launch(void* const* d_in, const int* in_sizes, int n_in,
                              void* d_out, int out_size)
{
    const float* x1    = (const float*)d_in[0];
    const float* x2    = (const float*)d_in[1];
    const float* Wq    = (const float*)d_in[2];
    const float* bq    = (const float*)d_in[3];
    const float* Wkv   = (const float*)d_in[4];
    const float* bkv   = (const float*)d_in[5];
    const float* Wp    = (const float*)d_in[6];
    const float* bp    = (const float*)d_in[7];
    const float* pos_q = (const float*)d_in[8];
    const float* pos_k = (const float*)d_in[9];
    const float* temp  = (const float*)d_in[10];
    const float* W1    = (const float*)d_in[11];
    const float* b1    = (const float*)d_in[12];
    const float* W2    = (const float*)d_in[13];
    const float* b2    = (const float*)d_in[14];

    float *q, *k, *v;
    u16 *x1h, *x1l, *x2h, *x2l, *xnh, *xnl, *hh, *hl;
    u16 *wqh, *wql, *wkvh, *wkvl, *w1h, *w1l, *w2h, *w2l, *wpth, *wptl;
    u16 *kTh, *kTl, *vTh, *vTl;
    cudaGetSymbolAddress((void**)&q, g_q);
    cudaGetSymbolAddress((void**)&k, g_k);
    cudaGetSymbolAddress((void**)&v, g_v);
    cudaGetSymbolAddress((void**)&x1h, g_x1h); cudaGetSymbolAddress((void**)&x1l, g_x1l);
    cudaGetSymbolAddress((void**)&x2h, g_x2h); cudaGetSymbolAddress((void**)&x2l, g_x2l);
    cudaGetSymbolAddress((void**)&xnh, g_xnh); cudaGetSymbolAddress((void**)&xnl, g_xnl);
    cudaGetSymbolAddress((void**)&hh, g_hh);   cudaGetSymbolAddress((void**)&hl, g_hl);
    cudaGetSymbolAddress((void**)&wqh, g_wq_hi);   cudaGetSymbolAddress((void**)&wql, g_wq_lo);
    cudaGetSymbolAddress((void**)&wkvh, g_wkv_hi); cudaGetSymbolAddress((void**)&wkvl, g_wkv_lo);
    cudaGetSymbolAddress((void**)&w1h, g_w1_hi);   cudaGetSymbolAddress((void**)&w1l, g_w1_lo);
    cudaGetSymbolAddress((void**)&w2h, g_w2_hi);   cudaGetSymbolAddress((void**)&w2l, g_w2_lo);
    cudaGetSymbolAddress((void**)&wpth, g_wpth);   cudaGetSymbolAddress((void**)&wptl, g_wptl);
    cudaGetSymbolAddress((void**)&kTh, g_kTh);     cudaGetSymbolAddress((void**)&kTl, g_kTl);
    cudaGetSymbolAddress((void**)&vTh, g_vTh);     cudaGetSymbolAddress((void**)&vTl, g_vTl);
    float* xa = k;
    float* xn = v;

    cudaFuncSetAttribute(attn_mma, cudaFuncAttributeMaxDynamicSharedMemorySize, ATT_SMEM);
    cudaFuncSetAttribute(kvp_mma,  cudaFuncAttributeMaxDynamicSharedMemorySize, KVP_SMEM);
    cudaFuncSetAttribute(tgemm<0>, cudaFuncAttributeMaxDynamicSharedMemorySize, TG_SMEM);
    cudaFuncSetAttribute(tgemm<1>, cudaFuncAttributeMaxDynamicSharedMemorySize, TG_SMEM);
    cudaFuncSetAttribute(tgemm<2>, cudaFuncAttributeMaxDynamicSharedMemorySize, TG_SMEM);
    cudaFuncSetAttribute(tgemm<3>, cudaFuncAttributeMaxDynamicSharedMemorySize, TG_SMEM);

    wsplit_k<<<dim3(C_ / 32, C_ / 32), 256>>>(Wq, wqh, wql, C_, C_);
    wsplit_k<<<dim3(2 * C_ / 32, C_ / 32), 256>>>(Wkv, wkvh, wkvl, C_, 2 * C_);
    wsplit_k<<<dim3(MLP_ / 32, C_ / 32), 256>>>(W1, w1h, w1l, C_, MLP_);
    wsplit_k<<<dim3(C_ / 32, MLP_ / 32), 256>>>(W2, w2h, w2l, MLP_, C_);
    wsplit_k<<<dim3(P_ / 32, N2_ / 32), 256>>>(Wp, wpth, wptl, N2_, P_);
    asplit_k<<<(M_ * C_) / 1024, 256>>>(x1, x1h, x1l);
    asplit_k<<<(M_ * C_) / 1024, 256>>>(x2, x2h, x2l);

    tgemm<0><<<dim3(C_ / 128, M_ / 128), 256, TG_SMEM>>>(
        x1h, x1l, wqh, wql, bq, pos_q, q, nullptr, M_, C_, C_);
    tgemm<1><<<dim3(2 * C_ / 128, M_ / 128), 256, TG_SMEM>>>(
        x2h, x2l, wkvh, wkvl, bkv, pos_k, k, v, M_, 2 * C_, C_);

    // transpose k/v: per batch, [n][c] fp32 -> [c][n] bf16 split
    for (int b = 0; b < B_; b++) {
        wsplit_k<<<dim3(C_ / 32, N2_ / 32), 256>>>(
            k + (size_t)b * N2_ * C_, kTh + (size_t)b * C_ * N2_,
            kTl + (size_t)b * C_ * N2_, N2_, C_);
        wsplit_k<<<dim3(C_ / 32, N2_ / 32), 256>>>(
            v + (size_t)b * N2_ * C_, vTh + (size_t)b * C_ * N2_,
            vTl + (size_t)b * C_ * N2_, N2_, C_);
    }

    kvp_mma<<<dim3(B_ * H_, 2), 256, KVP_SMEM>>>(bp);
    attn_mma<<<dim3(B_ * H_, N1_ / 64), 256, ATT_SMEM>>>(temp, xa);
    l2n_k<<<M_ / 8, 256>>>(xa, q, xn, xnh, xnl);
    tgemm<2><<<dim3(MLP_ / 128, M_ / 128), 256, TG_SMEM>>>(
        xnh, xnl, w1h, w1l, b1, nullptr, hh, hl, M_, MLP_, C_);
    tgemm<3><<<dim3(C_ / 128, M_ / 128), 256, TG_SMEM>>>(
        hh, hl, w2h, w2l, b2, xn, xa, nullptr, M_, C_, MLP_);
    l2n_k<<<M_ / 8, 256>>>(xa, nullptr, (float*)d_out, nullptr, nullptr);
}

// round 9
// speedup vs baseline: 2.2245x; 1.0211x over previous
#include <cuda_runtime.h>
#include <math.h>
#include <stdint.h>

#define B_   8
#define N1_  4096
#define N2_  4096
#define C_   512
#define P_   256
#define H_   8
#define HD_  64
#define MLP_ 2048
#define M_   (B_*N1_)

typedef unsigned short u16;

__device__ float g_q [M_*C_];
__device__ float g_k [M_*C_];     // scratch: xa
__device__ float g_v [M_*C_];     // scratch: xn
__device__ u16 g_qh [M_*C_],  g_ql [M_*C_];
__device__ u16 g_x1h[M_*C_],  g_x1l[M_*C_];
__device__ u16 g_x2h[M_*C_],  g_x2l[M_*C_];
__device__ u16 g_xnh[M_*C_],  g_xnl[M_*C_];
__device__ u16 g_hh [M_*MLP_], g_hl [M_*MLP_];
__device__ u16 g_kTh[B_*C_*N2_], g_kTl[B_*C_*N2_];          // kT [b][c][n]
__device__ u16 g_vTh[B_*C_*N2_], g_vTl[B_*C_*N2_];
__device__ u16 g_kpth[B_*H_*P_*HD_], g_kptl[B_*H_*P_*HD_];  // kp^T [bh][p][d]
__device__ u16 g_vph [B_*H_*HD_*P_], g_vpl [B_*H_*HD_*P_];  // vp   [bh][d][p]
__device__ u16 g_wq_hi [C_*C_],   g_wq_lo [C_*C_];
__device__ u16 g_wkv_hi[2*C_*C_], g_wkv_lo[2*C_*C_];
__device__ u16 g_w1_hi [MLP_*C_], g_w1_lo [MLP_*C_];
__device__ u16 g_w2_hi [C_*MLP_], g_w2_lo [C_*MLP_];
__device__ u16 g_wpth  [P_*N2_],  g_wptl  [P_*N2_];         // WpT [p][n]

__device__ __forceinline__ uint32_t smem_u32(const void* p) {
    uint32_t a;
    asm("{ .reg .u64 t; cvta.to.shared.u64 t, %1; cvt.u32.u64 %0, t; }" : "=r"(a) : "l"(p));
    return a;
}
#define SWZ(b) ((b) ^ (((b) >> 3) & 0x70))
#define CPA16(dst, src) asm volatile("cp.async.cg.shared.global [%0], [%1], 16;" :: "r"(dst), "l"(src))
#define CPA_COMMIT() asm volatile("cp.async.commit_group;" ::: "memory")
#define CPA_WAIT1()  asm volatile("cp.async.wait_group 1;" ::: "memory")
#define CPA_WAIT0()  asm volatile("cp.async.wait_group 0;" ::: "memory")

__device__ __forceinline__ void ldsm4(uint32_t* r, uint32_t a) {
    asm volatile("ldmatrix.sync.aligned.m8n8.x4.shared.b16 {%0,%1,%2,%3}, [%4];"
                 : "=r"(r[0]), "=r"(r[1]), "=r"(r[2]), "=r"(r[3]) : "r"(a));
}
__device__ __forceinline__ void mma_bf16(float* c, const uint32_t* a, uint32_t b0, uint32_t b1) {
    asm volatile("mma.sync.aligned.m16n8k16.row.col.f32.bf16.bf16.f32 "
        "{%0,%1,%2,%3}, {%4,%5,%6,%7}, {%8,%9}, {%0,%1,%2,%3};"
        : "+f"(c[0]), "+f"(c[1]), "+f"(c[2]), "+f"(c[3])
        : "r"(a[0]), "r"(a[1]), "r"(a[2]), "r"(a[3]), "r"(b0), "r"(b1));
}
__device__ __forceinline__ void bsplit(float a, uint32_t& hi, uint32_t& lo) {
    uint32_t u = __float_as_uint(a);
    uint32_t hr = (u + 0x7fffu + ((u >> 16) & 1u)) & 0xffff0000u;
    hi = hr >> 16;
    float l = a - __uint_as_float(hr);
    uint32_t ul = __float_as_uint(l);
    lo = (ul + 0x7fffu + ((ul >> 16) & 1u)) >> 16;
}
__device__ __forceinline__ void bsplit2(float a, float b, uint32_t& hi, uint32_t& lo) {
    uint32_t h0, l0, h1, l1;
    bsplit(a, h0, l0); bsplit(b, h1, l1);
    hi = h0 | (h1 << 16); lo = l0 | (l1 << 16);
}

// transpose+split: W[K][N] fp32 -> Wt[N][K] hi/lo bf16
__global__ __launch_bounds__(256)
void wsplit_k(const float* __restrict__ W, u16* __restrict__ hi, u16* __restrict__ lo, int K, int N)
{
    __shared__ float tile[32][33];
    const int n0 = blockIdx.x * 32, k0 = blockIdx.y * 32;
    const int tx = threadIdx.x & 31, ty = threadIdx.x >> 5;
#pragma unroll
    for (int r = 0; r < 4; r++)
        tile[ty + 8 * r][tx] = W[(size_t)(k0 + ty + 8 * r) * N + n0 + tx];
    __syncthreads();
#pragma unroll
    for (int r = 0; r < 4; r++) {
        const int n = n0 + ty + 8 * r, k = k0 + tx;
        uint32_t h, l;
        bsplit(tile[tx][ty + 8 * r], h, l);
        hi[(size_t)n * K + k] = (u16)h;
        lo[(size_t)n * K + k] = (u16)l;
    }
}

__global__ __launch_bounds__(256)
void asplit_k(const float* __restrict__ A, u16* __restrict__ hi, u16* __restrict__ lo)
{
    const size_t i4 = ((size_t)blockIdx.x * 256 + threadIdx.x) * 4;
    float4 f = *(const float4*)(A + i4);
    uint32_t a, b, c, d;
    bsplit2(f.x, f.y, a, c); bsplit2(f.z, f.w, b, d);
    *(uint2*)(hi + i4) = make_uint2(a, b);
    *(uint2*)(lo + i4) = make_uint2(c, d);
}

// ---- bf16x3 HMMA GEMM, 128x128 tile, 3-stage cp.async ----
// EPI 0: q fp32 (+bias+pos_q) AND qh/ql split
// EPI 1: k/v -> TRANSPOSED bf16 split kT/vT (k gets +pos_k); via smem tile
// EPI 2: gelu -> bf16 split
// EPI 3: fp32 out = acc + bias + extra
#define TG_SMEM (3 * 65536)
template<int EPI>
__global__ __launch_bounds__(256, 1)
void tgemm(const u16* __restrict__ Ahi, const u16* __restrict__ Alo,
           const u16* __restrict__ Bhi, const u16* __restrict__ Blo,
           const float* __restrict__ bias, const float* __restrict__ extra,
           void* __restrict__ out, void* __restrict__ out2, int M, int N, int K)
{
    extern __shared__ __align__(1024) char sm_raw[];
    const uint32_t sb = smem_u32(sm_raw);
    const int tid = threadIdx.x, wid = tid >> 5, lane = tid & 31;
    const int bm = blockIdx.y * 128, bn = blockIdx.x * 128;
    const int wm = (wid & 1) * 64, wn = (wid >> 1) * 32;
    const int nck = K >> 6;

    float acc[4][4][4];
#pragma unroll
    for (int i = 0; i < 4; i++)
#pragma unroll
        for (int j = 0; j < 4; j++)
#pragma unroll
            for (int r = 0; r < 4; r++) acc[i][j][r] = 0.0f;

    const int a_row = ((lane >> 3) & 1) * 8 + (lane & 7);
    const int a_col = (lane >> 4) * 8;
    const int b_row = (lane >> 4) * 8 + (lane & 7);
    const int b_col = ((lane >> 3) & 1) * 8;

    auto load_stage = [&](int ck, int stage) {
        if (ck < nck) {
            const int k0 = ck * 64;
            const uint32_t sbase = sb + stage * 65536;
#pragma unroll
            for (int i = 0; i < 4; i++) {
                const int id = tid + i * 256;
                const int row = id >> 3, c16 = id & 7;
                const uint32_t dsw = SWZ((uint32_t)(row * 128 + c16 * 16));
                const size_t asrc = (size_t)(bm + row) * K + k0 + c16 * 8;
                const size_t bsrc = (size_t)(bn + row) * K + k0 + c16 * 8;
                CPA16(sbase + dsw,         Ahi + asrc);
                CPA16(sbase + 16384 + dsw, Alo + asrc);
                CPA16(sbase + 32768 + dsw, Bhi + bsrc);
                CPA16(sbase + 49152 + dsw, Blo + bsrc);
            }
        }
        CPA_COMMIT();
    };

    load_stage(0, 0);
    load_stage(1, 1);

    for (int ck = 0; ck < nck; ck++) {
        CPA_WAIT1();
        __syncthreads();
        load_stage(ck + 2, (ck + 2) % 3);
        const uint32_t base = sb + (ck % 3) * 65536;
#pragma unroll
        for (int ks = 0; ks < 4; ks++) {
            const int kk = ks * 16;
            uint32_t ah[4][4], al[4][4], bh[2][4], bl[2][4];
#pragma unroll
            for (int mf = 0; mf < 4; mf++) {
                const uint32_t ao = SWZ((uint32_t)((wm + mf * 16 + a_row) * 128 + (kk + a_col) * 2));
                ldsm4(ah[mf], base + ao);
                ldsm4(al[mf], base + 16384 + ao);
            }
#pragma unroll
            for (int p = 0; p < 2; p++) {
                const uint32_t bo = SWZ((uint32_t)((wn + p * 16 + b_row) * 128 + (kk + b_col) * 2));
                ldsm4(bh[p], base + 32768 + bo);
                ldsm4(bl[p], base + 49152 + bo);
            }
#pragma unroll
            for (int mf = 0; mf < 4; mf++)
#pragma unroll
                for (int p = 0; p < 2; p++)
#pragma unroll
                    for (int s = 0; s < 2; s++) {
                        float* c = acc[mf][p * 2 + s];
                        mma_bf16(c, ah[mf], bh[p][s * 2], bh[p][s * 2 + 1]);
                        mma_bf16(c, al[mf], bh[p][s * 2], bh[p][s * 2 + 1]);
                        mma_bf16(c, ah[mf], bl[p][s * 2], bl[p][s * 2 + 1]);
                    }
        }
    }

    const int l4 = lane >> 2, l2 = (lane & 3) * 2;

    if (EPI == 1) {
        // stage tile transposed in smem: T[col_local][m_local], then coalesced
        // bf16-split row writes into kT/vT [b][c][n]
        CPA_WAIT0();
        __syncthreads();
        float* T = (float*)sm_raw;                       // 128 x 132 floats
        const bool is_k = (bn < C_);
#pragma unroll
        for (int mf = 0; mf < 4; mf++)
#pragma unroll
            for (int nf = 0; nf < 4; nf++) {
                const int colL = wn + nf * 8 + l2;
                const int col = bn + colL;
                const float bia0 = bias[col], bia1 = bias[col + 1];
#pragma unroll
                for (int half = 0; half < 2; half++) {
                    const int mL = wm + mf * 16 + l4 + half * 8;
                    float v0 = acc[mf][nf][half * 2]     + bia0;
                    float v1 = acc[mf][nf][half * 2 + 1] + bia1;
                    if (is_k) {
                        const int n = (bm + mL) & (N2_ - 1);
                        v0 += extra[(size_t)n * C_ + col];
                        v1 += extra[(size_t)n * C_ + col + 1];
                    }
                    T[colL * 132 + mL]       = v0;
                    T[(colL + 1) * 132 + mL] = v1;
                }
            }
        __syncthreads();
        u16* __restrict__ dh = is_k ? g_kTh : g_vTh;
        u16* __restrict__ dl = is_k ? g_kTl : g_vTl;
        const int bb = bm >> 12, n0 = bm & (N2_ - 1);
        const int r = tid >> 1, hh2 = (tid & 1) * 64;
        const int c = (bn + r) - (is_k ? 0 : C_);
        const size_t gbase = ((size_t)bb * C_ + c) * N2_ + n0 + hh2;
        const float* Tr = T + r * 132 + hh2;
#pragma unroll
        for (int j = 0; j < 64; j += 8) {
            uint32_t h0, l0, h1, l1, h2, l2x, h3, l3;
            bsplit2(Tr[j],     Tr[j + 1], h0, l0);
            bsplit2(Tr[j + 2], Tr[j + 3], h1, l1);
            bsplit2(Tr[j + 4], Tr[j + 5], h2, l2x);
            bsplit2(Tr[j + 6], Tr[j + 7], h3, l3);
            *(uint4*)(dh + gbase + j) = make_uint4(h0, h1, h2, h3);
            *(uint4*)(dl + gbase + j) = make_uint4(l0, l1, l2x, l3);
        }
        return;
    }

#pragma unroll
    for (int mf = 0; mf < 4; mf++)
#pragma unroll
        for (int nf = 0; nf < 4; nf++) {
            const int col = bn + wn + nf * 8 + l2;
            const float bia0 = bias[col], bia1 = bias[col + 1];
#pragma unroll
            for (int half = 0; half < 2; half++) {
                const int m = bm + wm + mf * 16 + l4 + half * 8;
                float v0 = acc[mf][nf][half * 2]     + bia0;
                float v1 = acc[mf][nf][half * 2 + 1] + bia1;
                if (EPI == 0) {
                    v0 += extra[(size_t)(m & (N1_ - 1)) * C_ + col];
                    v1 += extra[(size_t)(m & (N1_ - 1)) * C_ + col + 1];
                    *(float2*)((float*)out + (size_t)m * N + col) = make_float2(v0, v1);
                    uint32_t hi, lo;
                    bsplit2(v0, v1, hi, lo);
                    *(uint32_t*)(g_qh + (size_t)m * N + col) = hi;
                    *(uint32_t*)(g_ql + (size_t)m * N + col) = lo;
                } else if (EPI == 2) {
                    v0 = 0.5f * v0 * (1.0f + erff(v0 * 0.70710678118654752f));
                    v1 = 0.5f * v1 * (1.0f + erff(v1 * 0.70710678118654752f));
                    uint32_t hi, lo;
                    bsplit2(v0, v1, hi, lo);
                    *(uint32_t*)((u16*)out  + (size_t)m * N + col) = hi;
                    *(uint32_t*)((u16*)out2 + (size_t)m * N + col) = lo;
                } else {
                    v0 += extra[(size_t)m * N + col];
                    v1 += extra[(size_t)m * N + col + 1];
                    *(float2*)((float*)out + (size_t)m * N + col) = make_float2(v0, v1);
                }
            }
        }
}

// ---- kvp via bf16x3 HMMA (validated R7) ----
#define KVP_STG  81920
#define KVP_SMEM (2 * KVP_STG)
__global__ __launch_bounds__(256, 1)
void kvp_mma(const float* __restrict__ bp)
{
    extern __shared__ __align__(1024) char sm_raw[];
    const uint32_t sb = smem_u32(sm_raw);
    const int tid = threadIdx.x, wid = tid >> 5, lane = tid & 31;
    const int g = lane >> 2, t4 = lane & 3;
    const int bh = blockIdx.x, b = bh >> 3, h = bh & 7;
    const int mode = blockIdx.y;
    const u16* __restrict__ Dh = mode ? g_vTh : g_kTh;
    const u16* __restrict__ Dl = mode ? g_vTl : g_kTl;

    const int a_row = ((lane >> 3) & 1) * 8 + (lane & 7);
    const int a_col = (lane >> 4) * 8;
    const int b_row = (lane >> 4) * 8 + (lane & 7);
    const int b_col = ((lane >> 3) & 1) * 8;

    auto load_stage = [&](int ck) {
        if (ck < 64) {
            const uint32_t base = sb + (ck & 1) * KVP_STG;
            const int k0 = ck * 64;
#pragma unroll
            for (int t = 0; t < 8; t++) {
                const int i = tid + t * 256;
                const int row = i >> 3, c16 = i & 7;
                const uint32_t dsw = SWZ((uint32_t)(row * 128 + c16 * 16));
                const size_t src = (size_t)row * N2_ + k0 + c16 * 8;
                CPA16(base + dsw,         g_wpth + src);
                CPA16(base + 32768 + dsw, g_wptl + src);
            }
#pragma unroll
            for (int t = 0; t < 2; t++) {
                const int i = tid + t * 256;
                const int row = i >> 3, c16 = i & 7;
                const uint32_t dsw = SWZ((uint32_t)(row * 128 + c16 * 16));
                const size_t src = ((size_t)b * C_ + h * 64 + row) * N2_ + k0 + c16 * 8;
                CPA16(base + 65536 + dsw, Dh + src);
                CPA16(base + 73728 + dsw, Dl + src);
            }
        }
        CPA_COMMIT();
    };

    load_stage(0);
    load_stage(1);

    if (mode == 0) {
        const int wm = (wid & 3) * 64, wn = (wid >> 2) * 32;
        float acc[4][4][4];
#pragma unroll
        for (int i = 0; i < 4; i++)
#pragma unroll
            for (int j = 0; j < 4; j++)
#pragma unroll
                for (int r = 0; r < 4; r++) acc[i][j][r] = 0.0f;

        for (int ck = 0; ck < 64; ck++) {
            CPA_WAIT1();
            __syncthreads();
            const uint32_t base = sb + (ck & 1) * KVP_STG;
#pragma unroll
            for (int ks = 0; ks < 4; ks++) {
                const int kk = ks * 16;
                uint32_t ah[4][4], al[4][4], bhr[2][4], blr[2][4];
#pragma unroll
                for (int mf = 0; mf < 4; mf++) {
                    const uint32_t ao = SWZ((uint32_t)((wm + mf * 16 + a_row) * 128 + (kk + a_col) * 2));
                    ldsm4(ah[mf], base + ao);
                    ldsm4(al[mf], base + 32768 + ao);
                }
#pragma unroll
                for (int p = 0; p < 2; p++) {
                    const uint32_t bo = SWZ((uint32_t)((wn + p * 16 + b_row) * 128 + (kk + b_col) * 2));
                    ldsm4(bhr[p], base + 65536 + bo);
                    ldsm4(blr[p], base + 73728 + bo);
                }
#pragma unroll
                for (int mf = 0; mf < 4; mf++)
#pragma unroll
                    for (int p = 0; p < 2; p++)
#pragma unroll
                        for (int s = 0; s < 2; s++) {
                            float* c = acc[mf][p * 2 + s];
                            mma_bf16(c, ah[mf], bhr[p][s * 2], bhr[p][s * 2 + 1]);
                            mma_bf16(c, al[mf], bhr[p][s * 2], bhr[p][s * 2 + 1]);
                            mma_bf16(c, ah[mf], blr[p][s * 2], blr[p][s * 2 + 1]);
                        }
            }
            __syncthreads();
            load_stage(ck + 2);
        }
#pragma unroll
        for (int mf = 0; mf < 4; mf++)
#pragma unroll
            for (int hf = 0; hf < 2; hf++) {
                const int p = wm + mf * 16 + hf * 8 + g;
                const float bv = bp[p];
#pragma unroll
                for (int nf = 0; nf < 4; nf++) {
                    const int d = wn + nf * 8 + t4 * 2;
                    uint32_t hi, lo;
                    bsplit2(acc[mf][nf][hf * 2] + bv, acc[mf][nf][hf * 2 + 1] + bv, hi, lo);
                    *(uint32_t*)(g_kpth + (size_t)bh * (P_ * HD_) + p * 64 + d) = hi;
                    *(uint32_t*)(g_kptl + (size_t)bh * (P_ * HD_) + p * 64 + d) = lo;
                }
            }
    } else {
        const int wm = (wid & 1) * 32, wn = (wid >> 1) * 64;
        float acc[2][8][4];
#pragma unroll
        for (int i = 0; i < 2; i++)
#pragma unroll
            for (int j = 0; j < 8; j++)
#pragma unroll
                for (int r = 0; r < 4; r++) acc[i][j][r] = 0.0f;

        for (int ck = 0; ck < 64; ck++) {
            CPA_WAIT1();
            __syncthreads();
            const uint32_t base = sb + (ck & 1) * KVP_STG;
#pragma unroll
            for (int ks = 0; ks < 4; ks++) {
                const int kk = ks * 16;
                uint32_t ah[2][4], al[2][4];
#pragma unroll
                for (int mf = 0; mf < 2; mf++) {
                    const uint32_t ao = SWZ((uint32_t)((wm + mf * 16 + a_row) * 128 + (kk + a_col) * 2));
                    ldsm4(ah[mf], base + 65536 + ao);
                    ldsm4(al[mf], base + 73728 + ao);
                }
#pragma unroll
                for (int p = 0; p < 4; p++) {
                    uint32_t bhr[4], blr[4];
                    const uint32_t bo = SWZ((uint32_t)((wn + p * 16 + b_row) * 128 + (kk + b_col) * 2));
                    ldsm4(bhr, base + bo);
                    ldsm4(blr, base + 32768 + bo);
#pragma unroll
                    for (int mf = 0; mf < 2; mf++)
#pragma unroll
                        for (int s = 0; s < 2; s++) {
                            float* c = acc[mf][p * 2 + s];
                            mma_bf16(c, ah[mf], bhr[s * 2], bhr[s * 2 + 1]);
                            mma_bf16(c, al[mf], bhr[s * 2], bhr[s * 2 + 1]);
                            mma_bf16(c, ah[mf], blr[s * 2], blr[s * 2 + 1]);
                        }
                }
            }
            __syncthreads();
            load_stage(ck + 2);
        }
#pragma unroll
        for (int mf = 0; mf < 2; mf++)
#pragma unroll
            for (int hf = 0; hf < 2; hf++) {
                const int d = wm + mf * 16 + hf * 8 + g;
#pragma unroll
                for (int nf = 0; nf < 8; nf++) {
                    const int p = wn + nf * 8 + t4 * 2;
                    uint32_t hi, lo;
                    bsplit2(acc[mf][nf][hf * 2] + bp[p], acc[mf][nf][hf * 2 + 1] + bp[p + 1], hi, lo);
                    *(uint32_t*)(g_vph + (size_t)bh * (HD_ * P_) + d * 256 + p) = hi;
                    *(uint32_t*)(g_vpl + (size_t)bh * (HD_ * P_) + d * 256 + p) = lo;
                }
            }
    }
}

// ---- attention via bf16x3 HMMA (validated R6/R7) ----
#define A_QH   0
#define A_QL   8192
#define A_KH   16384
#define A_KL   49152
#define A_VH   81920
#define A_VL   114688
#define A_ST   147456
#define A_ZN   149504
#define ATT_SMEM (149504 + 4*64*66*4)

__global__ __launch_bounds__(256, 1)
void attn_mma(const float* __restrict__ temp, float* __restrict__ xa)
{
    extern __shared__ __align__(1024) char sm_raw[];
    const uint32_t sb = smem_u32(sm_raw);
    const int tid = threadIdx.x, wid = tid >> 5, lane = tid & 31;
    const int g = lane >> 2, t4 = lane & 3;
    const int bh = blockIdx.x, b = bh >> 3, h = bh & 7;
    const int q0 = blockIdx.y * 64;
    const int wm = (wid & 1) * 32, zn = wid >> 1, wn = zn * 64;

#pragma unroll
    for (int t = 0; t < 2; t++) {
        const int i = tid + t * 256;
        const int row = i >> 3, c16 = i & 7;
        const uint32_t dsw = SWZ((uint32_t)(row * 128 + c16 * 16));
        const size_t src = (size_t)(b * N1_ + q0 + row) * C_ + h * 64 + c16 * 8;
        CPA16(sb + A_QH + dsw, g_qh + src);
        CPA16(sb + A_QL + dsw, g_ql + src);
    }
#pragma unroll
    for (int t = 0; t < 8; t++) {
        const int i = tid + t * 256;
        const int row = i >> 3, c16 = i & 7;
        const uint32_t dsw = SWZ((uint32_t)(row * 128 + c16 * 16));
        const size_t src = (size_t)bh * (P_ * HD_) + row * 64 + c16 * 8;
        CPA16(sb + A_KH + dsw, g_kpth + src);
        CPA16(sb + A_KL + dsw, g_kptl + src);
    }
#pragma unroll
    for (int t = 0; t < 8; t++) {
        const int i = tid + t * 256;
        const int c16 = i & 7, d = (i >> 3) & 63, ch = i >> 9;
        const uint32_t dsw = (uint32_t)(ch * 8192) + SWZ((uint32_t)(d * 128 + c16 * 16));
        const size_t src = (size_t)bh * (HD_ * P_) + d * 256 + ch * 64 + c16 * 8;
        CPA16(sb + A_VH + dsw, g_vph + src);
        CPA16(sb + A_VL + dsw, g_vpl + src);
    }
    CPA_COMMIT();
    CPA_WAIT0();
    __syncthreads();

    const int a_row = ((lane >> 3) & 1) * 8 + (lane & 7);
    const int a_col = (lane >> 4) * 8;
    const int b_row = (lane >> 4) * 8 + (lane & 7);
    const int b_col = ((lane >> 3) & 1) * 8;

    float acc[2][8][4];
#pragma unroll
    for (int i = 0; i < 2; i++)
#pragma unroll
        for (int j = 0; j < 8; j++)
#pragma unroll
            for (int r = 0; r < 4; r++) acc[i][j][r] = 0.0f;

#pragma unroll
    for (int ks = 0; ks < 4; ks++) {
        const int kk = ks * 16;
        uint32_t ah[2][4], al[2][4];
#pragma unroll
        for (int mf = 0; mf < 2; mf++) {
            const uint32_t ao = SWZ((uint32_t)((wm + mf * 16 + a_row) * 128 + (kk + a_col) * 2));
            ldsm4(ah[mf], sb + A_QH + ao);
            ldsm4(al[mf], sb + A_QL + ao);
        }
#pragma unroll
        for (int p = 0; p < 4; p++) {
            uint32_t bhr[4], blr[4];
            const uint32_t bo = SWZ((uint32_t)((wn + p * 16 + b_row) * 128 + (kk + b_col) * 2));
            ldsm4(bhr, sb + A_KH + bo);
            ldsm4(blr, sb + A_KL + bo);
#pragma unroll
            for (int mf = 0; mf < 2; mf++)
#pragma unroll
                for (int s = 0; s < 2; s++) {
                    float* c = acc[mf][p * 2 + s];
                    mma_bf16(c, ah[mf], bhr[s * 2], bhr[s * 2 + 1]);
                    mma_bf16(c, al[mf], bhr[s * 2], bhr[s * 2 + 1]);
                    mma_bf16(c, ah[mf], blr[s * 2], blr[s * 2 + 1]);
                }
        }
    }

    const float tscale = temp[h];
    float* smax = (float*)(sm_raw + A_ST);
    float* ssum = smax + 256;
#pragma unroll
    for (int mf = 0; mf < 2; mf++)
#pragma unroll
        for (int nf = 0; nf < 8; nf++)
#pragma unroll
            for (int r = 0; r < 4; r++) acc[mf][nf][r] *= tscale;

    float rmx[2][2] = {{-1e30f, -1e30f}, {-1e30f, -1e30f}};
#pragma unroll
    for (int mf = 0; mf < 2; mf++)
#pragma unroll
        for (int nf = 0; nf < 8; nf++) {
            rmx[mf][0] = fmaxf(rmx[mf][0], fmaxf(acc[mf][nf][0], acc[mf][nf][1]));
            rmx[mf][1] = fmaxf(rmx[mf][1], fmaxf(acc[mf][nf][2], acc[mf][nf][3]));
        }
#pragma unroll
    for (int mf = 0; mf < 2; mf++)
#pragma unroll
        for (int hf = 0; hf < 2; hf++) {
            rmx[mf][hf] = fmaxf(rmx[mf][hf], __shfl_xor_sync(~0u, rmx[mf][hf], 1));
            rmx[mf][hf] = fmaxf(rmx[mf][hf], __shfl_xor_sync(~0u, rmx[mf][hf], 2));
        }
    if (t4 == 0)
#pragma unroll
        for (int mf = 0; mf < 2; mf++)
#pragma unroll
            for (int hf = 0; hf < 2; hf++)
                smax[(wm + mf * 16 + hf * 8 + g) * 4 + zn] = rmx[mf][hf];
    __syncthreads();
    float gmx[2][2], rsm[2][2] = {{0, 0}, {0, 0}};
#pragma unroll
    for (int mf = 0; mf < 2; mf++)
#pragma unroll
        for (int hf = 0; hf < 2; hf++) {
            const int r = wm + mf * 16 + hf * 8 + g;
            gmx[mf][hf] = fmaxf(fmaxf(smax[r * 4], smax[r * 4 + 1]),
                                fmaxf(smax[r * 4 + 2], smax[r * 4 + 3]));
        }
#pragma unroll
    for (int mf = 0; mf < 2; mf++)
#pragma unroll
        for (int nf = 0; nf < 8; nf++)
#pragma unroll
            for (int r = 0; r < 4; r++) {
                const int hf = r >> 1;
                const float e = __expf(acc[mf][nf][r] - gmx[mf][hf]);
                acc[mf][nf][r] = e;
                rsm[mf][hf] += e;
            }
#pragma unroll
    for (int mf = 0; mf < 2; mf++)
#pragma unroll
        for (int hf = 0; hf < 2; hf++) {
            rsm[mf][hf] += __shfl_xor_sync(~0u, rsm[mf][hf], 1);
            rsm[mf][hf] += __shfl_xor_sync(~0u, rsm[mf][hf], 2);
        }
    if (t4 == 0)
#pragma unroll
        for (int mf = 0; mf < 2; mf++)
#pragma unroll
            for (int hf = 0; hf < 2; hf++)
                ssum[(wm + mf * 16 + hf * 8 + g) * 4 + zn] = rsm[mf][hf];
    __syncthreads();
#pragma unroll
    for (int mf = 0; mf < 2; mf++)
#pragma unroll
        for (int hf = 0; hf < 2; hf++) {
            const int r = wm + mf * 16 + hf * 8 + g;
            const float inv = 1.0f / (ssum[r * 4] + ssum[r * 4 + 1] + ssum[r * 4 + 2] + ssum[r * 4 + 3]);
#pragma unroll
            for (int nf = 0; nf < 8; nf++) {
                acc[mf][nf][hf * 2]     *= inv;
                acc[mf][nf][hf * 2 + 1] *= inv;
            }
        }

    float acc2[2][8][4];
#pragma unroll
    for (int i = 0; i < 2; i++)
#pragma unroll
        for (int j = 0; j < 8; j++)
#pragma unroll
            for (int r = 0; r < 4; r++) acc2[i][j][r] = 0.0f;

#pragma unroll
    for (int kf = 0; kf < 4; kf++) {
        uint32_t pah[2][4], pal[2][4];
#pragma unroll
        for (int mf = 0; mf < 2; mf++) {
            bsplit2(acc[mf][2*kf][0],   acc[mf][2*kf][1],   pah[mf][0], pal[mf][0]);
            bsplit2(acc[mf][2*kf][2],   acc[mf][2*kf][3],   pah[mf][1], pal[mf][1]);
            bsplit2(acc[mf][2*kf+1][0], acc[mf][2*kf+1][1], pah[mf][2], pal[mf][2]);
            bsplit2(acc[mf][2*kf+1][2], acc[mf][2*kf+1][3], pah[mf][3], pal[mf][3]);
        }
#pragma unroll
        for (int df = 0; df < 4; df++) {
            uint32_t bhr[4], blr[4];
            const uint32_t bo = (uint32_t)(zn * 8192) +
                SWZ((uint32_t)((df * 16 + b_row) * 128 + (kf * 16 + b_col) * 2));
            ldsm4(bhr, sb + A_VH + bo);
            ldsm4(blr, sb + A_VL + bo);
#pragma unroll
            for (int mf = 0; mf < 2; mf++)
#pragma unroll
                for (int s = 0; s < 2; s++) {
                    float* c = acc2[mf][df * 2 + s];
                    mma_bf16(c, pah[mf], bhr[s * 2], bhr[s * 2 + 1]);
                    mma_bf16(c, pal[mf], bhr[s * 2], bhr[s * 2 + 1]);
                    mma_bf16(c, pah[mf], blr[s * 2], blr[s * 2 + 1]);
                }
        }
    }

    float* zone = (float*)(sm_raw + A_ZN) + zn * (64 * 66);
#pragma unroll
    for (int mf = 0; mf < 2; mf++)
#pragma unroll
        for (int nf = 0; nf < 8; nf++)
#pragma unroll
            for (int hf = 0; hf < 2; hf++) {
                const int row = wm + mf * 16 + hf * 8 + g;
                const int dc = nf * 8 + t4 * 2;
                *(float2*)&zone[row * 66 + dc] =
                    make_float2(acc2[mf][nf][hf * 2], acc2[mf][nf][hf * 2 + 1]);
            }
    __syncthreads();

    const int tx = tid & 15, ty = tid >> 4;
    float* z0 = (float*)(sm_raw + A_ZN);
    const size_t base = (size_t)b * (N1_ * C_) + (size_t)h * N1_ + q0 + tx * 4;
#pragma unroll
    for (int j = 0; j < 4; j++) {
        const int d = ty * 4 + j;
        float o[4];
#pragma unroll
        for (int qi = 0; qi < 4; qi++) {
            const int idx = (tx * 4 + qi) * 66 + d;
            o[qi] = z0[idx] + z0[64*66 + idx] + z0[2*64*66 + idx] + z0[3*64*66 + idx];
        }
        *(float4*)&xa[base + (size_t)d * (H_ * N1_)] = make_float4(o[0], o[1], o[2], o[3]);
    }
}

// ---- L2 norm + optional bf16 split ----
__global__ __launch_bounds__(256)
void l2n_k(const float* __restrict__ a, const float* __restrict__ bb,
           float* __restrict__ out, u16* __restrict__ oh, u16* __restrict__ ol)
{
    const int row = blockIdx.x * 8 + (threadIdx.x >> 5);
    const int lane = threadIdx.x & 31;
    const float4* pa = (const float4*)(a + (size_t)row * C_);
    const float4* pb = bb ? (const float4*)(bb + (size_t)row * C_) : nullptr;
    float4 v[4];
    float ss = 0.0f;
#pragma unroll
    for (int i = 0; i < 4; i++) {
        float4 t = pa[lane + 32 * i];
        if (pb) {
            float4 u = pb[lane + 32 * i];
            t.x += u.x; t.y += u.y; t.z += u.z; t.w += u.w;
        }
        v[i] = t;
        ss += t.x * t.x + t.y * t.y + t.z * t.z + t.w * t.w;
    }
#pragma unroll
    for (int o = 16; o > 0; o >>= 1) ss += __shfl_xor_sync(~0u, ss, o);
    const float inv = 1.0f / fmaxf(sqrtf(ss), 1e-12f);
    float4* po = (float4*)(out + (size_t)row * C_);
#pragma unroll
    for (int i = 0; i < 4; i++) {
        v[i].x *= inv; v[i].y *= inv; v[i].z *= inv; v[i].w *= inv;
        po[lane + 32 * i] = v[i];
        if (oh) {
            uint32_t a0, b0, c0, d0;
            bsplit2(v[i].x, v[i].y, a0, c0); bsplit2(v[i].z, v[i].w, b0, d0);
            const size_t off = (size_t)row * C_ + (lane + 32 * i) * 4;
            *(uint2*)(oh + off) = make_uint2(a0, b0);
            *(uint2*)(ol + off) = make_uint2(c0, d0);
        }
    }
}

extern "C" void kernel_launch(void* const* d_in, const int* in_sizes, int n_in,
                              void* d_out, int out_size)
{
    const float* x1    = (const float*)d_in[0];
    const float* x2    = (const float*)d_in[1];
    const float* Wq    = (const float*)d_in[2];
    const float* bq    = (const float*)d_in[3];
    const float* Wkv   = (const float*)d_in[4];
    const float* bkv   = (const float*)d_in[5];
    const float* Wp    = (const float*)d_in[6];
    const float* bp    = (const float*)d_in[7];
    const float* pos_q = (const float*)d_in[8];
    const float* pos_k = (const float*)d_in[9];
    const float* temp  = (const float*)d_in[10];
    const float* W1    = (const float*)d_in[11];
    const float* b1    = (const float*)d_in[12];
    const float* W2    = (const float*)d_in[13];
    const float* b2    = (const float*)d_in[14];

    float *q, *k, *v;
    u16 *x1h, *x1l, *x2h, *x2l, *xnh, *xnl, *hh, *hl;
    u16 *wqh, *wql, *wkvh, *wkvl, *w1h, *w1l, *w2h, *w2l, *wpth, *wptl;
    cudaGetSymbolAddress((void**)&q, g_q);
    cudaGetSymbolAddress((void**)&k, g_k);
    cudaGetSymbolAddress((void**)&v, g_v);
    cudaGetSymbolAddress((void**)&x1h, g_x1h); cudaGetSymbolAddress((void**)&x1l, g_x1l);
    cudaGetSymbolAddress((void**)&x2h, g_x2h); cudaGetSymbolAddress((void**)&x2l, g_x2l);
    cudaGetSymbolAddress((void**)&xnh, g_xnh); cudaGetSymbolAddress((void**)&xnl, g_xnl);
    cudaGetSymbolAddress((void**)&hh, g_hh);   cudaGetSymbolAddress((void**)&hl, g_hl);
    cudaGetSymbolAddress((void**)&wqh, g_wq_hi);   cudaGetSymbolAddress((void**)&wql, g_wq_lo);
    cudaGetSymbolAddress((void**)&wkvh, g_wkv_hi); cudaGetSymbolAddress((void**)&wkvl, g_wkv_lo);
    cudaGetSymbolAddress((void**)&w1h, g_w1_hi);   cudaGetSymbolAddress((void**)&w1l, g_w1_lo);
    cudaGetSymbolAddress((void**)&w2h, g_w2_hi);   cudaGetSymbolAddress((void**)&w2l, g_w2_lo);
    cudaGetSymbolAddress((void**)&wpth, g_wpth);   cudaGetSymbolAddress((void**)&wptl, g_wptl);
    float* xa = k;
    float* xn = v;

    cudaFuncSetAttribute(attn_mma, cudaFuncAttributeMaxDynamicSharedMemorySize, ATT_SMEM);
    cudaFuncSetAttribute(kvp_mma,  cudaFuncAttributeMaxDynamicSharedMemorySize, KVP_SMEM);
    cudaFuncSetAttribute(tgemm<0>, cudaFuncAttributeMaxDynamicSharedMemorySize, TG_SMEM);
    cudaFuncSetAttribute(tgemm<1>, cudaFuncAttributeMaxDynamicSharedMemorySize, TG_SMEM);
    cudaFuncSetAttribute(tgemm<2>, cudaFuncAttributeMaxDynamicSharedMemorySize, TG_SMEM);
    cudaFuncSetAttribute(tgemm<3>, cudaFuncAttributeMaxDynamicSharedMemorySize, TG_SMEM);

    wsplit_k<<<dim3(C_ / 32, C_ / 32), 256>>>(Wq, wqh, wql, C_, C_);
    wsplit_k<<<dim3(2 * C_ / 32, C_ / 32), 256>>>(Wkv, wkvh, wkvl, C_, 2 * C_);
    wsplit_k<<<dim3(MLP_ / 32, C_ / 32), 256>>>(W1, w1h, w1l, C_, MLP_);
    wsplit_k<<<dim3(C_ / 32, MLP_ / 32), 256>>>(W2, w2h, w2l, MLP_, C_);
    wsplit_k<<<dim3(P_ / 32, N2_ / 32), 256>>>(Wp, wpth, wptl, N2_, P_);
    asplit_k<<<(M_ * C_) / 1024, 256>>>(x1, x1h, x1l);
    asplit_k<<<(M_ * C_) / 1024, 256>>>(x2, x2h, x2l);

    tgemm<0><<<dim3(C_ / 128, M_ / 128), 256, TG_SMEM>>>(
        x1h, x1l, wqh, wql, bq, pos_q, q, nullptr, M_, C_, C_);
    // kv: writes kT/vT bf16-split transposed directly from epilogue
    tgemm<1><<<dim3(2 * C_ / 128, M_ / 128), 256, TG_SMEM>>>(
        x2h, x2l, wkvh, wkvl, bkv, pos_k, nullptr, nullptr, M_, 2 * C_, C_);
    kvp_mma<<<dim3(B_ * H_, 2), 256, KVP_SMEM>>>(bp);
    attn_mma<<<dim3(B_ * H_, N1_ / 64), 256, ATT_SMEM>>>(temp, xa);
    l2n_k<<<M_ / 8, 256>>>(xa, q, xn, xnh, xnl);
    tgemm<2><<<dim3(MLP_ / 128, M_ / 128), 256, TG_SMEM>>>(
        xnh, xnl, w1h, w1l, b1, nullptr, hh, hl, M_, MLP_, C_);
    tgemm<3><<<dim3(C_ / 128, M_ / 128), 256, TG_SMEM>>>(
        hh, hl, w2h, w2l, b2, xn, xa, nullptr, M_, C_, MLP_);
    l2n_k<<<M_ / 8, 256>>>(xa, nullptr, (float*)d_out, nullptr, nullptr);
}

// round 10
// speedup vs baseline: 2.2473x; 1.0103x over previous
#include <cuda_runtime.h>
#include <math.h>
#include <stdint.h>

#define B_   8
#define N1_  4096
#define N2_  4096
#define C_   512
#define P_   256
#define H_   8
#define HD_  64
#define MLP_ 2048
#define M_   (B_*N1_)

typedef unsigned short u16;

__device__ float g_xa[M_*C_];     // attn out / pre-final scratch
__device__ float g_xn[M_*C_];
__device__ u16 g_qh [M_*C_],  g_ql [M_*C_];
__device__ u16 g_x1h[M_*C_],  g_x1l[M_*C_];
__device__ u16 g_x2h[M_*C_],  g_x2l[M_*C_];
__device__ u16 g_xnh[M_*C_],  g_xnl[M_*C_];
__device__ u16 g_hh [M_*MLP_], g_hl [M_*MLP_];
__device__ u16 g_kTh[B_*C_*N2_], g_kTl[B_*C_*N2_];          // kT [b][c][n]
__device__ u16 g_vTh[B_*C_*N2_], g_vTl[B_*C_*N2_];
__device__ u16 g_kpth[B_*H_*P_*HD_], g_kptl[B_*H_*P_*HD_];  // kp^T [bh][p][d]
__device__ u16 g_vph [B_*H_*HD_*P_], g_vpl [B_*H_*HD_*P_];  // vp   [bh][d][p]
__device__ u16 g_wq_hi [C_*C_],   g_wq_lo [C_*C_];
__device__ u16 g_wkv_hi[2*C_*C_], g_wkv_lo[2*C_*C_];
__device__ u16 g_w1_hi [MLP_*C_], g_w1_lo [MLP_*C_];
__device__ u16 g_w2_hi [C_*MLP_], g_w2_lo [C_*MLP_];
__device__ u16 g_wpth  [P_*N2_],  g_wptl  [P_*N2_];         // WpT [p][n]

__device__ __forceinline__ uint32_t smem_u32(const void* p) {
    uint32_t a;
    asm("{ .reg .u64 t; cvta.to.shared.u64 t, %1; cvt.u32.u64 %0, t; }" : "=r"(a) : "l"(p));
    return a;
}
#define SWZ(b) ((b) ^ (((b) >> 3) & 0x70))
#define CPA16(dst, src) asm volatile("cp.async.cg.shared.global [%0], [%1], 16;" :: "r"(dst), "l"(src))
#define CPA_COMMIT() asm volatile("cp.async.commit_group;" ::: "memory")
#define CPA_WAIT1()  asm volatile("cp.async.wait_group 1;" ::: "memory")
#define CPA_WAIT0()  asm volatile("cp.async.wait_group 0;" ::: "memory")

__device__ __forceinline__ void ldsm4(uint32_t* r, uint32_t a) {
    asm volatile("ldmatrix.sync.aligned.m8n8.x4.shared.b16 {%0,%1,%2,%3}, [%4];"
                 : "=r"(r[0]), "=r"(r[1]), "=r"(r[2]), "=r"(r[3]) : "r"(a));
}
__device__ __forceinline__ void mma_bf16(float* c, const uint32_t* a, uint32_t b0, uint32_t b1) {
    asm volatile("mma.sync.aligned.m16n8k16.row.col.f32.bf16.bf16.f32 "
        "{%0,%1,%2,%3}, {%4,%5,%6,%7}, {%8,%9}, {%0,%1,%2,%3};"
        : "+f"(c[0]), "+f"(c[1]), "+f"(c[2]), "+f"(c[3])
        : "r"(a[0]), "r"(a[1]), "r"(a[2]), "r"(a[3]), "r"(b0), "r"(b1));
}
__device__ __forceinline__ void bsplit(float a, uint32_t& hi, uint32_t& lo) {
    uint32_t u = __float_as_uint(a);
    uint32_t hr = (u + 0x7fffu + ((u >> 16) & 1u)) & 0xffff0000u;
    hi = hr >> 16;
    float l = a - __uint_as_float(hr);
    uint32_t ul = __float_as_uint(l);
    lo = (ul + 0x7fffu + ((ul >> 16) & 1u)) >> 16;
}
__device__ __forceinline__ void bsplit2(float a, float b, uint32_t& hi, uint32_t& lo) {
    uint32_t h0, l0, h1, l1;
    bsplit(a, h0, l0); bsplit(b, h1, l1);
    hi = h0 | (h1 << 16); lo = l0 | (l1 << 16);
}

// transpose+split: W[K][N] fp32 -> Wt[N][K] hi/lo bf16
__global__ __launch_bounds__(256)
void wsplit_k(const float* __restrict__ W, u16* __restrict__ hi, u16* __restrict__ lo, int K, int N)
{
    __shared__ float tile[32][33];
    const int n0 = blockIdx.x * 32, k0 = blockIdx.y * 32;
    const int tx = threadIdx.x & 31, ty = threadIdx.x >> 5;
#pragma unroll
    for (int r = 0; r < 4; r++)
        tile[ty + 8 * r][tx] = W[(size_t)(k0 + ty + 8 * r) * N + n0 + tx];
    __syncthreads();
#pragma unroll
    for (int r = 0; r < 4; r++) {
        const int n = n0 + ty + 8 * r, k = k0 + tx;
        uint32_t h, l;
        bsplit(tile[tx][ty + 8 * r], h, l);
        hi[(size_t)n * K + k] = (u16)h;
        lo[(size_t)n * K + k] = (u16)l;
    }
}

__global__ __launch_bounds__(256)
void asplit_k(const float* __restrict__ A, u16* __restrict__ hi, u16* __restrict__ lo)
{
    const size_t i4 = ((size_t)blockIdx.x * 256 + threadIdx.x) * 4;
    float4 f = *(const float4*)(A + i4);
    uint32_t a, b, c, d;
    bsplit2(f.x, f.y, a, c); bsplit2(f.z, f.w, b, d);
    *(uint2*)(hi + i4) = make_uint2(a, b);
    *(uint2*)(lo + i4) = make_uint2(c, d);
}

// ---- bf16x3 HMMA GEMM, 128x128 tile, 3-stage cp.async ----
// EPI 0: q -> qh/ql split only (+bias+pos_q)
// EPI 1: k/v -> TRANSPOSED bf16 split kT/vT (k gets +pos_k); via smem tile
// EPI 2: gelu -> bf16 split
// EPI 3: fp32 out = acc + bias + extra
#define TG_SMEM (3 * 65536)
template<int EPI>
__global__ __launch_bounds__(256, 1)
void tgemm(const u16* __restrict__ Ahi, const u16* __restrict__ Alo,
           const u16* __restrict__ Bhi, const u16* __restrict__ Blo,
           const float* __restrict__ bias, const float* __restrict__ extra,
           void* __restrict__ out, void* __restrict__ out2, int M, int N, int K)
{
    extern __shared__ __align__(1024) char sm_raw[];
    const uint32_t sb = smem_u32(sm_raw);
    const int tid = threadIdx.x, wid = tid >> 5, lane = tid & 31;
    const int bm = blockIdx.y * 128, bn = blockIdx.x * 128;
    const int wm = (wid & 1) * 64, wn = (wid >> 1) * 32;
    const int nck = K >> 6;

    float acc[4][4][4];
#pragma unroll
    for (int i = 0; i < 4; i++)
#pragma unroll
        for (int j = 0; j < 4; j++)
#pragma unroll
            for (int r = 0; r < 4; r++) acc[i][j][r] = 0.0f;

    const int a_row = ((lane >> 3) & 1) * 8 + (lane & 7);
    const int a_col = (lane >> 4) * 8;
    const int b_row = (lane >> 4) * 8 + (lane & 7);
    const int b_col = ((lane >> 3) & 1) * 8;

    auto load_stage = [&](int ck, int stage) {
        if (ck < nck) {
            const int k0 = ck * 64;
            const uint32_t sbase = sb + stage * 65536;
#pragma unroll
            for (int i = 0; i < 4; i++) {
                const int id = tid + i * 256;
                const int row = id >> 3, c16 = id & 7;
                const uint32_t dsw = SWZ((uint32_t)(row * 128 + c16 * 16));
                const size_t asrc = (size_t)(bm + row) * K + k0 + c16 * 8;
                const size_t bsrc = (size_t)(bn + row) * K + k0 + c16 * 8;
                CPA16(sbase + dsw,         Ahi + asrc);
                CPA16(sbase + 16384 + dsw, Alo + asrc);
                CPA16(sbase + 32768 + dsw, Bhi + bsrc);
                CPA16(sbase + 49152 + dsw, Blo + bsrc);
            }
        }
        CPA_COMMIT();
    };

    load_stage(0, 0);
    load_stage(1, 1);

    for (int ck = 0; ck < nck; ck++) {
        CPA_WAIT1();
        __syncthreads();
        load_stage(ck + 2, (ck + 2) % 3);
        const uint32_t base = sb + (ck % 3) * 65536;
#pragma unroll
        for (int ks = 0; ks < 4; ks++) {
            const int kk = ks * 16;
            uint32_t ah[4][4], al[4][4], bh[2][4], bl[2][4];
#pragma unroll
            for (int mf = 0; mf < 4; mf++) {
                const uint32_t ao = SWZ((uint32_t)((wm + mf * 16 + a_row) * 128 + (kk + a_col) * 2));
                ldsm4(ah[mf], base + ao);
                ldsm4(al[mf], base + 16384 + ao);
            }
#pragma unroll
            for (int p = 0; p < 2; p++) {
                const uint32_t bo = SWZ((uint32_t)((wn + p * 16 + b_row) * 128 + (kk + b_col) * 2));
                ldsm4(bh[p], base + 32768 + bo);
                ldsm4(bl[p], base + 49152 + bo);
            }
#pragma unroll
            for (int mf = 0; mf < 4; mf++)
#pragma unroll
                for (int p = 0; p < 2; p++)
#pragma unroll
                    for (int s = 0; s < 2; s++) {
                        float* c = acc[mf][p * 2 + s];
                        mma_bf16(c, ah[mf], bh[p][s * 2], bh[p][s * 2 + 1]);
                        mma_bf16(c, al[mf], bh[p][s * 2], bh[p][s * 2 + 1]);
                        mma_bf16(c, ah[mf], bl[p][s * 2], bl[p][s * 2 + 1]);
                    }
        }
    }

    const int l4 = lane >> 2, l2 = (lane & 3) * 2;

    if (EPI == 1) {
        CPA_WAIT0();
        __syncthreads();
        float* T = (float*)sm_raw;                       // 128 x 132 floats
        const bool is_k = (bn < C_);
#pragma unroll
        for (int mf = 0; mf < 4; mf++)
#pragma unroll
            for (int nf = 0; nf < 4; nf++) {
                const int colL = wn + nf * 8 + l2;
                const int col = bn + colL;
                const float bia0 = bias[col], bia1 = bias[col + 1];
#pragma unroll
                for (int half = 0; half < 2; half++) {
                    const int mL = wm + mf * 16 + l4 + half * 8;
                    float v0 = acc[mf][nf][half * 2]     + bia0;
                    float v1 = acc[mf][nf][half * 2 + 1] + bia1;
                    if (is_k) {
                        const int n = (bm + mL) & (N2_ - 1);
                        v0 += extra[(size_t)n * C_ + col];
                        v1 += extra[(size_t)n * C_ + col + 1];
                    }
                    T[colL * 132 + mL]       = v0;
                    T[(colL + 1) * 132 + mL] = v1;
                }
            }
        __syncthreads();
        u16* __restrict__ dh = is_k ? g_kTh : g_vTh;
        u16* __restrict__ dl = is_k ? g_kTl : g_vTl;
        const int bb = bm >> 12, n0 = bm & (N2_ - 1);
        const int r = tid >> 1, hh2 = (tid & 1) * 64;
        const int c = (bn + r) - (is_k ? 0 : C_);
        const size_t gbase = ((size_t)bb * C_ + c) * N2_ + n0 + hh2;
        const float* Tr = T + r * 132 + hh2;
#pragma unroll
        for (int j = 0; j < 64; j += 8) {
            uint32_t h0, l0, h1, l1, h2, l2x, h3, l3;
            bsplit2(Tr[j],     Tr[j + 1], h0, l0);
            bsplit2(Tr[j + 2], Tr[j + 3], h1, l1);
            bsplit2(Tr[j + 4], Tr[j + 5], h2, l2x);
            bsplit2(Tr[j + 6], Tr[j + 7], h3, l3);
            *(uint4*)(dh + gbase + j) = make_uint4(h0, h1, h2, h3);
            *(uint4*)(dl + gbase + j) = make_uint4(l0, l1, l2x, l3);
        }
        return;
    }

#pragma unroll
    for (int mf = 0; mf < 4; mf++)
#pragma unroll
        for (int nf = 0; nf < 4; nf++) {
            const int col = bn + wn + nf * 8 + l2;
            const float bia0 = bias[col], bia1 = bias[col + 1];
#pragma unroll
            for (int half = 0; half < 2; half++) {
                const int m = bm + wm + mf * 16 + l4 + half * 8;
                float v0 = acc[mf][nf][half * 2]     + bia0;
                float v1 = acc[mf][nf][half * 2 + 1] + bia1;
                if (EPI == 0) {
                    v0 += extra[(size_t)(m & (N1_ - 1)) * C_ + col];
                    v1 += extra[(size_t)(m & (N1_ - 1)) * C_ + col + 1];
                    uint32_t hi, lo;
                    bsplit2(v0, v1, hi, lo);
                    *(uint32_t*)(g_qh + (size_t)m * N + col) = hi;
                    *(uint32_t*)(g_ql + (size_t)m * N + col) = lo;
                } else if (EPI == 2) {
                    v0 = 0.5f * v0 * (1.0f + erff(v0 * 0.70710678118654752f));
                    v1 = 0.5f * v1 * (1.0f + erff(v1 * 0.70710678118654752f));
                    uint32_t hi, lo;
                    bsplit2(v0, v1, hi, lo);
                    *(uint32_t*)((u16*)out  + (size_t)m * N + col) = hi;
                    *(uint32_t*)((u16*)out2 + (size_t)m * N + col) = lo;
                } else {
                    v0 += extra[(size_t)m * N + col];
                    v1 += extra[(size_t)m * N + col + 1];
                    *(float2*)((float*)out + (size_t)m * N + col) = make_float2(v0, v1);
                }
            }
        }
}

// ---- kvp via bf16x3 HMMA (validated R7) ----
#define KVP_STG  81920
#define KVP_SMEM (2 * KVP_STG)
__global__ __launch_bounds__(256, 1)
void kvp_mma(const float* __restrict__ bp)
{
    extern __shared__ __align__(1024) char sm_raw[];
    const uint32_t sb = smem_u32(sm_raw);
    const int tid = threadIdx.x, wid = tid >> 5, lane = tid & 31;
    const int g = lane >> 2, t4 = lane & 3;
    const int bh = blockIdx.x, b = bh >> 3, h = bh & 7;
    const int mode = blockIdx.y;
    const u16* __restrict__ Dh = mode ? g_vTh : g_kTh;
    const u16* __restrict__ Dl = mode ? g_vTl : g_kTl;

    const int a_row = ((lane >> 3) & 1) * 8 + (lane & 7);
    const int a_col = (lane >> 4) * 8;
    const int b_row = (lane >> 4) * 8 + (lane & 7);
    const int b_col = ((lane >> 3) & 1) * 8;

    auto load_stage = [&](int ck) {
        if (ck < 64) {
            const uint32_t base = sb + (ck & 1) * KVP_STG;
            const int k0 = ck * 64;
#pragma unroll
            for (int t = 0; t < 8; t++) {
                const int i = tid + t * 256;
                const int row = i >> 3, c16 = i & 7;
                const uint32_t dsw = SWZ((uint32_t)(row * 128 + c16 * 16));
                const size_t src = (size_t)row * N2_ + k0 + c16 * 8;
                CPA16(base + dsw,         g_wpth + src);
                CPA16(base + 32768 + dsw, g_wptl + src);
            }
#pragma unroll
            for (int t = 0; t < 2; t++) {
                const int i = tid + t * 256;
                const int row = i >> 3, c16 = i & 7;
                const uint32_t dsw = SWZ((uint32_t)(row * 128 + c16 * 16));
                const size_t src = ((size_t)b * C_ + h * 64 + row) * N2_ + k0 + c16 * 8;
                CPA16(base + 65536 + dsw, Dh + src);
                CPA16(base + 73728 + dsw, Dl + src);
            }
        }
        CPA_COMMIT();
    };

    load_stage(0);
    load_stage(1);

    if (mode == 0) {
        const int wm = (wid & 3) * 64, wn = (wid >> 2) * 32;
        float acc[4][4][4];
#pragma unroll
        for (int i = 0; i < 4; i++)
#pragma unroll
            for (int j = 0; j < 4; j++)
#pragma unroll
                for (int r = 0; r < 4; r++) acc[i][j][r] = 0.0f;

        for (int ck = 0; ck < 64; ck++) {
            CPA_WAIT1();
            __syncthreads();
            const uint32_t base = sb + (ck & 1) * KVP_STG;
#pragma unroll
            for (int ks = 0; ks < 4; ks++) {
                const int kk = ks * 16;
                uint32_t ah[4][4], al[4][4], bhr[2][4], blr[2][4];
#pragma unroll
                for (int mf = 0; mf < 4; mf++) {
                    const uint32_t ao = SWZ((uint32_t)((wm + mf * 16 + a_row) * 128 + (kk + a_col) * 2));
                    ldsm4(ah[mf], base + ao);
                    ldsm4(al[mf], base + 32768 + ao);
                }
#pragma unroll
                for (int p = 0; p < 2; p++) {
                    const uint32_t bo = SWZ((uint32_t)((wn + p * 16 + b_row) * 128 + (kk + b_col) * 2));
                    ldsm4(bhr[p], base + 65536 + bo);
                    ldsm4(blr[p], base + 73728 + bo);
                }
#pragma unroll
                for (int mf = 0; mf < 4; mf++)
#pragma unroll
                    for (int p = 0; p < 2; p++)
#pragma unroll
                        for (int s = 0; s < 2; s++) {
                            float* c = acc[mf][p * 2 + s];
                            mma_bf16(c, ah[mf], bhr[p][s * 2], bhr[p][s * 2 + 1]);
                            mma_bf16(c, al[mf], bhr[p][s * 2], bhr[p][s * 2 + 1]);
                            mma_bf16(c, ah[mf], blr[p][s * 2], blr[p][s * 2 + 1]);
                        }
            }
            __syncthreads();
            load_stage(ck + 2);
        }
#pragma unroll
        for (int mf = 0; mf < 4; mf++)
#pragma unroll
            for (int hf = 0; hf < 2; hf++) {
                const int p = wm + mf * 16 + hf * 8 + g;
                const float bv = bp[p];
#pragma unroll
                for (int nf = 0; nf < 4; nf++) {
                    const int d = wn + nf * 8 + t4 * 2;
                    uint32_t hi, lo;
                    bsplit2(acc[mf][nf][hf * 2] + bv, acc[mf][nf][hf * 2 + 1] + bv, hi, lo);
                    *(uint32_t*)(g_kpth + (size_t)bh * (P_ * HD_) + p * 64 + d) = hi;
                    *(uint32_t*)(g_kptl + (size_t)bh * (P_ * HD_) + p * 64 + d) = lo;
                }
            }
    } else {
        const int wm = (wid & 1) * 32, wn = (wid >> 1) * 64;
        float acc[2][8][4];
#pragma unroll
        for (int i = 0; i < 2; i++)
#pragma unroll
            for (int j = 0; j < 8; j++)
#pragma unroll
                for (int r = 0; r < 4; r++) acc[i][j][r] = 0.0f;

        for (int ck = 0; ck < 64; ck++) {
            CPA_WAIT1();
            __syncthreads();
            const uint32_t base = sb + (ck & 1) * KVP_STG;
#pragma unroll
            for (int ks = 0; ks < 4; ks++) {
                const int kk = ks * 16;
                uint32_t ah[2][4], al[2][4];
#pragma unroll
                for (int mf = 0; mf < 2; mf++) {
                    const uint32_t ao = SWZ((uint32_t)((wm + mf * 16 + a_row) * 128 + (kk + a_col) * 2));
                    ldsm4(ah[mf], base + 65536 + ao);
                    ldsm4(al[mf], base + 73728 + ao);
                }
#pragma unroll
                for (int p = 0; p < 4; p++) {
                    uint32_t bhr[4], blr[4];
                    const uint32_t bo = SWZ((uint32_t)((wn + p * 16 + b_row) * 128 + (kk + b_col) * 2));
                    ldsm4(bhr, base + bo);
                    ldsm4(blr, base + 32768 + bo);
#pragma unroll
                    for (int mf = 0; mf < 2; mf++)
#pragma unroll
                        for (int s = 0; s < 2; s++) {
                            float* c = acc[mf][p * 2 + s];
                            mma_bf16(c, ah[mf], bhr[s * 2], bhr[s * 2 + 1]);
                            mma_bf16(c, al[mf], bhr[s * 2], bhr[s * 2 + 1]);
                            mma_bf16(c, ah[mf], blr[s * 2], blr[s * 2 + 1]);
                        }
                }
            }
            __syncthreads();
            load_stage(ck + 2);
        }
#pragma unroll
        for (int mf = 0; mf < 2; mf++)
#pragma unroll
            for (int hf = 0; hf < 2; hf++) {
                const int d = wm + mf * 16 + hf * 8 + g;
#pragma unroll
                for (int nf = 0; nf < 8; nf++) {
                    const int p = wn + nf * 8 + t4 * 2;
                    uint32_t hi, lo;
                    bsplit2(acc[mf][nf][hf * 2] + bp[p], acc[mf][nf][hf * 2 + 1] + bp[p + 1], hi, lo);
                    *(uint32_t*)(g_vph + (size_t)bh * (HD_ * P_) + d * 256 + p) = hi;
                    *(uint32_t*)(g_vpl + (size_t)bh * (HD_ * P_) + d * 256 + p) = lo;
                }
            }
    }
}

// ---- attention via bf16x3 HMMA (validated R6-R9) ----
#define A_QH   0
#define A_QL   8192
#define A_KH   16384
#define A_KL   49152
#define A_VH   81920
#define A_VL   114688
#define A_ST   147456
#define A_ZN   149504
#define ATT_SMEM (149504 + 4*64*66*4)

__global__ __launch_bounds__(256, 1)
void attn_mma(const float* __restrict__ temp, float* __restrict__ xa)
{
    extern __shared__ __align__(1024) char sm_raw[];
    const uint32_t sb = smem_u32(sm_raw);
    const int tid = threadIdx.x, wid = tid >> 5, lane = tid & 31;
    const int g = lane >> 2, t4 = lane & 3;
    const int bh = blockIdx.x, b = bh >> 3, h = bh & 7;
    const int q0 = blockIdx.y * 64;
    const int wm = (wid & 1) * 32, zn = wid >> 1, wn = zn * 64;

#pragma unroll
    for (int t = 0; t < 2; t++) {
        const int i = tid + t * 256;
        const int row = i >> 3, c16 = i & 7;
        const uint32_t dsw = SWZ((uint32_t)(row * 128 + c16 * 16));
        const size_t src = (size_t)(b * N1_ + q0 + row) * C_ + h * 64 + c16 * 8;
        CPA16(sb + A_QH + dsw, g_qh + src);
        CPA16(sb + A_QL + dsw, g_ql + src);
    }
#pragma unroll
    for (int t = 0; t < 8; t++) {
        const int i = tid + t * 256;
        const int row = i >> 3, c16 = i & 7;
        const uint32_t dsw = SWZ((uint32_t)(row * 128 + c16 * 16));
        const size_t src = (size_t)bh * (P_ * HD_) + row * 64 + c16 * 8;
        CPA16(sb + A_KH + dsw, g_kpth + src);
        CPA16(sb + A_KL + dsw, g_kptl + src);
    }
#pragma unroll
    for (int t = 0; t < 8; t++) {
        const int i = tid + t * 256;
        const int c16 = i & 7, d = (i >> 3) & 63, ch = i >> 9;
        const uint32_t dsw = (uint32_t)(ch * 8192) + SWZ((uint32_t)(d * 128 + c16 * 16));
        const size_t src = (size_t)bh * (HD_ * P_) + d * 256 + ch * 64 + c16 * 8;
        CPA16(sb + A_VH + dsw, g_vph + src);
        CPA16(sb + A_VL + dsw, g_vpl + src);
    }
    CPA_COMMIT();
    CPA_WAIT0();
    __syncthreads();

    const int a_row = ((lane >> 3) & 1) * 8 + (lane & 7);
    const int a_col = (lane >> 4) * 8;
    const int b_row = (lane >> 4) * 8 + (lane & 7);
    const int b_col = ((lane >> 3) & 1) * 8;

    float acc[2][8][4];
#pragma unroll
    for (int i = 0; i < 2; i++)
#pragma unroll
        for (int j = 0; j < 8; j++)
#pragma unroll
            for (int r = 0; r < 4; r++) acc[i][j][r] = 0.0f;

#pragma unroll
    for (int ks = 0; ks < 4; ks++) {
        const int kk = ks * 16;
        uint32_t ah[2][4], al[2][4];
#pragma unroll
        for (int mf = 0; mf < 2; mf++) {
            const uint32_t ao = SWZ((uint32_t)((wm + mf * 16 + a_row) * 128 + (kk + a_col) * 2));
            ldsm4(ah[mf], sb + A_QH + ao);
            ldsm4(al[mf], sb + A_QL + ao);
        }
#pragma unroll
        for (int p = 0; p < 4; p++) {
            uint32_t bhr[4], blr[4];
            const uint32_t bo = SWZ((uint32_t)((wn + p * 16 + b_row) * 128 + (kk + b_col) * 2));
            ldsm4(bhr, sb + A_KH + bo);
            ldsm4(blr, sb + A_KL + bo);
#pragma unroll
            for (int mf = 0; mf < 2; mf++)
#pragma unroll
                for (int s = 0; s < 2; s++) {
                    float* c = acc[mf][p * 2 + s];
                    mma_bf16(c, ah[mf], bhr[s * 2], bhr[s * 2 + 1]);
                    mma_bf16(c, al[mf], bhr[s * 2], bhr[s * 2 + 1]);
                    mma_bf16(c, ah[mf], blr[s * 2], blr[s * 2 + 1]);
                }
        }
    }

    const float tscale = temp[h];
    float* smax = (float*)(sm_raw + A_ST);
    float* ssum = smax + 256;
#pragma unroll
    for (int mf = 0; mf < 2; mf++)
#pragma unroll
        for (int nf = 0; nf < 8; nf++)
#pragma unroll
            for (int r = 0; r < 4; r++) acc[mf][nf][r] *= tscale;

    float rmx[2][2] = {{-1e30f, -1e30f}, {-1e30f, -1e30f}};
#pragma unroll
    for (int mf = 0; mf < 2; mf++)
#pragma unroll
        for (int nf = 0; nf < 8; nf++) {
            rmx[mf][0] = fmaxf(rmx[mf][0], fmaxf(acc[mf][nf][0], acc[mf][nf][1]));
            rmx[mf][1] = fmaxf(rmx[mf][1], fmaxf(acc[mf][nf][2], acc[mf][nf][3]));
        }
#pragma unroll
    for (int mf = 0; mf < 2; mf++)
#pragma unroll
        for (int hf = 0; hf < 2; hf++) {
            rmx[mf][hf] = fmaxf(rmx[mf][hf], __shfl_xor_sync(~0u, rmx[mf][hf], 1));
            rmx[mf][hf] = fmaxf(rmx[mf][hf], __shfl_xor_sync(~0u, rmx[mf][hf], 2));
        }
    if (t4 == 0)
#pragma unroll
        for (int mf = 0; mf < 2; mf++)
#pragma unroll
            for (int hf = 0; hf < 2; hf++)
                smax[(wm + mf * 16 + hf * 8 + g) * 4 + zn] = rmx[mf][hf];
    __syncthreads();
    float gmx[2][2], rsm[2][2] = {{0, 0}, {0, 0}};
#pragma unroll
    for (int mf = 0; mf < 2; mf++)
#pragma unroll
        for (int hf = 0; hf < 2; hf++) {
            const int r = wm + mf * 16 + hf * 8 + g;
            gmx[mf][hf] = fmaxf(fmaxf(smax[r * 4], smax[r * 4 + 1]),
                                fmaxf(smax[r * 4 + 2], smax[r * 4 + 3]));
        }
#pragma unroll
    for (int mf = 0; mf < 2; mf++)
#pragma unroll
        for (int nf = 0; nf < 8; nf++)
#pragma unroll
            for (int r = 0; r < 4; r++) {
                const int hf = r >> 1;
                const float e = __expf(acc[mf][nf][r] - gmx[mf][hf]);
                acc[mf][nf][r] = e;
                rsm[mf][hf] += e;
            }
#pragma unroll
    for (int mf = 0; mf < 2; mf++)
#pragma unroll
        for (int hf = 0; hf < 2; hf++) {
            rsm[mf][hf] += __shfl_xor_sync(~0u, rsm[mf][hf], 1);
            rsm[mf][hf] += __shfl_xor_sync(~0u, rsm[mf][hf], 2);
        }
    if (t4 == 0)
#pragma unroll
        for (int mf = 0; mf < 2; mf++)
#pragma unroll
            for (int hf = 0; hf < 2; hf++)
                ssum[(wm + mf * 16 + hf * 8 + g) * 4 + zn] = rsm[mf][hf];
    __syncthreads();
#pragma unroll
    for (int mf = 0; mf < 2; mf++)
#pragma unroll
        for (int hf = 0; hf < 2; hf++) {
            const int r = wm + mf * 16 + hf * 8 + g;
            const float inv = 1.0f / (ssum[r * 4] + ssum[r * 4 + 1] + ssum[r * 4 + 2] + ssum[r * 4 + 3]);
#pragma unroll
            for (int nf = 0; nf < 8; nf++) {
                acc[mf][nf][hf * 2]     *= inv;
                acc[mf][nf][hf * 2 + 1] *= inv;
            }
        }

    float acc2[2][8][4];
#pragma unroll
    for (int i = 0; i < 2; i++)
#pragma unroll
        for (int j = 0; j < 8; j++)
#pragma unroll
            for (int r = 0; r < 4; r++) acc2[i][j][r] = 0.0f;

#pragma unroll
    for (int kf = 0; kf < 4; kf++) {
        uint32_t pah[2][4], pal[2][4];
#pragma unroll
        for (int mf = 0; mf < 2; mf++) {
            bsplit2(acc[mf][2*kf][0],   acc[mf][2*kf][1],   pah[mf][0], pal[mf][0]);
            bsplit2(acc[mf][2*kf][2],   acc[mf][2*kf][3],   pah[mf][1], pal[mf][1]);
            bsplit2(acc[mf][2*kf+1][0], acc[mf][2*kf+1][1], pah[mf][2], pal[mf][2]);
            bsplit2(acc[mf][2*kf+1][2], acc[mf][2*kf+1][3], pah[mf][3], pal[mf][3]);
        }
#pragma unroll
        for (int df = 0; df < 4; df++) {
            uint32_t bhr[4], blr[4];
            const uint32_t bo = (uint32_t)(zn * 8192) +
                SWZ((uint32_t)((df * 16 + b_row) * 128 + (kf * 16 + b_col) * 2));
            ldsm4(bhr, sb + A_VH + bo);
            ldsm4(blr, sb + A_VL + bo);
#pragma unroll
            for (int mf = 0; mf < 2; mf++)
#pragma unroll
                for (int s = 0; s < 2; s++) {
                    float* c = acc2[mf][df * 2 + s];
                    mma_bf16(c, pah[mf], bhr[s * 2], bhr[s * 2 + 1]);
                    mma_bf16(c, pal[mf], bhr[s * 2], bhr[s * 2 + 1]);
                    mma_bf16(c, pah[mf], blr[s * 2], blr[s * 2 + 1]);
                }
        }
    }

    float* zone = (float*)(sm_raw + A_ZN) + zn * (64 * 66);
#pragma unroll
    for (int mf = 0; mf < 2; mf++)
#pragma unroll
        for (int nf = 0; nf < 8; nf++)
#pragma unroll
            for (int hf = 0; hf < 2; hf++) {
                const int row = wm + mf * 16 + hf * 8 + g;
                const int dc = nf * 8 + t4 * 2;
                *(float2*)&zone[row * 66 + dc] =
                    make_float2(acc2[mf][nf][hf * 2], acc2[mf][nf][hf * 2 + 1]);
            }
    __syncthreads();

    const int tx = tid & 15, ty = tid >> 4;
    float* z0 = (float*)(sm_raw + A_ZN);
    const size_t base = (size_t)b * (N1_ * C_) + (size_t)h * N1_ + q0 + tx * 4;
#pragma unroll
    for (int j = 0; j < 4; j++) {
        const int d = ty * 4 + j;
        float o[4];
#pragma unroll
        for (int qi = 0; qi < 4; qi++) {
            const int idx = (tx * 4 + qi) * 66 + d;
            o[qi] = z0[idx] + z0[64*66 + idx] + z0[2*64*66 + idx] + z0[3*64*66 + idx];
        }
        *(float4*)&xa[base + (size_t)d * (H_ * N1_)] = make_float4(o[0], o[1], o[2], o[3]);
    }
}

// ---- L2 norm with bf16-split residual input (q = hi+lo) + split output ----
__global__ __launch_bounds__(256)
void l2nq_k(const float* __restrict__ a, const u16* __restrict__ qh,
            const u16* __restrict__ ql, float* __restrict__ out,
            u16* __restrict__ oh, u16* __restrict__ ol)
{
    const int row = blockIdx.x * 8 + (threadIdx.x >> 5);
    const int lane = threadIdx.x & 31;
    const float4* pa = (const float4*)(a + (size_t)row * C_);
    float4 v[4];
    float ss = 0.0f;
#pragma unroll
    for (int i = 0; i < 4; i++) {
        float4 t = pa[lane + 32 * i];
        const size_t off = (size_t)row * C_ + (lane + 32 * i) * 4;
        const uint2 hq = *(const uint2*)(qh + off);
        const uint2 lq = *(const uint2*)(ql + off);
        t.x += __uint_as_float(hq.x << 16)          + __uint_as_float(lq.x << 16);
        t.y += __uint_as_float(hq.x & 0xffff0000u)  + __uint_as_float(lq.x & 0xffff0000u);
        t.z += __uint_as_float(hq.y << 16)          + __uint_as_float(lq.y << 16);
        t.w += __uint_as_float(hq.y & 0xffff0000u)  + __uint_as_float(lq.y & 0xffff0000u);
        v[i] = t;
        ss += t.x * t.x + t.y * t.y + t.z * t.z + t.w * t.w;
    }
#pragma unroll
    for (int o = 16; o > 0; o >>= 1) ss += __shfl_xor_sync(~0u, ss, o);
    const float inv = 1.0f / fmaxf(sqrtf(ss), 1e-12f);
    float4* po = (float4*)(out + (size_t)row * C_);
#pragma unroll
    for (int i = 0; i < 4; i++) {
        v[i].x *= inv; v[i].y *= inv; v[i].z *= inv; v[i].w *= inv;
        po[lane + 32 * i] = v[i];
        uint32_t a0, b0, c0, d0;
        bsplit2(v[i].x, v[i].y, a0, c0); bsplit2(v[i].z, v[i].w, b0, d0);
        const size_t off = (size_t)row * C_ + (lane + 32 * i) * 4;
        *(uint2*)(oh + off) = make_uint2(a0, b0);
        *(uint2*)(ol + off) = make_uint2(c0, d0);
    }
}

// ---- plain L2 norm (final) ----
__global__ __launch_bounds__(256)
void l2n_k(const float* __restrict__ a, float* __restrict__ out)
{
    const int row = blockIdx.x * 8 + (threadIdx.x >> 5);
    const int lane = threadIdx.x & 31;
    const float4* pa = (const float4*)(a + (size_t)row * C_);
    float4 v[4];
    float ss = 0.0f;
#pragma unroll
    for (int i = 0; i < 4; i++) {
        float4 t = pa[lane + 32 * i];
        v[i] = t;
        ss += t.x * t.x + t.y * t.y + t.z * t.z + t.w * t.w;
    }
#pragma unroll
    for (int o = 16; o > 0; o >>= 1) ss += __shfl_xor_sync(~0u, ss, o);
    const float inv = 1.0f / fmaxf(sqrtf(ss), 1e-12f);
    float4* po = (float4*)(out + (size_t)row * C_);
#pragma unroll
    for (int i = 0; i < 4; i++) {
        v[i].x *= inv; v[i].y *= inv; v[i].z *= inv; v[i].w *= inv;
        po[lane + 32 * i] = v[i];
    }
}

extern "C" void kernel_launch(void* const* d_in, const int* in_sizes, int n_in,
                              void* d_out, int out_size)
{
    const float* x1    = (const float*)d_in[0];
    const float* x2    = (const float*)d_in[1];
    const float* Wq    = (const float*)d_in[2];
    const float* bq    = (const float*)d_in[3];
    const float* Wkv   = (const float*)d_in[4];
    const float* bkv   = (const float*)d_in[5];
    const float* Wp    = (const float*)d_in[6];
    const float* bp    = (const float*)d_in[7];
    const float* pos_q = (const float*)d_in[8];
    const float* pos_k = (const float*)d_in[9];
    const float* temp  = (const float*)d_in[10];
    const float* W1    = (const float*)d_in[11];
    const float* b1    = (const float*)d_in[12];
    const float* W2    = (const float*)d_in[13];
    const float* b2    = (const float*)d_in[14];

    float *xa, *xn;
    u16 *qh, *ql, *x1h, *x1l, *x2h, *x2l, *xnh, *xnl, *hh, *hl;
    u16 *wqh, *wql, *wkvh, *wkvl, *w1h, *w1l, *w2h, *w2l, *wpth, *wptl;
    cudaGetSymbolAddress((void**)&xa, g_xa);
    cudaGetSymbolAddress((void**)&xn, g_xn);
    cudaGetSymbolAddress((void**)&qh, g_qh);   cudaGetSymbolAddress((void**)&ql, g_ql);
    cudaGetSymbolAddress((void**)&x1h, g_x1h); cudaGetSymbolAddress((void**)&x1l, g_x1l);
    cudaGetSymbolAddress((void**)&x2h, g_x2h); cudaGetSymbolAddress((void**)&x2l, g_x2l);
    cudaGetSymbolAddress((void**)&xnh, g_xnh); cudaGetSymbolAddress((void**)&xnl, g_xnl);
    cudaGetSymbolAddress((void**)&hh, g_hh);   cudaGetSymbolAddress((void**)&hl, g_hl);
    cudaGetSymbolAddress((void**)&wqh, g_wq_hi);   cudaGetSymbolAddress((void**)&wql, g_wq_lo);
    cudaGetSymbolAddress((void**)&wkvh, g_wkv_hi); cudaGetSymbolAddress((void**)&wkvl, g_wkv_lo);
    cudaGetSymbolAddress((void**)&w1h, g_w1_hi);   cudaGetSymbolAddress((void**)&w1l, g_w1_lo);
    cudaGetSymbolAddress((void**)&w2h, g_w2_hi);   cudaGetSymbolAddress((void**)&w2l, g_w2_lo);
    cudaGetSymbolAddress((void**)&wpth, g_wpth);   cudaGetSymbolAddress((void**)&wptl, g_wptl);

    cudaFuncSetAttribute(attn_mma, cudaFuncAttributeMaxDynamicSharedMemorySize, ATT_SMEM);
    cudaFuncSetAttribute(kvp_mma,  cudaFuncAttributeMaxDynamicSharedMemorySize, KVP_SMEM);
    cudaFuncSetAttribute(tgemm<0>, cudaFuncAttributeMaxDynamicSharedMemorySize, TG_SMEM);
    cudaFuncSetAttribute(tgemm<1>, cudaFuncAttributeMaxDynamicSharedMemorySize, TG_SMEM);
    cudaFuncSetAttribute(tgemm<2>, cudaFuncAttributeMaxDynamicSharedMemorySize, TG_SMEM);
    cudaFuncSetAttribute(tgemm<3>, cudaFuncAttributeMaxDynamicSharedMemorySize, TG_SMEM);

    // fork a non-blocking side stream for the independent Q-projection chain.
    // (host-side objects created fresh each call; kernel_launch runs only a
    // couple of times — correctness pass + capture — so not destroying them
    // is a bounded, harmless host-side leak. No device memory is allocated.)
    cudaStream_t s2;
    cudaStreamCreateWithFlags(&s2, cudaStreamNonBlocking);
    cudaEvent_t eF, eJ;
    cudaEventCreateWithFlags(&eF, cudaEventDisableTiming);
    cudaEventCreateWithFlags(&eJ, cudaEventDisableTiming);

    cudaEventRecord(eF, 0);
    cudaStreamWaitEvent(s2, eF, 0);

    // branch (s2): Q chain
    wsplit_k<<<dim3(C_ / 32, C_ / 32), 256, 0, s2>>>(Wq, wqh, wql, C_, C_);
    asplit_k<<<(M_ * C_) / 1024, 256, 0, s2>>>(x1, x1h, x1l);
    tgemm<0><<<dim3(C_ / 128, M_ / 128), 256, TG_SMEM, s2>>>(
        x1h, x1l, wqh, wql, bq, pos_q, nullptr, nullptr, M_, C_, C_);
    cudaEventRecord(eJ, s2);

    // legacy stream: KV chain + MLP weight prep
    wsplit_k<<<dim3(2 * C_ / 32, C_ / 32), 256>>>(Wkv, wkvh, wkvl, C_, 2 * C_);
    wsplit_k<<<dim3(P_ / 32, N2_ / 32), 256>>>(Wp, wpth, wptl, N2_, P_);
    wsplit_k<<<dim3(MLP_ / 32, C_ / 32), 256>>>(W1, w1h, w1l, C_, MLP_);
    wsplit_k<<<dim3(C_ / 32, MLP_ / 32), 256>>>(W2, w2h, w2l, MLP_, C_);
    asplit_k<<<(M_ * C_) / 1024, 256>>>(x2, x2h, x2l);
    tgemm<1><<<dim3(2 * C_ / 128, M_ / 128), 256, TG_SMEM>>>(
        x2h, x2l, wkvh, wkvl, bkv, pos_k, nullptr, nullptr, M_, 2 * C_, C_);
    kvp_mma<<<dim3(B_ * H_, 2), 256, KVP_SMEM>>>(bp);

    // join: attention needs both q splits and kp/vp
    cudaStreamWaitEvent(0, eJ, 0);
    attn_mma<<<dim3(B_ * H_, N1_ / 64), 256, ATT_SMEM>>>(temp, xa);
    l2nq_k<<<M_ / 8, 256>>>(xa, qh, ql, xn, xnh, xnl);
    tgemm<2><<<dim3(MLP_ / 128, M_ / 128), 256, TG_SMEM>>>(
        xnh, xnl, w1h, w1l, b1, nullptr, hh, hl, M_, MLP_, C_);
    tgemm<3><<<dim3(C_ / 128, M_ / 128), 256, TG_SMEM>>>(
        hh, hl, w2h, w2l, b2, xn, xa, nullptr, M_, C_, MLP_);
    l2n_k<<<M_ / 8, 256>>>(xa, (float*)d_out);
}

// round 11
// speedup vs baseline: 2.4272x; 1.0801x over previous
#include <cuda_runtime.h>
#include <math.h>
#include <stdint.h>

#define B_   8
#define N1_  4096
#define N2_  4096
#define C_   512
#define P_   256
#define H_   8
#define HD_  64
#define MLP_ 2048
#define M_   (B_*N1_)

typedef unsigned short u16;

__device__ float g_xa[M_*C_];
__device__ float g_xn[M_*C_];
__device__ u16 g_qh [M_*C_],  g_ql [M_*C_];
__device__ u16 g_x1h[M_*C_],  g_x1l[M_*C_];
__device__ u16 g_x2h[M_*C_],  g_x2l[M_*C_];
__device__ u16 g_xnh[M_*C_],  g_xnl[M_*C_];
__device__ u16 g_hh [M_*MLP_], g_hl [M_*MLP_];
__device__ u16 g_kTh[B_*C_*N2_], g_kTl[B_*C_*N2_];
__device__ u16 g_vTh[B_*C_*N2_], g_vTl[B_*C_*N2_];
__device__ u16 g_kpth[B_*H_*P_*HD_], g_kptl[B_*H_*P_*HD_];
__device__ u16 g_vph [B_*H_*HD_*P_], g_vpl [B_*H_*HD_*P_];
__device__ u16 g_wq_hi [C_*C_],   g_wq_lo [C_*C_];
__device__ u16 g_wkv_hi[2*C_*C_], g_wkv_lo[2*C_*C_];
__device__ u16 g_w1_hi [MLP_*C_], g_w1_lo [MLP_*C_];
__device__ u16 g_w2_hi [C_*MLP_], g_w2_lo [C_*MLP_];
__device__ u16 g_wpth  [P_*N2_],  g_wptl  [P_*N2_];

__device__ __forceinline__ uint32_t smem_u32(const void* p) {
    uint32_t a;
    asm("{ .reg .u64 t; cvta.to.shared.u64 t, %1; cvt.u32.u64 %0, t; }" : "=r"(a) : "l"(p));
    return a;
}
#define SWZ(b) ((b) ^ (((b) >> 3) & 0x70))
#define CPA16(dst, src) asm volatile("cp.async.cg.shared.global [%0], [%1], 16;" :: "r"(dst), "l"(src))
#define CPA_COMMIT() asm volatile("cp.async.commit_group;" ::: "memory")
#define CPA_WAIT1()  asm volatile("cp.async.wait_group 1;" ::: "memory")
#define CPA_WAIT0()  asm volatile("cp.async.wait_group 0;" ::: "memory")

__device__ __forceinline__ void ldsm4(uint32_t* r, uint32_t a) {
    asm volatile("ldmatrix.sync.aligned.m8n8.x4.shared.b16 {%0,%1,%2,%3}, [%4];"
                 : "=r"(r[0]), "=r"(r[1]), "=r"(r[2]), "=r"(r[3]) : "r"(a));
}
__device__ __forceinline__ void mma_bf16(float* c, const uint32_t* a, uint32_t b0, uint32_t b1) {
    asm volatile("mma.sync.aligned.m16n8k16.row.col.f32.bf16.bf16.f32 "
        "{%0,%1,%2,%3}, {%4,%5,%6,%7}, {%8,%9}, {%0,%1,%2,%3};"
        : "+f"(c[0]), "+f"(c[1]), "+f"(c[2]), "+f"(c[3])
        : "r"(a[0]), "r"(a[1]), "r"(a[2]), "r"(a[3]), "r"(b0), "r"(b1));
}
__device__ __forceinline__ void bsplit(float a, uint32_t& hi, uint32_t& lo) {
    uint32_t u = __float_as_uint(a);
    uint32_t hr = (u + 0x7fffu + ((u >> 16) & 1u)) & 0xffff0000u;
    hi = hr >> 16;
    float l = a - __uint_as_float(hr);
    uint32_t ul = __float_as_uint(l);
    lo = (ul + 0x7fffu + ((ul >> 16) & 1u)) >> 16;
}
__device__ __forceinline__ void bsplit2(float a, float b, uint32_t& hi, uint32_t& lo) {
    uint32_t h0, l0, h1, l1;
    bsplit(a, h0, l0); bsplit(b, h1, l1);
    hi = h0 | (h1 << 16); lo = l0 | (l1 << 16);
}

// transpose+split: W[K][N] fp32 -> Wt[N][K] hi/lo bf16
__global__ __launch_bounds__(256)
void wsplit_k(const float* __restrict__ W, u16* __restrict__ hi, u16* __restrict__ lo, int K, int N)
{
    __shared__ float tile[32][33];
    const int n0 = blockIdx.x * 32, k0 = blockIdx.y * 32;
    const int tx = threadIdx.x & 31, ty = threadIdx.x >> 5;
#pragma unroll
    for (int r = 0; r < 4; r++)
        tile[ty + 8 * r][tx] = W[(size_t)(k0 + ty + 8 * r) * N + n0 + tx];
    __syncthreads();
#pragma unroll
    for (int r = 0; r < 4; r++) {
        const int n = n0 + ty + 8 * r, k = k0 + tx;
        uint32_t h, l;
        bsplit(tile[tx][ty + 8 * r], h, l);
        hi[(size_t)n * K + k] = (u16)h;
        lo[(size_t)n * K + k] = (u16)l;
    }
}

__global__ __launch_bounds__(256)
void asplit_k(const float* __restrict__ A, u16* __restrict__ hi, u16* __restrict__ lo)
{
    const size_t i4 = ((size_t)blockIdx.x * 256 + threadIdx.x) * 4;
    float4 f = *(const float4*)(A + i4);
    uint32_t a, b, c, d;
    bsplit2(f.x, f.y, a, c); bsplit2(f.z, f.w, b, d);
    *(uint2*)(hi + i4) = make_uint2(a, b);
    *(uint2*)(lo + i4) = make_uint2(c, d);
}

// ---- bf16 HMMA GEMM, 128x128 tile, 3-stage cp.async ----
// NTERM=3: hi*Bhi + Alo*Bhi + Ahi*Blo.  NTERM=2 (MLP1): drop Ahi*Blo.
// EPI 0: q -> qh/ql split (+bias+pos_q)
// EPI 1: k/v -> transposed bf16 split kT/vT (k gets +pos_k)
// EPI 2: gelu -> bf16 split
// EPI 3: fp32 out = acc + bias + extra
#define TG_SMEM (3 * 65536)
template<int EPI, int NTERM>
__global__ __launch_bounds__(256, 1)
void tgemm(const u16* __restrict__ Ahi, const u16* __restrict__ Alo,
           const u16* __restrict__ Bhi, const u16* __restrict__ Blo,
           const float* __restrict__ bias, const float* __restrict__ extra,
           void* __restrict__ out, void* __restrict__ out2, int M, int N, int K)
{
    extern __shared__ __align__(1024) char sm_raw[];
    const uint32_t sb = smem_u32(sm_raw);
    const int tid = threadIdx.x, wid = tid >> 5, lane = tid & 31;
    const int bm = blockIdx.y * 128, bn = blockIdx.x * 128;
    const int wm = (wid & 1) * 64, wn = (wid >> 1) * 32;
    const int nck = K >> 6;

    float acc[4][4][4];
#pragma unroll
    for (int i = 0; i < 4; i++)
#pragma unroll
        for (int j = 0; j < 4; j++)
#pragma unroll
            for (int r = 0; r < 4; r++) acc[i][j][r] = 0.0f;

    const int a_row = ((lane >> 3) & 1) * 8 + (lane & 7);
    const int a_col = (lane >> 4) * 8;
    const int b_row = (lane >> 4) * 8 + (lane & 7);
    const int b_col = ((lane >> 3) & 1) * 8;

    auto load_stage = [&](int ck, int stage) {
        if (ck < nck) {
            const int k0 = ck * 64;
            const uint32_t sbase = sb + stage * 65536;
#pragma unroll
            for (int i = 0; i < 4; i++) {
                const int id = tid + i * 256;
                const int row = id >> 3, c16 = id & 7;
                const uint32_t dsw = SWZ((uint32_t)(row * 128 + c16 * 16));
                const size_t asrc = (size_t)(bm + row) * K + k0 + c16 * 8;
                const size_t bsrc = (size_t)(bn + row) * K + k0 + c16 * 8;
                CPA16(sbase + dsw,         Ahi + asrc);
                CPA16(sbase + 16384 + dsw, Alo + asrc);
                CPA16(sbase + 32768 + dsw, Bhi + bsrc);
                if (NTERM == 3) CPA16(sbase + 49152 + dsw, Blo + bsrc);
            }
        }
        CPA_COMMIT();
    };

    load_stage(0, 0);
    load_stage(1, 1);

    for (int ck = 0; ck < nck; ck++) {
        CPA_WAIT1();
        __syncthreads();
        load_stage(ck + 2, (ck + 2) % 3);
        const uint32_t base = sb + (ck % 3) * 65536;
#pragma unroll
        for (int ks = 0; ks < 4; ks++) {
            const int kk = ks * 16;
            uint32_t ah[4][4], al[4][4], bh[2][4], bl[2][4];
#pragma unroll
            for (int mf = 0; mf < 4; mf++) {
                const uint32_t ao = SWZ((uint32_t)((wm + mf * 16 + a_row) * 128 + (kk + a_col) * 2));
                ldsm4(ah[mf], base + ao);
                ldsm4(al[mf], base + 16384 + ao);
            }
#pragma unroll
            for (int p = 0; p < 2; p++) {
                const uint32_t bo = SWZ((uint32_t)((wn + p * 16 + b_row) * 128 + (kk + b_col) * 2));
                ldsm4(bh[p], base + 32768 + bo);
                if (NTERM == 3) ldsm4(bl[p], base + 49152 + bo);
            }
#pragma unroll
            for (int mf = 0; mf < 4; mf++)
#pragma unroll
                for (int p = 0; p < 2; p++)
#pragma unroll
                    for (int s = 0; s < 2; s++) {
                        float* c = acc[mf][p * 2 + s];
                        mma_bf16(c, ah[mf], bh[p][s * 2], bh[p][s * 2 + 1]);
                        mma_bf16(c, al[mf], bh[p][s * 2], bh[p][s * 2 + 1]);
                        if (NTERM == 3)
                            mma_bf16(c, ah[mf], bl[p][s * 2], bl[p][s * 2 + 1]);
                    }
        }
    }

    const int l4 = lane >> 2, l2 = (lane & 3) * 2;

    if (EPI == 1) {
        CPA_WAIT0();
        __syncthreads();
        float* T = (float*)sm_raw;                       // 128 x 132 floats
        const bool is_k = (bn < C_);
#pragma unroll
        for (int mf = 0; mf < 4; mf++)
#pragma unroll
            for (int nf = 0; nf < 4; nf++) {
                const int colL = wn + nf * 8 + l2;
                const int col = bn + colL;
                const float bia0 = bias[col], bia1 = bias[col + 1];
#pragma unroll
                for (int half = 0; half < 2; half++) {
                    const int mL = wm + mf * 16 + l4 + half * 8;
                    float v0 = acc[mf][nf][half * 2]     + bia0;
                    float v1 = acc[mf][nf][half * 2 + 1] + bia1;
                    if (is_k) {
                        const int n = (bm + mL) & (N2_ - 1);
                        v0 += extra[(size_t)n * C_ + col];
                        v1 += extra[(size_t)n * C_ + col + 1];
                    }
                    T[colL * 132 + mL]       = v0;
                    T[(colL + 1) * 132 + mL] = v1;
                }
            }
        __syncthreads();
        u16* __restrict__ dh = is_k ? g_kTh : g_vTh;
        u16* __restrict__ dl = is_k ? g_kTl : g_vTl;
        const int bb = bm >> 12, n0 = bm & (N2_ - 1);
        const int r = tid >> 1, hh2 = (tid & 1) * 64;
        const int c = (bn + r) - (is_k ? 0 : C_);
        const size_t gbase = ((size_t)bb * C_ + c) * N2_ + n0 + hh2;
        const float* Tr = T + r * 132 + hh2;
#pragma unroll
        for (int j = 0; j < 64; j += 8) {
            uint32_t h0, l0, h1, l1, h2, l2x, h3, l3;
            bsplit2(Tr[j],     Tr[j + 1], h0, l0);
            bsplit2(Tr[j + 2], Tr[j + 3], h1, l1);
            bsplit2(Tr[j + 4], Tr[j + 5], h2, l2x);
            bsplit2(Tr[j + 6], Tr[j + 7], h3, l3);
            *(uint4*)(dh + gbase + j) = make_uint4(h0, h1, h2, h3);
            *(uint4*)(dl + gbase + j) = make_uint4(l0, l1, l2x, l3);
        }
        return;
    }

#pragma unroll
    for (int mf = 0; mf < 4; mf++)
#pragma unroll
        for (int nf = 0; nf < 4; nf++) {
            const int col = bn + wn + nf * 8 + l2;
            const float bia0 = bias[col], bia1 = bias[col + 1];
#pragma unroll
            for (int half = 0; half < 2; half++) {
                const int m = bm + wm + mf * 16 + l4 + half * 8;
                float v0 = acc[mf][nf][half * 2]     + bia0;
                float v1 = acc[mf][nf][half * 2 + 1] + bia1;
                if (EPI == 0) {
                    v0 += extra[(size_t)(m & (N1_ - 1)) * C_ + col];
                    v1 += extra[(size_t)(m & (N1_ - 1)) * C_ + col + 1];
                    uint32_t hi, lo;
                    bsplit2(v0, v1, hi, lo);
                    *(uint32_t*)(g_qh + (size_t)m * N + col) = hi;
                    *(uint32_t*)(g_ql + (size_t)m * N + col) = lo;
                } else if (EPI == 2) {
                    v0 = 0.5f * v0 * (1.0f + erff(v0 * 0.70710678118654752f));
                    v1 = 0.5f * v1 * (1.0f + erff(v1 * 0.70710678118654752f));
                    uint32_t hi, lo;
                    bsplit2(v0, v1, hi, lo);
                    *(uint32_t*)((u16*)out  + (size_t)m * N + col) = hi;
                    *(uint32_t*)((u16*)out2 + (size_t)m * N + col) = lo;
                } else {
                    v0 += extra[(size_t)m * N + col];
                    v1 += extra[(size_t)m * N + col + 1];
                    *(float2*)((float*)out + (size_t)m * N + col) = make_float2(v0, v1);
                }
            }
        }
}

// ---- kvp via bf16x3 HMMA ----
#define KVP_STG  81920
#define KVP_SMEM (2 * KVP_STG)
__global__ __launch_bounds__(256, 1)
void kvp_mma(const float* __restrict__ bp)
{
    extern __shared__ __align__(1024) char sm_raw[];
    const uint32_t sb = smem_u32(sm_raw);
    const int tid = threadIdx.x, wid = tid >> 5, lane = tid & 31;
    const int g = lane >> 2, t4 = lane & 3;
    const int bh = blockIdx.x, b = bh >> 3, h = bh & 7;
    const int mode = blockIdx.y;
    const u16* __restrict__ Dh = mode ? g_vTh : g_kTh;
    const u16* __restrict__ Dl = mode ? g_vTl : g_kTl;

    const int a_row = ((lane >> 3) & 1) * 8 + (lane & 7);
    const int a_col = (lane >> 4) * 8;
    const int b_row = (lane >> 4) * 8 + (lane & 7);
    const int b_col = ((lane >> 3) & 1) * 8;

    auto load_stage = [&](int ck) {
        if (ck < 64) {
            const uint32_t base = sb + (ck & 1) * KVP_STG;
            const int k0 = ck * 64;
#pragma unroll
            for (int t = 0; t < 8; t++) {
                const int i = tid + t * 256;
                const int row = i >> 3, c16 = i & 7;
                const uint32_t dsw = SWZ((uint32_t)(row * 128 + c16 * 16));
                const size_t src = (size_t)row * N2_ + k0 + c16 * 8;
                CPA16(base + dsw,         g_wpth + src);
                CPA16(base + 32768 + dsw, g_wptl + src);
            }
#pragma unroll
            for (int t = 0; t < 2; t++) {
                const int i = tid + t * 256;
                const int row = i >> 3, c16 = i & 7;
                const uint32_t dsw = SWZ((uint32_t)(row * 128 + c16 * 16));
                const size_t src = ((size_t)b * C_ + h * 64 + row) * N2_ + k0 + c16 * 8;
                CPA16(base + 65536 + dsw, Dh + src);
                CPA16(base + 73728 + dsw, Dl + src);
            }
        }
        CPA_COMMIT();
    };

    load_stage(0);
    load_stage(1);

    if (mode == 0) {
        const int wm = (wid & 3) * 64, wn = (wid >> 2) * 32;
        float acc[4][4][4];
#pragma unroll
        for (int i = 0; i < 4; i++)
#pragma unroll
            for (int j = 0; j < 4; j++)
#pragma unroll
                for (int r = 0; r < 4; r++) acc[i][j][r] = 0.0f;

        for (int ck = 0; ck < 64; ck++) {
            CPA_WAIT1();
            __syncthreads();
            const uint32_t base = sb + (ck & 1) * KVP_STG;
#pragma unroll
            for (int ks = 0; ks < 4; ks++) {
                const int kk = ks * 16;
                uint32_t ah[4][4], al[4][4], bhr[2][4], blr[2][4];
#pragma unroll
                for (int mf = 0; mf < 4; mf++) {
                    const uint32_t ao = SWZ((uint32_t)((wm + mf * 16 + a_row) * 128 + (kk + a_col) * 2));
                    ldsm4(ah[mf], base + ao);
                    ldsm4(al[mf], base + 32768 + ao);
                }
#pragma unroll
                for (int p = 0; p < 2; p++) {
                    const uint32_t bo = SWZ((uint32_t)((wn + p * 16 + b_row) * 128 + (kk + b_col) * 2));
                    ldsm4(bhr[p], base + 65536 + bo);
                    ldsm4(blr[p], base + 73728 + bo);
                }
#pragma unroll
                for (int mf = 0; mf < 4; mf++)
#pragma unroll
                    for (int p = 0; p < 2; p++)
#pragma unroll
                        for (int s = 0; s < 2; s++) {
                            float* c = acc[mf][p * 2 + s];
                            mma_bf16(c, ah[mf], bhr[p][s * 2], bhr[p][s * 2 + 1]);
                            mma_bf16(c, al[mf], bhr[p][s * 2], bhr[p][s * 2 + 1]);
                            mma_bf16(c, ah[mf], blr[p][s * 2], blr[p][s * 2 + 1]);
                        }
            }
            __syncthreads();
            load_stage(ck + 2);
        }
#pragma unroll
        for (int mf = 0; mf < 4; mf++)
#pragma unroll
            for (int hf = 0; hf < 2; hf++) {
                const int p = wm + mf * 16 + hf * 8 + g;
                const float bv = bp[p];
#pragma unroll
                for (int nf = 0; nf < 4; nf++) {
                    const int d = wn + nf * 8 + t4 * 2;
                    uint32_t hi, lo;
                    bsplit2(acc[mf][nf][hf * 2] + bv, acc[mf][nf][hf * 2 + 1] + bv, hi, lo);
                    *(uint32_t*)(g_kpth + (size_t)bh * (P_ * HD_) + p * 64 + d) = hi;
                    *(uint32_t*)(g_kptl + (size_t)bh * (P_ * HD_) + p * 64 + d) = lo;
                }
            }
    } else {
        const int wm = (wid & 1) * 32, wn = (wid >> 1) * 64;
        float acc[2][8][4];
#pragma unroll
        for (int i = 0; i < 2; i++)
#pragma unroll
            for (int j = 0; j < 8; j++)
#pragma unroll
                for (int r = 0; r < 4; r++) acc[i][j][r] = 0.0f;

        for (int ck = 0; ck < 64; ck++) {
            CPA_WAIT1();
            __syncthreads();
            const uint32_t base = sb + (ck & 1) * KVP_STG;
#pragma unroll
            for (int ks = 0; ks < 4; ks++) {
                const int kk = ks * 16;
                uint32_t ah[2][4], al[2][4];
#pragma unroll
                for (int mf = 0; mf < 2; mf++) {
                    const uint32_t ao = SWZ((uint32_t)((wm + mf * 16 + a_row) * 128 + (kk + a_col) * 2));
                    ldsm4(ah[mf], base + 65536 + ao);
                    ldsm4(al[mf], base + 73728 + ao);
                }
#pragma unroll
                for (int p = 0; p < 4; p++) {
                    uint32_t bhr[4], blr[4];
                    const uint32_t bo = SWZ((uint32_t)((wn + p * 16 + b_row) * 128 + (kk + b_col) * 2));
                    ldsm4(bhr, base + bo);
                    ldsm4(blr, base + 32768 + bo);
#pragma unroll
                    for (int mf = 0; mf < 2; mf++)
#pragma unroll
                        for (int s = 0; s < 2; s++) {
                            float* c = acc[mf][p * 2 + s];
                            mma_bf16(c, ah[mf], bhr[s * 2], bhr[s * 2 + 1]);
                            mma_bf16(c, al[mf], bhr[s * 2], bhr[s * 2 + 1]);
                            mma_bf16(c, ah[mf], blr[s * 2], blr[s * 2 + 1]);
                        }
                }
            }
            __syncthreads();
            load_stage(ck + 2);
        }
#pragma unroll
        for (int mf = 0; mf < 2; mf++)
#pragma unroll
            for (int hf = 0; hf < 2; hf++) {
                const int d = wm + mf * 16 + hf * 8 + g;
#pragma unroll
                for (int nf = 0; nf < 8; nf++) {
                    const int p = wn + nf * 8 + t4 * 2;
                    uint32_t hi, lo;
                    bsplit2(acc[mf][nf][hf * 2] + bp[p], acc[mf][nf][hf * 2 + 1] + bp[p + 1], hi, lo);
                    *(uint32_t*)(g_vph + (size_t)bh * (HD_ * P_) + d * 256 + p) = hi;
                    *(uint32_t*)(g_vpl + (size_t)bh * (HD_ * P_) + d * 256 + p) = lo;
                }
            }
    }
}

// ---- attention via bf16x3 HMMA ----
#define A_QH   0
#define A_QL   8192
#define A_KH   16384
#define A_KL   49152
#define A_VH   81920
#define A_VL   114688
#define A_ST   147456
#define A_ZN   149504
#define ATT_SMEM (149504 + 4*64*66*4)

__global__ __launch_bounds__(256, 1)
void attn_mma(const float* __restrict__ temp, float* __restrict__ xa)
{
    extern __shared__ __align__(1024) char sm_raw[];
    const uint32_t sb = smem_u32(sm_raw);
    const int tid = threadIdx.x, wid = tid >> 5, lane = tid & 31;
    const int g = lane >> 2, t4 = lane & 3;
    const int bh = blockIdx.x, b = bh >> 3, h = bh & 7;
    const int q0 = blockIdx.y * 64;
    const int wm = (wid & 1) * 32, zn = wid >> 1, wn = zn * 64;

#pragma unroll
    for (int t = 0; t < 2; t++) {
        const int i = tid + t * 256;
        const int row = i >> 3, c16 = i & 7;
        const uint32_t dsw = SWZ((uint32_t)(row * 128 + c16 * 16));
        const size_t src = (size_t)(b * N1_ + q0 + row) * C_ + h * 64 + c16 * 8;
        CPA16(sb + A_QH + dsw, g_qh + src);
        CPA16(sb + A_QL + dsw, g_ql + src);
    }
#pragma unroll
    for (int t = 0; t < 8; t++) {
        const int i = tid + t * 256;
        const int row = i >> 3, c16 = i & 7;
        const uint32_t dsw = SWZ((uint32_t)(row * 128 + c16 * 16));
        const size_t src = (size_t)bh * (P_ * HD_) + row * 64 + c16 * 8;
        CPA16(sb + A_KH + dsw, g_kpth + src);
        CPA16(sb + A_KL + dsw, g_kptl + src);
    }
#pragma unroll
    for (int t = 0; t < 8; t++) {
        const int i = tid + t * 256;
        const int c16 = i & 7, d = (i >> 3) & 63, ch = i >> 9;
        const uint32_t dsw = (uint32_t)(ch * 8192) + SWZ((uint32_t)(d * 128 + c16 * 16));
        const size_t src = (size_t)bh * (HD_ * P_) + d * 256 + ch * 64 + c16 * 8;
        CPA16(sb + A_VH + dsw, g_vph + src);
        CPA16(sb + A_VL + dsw, g_vpl + src);
    }
    CPA_COMMIT();
    CPA_WAIT0();
    __syncthreads();

    const int a_row = ((lane >> 3) & 1) * 8 + (lane & 7);
    const int a_col = (lane >> 4) * 8;
    const int b_row = (lane >> 4) * 8 + (lane & 7);
    const int b_col = ((lane >> 3) & 1) * 8;

    float acc[2][8][4];
#pragma unroll
    for (int i = 0; i < 2; i++)
#pragma unroll
        for (int j = 0; j < 8; j++)
#pragma unroll
            for (int r = 0; r < 4; r++) acc[i][j][r] = 0.0f;

#pragma unroll
    for (int ks = 0; ks < 4; ks++) {
        const int kk = ks * 16;
        uint32_t ah[2][4], al[2][4];
#pragma unroll
        for (int mf = 0; mf < 2; mf++) {
            const uint32_t ao = SWZ((uint32_t)((wm + mf * 16 + a_row) * 128 + (kk + a_col) * 2));
            ldsm4(ah[mf], sb + A_QH + ao);
            ldsm4(al[mf], sb + A_QL + ao);
        }
#pragma unroll
        for (int p = 0; p < 4; p++) {
            uint32_t bhr[4], blr[4];
            const uint32_t bo = SWZ((uint32_t)((wn + p * 16 + b_row) * 128 + (kk + b_col) * 2));
            ldsm4(bhr, sb + A_KH + bo);
            ldsm4(blr, sb + A_KL + bo);
#pragma unroll
            for (int mf = 0; mf < 2; mf++)
#pragma unroll
                for (int s = 0; s < 2; s++) {
                    float* c = acc[mf][p * 2 + s];
                    mma_bf16(c, ah[mf], bhr[s * 2], bhr[s * 2 + 1]);
                    mma_bf16(c, al[mf], bhr[s * 2], bhr[s * 2 + 1]);
                    mma_bf16(c, ah[mf], blr[s * 2], blr[s * 2 + 1]);
                }
        }
    }

    const float tscale = temp[h];
    float* smax = (float*)(sm_raw + A_ST);
    float* ssum = smax + 256;
#pragma unroll
    for (int mf = 0; mf < 2; mf++)
#pragma unroll
        for (int nf = 0; nf < 8; nf++)
#pragma unroll
            for (int r = 0; r < 4; r++) acc[mf][nf][r] *= tscale;

    float rmx[2][2] = {{-1e30f, -1e30f}, {-1e30f, -1e30f}};
#pragma unroll
    for (int mf = 0; mf < 2; mf++)
#pragma unroll
        for (int nf = 0; nf < 8; nf++) {
            rmx[mf][0] = fmaxf(rmx[mf][0], fmaxf(acc[mf][nf][0], acc[mf][nf][1]));
            rmx[mf][1] = fmaxf(rmx[mf][1], fmaxf(acc[mf][nf][2], acc[mf][nf][3]));
        }
#pragma unroll
    for (int mf = 0; mf < 2; mf++)
#pragma unroll
        for (int hf = 0; hf < 2; hf++) {
            rmx[mf][hf] = fmaxf(rmx[mf][hf], __shfl_xor_sync(~0u, rmx[mf][hf], 1));
            rmx[mf][hf] = fmaxf(rmx[mf][hf], __shfl_xor_sync(~0u, rmx[mf][hf], 2));
        }
    if (t4 == 0)
#pragma unroll
        for (int mf = 0; mf < 2; mf++)
#pragma unroll
            for (int hf = 0; hf < 2; hf++)
                smax[(wm + mf * 16 + hf * 8 + g) * 4 + zn] = rmx[mf][hf];
    __syncthreads();
    float gmx[2][2], rsm[2][2] = {{0, 0}, {0, 0}};
#pragma unroll
    for (int mf = 0; mf < 2; mf++)
#pragma unroll
        for (int hf = 0; hf < 2; hf++) {
            const int r = wm + mf * 16 + hf * 8 + g;
            gmx[mf][hf] = fmaxf(fmaxf(smax[r * 4], smax[r * 4 + 1]),
                                fmaxf(smax[r * 4 + 2], smax[r * 4 + 3]));
        }
#pragma unroll
    for (int mf = 0; mf < 2; mf++)
#pragma unroll
        for (int nf = 0; nf < 8; nf++)
#pragma unroll
            for (int r = 0; r < 4; r++) {
                const int hf = r >> 1;
                const float e = __expf(acc[mf][nf][r] - gmx[mf][hf]);
                acc[mf][nf][r] = e;
                rsm[mf][hf] += e;
            }
#pragma unroll
    for (int mf = 0; mf < 2; mf++)
#pragma unroll
        for (int hf = 0; hf < 2; hf++) {
            rsm[mf][hf] += __shfl_xor_sync(~0u, rsm[mf][hf], 1);
            rsm[mf][hf] += __shfl_xor_sync(~0u, rsm[mf][hf], 2);
        }
    if (t4 == 0)
#pragma unroll
        for (int mf = 0; mf < 2; mf++)
#pragma unroll
            for (int hf = 0; hf < 2; hf++)
                ssum[(wm + mf * 16 + hf * 8 + g) * 4 + zn] = rsm[mf][hf];
    __syncthreads();
#pragma unroll
    for (int mf = 0; mf < 2; mf++)
#pragma unroll
        for (int hf = 0; hf < 2; hf++) {
            const int r = wm + mf * 16 + hf * 8 + g;
            const float inv = 1.0f / (ssum[r * 4] + ssum[r * 4 + 1] + ssum[r * 4 + 2] + ssum[r * 4 + 3]);
#pragma unroll
            for (int nf = 0; nf < 8; nf++) {
                acc[mf][nf][hf * 2]     *= inv;
                acc[mf][nf][hf * 2 + 1] *= inv;
            }
        }

    float acc2[2][8][4];
#pragma unroll
    for (int i = 0; i < 2; i++)
#pragma unroll
        for (int j = 0; j < 8; j++)
#pragma unroll
            for (int r = 0; r < 4; r++) acc2[i][j][r] = 0.0f;

#pragma unroll
    for (int kf = 0; kf < 4; kf++) {
        uint32_t pah[2][4], pal[2][4];
#pragma unroll
        for (int mf = 0; mf < 2; mf++) {
            bsplit2(acc[mf][2*kf][0],   acc[mf][2*kf][1],   pah[mf][0], pal[mf][0]);
            bsplit2(acc[mf][2*kf][2],   acc[mf][2*kf][3],   pah[mf][1], pal[mf][1]);
            bsplit2(acc[mf][2*kf+1][0], acc[mf][2*kf+1][1], pah[mf][2], pal[mf][2]);
            bsplit2(acc[mf][2*kf+1][2], acc[mf][2*kf+1][3], pah[mf][3], pal[mf][3]);
        }
#pragma unroll
        for (int df = 0; df < 4; df++) {
            uint32_t bhr[4], blr[4];
            const uint32_t bo = (uint32_t)(zn * 8192) +
                SWZ((uint32_t)((df * 16 + b_row) * 128 + (kf * 16 + b_col) * 2));
            ldsm4(bhr, sb + A_VH + bo);
            ldsm4(blr, sb + A_VL + bo);
#pragma unroll
            for (int mf = 0; mf < 2; mf++)
#pragma unroll
                for (int s = 0; s < 2; s++) {
                    float* c = acc2[mf][df * 2 + s];
                    mma_bf16(c, pah[mf], bhr[s * 2], bhr[s * 2 + 1]);
                    mma_bf16(c, pal[mf], bhr[s * 2], bhr[s * 2 + 1]);
                    mma_bf16(c, pah[mf], blr[s * 2], blr[s * 2 + 1]);
                }
        }
    }

    float* zone = (float*)(sm_raw + A_ZN) + zn * (64 * 66);
#pragma unroll
    for (int mf = 0; mf < 2; mf++)
#pragma unroll
        for (int nf = 0; nf < 8; nf++)
#pragma unroll
            for (int hf = 0; hf < 2; hf++) {
                const int row = wm + mf * 16 + hf * 8 + g;
                const int dc = nf * 8 + t4 * 2;
                *(float2*)&zone[row * 66 + dc] =
                    make_float2(acc2[mf][nf][hf * 2], acc2[mf][nf][hf * 2 + 1]);
            }
    __syncthreads();

    const int tx = tid & 15, ty = tid >> 4;
    float* z0 = (float*)(sm_raw + A_ZN);
    const size_t base = (size_t)b * (N1_ * C_) + (size_t)h * N1_ + q0 + tx * 4;
#pragma unroll
    for (int j = 0; j < 4; j++) {
        const int d = ty * 4 + j;
        float o[4];
#pragma unroll
        for (int qi = 0; qi < 4; qi++) {
            const int idx = (tx * 4 + qi) * 66 + d;
            o[qi] = z0[idx] + z0[64*66 + idx] + z0[2*64*66 + idx] + z0[3*64*66 + idx];
        }
        *(float4*)&xa[base + (size_t)d * (H_ * N1_)] = make_float4(o[0], o[1], o[2], o[3]);
    }
}

// ---- L2 norm with bf16-split residual input (q = hi+lo) + split output ----
__global__ __launch_bounds__(256)
void l2nq_k(const float* __restrict__ a, const u16* __restrict__ qh,
            const u16* __restrict__ ql, float* __restrict__ out,
            u16* __restrict__ oh, u16* __restrict__ ol)
{
    const int row = blockIdx.x * 8 + (threadIdx.x >> 5);
    const int lane = threadIdx.x & 31;
    const float4* pa = (const float4*)(a + (size_t)row * C_);
    float4 v[4];
    float ss = 0.0f;
#pragma unroll
    for (int i = 0; i < 4; i++) {
        float4 t = pa[lane + 32 * i];
        const size_t off = (size_t)row * C_ + (lane + 32 * i) * 4;
        const uint2 hq = *(const uint2*)(qh + off);
        const uint2 lq = *(const uint2*)(ql + off);
        t.x += __uint_as_float(hq.x << 16)          + __uint_as_float(lq.x << 16);
        t.y += __uint_as_float(hq.x & 0xffff0000u)  + __uint_as_float(lq.x & 0xffff0000u);
        t.z += __uint_as_float(hq.y << 16)          + __uint_as_float(lq.y << 16);
        t.w += __uint_as_float(hq.y & 0xffff0000u)  + __uint_as_float(lq.y & 0xffff0000u);
        v[i] = t;
        ss += t.x * t.x + t.y * t.y + t.z * t.z + t.w * t.w;
    }
#pragma unroll
    for (int o = 16; o > 0; o >>= 1) ss += __shfl_xor_sync(~0u, ss, o);
    const float inv = 1.0f / fmaxf(sqrtf(ss), 1e-12f);
    float4* po = (float4*)(out + (size_t)row * C_);
#pragma unroll
    for (int i = 0; i < 4; i++) {
        v[i].x *= inv; v[i].y *= inv; v[i].z *= inv; v[i].w *= inv;
        po[lane + 32 * i] = v[i];
        uint32_t a0, b0, c0, d0;
        bsplit2(v[i].x, v[i].y, a0, c0); bsplit2(v[i].z, v[i].w, b0, d0);
        const size_t off = (size_t)row * C_ + (lane + 32 * i) * 4;
        *(uint2*)(oh + off) = make_uint2(a0, b0);
        *(uint2*)(ol + off) = make_uint2(c0, d0);
    }
}

// ---- plain L2 norm (final) ----
__global__ __launch_bounds__(256)
void l2n_k(const float* __restrict__ a, float* __restrict__ out)
{
    const int row = blockIdx.x * 8 + (threadIdx.x >> 5);
    const int lane = threadIdx.x & 31;
    const float4* pa = (const float4*)(a + (size_t)row * C_);
    float4 v[4];
    float ss = 0.0f;
#pragma unroll
    for (int i = 0; i < 4; i++) {
        float4 t = pa[lane + 32 * i];
        v[i] = t;
        ss += t.x * t.x + t.y * t.y + t.z * t.z + t.w * t.w;
    }
#pragma unroll
    for (int o = 16; o > 0; o >>= 1) ss += __shfl_xor_sync(~0u, ss, o);
    const float inv = 1.0f / fmaxf(sqrtf(ss), 1e-12f);
    float4* po = (float4*)(out + (size_t)row * C_);
#pragma unroll
    for (int i = 0; i < 4; i++) {
        v[i].x *= inv; v[i].y *= inv; v[i].z *= inv; v[i].w *= inv;
        po[lane + 32 * i] = v[i];
    }
}

extern "C" void kernel_launch(void* const* d_in, const int* in_sizes, int n_in,
                              void* d_out, int out_size)
{
    const float* x1    = (const float*)d_in[0];
    const float* x2    = (const float*)d_in[1];
    const float* Wq    = (const float*)d_in[2];
    const float* bq    = (const float*)d_in[3];
    const float* Wkv   = (const float*)d_in[4];
    const float* bkv   = (const float*)d_in[5];
    const float* Wp    = (const float*)d_in[6];
    const float* bp    = (const float*)d_in[7];
    const float* pos_q = (const float*)d_in[8];
    const float* pos_k = (const float*)d_in[9];
    const float* temp  = (const float*)d_in[10];
    const float* W1    = (const float*)d_in[11];
    const float* b1    = (const float*)d_in[12];
    const float* W2    = (const float*)d_in[13];
    const float* b2    = (const float*)d_in[14];

    float *xa, *xn;
    u16 *qh, *ql, *x1h, *x1l, *x2h, *x2l, *xnh, *xnl, *hh, *hl;
    u16 *wqh, *wql, *wkvh, *wkvl, *w1h, *w1l, *w2h, *w2l, *wpth, *wptl;
    cudaGetSymbolAddress((void**)&xa, g_xa);
    cudaGetSymbolAddress((void**)&xn, g_xn);
    cudaGetSymbolAddress((void**)&qh, g_qh);   cudaGetSymbolAddress((void**)&ql, g_ql);
    cudaGetSymbolAddress((void**)&x1h, g_x1h); cudaGetSymbolAddress((void**)&x1l, g_x1l);
    cudaGetSymbolAddress((void**)&x2h, g_x2h); cudaGetSymbolAddress((void**)&x2l, g_x2l);
    cudaGetSymbolAddress((void**)&xnh, g_xnh); cudaGetSymbolAddress((void**)&xnl, g_xnl);
    cudaGetSymbolAddress((void**)&hh, g_hh);   cudaGetSymbolAddress((void**)&hl, g_hl);
    cudaGetSymbolAddress((void**)&wqh, g_wq_hi);   cudaGetSymbolAddress((void**)&wql, g_wq_lo);
    cudaGetSymbolAddress((void**)&wkvh, g_wkv_hi); cudaGetSymbolAddress((void**)&wkvl, g_wkv_lo);
    cudaGetSymbolAddress((void**)&w1h, g_w1_hi);   cudaGetSymbolAddress((void**)&w1l, g_w1_lo);
    cudaGetSymbolAddress((void**)&w2h, g_w2_hi);   cudaGetSymbolAddress((void**)&w2l, g_w2_lo);
    cudaGetSymbolAddress((void**)&wpth, g_wpth);   cudaGetSymbolAddress((void**)&wptl, g_wptl);

    cudaFuncSetAttribute(attn_mma, cudaFuncAttributeMaxDynamicSharedMemorySize, ATT_SMEM);
    cudaFuncSetAttribute(kvp_mma,  cudaFuncAttributeMaxDynamicSharedMemorySize, KVP_SMEM);
    cudaFuncSetAttribute((const void*)tgemm<0,3>, cudaFuncAttributeMaxDynamicSharedMemorySize, TG_SMEM);
    cudaFuncSetAttribute((const void*)tgemm<1,3>, cudaFuncAttributeMaxDynamicSharedMemorySize, TG_SMEM);
    cudaFuncSetAttribute((const void*)tgemm<2,2>, cudaFuncAttributeMaxDynamicSharedMemorySize, TG_SMEM);
    cudaFuncSetAttribute((const void*)tgemm<3,3>, cudaFuncAttributeMaxDynamicSharedMemorySize, TG_SMEM);

    cudaStream_t s2;
    cudaStreamCreateWithFlags(&s2, cudaStreamNonBlocking);
    cudaEvent_t eF, eJ;
    cudaEventCreateWithFlags(&eF, cudaEventDisableTiming);
    cudaEventCreateWithFlags(&eJ, cudaEventDisableTiming);

    cudaEventRecord(eF, 0);
    cudaStreamWaitEvent(s2, eF, 0);

    // branch (s2): Q chain
    wsplit_k<<<dim3(C_ / 32, C_ / 32), 256, 0, s2>>>(Wq, wqh, wql, C_, C_);
    asplit_k<<<(M_ * C_) / 1024, 256, 0, s2>>>(x1, x1h, x1l);
    tgemm<0,3><<<dim3(C_ / 128, M_ / 128), 256, TG_SMEM, s2>>>(
        x1h, x1l, wqh, wql, bq, pos_q, nullptr, nullptr, M_, C_, C_);
    cudaEventRecord(eJ, s2);

    // legacy stream: KV chain + MLP weight prep
    wsplit_k<<<dim3(2 * C_ / 32, C_ / 32), 256>>>(Wkv, wkvh, wkvl, C_, 2 * C_);
    wsplit_k<<<dim3(P_ / 32, N2_ / 32), 256>>>(Wp, wpth, wptl, N2_, P_);
    wsplit_k<<<dim3(MLP_ / 32, C_ / 32), 256>>>(W1, w1h, w1l, C_, MLP_);
    wsplit_k<<<dim3(C_ / 32, MLP_ / 32), 256>>>(W2, w2h, w2l, MLP_, C_);
    asplit_k<<<(M_ * C_) / 1024, 256>>>(x2, x2h, x2l);
    tgemm<1,3><<<dim3(2 * C_ / 128, M_ / 128), 256, TG_SMEM>>>(
        x2h, x2l, wkvh, wkvl, bkv, pos_k, nullptr, nullptr, M_, 2 * C_, C_);
    kvp_mma<<<dim3(B_ * H_, 2), 256, KVP_SMEM>>>(bp);

    // join: attention needs both q splits and kp/vp
    cudaStreamWaitEvent(0, eJ, 0);
    attn_mma<<<dim3(B_ * H_, N1_ / 64), 256, ATT_SMEM>>>(temp, xa);
    l2nq_k<<<M_ / 8, 256>>>(xa, qh, ql, xn, xnh, xnl);
    // MLP1: 2-term (weight-lo dropped; error diluted by gelu->W2->residual->l2n)
    tgemm<2,2><<<dim3(MLP_ / 128, M_ / 128), 256, TG_SMEM>>>(
        xnh, xnl, w1h, w1l, b1, nullptr, hh, hl, M_, MLP_, C_);
    tgemm<3,3><<<dim3(C_ / 128, M_ / 128), 256, TG_SMEM>>>(
        hh, hl, w2h, w2l, b2, xn, xa, nullptr, M_, C_, MLP_);
    l2n_k<<<M_ / 8, 256>>>(xa, (float*)d_out);
}

// round 12
// speedup vs baseline: 2.4557x; 1.0117x over previous
#include <cuda_runtime.h>
#include <math.h>
#include <stdint.h>

#define B_   8
#define N1_  4096
#define N2_  4096
#define C_   512
#define P_   256
#define H_   8
#define HD_  64
#define MLP_ 2048
#define M_   (B_*N1_)

typedef unsigned short u16;

__device__ float g_xa[M_*C_];
__device__ float g_xn[M_*C_];
__device__ u16 g_qh [M_*C_],  g_ql [M_*C_];
__device__ u16 g_x1h[M_*C_],  g_x1l[M_*C_];
__device__ u16 g_x2h[M_*C_],  g_x2l[M_*C_];
__device__ u16 g_xnh[M_*C_],  g_xnl[M_*C_];
__device__ u16 g_hh [M_*MLP_], g_hl [M_*MLP_];
__device__ u16 g_kTh[B_*C_*N2_], g_kTl[B_*C_*N2_];
__device__ u16 g_vTh[B_*C_*N2_], g_vTl[B_*C_*N2_];
__device__ u16 g_kpth[B_*H_*P_*HD_], g_kptl[B_*H_*P_*HD_];
__device__ u16 g_vph [B_*H_*HD_*P_], g_vpl [B_*H_*HD_*P_];
__device__ u16 g_wq_hi [C_*C_],   g_wq_lo [C_*C_];
__device__ u16 g_wkv_hi[2*C_*C_], g_wkv_lo[2*C_*C_];
__device__ u16 g_w1_hi [MLP_*C_], g_w1_lo [MLP_*C_];
__device__ u16 g_w2_hi [C_*MLP_], g_w2_lo [C_*MLP_];
__device__ u16 g_wpth  [P_*N2_],  g_wptl  [P_*N2_];

__device__ __forceinline__ uint32_t smem_u32(const void* p) {
    uint32_t a;
    asm("{ .reg .u64 t; cvta.to.shared.u64 t, %1; cvt.u32.u64 %0, t; }" : "=r"(a) : "l"(p));
    return a;
}
#define SWZ(b) ((b) ^ (((b) >> 3) & 0x70))
#define CPA16(dst, src) asm volatile("cp.async.cg.shared.global [%0], [%1], 16;" :: "r"(dst), "l"(src))
#define CPA_COMMIT() asm volatile("cp.async.commit_group;" ::: "memory")
#define CPA_WAIT1()  asm volatile("cp.async.wait_group 1;" ::: "memory")
#define CPA_WAIT0()  asm volatile("cp.async.wait_group 0;" ::: "memory")

__device__ __forceinline__ void ldsm4(uint32_t* r, uint32_t a) {
    asm volatile("ldmatrix.sync.aligned.m8n8.x4.shared.b16 {%0,%1,%2,%3}, [%4];"
                 : "=r"(r[0]), "=r"(r[1]), "=r"(r[2]), "=r"(r[3]) : "r"(a));
}
__device__ __forceinline__ void mma_bf16(float* c, const uint32_t* a, uint32_t b0, uint32_t b1) {
    asm volatile("mma.sync.aligned.m16n8k16.row.col.f32.bf16.bf16.f32 "
        "{%0,%1,%2,%3}, {%4,%5,%6,%7}, {%8,%9}, {%0,%1,%2,%3};"
        : "+f"(c[0]), "+f"(c[1]), "+f"(c[2]), "+f"(c[3])
        : "r"(a[0]), "r"(a[1]), "r"(a[2]), "r"(a[3]), "r"(b0), "r"(b1));
}
__device__ __forceinline__ void bsplit(float a, uint32_t& hi, uint32_t& lo) {
    uint32_t u = __float_as_uint(a);
    uint32_t hr = (u + 0x7fffu + ((u >> 16) & 1u)) & 0xffff0000u;
    hi = hr >> 16;
    float l = a - __uint_as_float(hr);
    uint32_t ul = __float_as_uint(l);
    lo = (ul + 0x7fffu + ((ul >> 16) & 1u)) >> 16;
}
__device__ __forceinline__ void bsplit2(float a, float b, uint32_t& hi, uint32_t& lo) {
    uint32_t h0, l0, h1, l1;
    bsplit(a, h0, l0); bsplit(b, h1, l1);
    hi = h0 | (h1 << 16); lo = l0 | (l1 << 16);
}

__global__ __launch_bounds__(256)
void wsplit_k(const float* __restrict__ W, u16* __restrict__ hi, u16* __restrict__ lo, int K, int N)
{
    __shared__ float tile[32][33];
    const int n0 = blockIdx.x * 32, k0 = blockIdx.y * 32;
    const int tx = threadIdx.x & 31, ty = threadIdx.x >> 5;
#pragma unroll
    for (int r = 0; r < 4; r++)
        tile[ty + 8 * r][tx] = W[(size_t)(k0 + ty + 8 * r) * N + n0 + tx];
    __syncthreads();
#pragma unroll
    for (int r = 0; r < 4; r++) {
        const int n = n0 + ty + 8 * r, k = k0 + tx;
        uint32_t h, l;
        bsplit(tile[tx][ty + 8 * r], h, l);
        hi[(size_t)n * K + k] = (u16)h;
        lo[(size_t)n * K + k] = (u16)l;
    }
}

__global__ __launch_bounds__(256)
void asplit_k(const float* __restrict__ A, u16* __restrict__ hi, u16* __restrict__ lo)
{
    const size_t i4 = ((size_t)blockIdx.x * 256 + threadIdx.x) * 4;
    float4 f = *(const float4*)(A + i4);
    uint32_t a, b, c, d;
    bsplit2(f.x, f.y, a, c); bsplit2(f.z, f.w, b, d);
    *(uint2*)(hi + i4) = make_uint2(a, b);
    *(uint2*)(lo + i4) = make_uint2(c, d);
}

// ---- bf16 HMMA GEMM, 128x128 tile, 3-stage cp.async ----
#define TG_SMEM (3 * 65536)
template<int EPI, int NTERM>
__global__ __launch_bounds__(256, 1)
void tgemm(const u16* __restrict__ Ahi, const u16* __restrict__ Alo,
           const u16* __restrict__ Bhi, const u16* __restrict__ Blo,
           const float* __restrict__ bias, const float* __restrict__ extra,
           void* __restrict__ out, void* __restrict__ out2, int M, int N, int K)
{
    extern __shared__ __align__(1024) char sm_raw[];
    const uint32_t sb = smem_u32(sm_raw);
    const int tid = threadIdx.x, wid = tid >> 5, lane = tid & 31;
    const int bm = blockIdx.y * 128, bn = blockIdx.x * 128;
    const int wm = (wid & 1) * 64, wn = (wid >> 1) * 32;
    const int nck = K >> 6;

    float acc[4][4][4];
#pragma unroll
    for (int i = 0; i < 4; i++)
#pragma unroll
        for (int j = 0; j < 4; j++)
#pragma unroll
            for (int r = 0; r < 4; r++) acc[i][j][r] = 0.0f;

    const int a_row = ((lane >> 3) & 1) * 8 + (lane & 7);
    const int a_col = (lane >> 4) * 8;
    const int b_row = (lane >> 4) * 8 + (lane & 7);
    const int b_col = ((lane >> 3) & 1) * 8;

    auto load_stage = [&](int ck, int stage) {
        if (ck < nck) {
            const int k0 = ck * 64;
            const uint32_t sbase = sb + stage * 65536;
#pragma unroll
            for (int i = 0; i < 4; i++) {
                const int id = tid + i * 256;
                const int row = id >> 3, c16 = id & 7;
                const uint32_t dsw = SWZ((uint32_t)(row * 128 + c16 * 16));
                const size_t asrc = (size_t)(bm + row) * K + k0 + c16 * 8;
                const size_t bsrc = (size_t)(bn + row) * K + k0 + c16 * 8;
                CPA16(sbase + dsw,         Ahi + asrc);
                CPA16(sbase + 16384 + dsw, Alo + asrc);
                CPA16(sbase + 32768 + dsw, Bhi + bsrc);
                if (NTERM == 3) CPA16(sbase + 49152 + dsw, Blo + bsrc);
            }
        }
        CPA_COMMIT();
    };

    load_stage(0, 0);
    load_stage(1, 1);

    for (int ck = 0; ck < nck; ck++) {
        CPA_WAIT1();
        __syncthreads();
        load_stage(ck + 2, (ck + 2) % 3);
        const uint32_t base = sb + (ck % 3) * 65536;
#pragma unroll
        for (int ks = 0; ks < 4; ks++) {
            const int kk = ks * 16;
            uint32_t ah[4][4], al[4][4], bh[2][4], bl[2][4];
#pragma unroll
            for (int mf = 0; mf < 4; mf++) {
                const uint32_t ao = SWZ((uint32_t)((wm + mf * 16 + a_row) * 128 + (kk + a_col) * 2));
                ldsm4(ah[mf], base + ao);
                ldsm4(al[mf], base + 16384 + ao);
            }
#pragma unroll
            for (int p = 0; p < 2; p++) {
                const uint32_t bo = SWZ((uint32_t)((wn + p * 16 + b_row) * 128 + (kk + b_col) * 2));
                ldsm4(bh[p], base + 32768 + bo);
                if (NTERM == 3) ldsm4(bl[p], base + 49152 + bo);
            }
#pragma unroll
            for (int mf = 0; mf < 4; mf++)
#pragma unroll
                for (int p = 0; p < 2; p++)
#pragma unroll
                    for (int s = 0; s < 2; s++) {
                        float* c = acc[mf][p * 2 + s];
                        mma_bf16(c, ah[mf], bh[p][s * 2], bh[p][s * 2 + 1]);
                        mma_bf16(c, al[mf], bh[p][s * 2], bh[p][s * 2 + 1]);
                        if (NTERM == 3)
                            mma_bf16(c, ah[mf], bl[p][s * 2], bl[p][s * 2 + 1]);
                    }
        }
    }

    const int l4 = lane >> 2, l2 = (lane & 3) * 2;

    if (EPI == 1) {
        CPA_WAIT0();
        __syncthreads();
        float* T = (float*)sm_raw;                       // 128 x 132 floats
        const bool is_k = (bn < C_);
#pragma unroll
        for (int mf = 0; mf < 4; mf++)
#pragma unroll
            for (int nf = 0; nf < 4; nf++) {
                const int colL = wn + nf * 8 + l2;
                const int col = bn + colL;
                const float bia0 = bias[col], bia1 = bias[col + 1];
#pragma unroll
                for (int half = 0; half < 2; half++) {
                    const int mL = wm + mf * 16 + l4 + half * 8;
                    float v0 = acc[mf][nf][half * 2]     + bia0;
                    float v1 = acc[mf][nf][half * 2 + 1] + bia1;
                    if (is_k) {
                        const int n = (bm + mL) & (N2_ - 1);
                        v0 += extra[(size_t)n * C_ + col];
                        v1 += extra[(size_t)n * C_ + col + 1];
                    }
                    T[colL * 132 + mL]       = v0;
                    T[(colL + 1) * 132 + mL] = v1;
                }
            }
        __syncthreads();
        u16* __restrict__ dh = is_k ? g_kTh : g_vTh;
        u16* __restrict__ dl = is_k ? g_kTl : g_vTl;
        const int bb = bm >> 12, n0 = bm & (N2_ - 1);
        const int r = tid >> 1, hh2 = (tid & 1) * 64;
        const int c = (bn + r) - (is_k ? 0 : C_);
        const size_t gbase = ((size_t)bb * C_ + c) * N2_ + n0 + hh2;
        const float* Tr = T + r * 132 + hh2;
#pragma unroll
        for (int j = 0; j < 64; j += 8) {
            uint32_t h0, l0, h1, l1, h2, l2x, h3, l3;
            bsplit2(Tr[j],     Tr[j + 1], h0, l0);
            bsplit2(Tr[j + 2], Tr[j + 3], h1, l1);
            bsplit2(Tr[j + 4], Tr[j + 5], h2, l2x);
            bsplit2(Tr[j + 6], Tr[j + 7], h3, l3);
            *(uint4*)(dh + gbase + j) = make_uint4(h0, h1, h2, h3);
            *(uint4*)(dl + gbase + j) = make_uint4(l0, l1, l2x, l3);
        }
        return;
    }

#pragma unroll
    for (int mf = 0; mf < 4; mf++)
#pragma unroll
        for (int nf = 0; nf < 4; nf++) {
            const int col = bn + wn + nf * 8 + l2;
            const float bia0 = bias[col], bia1 = bias[col + 1];
#pragma unroll
            for (int half = 0; half < 2; half++) {
                const int m = bm + wm + mf * 16 + l4 + half * 8;
                float v0 = acc[mf][nf][half * 2]     + bia0;
                float v1 = acc[mf][nf][half * 2 + 1] + bia1;
                if (EPI == 0) {
                    v0 += extra[(size_t)(m & (N1_ - 1)) * C_ + col];
                    v1 += extra[(size_t)(m & (N1_ - 1)) * C_ + col + 1];
                    uint32_t hi, lo;
                    bsplit2(v0, v1, hi, lo);
                    *(uint32_t*)(g_qh + (size_t)m * N + col) = hi;
                    *(uint32_t*)(g_ql + (size_t)m * N + col) = lo;
                } else if (EPI == 2) {
                    v0 = 0.5f * v0 * (1.0f + erff(v0 * 0.70710678118654752f));
                    v1 = 0.5f * v1 * (1.0f + erff(v1 * 0.70710678118654752f));
                    uint32_t hi, lo;
                    bsplit2(v0, v1, hi, lo);
                    *(uint32_t*)((u16*)out  + (size_t)m * N + col) = hi;
                    *(uint32_t*)((u16*)out2 + (size_t)m * N + col) = lo;
                } else {
                    v0 += extra[(size_t)m * N + col];
                    v1 += extra[(size_t)m * N + col + 1];
                    *(float2*)((float*)out + (size_t)m * N + col) = make_float2(v0, v1);
                }
            }
        }
}

// ---- kvp via bf16x3 HMMA ----
#define KVP_STG  81920
#define KVP_SMEM (2 * KVP_STG)
__global__ __launch_bounds__(256, 1)
void kvp_mma(const float* __restrict__ bp)
{
    extern __shared__ __align__(1024) char sm_raw[];
    const uint32_t sb = smem_u32(sm_raw);
    const int tid = threadIdx.x, wid = tid >> 5, lane = tid & 31;
    const int g = lane >> 2, t4 = lane & 3;
    const int bh = blockIdx.x, b = bh >> 3, h = bh & 7;
    const int mode = blockIdx.y;
    const u16* __restrict__ Dh = mode ? g_vTh : g_kTh;
    const u16* __restrict__ Dl = mode ? g_vTl : g_kTl;

    const int a_row = ((lane >> 3) & 1) * 8 + (lane & 7);
    const int a_col = (lane >> 4) * 8;
    const int b_row = (lane >> 4) * 8 + (lane & 7);
    const int b_col = ((lane >> 3) & 1) * 8;

    auto load_stage = [&](int ck) {
        if (ck < 64) {
            const uint32_t base = sb + (ck & 1) * KVP_STG;
            const int k0 = ck * 64;
#pragma unroll
            for (int t = 0; t < 8; t++) {
                const int i = tid + t * 256;
                const int row = i >> 3, c16 = i & 7;
                const uint32_t dsw = SWZ((uint32_t)(row * 128 + c16 * 16));
                const size_t src = (size_t)row * N2_ + k0 + c16 * 8;
                CPA16(base + dsw,         g_wpth + src);
                CPA16(base + 32768 + dsw, g_wptl + src);
            }
#pragma unroll
            for (int t = 0; t < 2; t++) {
                const int i = tid + t * 256;
                const int row = i >> 3, c16 = i & 7;
                const uint32_t dsw = SWZ((uint32_t)(row * 128 + c16 * 16));
                const size_t src = ((size_t)b * C_ + h * 64 + row) * N2_ + k0 + c16 * 8;
                CPA16(base + 65536 + dsw, Dh + src);
                CPA16(base + 73728 + dsw, Dl + src);
            }
        }
        CPA_COMMIT();
    };

    load_stage(0);
    load_stage(1);

    if (mode == 0) {
        const int wm = (wid & 3) * 64, wn = (wid >> 2) * 32;
        float acc[4][4][4];
#pragma unroll
        for (int i = 0; i < 4; i++)
#pragma unroll
            for (int j = 0; j < 4; j++)
#pragma unroll
                for (int r = 0; r < 4; r++) acc[i][j][r] = 0.0f;

        for (int ck = 0; ck < 64; ck++) {
            CPA_WAIT1();
            __syncthreads();
            const uint32_t base = sb + (ck & 1) * KVP_STG;
#pragma unroll
            for (int ks = 0; ks < 4; ks++) {
                const int kk = ks * 16;
                uint32_t ah[4][4], al[4][4], bhr[2][4], blr[2][4];
#pragma unroll
                for (int mf = 0; mf < 4; mf++) {
                    const uint32_t ao = SWZ((uint32_t)((wm + mf * 16 + a_row) * 128 + (kk + a_col) * 2));
                    ldsm4(ah[mf], base + ao);
                    ldsm4(al[mf], base + 32768 + ao);
                }
#pragma unroll
                for (int p = 0; p < 2; p++) {
                    const uint32_t bo = SWZ((uint32_t)((wn + p * 16 + b_row) * 128 + (kk + b_col) * 2));
                    ldsm4(bhr[p], base + 65536 + bo);
                    ldsm4(blr[p], base + 73728 + bo);
                }
#pragma unroll
                for (int mf = 0; mf < 4; mf++)
#pragma unroll
                    for (int p = 0; p < 2; p++)
#pragma unroll
                        for (int s = 0; s < 2; s++) {
                            float* c = acc[mf][p * 2 + s];
                            mma_bf16(c, ah[mf], bhr[p][s * 2], bhr[p][s * 2 + 1]);
                            mma_bf16(c, al[mf], bhr[p][s * 2], bhr[p][s * 2 + 1]);
                            mma_bf16(c, ah[mf], blr[p][s * 2], blr[p][s * 2 + 1]);
                        }
            }
            __syncthreads();
            load_stage(ck + 2);
        }
#pragma unroll
        for (int mf = 0; mf < 4; mf++)
#pragma unroll
            for (int hf = 0; hf < 2; hf++) {
                const int p = wm + mf * 16 + hf * 8 + g;
                const float bv = bp[p];
#pragma unroll
                for (int nf = 0; nf < 4; nf++) {
                    const int d = wn + nf * 8 + t4 * 2;
                    uint32_t hi, lo;
                    bsplit2(acc[mf][nf][hf * 2] + bv, acc[mf][nf][hf * 2 + 1] + bv, hi, lo);
                    *(uint32_t*)(g_kpth + (size_t)bh * (P_ * HD_) + p * 64 + d) = hi;
                    *(uint32_t*)(g_kptl + (size_t)bh * (P_ * HD_) + p * 64 + d) = lo;
                }
            }
    } else {
        const int wm = (wid & 1) * 32, wn = (wid >> 1) * 64;
        float acc[2][8][4];
#pragma unroll
        for (int i = 0; i < 2; i++)
#pragma unroll
            for (int j = 0; j < 8; j++)
#pragma unroll
                for (int r = 0; r < 4; r++) acc[i][j][r] = 0.0f;

        for (int ck = 0; ck < 64; ck++) {
            CPA_WAIT1();
            __syncthreads();
            const uint32_t base = sb + (ck & 1) * KVP_STG;
#pragma unroll
            for (int ks = 0; ks < 4; ks++) {
                const int kk = ks * 16;
                uint32_t ah[2][4], al[2][4];
#pragma unroll
                for (int mf = 0; mf < 2; mf++) {
                    const uint32_t ao = SWZ((uint32_t)((wm + mf * 16 + a_row) * 128 + (kk + a_col) * 2));
                    ldsm4(ah[mf], base + 65536 + ao);
                    ldsm4(al[mf], base + 73728 + ao);
                }
#pragma unroll
                for (int p = 0; p < 4; p++) {
                    uint32_t bhr[4], blr[4];
                    const uint32_t bo = SWZ((uint32_t)((wn + p * 16 + b_row) * 128 + (kk + b_col) * 2));
                    ldsm4(bhr, base + bo);
                    ldsm4(blr, base + 32768 + bo);
#pragma unroll
                    for (int mf = 0; mf < 2; mf++)
#pragma unroll
                        for (int s = 0; s < 2; s++) {
                            float* c = acc[mf][p * 2 + s];
                            mma_bf16(c, ah[mf], bhr[s * 2], bhr[s * 2 + 1]);
                            mma_bf16(c, al[mf], bhr[s * 2], bhr[s * 2 + 1]);
                            mma_bf16(c, ah[mf], blr[s * 2], blr[s * 2 + 1]);
                        }
                }
            }
            __syncthreads();
            load_stage(ck + 2);
        }
#pragma unroll
        for (int mf = 0; mf < 2; mf++)
#pragma unroll
            for (int hf = 0; hf < 2; hf++) {
                const int d = wm + mf * 16 + hf * 8 + g;
#pragma unroll
                for (int nf = 0; nf < 8; nf++) {
                    const int p = wn + nf * 8 + t4 * 2;
                    uint32_t hi, lo;
                    bsplit2(acc[mf][nf][hf * 2] + bp[p], acc[mf][nf][hf * 2 + 1] + bp[p + 1], hi, lo);
                    *(uint32_t*)(g_vph + (size_t)bh * (HD_ * P_) + d * 256 + p) = hi;
                    *(uint32_t*)(g_vpl + (size_t)bh * (HD_ * P_) + d * 256 + p) = lo;
                }
            }
    }
}

// ---- attention via bf16x3 HMMA ----
#define A_QH   0
#define A_QL   8192
#define A_KH   16384
#define A_KL   49152
#define A_VH   81920
#define A_VL   114688
#define A_ST   147456
#define A_ZN   149504
#define ATT_SMEM (149504 + 4*64*66*4)

__global__ __launch_bounds__(256, 1)
void attn_mma(const float* __restrict__ temp, float* __restrict__ xa)
{
    extern __shared__ __align__(1024) char sm_raw[];
    const uint32_t sb = smem_u32(sm_raw);
    const int tid = threadIdx.x, wid = tid >> 5, lane = tid & 31;
    const int g = lane >> 2, t4 = lane & 3;
    const int bh = blockIdx.x, b = bh >> 3, h = bh & 7;
    const int q0 = blockIdx.y * 64;
    const int wm = (wid & 1) * 32, zn = wid >> 1, wn = zn * 64;

#pragma unroll
    for (int t = 0; t < 2; t++) {
        const int i = tid + t * 256;
        const int row = i >> 3, c16 = i & 7;
        const uint32_t dsw = SWZ((uint32_t)(row * 128 + c16 * 16));
        const size_t src = (size_t)(b * N1_ + q0 + row) * C_ + h * 64 + c16 * 8;
        CPA16(sb + A_QH + dsw, g_qh + src);
        CPA16(sb + A_QL + dsw, g_ql + src);
    }
#pragma unroll
    for (int t = 0; t < 8; t++) {
        const int i = tid + t * 256;
        const int row = i >> 3, c16 = i & 7;
        const uint32_t dsw = SWZ((uint32_t)(row * 128 + c16 * 16));
        const size_t src = (size_t)bh * (P_ * HD_) + row * 64 + c16 * 8;
        CPA16(sb + A_KH + dsw, g_kpth + src);
        CPA16(sb + A_KL + dsw, g_kptl + src);
    }
#pragma unroll
    for (int t = 0; t < 8; t++) {
        const int i = tid + t * 256;
        const int c16 = i & 7, d = (i >> 3) & 63, ch = i >> 9;
        const uint32_t dsw = (uint32_t)(ch * 8192) + SWZ((uint32_t)(d * 128 + c16 * 16));
        const size_t src = (size_t)bh * (HD_ * P_) + d * 256 + ch * 64 + c16 * 8;
        CPA16(sb + A_VH + dsw, g_vph + src);
        CPA16(sb + A_VL + dsw, g_vpl + src);
    }
    CPA_COMMIT();
    CPA_WAIT0();
    __syncthreads();

    const int a_row = ((lane >> 3) & 1) * 8 + (lane & 7);
    const int a_col = (lane >> 4) * 8;
    const int b_row = (lane >> 4) * 8 + (lane & 7);
    const int b_col = ((lane >> 3) & 1) * 8;

    float acc[2][8][4];
#pragma unroll
    for (int i = 0; i < 2; i++)
#pragma unroll
        for (int j = 0; j < 8; j++)
#pragma unroll
            for (int r = 0; r < 4; r++) acc[i][j][r] = 0.0f;

#pragma unroll
    for (int ks = 0; ks < 4; ks++) {
        const int kk = ks * 16;
        uint32_t ah[2][4], al[2][4];
#pragma unroll
        for (int mf = 0; mf < 2; mf++) {
            const uint32_t ao = SWZ((uint32_t)((wm + mf * 16 + a_row) * 128 + (kk + a_col) * 2));
            ldsm4(ah[mf], sb + A_QH + ao);
            ldsm4(al[mf], sb + A_QL + ao);
        }
#pragma unroll
        for (int p = 0; p < 4; p++) {
            uint32_t bhr[4], blr[4];
            const uint32_t bo = SWZ((uint32_t)((wn + p * 16 + b_row) * 128 + (kk + b_col) * 2));
            ldsm4(bhr, sb + A_KH + bo);
            ldsm4(blr, sb + A_KL + bo);
#pragma unroll
            for (int mf = 0; mf < 2; mf++)
#pragma unroll
                for (int s = 0; s < 2; s++) {
                    float* c = acc[mf][p * 2 + s];
                    mma_bf16(c, ah[mf], bhr[s * 2], bhr[s * 2 + 1]);
                    mma_bf16(c, al[mf], bhr[s * 2], bhr[s * 2 + 1]);
                    mma_bf16(c, ah[mf], blr[s * 2], blr[s * 2 + 1]);
                }
        }
    }

    const float tscale = temp[h];
    float* smax = (float*)(sm_raw + A_ST);
    float* ssum = smax + 256;
#pragma unroll
    for (int mf = 0; mf < 2; mf++)
#pragma unroll
        for (int nf = 0; nf < 8; nf++)
#pragma unroll
            for (int r = 0; r < 4; r++) acc[mf][nf][r] *= tscale;

    float rmx[2][2] = {{-1e30f, -1e30f}, {-1e30f, -1e30f}};
#pragma unroll
    for (int mf = 0; mf < 2; mf++)
#pragma unroll
        for (int nf = 0; nf < 8; nf++) {
            rmx[mf][0] = fmaxf(rmx[mf][0], fmaxf(acc[mf][nf][0], acc[mf][nf][1]));
            rmx[mf][1] = fmaxf(rmx[mf][1], fmaxf(acc[mf][nf][2], acc[mf][nf][3]));
        }
#pragma unroll
    for (int mf = 0; mf < 2; mf++)
#pragma unroll
        for (int hf = 0; hf < 2; hf++) {
            rmx[mf][hf] = fmaxf(rmx[mf][hf], __shfl_xor_sync(~0u, rmx[mf][hf], 1));
            rmx[mf][hf] = fmaxf(rmx[mf][hf], __shfl_xor_sync(~0u, rmx[mf][hf], 2));
        }
    if (t4 == 0)
#pragma unroll
        for (int mf = 0; mf < 2; mf++)
#pragma unroll
            for (int hf = 0; hf < 2; hf++)
                smax[(wm + mf * 16 + hf * 8 + g) * 4 + zn] = rmx[mf][hf];
    __syncthreads();
    float gmx[2][2], rsm[2][2] = {{0, 0}, {0, 0}};
#pragma unroll
    for (int mf = 0; mf < 2; mf++)
#pragma unroll
        for (int hf = 0; hf < 2; hf++) {
            const int r = wm + mf * 16 + hf * 8 + g;
            gmx[mf][hf] = fmaxf(fmaxf(smax[r * 4], smax[r * 4 + 1]),
                                fmaxf(smax[r * 4 + 2], smax[r * 4 + 3]));
        }
#pragma unroll
    for (int mf = 0; mf < 2; mf++)
#pragma unroll
        for (int nf = 0; nf < 8; nf++)
#pragma unroll
            for (int r = 0; r < 4; r++) {
                const int hf = r >> 1;
                const float e = __expf(acc[mf][nf][r] - gmx[mf][hf]);
                acc[mf][nf][r] = e;
                rsm[mf][hf] += e;
            }
#pragma unroll
    for (int mf = 0; mf < 2; mf++)
#pragma unroll
        for (int hf = 0; hf < 2; hf++) {
            rsm[mf][hf] += __shfl_xor_sync(~0u, rsm[mf][hf], 1);
            rsm[mf][hf] += __shfl_xor_sync(~0u, rsm[mf][hf], 2);
        }
    if (t4 == 0)
#pragma unroll
        for (int mf = 0; mf < 2; mf++)
#pragma unroll
            for (int hf = 0; hf < 2; hf++)
                ssum[(wm + mf * 16 + hf * 8 + g) * 4 + zn] = rsm[mf][hf];
    __syncthreads();
#pragma unroll
    for (int mf = 0; mf < 2; mf++)
#pragma unroll
        for (int hf = 0; hf < 2; hf++) {
            const int r = wm + mf * 16 + hf * 8 + g;
            const float inv = 1.0f / (ssum[r * 4] + ssum[r * 4 + 1] + ssum[r * 4 + 2] + ssum[r * 4 + 3]);
#pragma unroll
            for (int nf = 0; nf < 8; nf++) {
                acc[mf][nf][hf * 2]     *= inv;
                acc[mf][nf][hf * 2 + 1] *= inv;
            }
        }

    float acc2[2][8][4];
#pragma unroll
    for (int i = 0; i < 2; i++)
#pragma unroll
        for (int j = 0; j < 8; j++)
#pragma unroll
            for (int r = 0; r < 4; r++) acc2[i][j][r] = 0.0f;

#pragma unroll
    for (int kf = 0; kf < 4; kf++) {
        uint32_t pah[2][4], pal[2][4];
#pragma unroll
        for (int mf = 0; mf < 2; mf++) {
            bsplit2(acc[mf][2*kf][0],   acc[mf][2*kf][1],   pah[mf][0], pal[mf][0]);
            bsplit2(acc[mf][2*kf][2],   acc[mf][2*kf][3],   pah[mf][1], pal[mf][1]);
            bsplit2(acc[mf][2*kf+1][0], acc[mf][2*kf+1][1], pah[mf][2], pal[mf][2]);
            bsplit2(acc[mf][2*kf+1][2], acc[mf][2*kf+1][3], pah[mf][3], pal[mf][3]);
        }
#pragma unroll
        for (int df = 0; df < 4; df++) {
            uint32_t bhr[4], blr[4];
            const uint32_t bo = (uint32_t)(zn * 8192) +
                SWZ((uint32_t)((df * 16 + b_row) * 128 + (kf * 16 + b_col) * 2));
            ldsm4(bhr, sb + A_VH + bo);
            ldsm4(blr, sb + A_VL + bo);
#pragma unroll
            for (int mf = 0; mf < 2; mf++)
#pragma unroll
                for (int s = 0; s < 2; s++) {
                    float* c = acc2[mf][df * 2 + s];
                    mma_bf16(c, pah[mf], bhr[s * 2], bhr[s * 2 + 1]);
                    mma_bf16(c, pal[mf], bhr[s * 2], bhr[s * 2 + 1]);
                    mma_bf16(c, pah[mf], blr[s * 2], blr[s * 2 + 1]);
                }
        }
    }

    float* zone = (float*)(sm_raw + A_ZN) + zn * (64 * 66);
#pragma unroll
    for (int mf = 0; mf < 2; mf++)
#pragma unroll
        for (int nf = 0; nf < 8; nf++)
#pragma unroll
            for (int hf = 0; hf < 2; hf++) {
                const int row = wm + mf * 16 + hf * 8 + g;
                const int dc = nf * 8 + t4 * 2;
                *(float2*)&zone[row * 66 + dc] =
                    make_float2(acc2[mf][nf][hf * 2], acc2[mf][nf][hf * 2 + 1]);
            }
    __syncthreads();

    const int tx = tid & 15, ty = tid >> 4;
    float* z0 = (float*)(sm_raw + A_ZN);
    const size_t base = (size_t)b * (N1_ * C_) + (size_t)h * N1_ + q0 + tx * 4;
#pragma unroll
    for (int j = 0; j < 4; j++) {
        const int d = ty * 4 + j;
        float o[4];
#pragma unroll
        for (int qi = 0; qi < 4; qi++) {
            const int idx = (tx * 4 + qi) * 66 + d;
            o[qi] = z0[idx] + z0[64*66 + idx] + z0[2*64*66 + idx] + z0[3*64*66 + idx];
        }
        *(float4*)&xa[base + (size_t)d * (H_ * N1_)] = make_float4(o[0], o[1], o[2], o[3]);
    }
}

// ---- L2 norm with bf16-split residual input + split output ----
__global__ __launch_bounds__(256)
void l2nq_k(const float* __restrict__ a, const u16* __restrict__ qh,
            const u16* __restrict__ ql, float* __restrict__ out,
            u16* __restrict__ oh, u16* __restrict__ ol)
{
    const int row = blockIdx.x * 8 + (threadIdx.x >> 5);
    const int lane = threadIdx.x & 31;
    const float4* pa = (const float4*)(a + (size_t)row * C_);
    float4 v[4];
    float ss = 0.0f;
#pragma unroll
    for (int i = 0; i < 4; i++) {
        float4 t = pa[lane + 32 * i];
        const size_t off = (size_t)row * C_ + (lane + 32 * i) * 4;
        const uint2 hq = *(const uint2*)(qh + off);
        const uint2 lq = *(const uint2*)(ql + off);
        t.x += __uint_as_float(hq.x << 16)          + __uint_as_float(lq.x << 16);
        t.y += __uint_as_float(hq.x & 0xffff0000u)  + __uint_as_float(lq.x & 0xffff0000u);
        t.z += __uint_as_float(hq.y << 16)          + __uint_as_float(lq.y << 16);
        t.w += __uint_as_float(hq.y & 0xffff0000u)  + __uint_as_float(lq.y & 0xffff0000u);
        v[i] = t;
        ss += t.x * t.x + t.y * t.y + t.z * t.z + t.w * t.w;
    }
#pragma unroll
    for (int o = 16; o > 0; o >>= 1) ss += __shfl_xor_sync(~0u, ss, o);
    const float inv = 1.0f / fmaxf(sqrtf(ss), 1e-12f);
    float4* po = (float4*)(out + (size_t)row * C_);
#pragma unroll
    for (int i = 0; i < 4; i++) {
        v[i].x *= inv; v[i].y *= inv; v[i].z *= inv; v[i].w *= inv;
        po[lane + 32 * i] = v[i];
        uint32_t a0, b0, c0, d0;
        bsplit2(v[i].x, v[i].y, a0, c0); bsplit2(v[i].z, v[i].w, b0, d0);
        const size_t off = (size_t)row * C_ + (lane + 32 * i) * 4;
        *(uint2*)(oh + off) = make_uint2(a0, b0);
        *(uint2*)(ol + off) = make_uint2(c0, d0);
    }
}

__global__ __launch_bounds__(256)
void l2n_k(const float* __restrict__ a, float* __restrict__ out)
{
    const int row = blockIdx.x * 8 + (threadIdx.x >> 5);
    const int lane = threadIdx.x & 31;
    const float4* pa = (const float4*)(a + (size_t)row * C_);
    float4 v[4];
    float ss = 0.0f;
#pragma unroll
    for (int i = 0; i < 4; i++) {
        float4 t = pa[lane + 32 * i];
        v[i] = t;
        ss += t.x * t.x + t.y * t.y + t.z * t.z + t.w * t.w;
    }
#pragma unroll
    for (int o = 16; o > 0; o >>= 1) ss += __shfl_xor_sync(~0u, ss, o);
    const float inv = 1.0f / fmaxf(sqrtf(ss), 1e-12f);
    float4* po = (float4*)(out + (size_t)row * C_);
#pragma unroll
    for (int i = 0; i < 4; i++) {
        v[i].x *= inv; v[i].y *= inv; v[i].z *= inv; v[i].w *= inv;
        po[lane + 32 * i] = v[i];
    }
}

extern "C" void kernel_launch(void* const* d_in, const int* in_sizes, int n_in,
                              void* d_out, int out_size)
{
    const float* x1    = (const float*)d_in[0];
    const float* x2    = (const float*)d_in[1];
    const float* Wq    = (const float*)d_in[2];
    const float* bq    = (const float*)d_in[3];
    const float* Wkv   = (const float*)d_in[4];
    const float* bkv   = (const float*)d_in[5];
    const float* Wp    = (const float*)d_in[6];
    const float* bp    = (const float*)d_in[7];
    const float* pos_q = (const float*)d_in[8];
    const float* pos_k = (const float*)d_in[9];
    const float* temp  = (const float*)d_in[10];
    const float* W1    = (const float*)d_in[11];
    const float* b1    = (const float*)d_in[12];
    const float* W2    = (const float*)d_in[13];
    const float* b2    = (const float*)d_in[14];

    float *xa, *xn;
    u16 *qh, *ql, *x1h, *x1l, *x2h, *x2l, *xnh, *xnl, *hh, *hl;
    u16 *wqh, *wql, *wkvh, *wkvl, *w1h, *w1l, *w2h, *w2l, *wpth, *wptl;
    cudaGetSymbolAddress((void**)&xa, g_xa);
    cudaGetSymbolAddress((void**)&xn, g_xn);
    cudaGetSymbolAddress((void**)&qh, g_qh);   cudaGetSymbolAddress((void**)&ql, g_ql);
    cudaGetSymbolAddress((void**)&x1h, g_x1h); cudaGetSymbolAddress((void**)&x1l, g_x1l);
    cudaGetSymbolAddress((void**)&x2h, g_x2h); cudaGetSymbolAddress((void**)&x2l, g_x2l);
    cudaGetSymbolAddress((void**)&xnh, g_xnh); cudaGetSymbolAddress((void**)&xnl, g_xnl);
    cudaGetSymbolAddress((void**)&hh, g_hh);   cudaGetSymbolAddress((void**)&hl, g_hl);
    cudaGetSymbolAddress((void**)&wqh, g_wq_hi);   cudaGetSymbolAddress((void**)&wql, g_wq_lo);
    cudaGetSymbolAddress((void**)&wkvh, g_wkv_hi); cudaGetSymbolAddress((void**)&wkvl, g_wkv_lo);
    cudaGetSymbolAddress((void**)&w1h, g_w1_hi);   cudaGetSymbolAddress((void**)&w1l, g_w1_lo);
    cudaGetSymbolAddress((void**)&w2h, g_w2_hi);   cudaGetSymbolAddress((void**)&w2l, g_w2_lo);
    cudaGetSymbolAddress((void**)&wpth, g_wpth);   cudaGetSymbolAddress((void**)&wptl, g_wptl);

    cudaFuncSetAttribute(attn_mma, cudaFuncAttributeMaxDynamicSharedMemorySize, ATT_SMEM);
    cudaFuncSetAttribute(kvp_mma,  cudaFuncAttributeMaxDynamicSharedMemorySize, KVP_SMEM);
    cudaFuncSetAttribute((const void*)tgemm<0,3>, cudaFuncAttributeMaxDynamicSharedMemorySize, TG_SMEM);
    cudaFuncSetAttribute((const void*)tgemm<1,3>, cudaFuncAttributeMaxDynamicSharedMemorySize, TG_SMEM);
    cudaFuncSetAttribute((const void*)tgemm<2,2>, cudaFuncAttributeMaxDynamicSharedMemorySize, TG_SMEM);
    cudaFuncSetAttribute((const void*)tgemm<3,3>, cudaFuncAttributeMaxDynamicSharedMemorySize, TG_SMEM);

    cudaStream_t s2;
    cudaStreamCreateWithFlags(&s2, cudaStreamNonBlocking);
    cudaEvent_t eF, eKV, eJ, eW;
    cudaEventCreateWithFlags(&eF,  cudaEventDisableTiming);
    cudaEventCreateWithFlags(&eKV, cudaEventDisableTiming);
    cudaEventCreateWithFlags(&eJ,  cudaEventDisableTiming);
    cudaEventCreateWithFlags(&eW,  cudaEventDisableTiming);

    cudaEventRecord(eF, 0);
    cudaStreamWaitEvent(s2, eF, 0);

    // s2: Q-chain prep (runs during legacy prep + tgemm<1>)
    wsplit_k<<<dim3(C_ / 32, C_ / 32), 256, 0, s2>>>(Wq, wqh, wql, C_, C_);
    asplit_k<<<(M_ * C_) / 1024, 256, 0, s2>>>(x1, x1h, x1l);

    // legacy: KV chain
    wsplit_k<<<dim3(2 * C_ / 32, C_ / 32), 256>>>(Wkv, wkvh, wkvl, C_, 2 * C_);
    wsplit_k<<<dim3(P_ / 32, N2_ / 32), 256>>>(Wp, wpth, wptl, N2_, P_);
    asplit_k<<<(M_ * C_) / 1024, 256>>>(x2, x2h, x2l);
    tgemm<1,3><<<dim3(2 * C_ / 128, M_ / 128), 256, TG_SMEM>>>(
        x2h, x2l, wkvh, wkvl, bkv, pos_k, nullptr, nullptr, M_, 2 * C_, C_);
    cudaEventRecord(eKV, 0);

    // s2: hold tgemm<0> + W1/W2 splits until kvp starts, so they fill
    // kvp's idle SMs (kvp launches only 128 CTAs on 148 SMs).
    cudaStreamWaitEvent(s2, eKV, 0);
    tgemm<0,3><<<dim3(C_ / 128, M_ / 128), 256, TG_SMEM, s2>>>(
        x1h, x1l, wqh, wql, bq, pos_q, nullptr, nullptr, M_, C_, C_);
    cudaEventRecord(eJ, s2);
    wsplit_k<<<dim3(MLP_ / 32, C_ / 32), 256, 0, s2>>>(W1, w1h, w1l, C_, MLP_);
    wsplit_k<<<dim3(C_ / 32, MLP_ / 32), 256, 0, s2>>>(W2, w2h, w2l, MLP_, C_);
    cudaEventRecord(eW, s2);

    // legacy: kvp co-runs with s2's tgemm<0> / W-splits
    kvp_mma<<<dim3(B_ * H_, 2), 256, KVP_SMEM>>>(bp);

    // join: attention needs q splits (eJ) and kp/vp
    cudaStreamWaitEvent(0, eJ, 0);
    attn_mma<<<dim3(B_ * H_, N1_ / 64), 256, ATT_SMEM>>>(temp, xa);
    l2nq_k<<<M_ / 8, 256>>>(xa, qh, ql, xn, xnh, xnl);
    // MLP needs W1/W2 splits from s2
    cudaStreamWaitEvent(0, eW, 0);
    tgemm<2,2><<<dim3(MLP_ / 128, M_ / 128), 256, TG_SMEM>>>(
        xnh, xnl, w1h, w1l, b1, nullptr, hh, hl, M_, MLP_, C_);
    tgemm<3,3><<<dim3(C_ / 128, M_ / 128), 256, TG_SMEM>>>(
        hh, hl, w2h, w2l, b2, xn, xa, nullptr, M_, C_, MLP_);
    l2n_k<<<M_ / 8, 256>>>(xa, (float*)d_out);
}

// round 13
// speedup vs baseline: 2.7440x; 1.1174x over previous
#include <cuda_runtime.h>
#include <math.h>
#include <stdint.h>

#define B_   8
#define N1_  4096
#define N2_  4096
#define C_   512
#define P_   256
#define H_   8
#define HD_  64
#define MLP_ 2048
#define M_   (B_*N1_)

typedef unsigned short u16;

__device__ float g_xa[M_*C_];
__device__ float g_xn[M_*C_];
__device__ u16 g_qh [M_*C_],  g_ql [M_*C_];
__device__ u16 g_x1h[M_*C_],  g_x1l[M_*C_];
__device__ u16 g_x2h[M_*C_],  g_x2l[M_*C_];
__device__ u16 g_xnh[M_*C_],  g_xnl[M_*C_];
__device__ u16 g_hh [M_*MLP_];
__device__ u16 g_kTh[B_*C_*N2_], g_kTl[B_*C_*N2_];
__device__ u16 g_vTh[B_*C_*N2_], g_vTl[B_*C_*N2_];
__device__ u16 g_kpth[B_*H_*P_*HD_], g_kptl[B_*H_*P_*HD_];
__device__ u16 g_vph [B_*H_*HD_*P_], g_vpl [B_*H_*HD_*P_];
__device__ u16 g_wq_hi [C_*C_],   g_wq_lo [C_*C_];
__device__ u16 g_wkv_hi[2*C_*C_], g_wkv_lo[2*C_*C_];
__device__ u16 g_w1_hi [MLP_*C_], g_w1_lo [MLP_*C_];
__device__ u16 g_w2_hi [C_*MLP_], g_w2_lo [C_*MLP_];
__device__ u16 g_wpth  [P_*N2_],  g_wptl  [P_*N2_];

__device__ __forceinline__ uint32_t smem_u32(const void* p) {
    uint32_t a;
    asm("{ .reg .u64 t; cvta.to.shared.u64 t, %1; cvt.u32.u64 %0, t; }" : "=r"(a) : "l"(p));
    return a;
}
#define SWZ(b) ((b) ^ (((b) >> 3) & 0x70))
#define CPA16(dst, src) asm volatile("cp.async.cg.shared.global [%0], [%1], 16;" :: "r"(dst), "l"(src))
#define CPA_COMMIT() asm volatile("cp.async.commit_group;" ::: "memory")
#define CPA_WAIT1()  asm volatile("cp.async.wait_group 1;" ::: "memory")
#define CPA_WAIT0()  asm volatile("cp.async.wait_group 0;" ::: "memory")

__device__ __forceinline__ void ldsm4(uint32_t* r, uint32_t a) {
    asm volatile("ldmatrix.sync.aligned.m8n8.x4.shared.b16 {%0,%1,%2,%3}, [%4];"
                 : "=r"(r[0]), "=r"(r[1]), "=r"(r[2]), "=r"(r[3]) : "r"(a));
}
__device__ __forceinline__ void mma_bf16(float* c, const uint32_t* a, uint32_t b0, uint32_t b1) {
    asm volatile("mma.sync.aligned.m16n8k16.row.col.f32.bf16.bf16.f32 "
        "{%0,%1,%2,%3}, {%4,%5,%6,%7}, {%8,%9}, {%0,%1,%2,%3};"
        : "+f"(c[0]), "+f"(c[1]), "+f"(c[2]), "+f"(c[3])
        : "r"(a[0]), "r"(a[1]), "r"(a[2]), "r"(a[3]), "r"(b0), "r"(b1));
}
__device__ __forceinline__ void bsplit(float a, uint32_t& hi, uint32_t& lo) {
    uint32_t u = __float_as_uint(a);
    uint32_t hr = (u + 0x7fffu + ((u >> 16) & 1u)) & 0xffff0000u;
    hi = hr >> 16;
    float l = a - __uint_as_float(hr);
    uint32_t ul = __float_as_uint(l);
    lo = (ul + 0x7fffu + ((ul >> 16) & 1u)) >> 16;
}
__device__ __forceinline__ void bsplit2(float a, float b, uint32_t& hi, uint32_t& lo) {
    uint32_t h0, l0, h1, l1;
    bsplit(a, h0, l0); bsplit(b, h1, l1);
    hi = h0 | (h1 << 16); lo = l0 | (l1 << 16);
}

__global__ __launch_bounds__(256)
void wsplit_k(const float* __restrict__ W, u16* __restrict__ hi, u16* __restrict__ lo, int K, int N)
{
    __shared__ float tile[32][33];
    const int n0 = blockIdx.x * 32, k0 = blockIdx.y * 32;
    const int tx = threadIdx.x & 31, ty = threadIdx.x >> 5;
#pragma unroll
    for (int r = 0; r < 4; r++)
        tile[ty + 8 * r][tx] = W[(size_t)(k0 + ty + 8 * r) * N + n0 + tx];
    __syncthreads();
#pragma unroll
    for (int r = 0; r < 4; r++) {
        const int n = n0 + ty + 8 * r, k = k0 + tx;
        uint32_t h, l;
        bsplit(tile[tx][ty + 8 * r], h, l);
        hi[(size_t)n * K + k] = (u16)h;
        lo[(size_t)n * K + k] = (u16)l;
    }
}

__global__ __launch_bounds__(256)
void asplit_k(const float* __restrict__ A, u16* __restrict__ hi, u16* __restrict__ lo)
{
    const size_t i4 = ((size_t)blockIdx.x * 256 + threadIdx.x) * 4;
    float4 f = *(const float4*)(A + i4);
    uint32_t a, b, c, d;
    bsplit2(f.x, f.y, a, c); bsplit2(f.z, f.w, b, d);
    *(uint2*)(hi + i4) = make_uint2(a, b);
    *(uint2*)(lo + i4) = make_uint2(c, d);
}

// ---- bf16 HMMA GEMM, 128x128 tile, 3-stage cp.async ----
// NTERM 3: Ah*Bh + Al*Bh + Ah*Bl
// NTERM 2: Ah*Bh + Al*Bh              (B-lo dropped; MLP1)
// NTERM 1: Ah*Bh + Ah*Bl              (A-lo dropped, Alo never loaded; MLP2)
// EPI 0: q -> qh/ql split (+bias+pos_q)
// EPI 1: k/v -> transposed bf16 split kT/vT (k gets +pos_k)
// EPI 2: gelu -> bf16 HI ONLY
// EPI 3: fp32 out = acc + bias + extra
#define TG_SMEM (3 * 65536)
template<int EPI, int NTERM>
__global__ __launch_bounds__(256, 1)
void tgemm(const u16* __restrict__ Ahi, const u16* __restrict__ Alo,
           const u16* __restrict__ Bhi, const u16* __restrict__ Blo,
           const float* __restrict__ bias, const float* __restrict__ extra,
           void* __restrict__ out, void* __restrict__ out2, int M, int N, int K)
{
    extern __shared__ __align__(1024) char sm_raw[];
    const uint32_t sb = smem_u32(sm_raw);
    const int tid = threadIdx.x, wid = tid >> 5, lane = tid & 31;
    const int bm = blockIdx.y * 128, bn = blockIdx.x * 128;
    const int wm = (wid & 1) * 64, wn = (wid >> 1) * 32;
    const int nck = K >> 6;

    float acc[4][4][4];
#pragma unroll
    for (int i = 0; i < 4; i++)
#pragma unroll
        for (int j = 0; j < 4; j++)
#pragma unroll
            for (int r = 0; r < 4; r++) acc[i][j][r] = 0.0f;

    const int a_row = ((lane >> 3) & 1) * 8 + (lane & 7);
    const int a_col = (lane >> 4) * 8;
    const int b_row = (lane >> 4) * 8 + (lane & 7);
    const int b_col = ((lane >> 3) & 1) * 8;

    auto load_stage = [&](int ck, int stage) {
        if (ck < nck) {
            const int k0 = ck * 64;
            const uint32_t sbase = sb + stage * 65536;
#pragma unroll
            for (int i = 0; i < 4; i++) {
                const int id = tid + i * 256;
                const int row = id >> 3, c16 = id & 7;
                const uint32_t dsw = SWZ((uint32_t)(row * 128 + c16 * 16));
                const size_t asrc = (size_t)(bm + row) * K + k0 + c16 * 8;
                const size_t bsrc = (size_t)(bn + row) * K + k0 + c16 * 8;
                CPA16(sbase + dsw, Ahi + asrc);
                if (NTERM != 1) CPA16(sbase + 16384 + dsw, Alo + asrc);
                CPA16(sbase + 32768 + dsw, Bhi + bsrc);
                if (NTERM != 2) CPA16(sbase + 49152 + dsw, Blo + bsrc);
            }
        }
        CPA_COMMIT();
    };

    load_stage(0, 0);
    load_stage(1, 1);

    for (int ck = 0; ck < nck; ck++) {
        CPA_WAIT1();
        __syncthreads();
        load_stage(ck + 2, (ck + 2) % 3);
        const uint32_t base = sb + (ck % 3) * 65536;
#pragma unroll
        for (int ks = 0; ks < 4; ks++) {
            const int kk = ks * 16;
            uint32_t ah[4][4], al[4][4], bh[2][4], bl[2][4];
#pragma unroll
            for (int mf = 0; mf < 4; mf++) {
                const uint32_t ao = SWZ((uint32_t)((wm + mf * 16 + a_row) * 128 + (kk + a_col) * 2));
                ldsm4(ah[mf], base + ao);
                if (NTERM != 1) ldsm4(al[mf], base + 16384 + ao);
            }
#pragma unroll
            for (int p = 0; p < 2; p++) {
                const uint32_t bo = SWZ((uint32_t)((wn + p * 16 + b_row) * 128 + (kk + b_col) * 2));
                ldsm4(bh[p], base + 32768 + bo);
                if (NTERM != 2) ldsm4(bl[p], base + 49152 + bo);
            }
#pragma unroll
            for (int mf = 0; mf < 4; mf++)
#pragma unroll
                for (int p = 0; p < 2; p++)
#pragma unroll
                    for (int s = 0; s < 2; s++) {
                        float* c = acc[mf][p * 2 + s];
                        mma_bf16(c, ah[mf], bh[p][s * 2], bh[p][s * 2 + 1]);
                        if (NTERM != 1)
                            mma_bf16(c, al[mf], bh[p][s * 2], bh[p][s * 2 + 1]);
                        if (NTERM != 2)
                            mma_bf16(c, ah[mf], bl[p][s * 2], bl[p][s * 2 + 1]);
                    }
        }
    }

    const int l4 = lane >> 2, l2 = (lane & 3) * 2;

    if (EPI == 1) {
        CPA_WAIT0();
        __syncthreads();
        float* T = (float*)sm_raw;                       // 128 x 132 floats
        const bool is_k = (bn < C_);
#pragma unroll
        for (int mf = 0; mf < 4; mf++)
#pragma unroll
            for (int nf = 0; nf < 4; nf++) {
                const int colL = wn + nf * 8 + l2;
                const int col = bn + colL;
                const float bia0 = bias[col], bia1 = bias[col + 1];
#pragma unroll
                for (int half = 0; half < 2; half++) {
                    const int mL = wm + mf * 16 + l4 + half * 8;
                    float v0 = acc[mf][nf][half * 2]     + bia0;
                    float v1 = acc[mf][nf][half * 2 + 1] + bia1;
                    if (is_k) {
                        const int n = (bm + mL) & (N2_ - 1);
                        v0 += extra[(size_t)n * C_ + col];
                        v1 += extra[(size_t)n * C_ + col + 1];
                    }
                    T[colL * 132 + mL]       = v0;
                    T[(colL + 1) * 132 + mL] = v1;
                }
            }
        __syncthreads();
        u16* __restrict__ dh = is_k ? g_kTh : g_vTh;
        u16* __restrict__ dl = is_k ? g_kTl : g_vTl;
        const int bb = bm >> 12, n0 = bm & (N2_ - 1);
        const int r = tid >> 1, hh2 = (tid & 1) * 64;
        const int c = (bn + r) - (is_k ? 0 : C_);
        const size_t gbase = ((size_t)bb * C_ + c) * N2_ + n0 + hh2;
        const float* Tr = T + r * 132 + hh2;
#pragma unroll
        for (int j = 0; j < 64; j += 8) {
            uint32_t h0, l0, h1, l1, h2, l2x, h3, l3;
            bsplit2(Tr[j],     Tr[j + 1], h0, l0);
            bsplit2(Tr[j + 2], Tr[j + 3], h1, l1);
            bsplit2(Tr[j + 4], Tr[j + 5], h2, l2x);
            bsplit2(Tr[j + 6], Tr[j + 7], h3, l3);
            *(uint4*)(dh + gbase + j) = make_uint4(h0, h1, h2, h3);
            *(uint4*)(dl + gbase + j) = make_uint4(l0, l1, l2x, l3);
        }
        return;
    }

#pragma unroll
    for (int mf = 0; mf < 4; mf++)
#pragma unroll
        for (int nf = 0; nf < 4; nf++) {
            const int col = bn + wn + nf * 8 + l2;
            const float bia0 = bias[col], bia1 = bias[col + 1];
#pragma unroll
            for (int half = 0; half < 2; half++) {
                const int m = bm + wm + mf * 16 + l4 + half * 8;
                float v0 = acc[mf][nf][half * 2]     + bia0;
                float v1 = acc[mf][nf][half * 2 + 1] + bia1;
                if (EPI == 0) {
                    v0 += extra[(size_t)(m & (N1_ - 1)) * C_ + col];
                    v1 += extra[(size_t)(m & (N1_ - 1)) * C_ + col + 1];
                    uint32_t hi, lo;
                    bsplit2(v0, v1, hi, lo);
                    *(uint32_t*)(g_qh + (size_t)m * N + col) = hi;
                    *(uint32_t*)(g_ql + (size_t)m * N + col) = lo;
                } else if (EPI == 2) {
                    v0 = 0.5f * v0 * (1.0f + erff(v0 * 0.70710678118654752f));
                    v1 = 0.5f * v1 * (1.0f + erff(v1 * 0.70710678118654752f));
                    // hi-only rounded store
                    uint32_t hi, lo;
                    bsplit2(v0, v1, hi, lo);
                    *(uint32_t*)((u16*)out + (size_t)m * N + col) = hi;
                } else {
                    v0 += extra[(size_t)m * N + col];
                    v1 += extra[(size_t)m * N + col + 1];
                    *(float2*)((float*)out + (size_t)m * N + col) = make_float2(v0, v1);
                }
            }
        }
}

// ---- kvp via bf16x3 HMMA ----
#define KVP_STG  81920
#define KVP_SMEM (2 * KVP_STG)
__global__ __launch_bounds__(256, 1)
void kvp_mma(const float* __restrict__ bp)
{
    extern __shared__ __align__(1024) char sm_raw[];
    const uint32_t sb = smem_u32(sm_raw);
    const int tid = threadIdx.x, wid = tid >> 5, lane = tid & 31;
    const int g = lane >> 2, t4 = lane & 3;
    const int bh = blockIdx.x, b = bh >> 3, h = bh & 7;
    const int mode = blockIdx.y;
    const u16* __restrict__ Dh = mode ? g_vTh : g_kTh;
    const u16* __restrict__ Dl = mode ? g_vTl : g_kTl;

    const int a_row = ((lane >> 3) & 1) * 8 + (lane & 7);
    const int a_col = (lane >> 4) * 8;
    const int b_row = (lane >> 4) * 8 + (lane & 7);
    const int b_col = ((lane >> 3) & 1) * 8;

    auto load_stage = [&](int ck) {
        if (ck < 64) {
            const uint32_t base = sb + (ck & 1) * KVP_STG;
            const int k0 = ck * 64;
#pragma unroll
            for (int t = 0; t < 8; t++) {
                const int i = tid + t * 256;
                const int row = i >> 3, c16 = i & 7;
                const uint32_t dsw = SWZ((uint32_t)(row * 128 + c16 * 16));
                const size_t src = (size_t)row * N2_ + k0 + c16 * 8;
                CPA16(base + dsw,         g_wpth + src);
                CPA16(base + 32768 + dsw, g_wptl + src);
            }
#pragma unroll
            for (int t = 0; t < 2; t++) {
                const int i = tid + t * 256;
                const int row = i >> 3, c16 = i & 7;
                const uint32_t dsw = SWZ((uint32_t)(row * 128 + c16 * 16));
                const size_t src = ((size_t)b * C_ + h * 64 + row) * N2_ + k0 + c16 * 8;
                CPA16(base + 65536 + dsw, Dh + src);
                CPA16(base + 73728 + dsw, Dl + src);
            }
        }
        CPA_COMMIT();
    };

    load_stage(0);
    load_stage(1);

    if (mode == 0) {
        const int wm = (wid & 3) * 64, wn = (wid >> 2) * 32;
        float acc[4][4][4];
#pragma unroll
        for (int i = 0; i < 4; i++)
#pragma unroll
            for (int j = 0; j < 4; j++)
#pragma unroll
                for (int r = 0; r < 4; r++) acc[i][j][r] = 0.0f;

        for (int ck = 0; ck < 64; ck++) {
            CPA_WAIT1();
            __syncthreads();
            const uint32_t base = sb + (ck & 1) * KVP_STG;
#pragma unroll
            for (int ks = 0; ks < 4; ks++) {
                const int kk = ks * 16;
                uint32_t ah[4][4], al[4][4], bhr[2][4], blr[2][4];
#pragma unroll
                for (int mf = 0; mf < 4; mf++) {
                    const uint32_t ao = SWZ((uint32_t)((wm + mf * 16 + a_row) * 128 + (kk + a_col) * 2));
                    ldsm4(ah[mf], base + ao);
                    ldsm4(al[mf], base + 32768 + ao);
                }
#pragma unroll
                for (int p = 0; p < 2; p++) {
                    const uint32_t bo = SWZ((uint32_t)((wn + p * 16 + b_row) * 128 + (kk + b_col) * 2));
                    ldsm4(bhr[p], base + 65536 + bo);
                    ldsm4(blr[p], base + 73728 + bo);
                }
#pragma unroll
                for (int mf = 0; mf < 4; mf++)
#pragma unroll
                    for (int p = 0; p < 2; p++)
#pragma unroll
                        for (int s = 0; s < 2; s++) {
                            float* c = acc[mf][p * 2 + s];
                            mma_bf16(c, ah[mf], bhr[p][s * 2], bhr[p][s * 2 + 1]);
                            mma_bf16(c, al[mf], bhr[p][s * 2], bhr[p][s * 2 + 1]);
                            mma_bf16(c, ah[mf], blr[p][s * 2], blr[p][s * 2 + 1]);
                        }
            }
            __syncthreads();
            load_stage(ck + 2);
        }
#pragma unroll
        for (int mf = 0; mf < 4; mf++)
#pragma unroll
            for (int hf = 0; hf < 2; hf++) {
                const int p = wm + mf * 16 + hf * 8 + g;
                const float bv = bp[p];
#pragma unroll
                for (int nf = 0; nf < 4; nf++) {
                    const int d = wn + nf * 8 + t4 * 2;
                    uint32_t hi, lo;
                    bsplit2(acc[mf][nf][hf * 2] + bv, acc[mf][nf][hf * 2 + 1] + bv, hi, lo);
                    *(uint32_t*)(g_kpth + (size_t)bh * (P_ * HD_) + p * 64 + d) = hi;
                    *(uint32_t*)(g_kptl + (size_t)bh * (P_ * HD_) + p * 64 + d) = lo;
                }
            }
    } else {
        const int wm = (wid & 1) * 32, wn = (wid >> 1) * 64;
        float acc[2][8][4];
#pragma unroll
        for (int i = 0; i < 2; i++)
#pragma unroll
            for (int j = 0; j < 8; j++)
#pragma unroll
                for (int r = 0; r < 4; r++) acc[i][j][r] = 0.0f;

        for (int ck = 0; ck < 64; ck++) {
            CPA_WAIT1();
            __syncthreads();
            const uint32_t base = sb + (ck & 1) * KVP_STG;
#pragma unroll
            for (int ks = 0; ks < 4; ks++) {
                const int kk = ks * 16;
                uint32_t ah[2][4], al[2][4];
#pragma unroll
                for (int mf = 0; mf < 2; mf++) {
                    const uint32_t ao = SWZ((uint32_t)((wm + mf * 16 + a_row) * 128 + (kk + a_col) * 2));
                    ldsm4(ah[mf], base + 65536 + ao);
                    ldsm4(al[mf], base + 73728 + ao);
                }
#pragma unroll
                for (int p = 0; p < 4; p++) {
                    uint32_t bhr[4], blr[4];
                    const uint32_t bo = SWZ((uint32_t)((wn + p * 16 + b_row) * 128 + (kk + b_col) * 2));
                    ldsm4(bhr, base + bo);
                    ldsm4(blr, base + 32768 + bo);
#pragma unroll
                    for (int mf = 0; mf < 2; mf++)
#pragma unroll
                        for (int s = 0; s < 2; s++) {
                            float* c = acc[mf][p * 2 + s];
                            mma_bf16(c, ah[mf], bhr[s * 2], bhr[s * 2 + 1]);
                            mma_bf16(c, al[mf], bhr[s * 2], bhr[s * 2 + 1]);
                            mma_bf16(c, ah[mf], blr[s * 2], blr[s * 2 + 1]);
                        }
                }
            }
            __syncthreads();
            load_stage(ck + 2);
        }
#pragma unroll
        for (int mf = 0; mf < 2; mf++)
#pragma unroll
            for (int hf = 0; hf < 2; hf++) {
                const int d = wm + mf * 16 + hf * 8 + g;
#pragma unroll
                for (int nf = 0; nf < 8; nf++) {
                    const int p = wn + nf * 8 + t4 * 2;
                    uint32_t hi, lo;
                    bsplit2(acc[mf][nf][hf * 2] + bp[p], acc[mf][nf][hf * 2 + 1] + bp[p + 1], hi, lo);
                    *(uint32_t*)(g_vph + (size_t)bh * (HD_ * P_) + d * 256 + p) = hi;
                    *(uint32_t*)(g_vpl + (size_t)bh * (HD_ * P_) + d * 256 + p) = lo;
                }
            }
    }
}

// ---- attention via bf16x3 HMMA ----
#define A_QH   0
#define A_QL   8192
#define A_KH   16384
#define A_KL   49152
#define A_VH   81920
#define A_VL   114688
#define A_ST   147456
#define A_ZN   149504
#define ATT_SMEM (149504 + 4*64*66*4)

__global__ __launch_bounds__(256, 1)
void attn_mma(const float* __restrict__ temp, float* __restrict__ xa)
{
    extern __shared__ __align__(1024) char sm_raw[];
    const uint32_t sb = smem_u32(sm_raw);
    const int tid = threadIdx.x, wid = tid >> 5, lane = tid & 31;
    const int g = lane >> 2, t4 = lane & 3;
    const int bh = blockIdx.x, b = bh >> 3, h = bh & 7;
    const int q0 = blockIdx.y * 64;
    const int wm = (wid & 1) * 32, zn = wid >> 1, wn = zn * 64;

#pragma unroll
    for (int t = 0; t < 2; t++) {
        const int i = tid + t * 256;
        const int row = i >> 3, c16 = i & 7;
        const uint32_t dsw = SWZ((uint32_t)(row * 128 + c16 * 16));
        const size_t src = (size_t)(b * N1_ + q0 + row) * C_ + h * 64 + c16 * 8;
        CPA16(sb + A_QH + dsw, g_qh + src);
        CPA16(sb + A_QL + dsw, g_ql + src);
    }
#pragma unroll
    for (int t = 0; t < 8; t++) {
        const int i = tid + t * 256;
        const int row = i >> 3, c16 = i & 7;
        const uint32_t dsw = SWZ((uint32_t)(row * 128 + c16 * 16));
        const size_t src = (size_t)bh * (P_ * HD_) + row * 64 + c16 * 8;
        CPA16(sb + A_KH + dsw, g_kpth + src);
        CPA16(sb + A_KL + dsw, g_kptl + src);
    }
#pragma unroll
    for (int t = 0; t < 8; t++) {
        const int i = tid + t * 256;
        const int c16 = i & 7, d = (i >> 3) & 63, ch = i >> 9;
        const uint32_t dsw = (uint32_t)(ch * 8192) + SWZ((uint32_t)(d * 128 + c16 * 16));
        const size_t src = (size_t)bh * (HD_ * P_) + d * 256 + ch * 64 + c16 * 8;
        CPA16(sb + A_VH + dsw, g_vph + src);
        CPA16(sb + A_VL + dsw, g_vpl + src);
    }
    CPA_COMMIT();
    CPA_WAIT0();
    __syncthreads();

    const int a_row = ((lane >> 3) & 1) * 8 + (lane & 7);
    const int a_col = (lane >> 4) * 8;
    const int b_row = (lane >> 4) * 8 + (lane & 7);
    const int b_col = ((lane >> 3) & 1) * 8;

    float acc[2][8][4];
#pragma unroll
    for (int i = 0; i < 2; i++)
#pragma unroll
        for (int j = 0; j < 8; j++)
#pragma unroll
            for (int r = 0; r < 4; r++) acc[i][j][r] = 0.0f;

#pragma unroll
    for (int ks = 0; ks < 4; ks++) {
        const int kk = ks * 16;
        uint32_t ah[2][4], al[2][4];
#pragma unroll
        for (int mf = 0; mf < 2; mf++) {
            const uint32_t ao = SWZ((uint32_t)((wm + mf * 16 + a_row) * 128 + (kk + a_col) * 2));
            ldsm4(ah[mf], sb + A_QH + ao);
            ldsm4(al[mf], sb + A_QL + ao);
        }
#pragma unroll
        for (int p = 0; p < 4; p++) {
            uint32_t bhr[4], blr[4];
            const uint32_t bo = SWZ((uint32_t)((wn + p * 16 + b_row) * 128 + (kk + b_col) * 2));
            ldsm4(bhr, sb + A_KH + bo);
            ldsm4(blr, sb + A_KL + bo);
#pragma unroll
            for (int mf = 0; mf < 2; mf++)
#pragma unroll
                for (int s = 0; s < 2; s++) {
                    float* c = acc[mf][p * 2 + s];
                    mma_bf16(c, ah[mf], bhr[s * 2], bhr[s * 2 + 1]);
                    mma_bf16(c, al[mf], bhr[s * 2], bhr[s * 2 + 1]);
                    mma_bf16(c, ah[mf], blr[s * 2], blr[s * 2 + 1]);
                }
        }
    }

    const float tscale = temp[h];
    float* smax = (float*)(sm_raw + A_ST);
    float* ssum = smax + 256;
#pragma unroll
    for (int mf = 0; mf < 2; mf++)
#pragma unroll
        for (int nf = 0; nf < 8; nf++)
#pragma unroll
            for (int r = 0; r < 4; r++) acc[mf][nf][r] *= tscale;

    float rmx[2][2] = {{-1e30f, -1e30f}, {-1e30f, -1e30f}};
#pragma unroll
    for (int mf = 0; mf < 2; mf++)
#pragma unroll
        for (int nf = 0; nf < 8; nf++) {
            rmx[mf][0] = fmaxf(rmx[mf][0], fmaxf(acc[mf][nf][0], acc[mf][nf][1]));
            rmx[mf][1] = fmaxf(rmx[mf][1], fmaxf(acc[mf][nf][2], acc[mf][nf][3]));
        }
#pragma unroll
    for (int mf = 0; mf < 2; mf++)
#pragma unroll
        for (int hf = 0; hf < 2; hf++) {
            rmx[mf][hf] = fmaxf(rmx[mf][hf], __shfl_xor_sync(~0u, rmx[mf][hf], 1));
            rmx[mf][hf] = fmaxf(rmx[mf][hf], __shfl_xor_sync(~0u, rmx[mf][hf], 2));
        }
    if (t4 == 0)
#pragma unroll
        for (int mf = 0; mf < 2; mf++)
#pragma unroll
            for (int hf = 0; hf < 2; hf++)
                smax[(wm + mf * 16 + hf * 8 + g) * 4 + zn] = rmx[mf][hf];
    __syncthreads();
    float gmx[2][2], rsm[2][2] = {{0, 0}, {0, 0}};
#pragma unroll
    for (int mf = 0; mf < 2; mf++)
#pragma unroll
        for (int hf = 0; hf < 2; hf++) {
            const int r = wm + mf * 16 + hf * 8 + g;
            gmx[mf][hf] = fmaxf(fmaxf(smax[r * 4], smax[r * 4 + 1]),
                                fmaxf(smax[r * 4 + 2], smax[r * 4 + 3]));
        }
#pragma unroll
    for (int mf = 0; mf < 2; mf++)
#pragma unroll
        for (int nf = 0; nf < 8; nf++)
#pragma unroll
            for (int r = 0; r < 4; r++) {
                const int hf = r >> 1;
                const float e = __expf(acc[mf][nf][r] - gmx[mf][hf]);
                acc[mf][nf][r] = e;
                rsm[mf][hf] += e;
            }
#pragma unroll
    for (int mf = 0; mf < 2; mf++)
#pragma unroll
        for (int hf = 0; hf < 2; hf++) {
            rsm[mf][hf] += __shfl_xor_sync(~0u, rsm[mf][hf], 1);
            rsm[mf][hf] += __shfl_xor_sync(~0u, rsm[mf][hf], 2);
        }
    if (t4 == 0)
#pragma unroll
        for (int mf = 0; mf < 2; mf++)
#pragma unroll
            for (int hf = 0; hf < 2; hf++)
                ssum[(wm + mf * 16 + hf * 8 + g) * 4 + zn] = rsm[mf][hf];
    __syncthreads();
#pragma unroll
    for (int mf = 0; mf < 2; mf++)
#pragma unroll
        for (int hf = 0; hf < 2; hf++) {
            const int r = wm + mf * 16 + hf * 8 + g;
            const float inv = 1.0f / (ssum[r * 4] + ssum[r * 4 + 1] + ssum[r * 4 + 2] + ssum[r * 4 + 3]);
#pragma unroll
            for (int nf = 0; nf < 8; nf++) {
                acc[mf][nf][hf * 2]     *= inv;
                acc[mf][nf][hf * 2 + 1] *= inv;
            }
        }

    float acc2[2][8][4];
#pragma unroll
    for (int i = 0; i < 2; i++)
#pragma unroll
        for (int j = 0; j < 8; j++)
#pragma unroll
            for (int r = 0; r < 4; r++) acc2[i][j][r] = 0.0f;

#pragma unroll
    for (int kf = 0; kf < 4; kf++) {
        uint32_t pah[2][4], pal[2][4];
#pragma unroll
        for (int mf = 0; mf < 2; mf++) {
            bsplit2(acc[mf][2*kf][0],   acc[mf][2*kf][1],   pah[mf][0], pal[mf][0]);
            bsplit2(acc[mf][2*kf][2],   acc[mf][2*kf][3],   pah[mf][1], pal[mf][1]);
            bsplit2(acc[mf][2*kf+1][0], acc[mf][2*kf+1][1], pah[mf][2], pal[mf][2]);
            bsplit2(acc[mf][2*kf+1][2], acc[mf][2*kf+1][3], pah[mf][3], pal[mf][3]);
        }
#pragma unroll
        for (int df = 0; df < 4; df++) {
            uint32_t bhr[4], blr[4];
            const uint32_t bo = (uint32_t)(zn * 8192) +
                SWZ((uint32_t)((df * 16 + b_row) * 128 + (kf * 16 + b_col) * 2));
            ldsm4(bhr, sb + A_VH + bo);
            ldsm4(blr, sb + A_VL + bo);
#pragma unroll
            for (int mf = 0; mf < 2; mf++)
#pragma unroll
                for (int s = 0; s < 2; s++) {
                    float* c = acc2[mf][df * 2 + s];
                    mma_bf16(c, pah[mf], bhr[s * 2], bhr[s * 2 + 1]);
                    mma_bf16(c, pal[mf], bhr[s * 2], bhr[s * 2 + 1]);
                    mma_bf16(c, pah[mf], blr[s * 2], blr[s * 2 + 1]);
                }
        }
    }

    float* zone = (float*)(sm_raw + A_ZN) + zn * (64 * 66);
#pragma unroll
    for (int mf = 0; mf < 2; mf++)
#pragma unroll
        for (int nf = 0; nf < 8; nf++)
#pragma unroll
            for (int hf = 0; hf < 2; hf++) {
                const int row = wm + mf * 16 + hf * 8 + g;
                const int dc = nf * 8 + t4 * 2;
                *(float2*)&zone[row * 66 + dc] =
                    make_float2(acc2[mf][nf][hf * 2], acc2[mf][nf][hf * 2 + 1]);
            }
    __syncthreads();

    const int tx = tid & 15, ty = tid >> 4;
    float* z0 = (float*)(sm_raw + A_ZN);
    const size_t base = (size_t)b * (N1_ * C_) + (size_t)h * N1_ + q0 + tx * 4;
#pragma unroll
    for (int j = 0; j < 4; j++) {
        const int d = ty * 4 + j;
        float o[4];
#pragma unroll
        for (int qi = 0; qi < 4; qi++) {
            const int idx = (tx * 4 + qi) * 66 + d;
            o[qi] = z0[idx] + z0[64*66 + idx] + z0[2*64*66 + idx] + z0[3*64*66 + idx];
        }
        *(float4*)&xa[base + (size_t)d * (H_ * N1_)] = make_float4(o[0], o[1], o[2], o[3]);
    }
}

// ---- L2 norm with bf16-split residual input + split output ----
__global__ __launch_bounds__(256)
void l2nq_k(const float* __restrict__ a, const u16* __restrict__ qh,
            const u16* __restrict__ ql, float* __restrict__ out,
            u16* __restrict__ oh, u16* __restrict__ ol)
{
    const int row = blockIdx.x * 8 + (threadIdx.x >> 5);
    const int lane = threadIdx.x & 31;
    const float4* pa = (const float4*)(a + (size_t)row * C_);
    float4 v[4];
    float ss = 0.0f;
#pragma unroll
    for (int i = 0; i < 4; i++) {
        float4 t = pa[lane + 32 * i];
        const size_t off = (size_t)row * C_ + (lane + 32 * i) * 4;
        const uint2 hq = *(const uint2*)(qh + off);
        const uint2 lq = *(const uint2*)(ql + off);
        t.x += __uint_as_float(hq.x << 16)          + __uint_as_float(lq.x << 16);
        t.y += __uint_as_float(hq.x & 0xffff0000u)  + __uint_as_float(lq.x & 0xffff0000u);
        t.z += __uint_as_float(hq.y << 16)          + __uint_as_float(lq.y << 16);
        t.w += __uint_as_float(hq.y & 0xffff0000u)  + __uint_as_float(lq.y & 0xffff0000u);
        v[i] = t;
        ss += t.x * t.x + t.y * t.y + t.z * t.z + t.w * t.w;
    }
#pragma unroll
    for (int o = 16; o > 0; o >>= 1) ss += __shfl_xor_sync(~0u, ss, o);
    const float inv = 1.0f / fmaxf(sqrtf(ss), 1e-12f);
    float4* po = (float4*)(out + (size_t)row * C_);
#pragma unroll
    for (int i = 0; i < 4; i++) {
        v[i].x *= inv; v[i].y *= inv; v[i].z *= inv; v[i].w *= inv;
        po[lane + 32 * i] = v[i];
        uint32_t a0, b0, c0, d0;
        bsplit2(v[i].x, v[i].y, a0, c0); bsplit2(v[i].z, v[i].w, b0, d0);
        const size_t off = (size_t)row * C_ + (lane + 32 * i) * 4;
        *(uint2*)(oh + off) = make_uint2(a0, b0);
        *(uint2*)(ol + off) = make_uint2(c0, d0);
    }
}

__global__ __launch_bounds__(256)
void l2n_k(const float* __restrict__ a, float* __restrict__ out)
{
    const int row = blockIdx.x * 8 + (threadIdx.x >> 5);
    const int lane = threadIdx.x & 31;
    const float4* pa = (const float4*)(a + (size_t)row * C_);
    float4 v[4];
    float ss = 0.0f;
#pragma unroll
    for (int i = 0; i < 4; i++) {
        float4 t = pa[lane + 32 * i];
        v[i] = t;
        ss += t.x * t.x + t.y * t.y + t.z * t.z + t.w * t.w;
    }
#pragma unroll
    for (int o = 16; o > 0; o >>= 1) ss += __shfl_xor_sync(~0u, ss, o);
    const float inv = 1.0f / fmaxf(sqrtf(ss), 1e-12f);
    float4* po = (float4*)(out + (size_t)row * C_);
#pragma unroll
    for (int i = 0; i < 4; i++) {
        v[i].x *= inv; v[i].y *= inv; v[i].z *= inv; v[i].w *= inv;
        po[lane + 32 * i] = v[i];
    }
}

extern "C" void kernel_launch(void* const* d_in, const int* in_sizes, int n_in,
                              void* d_out, int out_size)
{
    const float* x1    = (const float*)d_in[0];
    const float* x2    = (const float*)d_in[1];
    const float* Wq    = (const float*)d_in[2];
    const float* bq    = (const float*)d_in[3];
    const float* Wkv   = (const float*)d_in[4];
    const float* bkv   = (const float*)d_in[5];
    const float* Wp    = (const float*)d_in[6];
    const float* bp    = (const float*)d_in[7];
    const float* pos_q = (const float*)d_in[8];
    const float* pos_k = (const float*)d_in[9];
    const float* temp  = (const float*)d_in[10];
    const float* W1    = (const float*)d_in[11];
    const float* b1    = (const float*)d_in[12];
    const float* W2    = (const float*)d_in[13];
    const float* b2    = (const float*)d_in[14];

    float *xa, *xn;
    u16 *qh, *ql, *x1h, *x1l, *x2h, *x2l, *xnh, *xnl, *hh;
    u16 *wqh, *wql, *wkvh, *wkvl, *w1h, *w1l, *w2h, *w2l, *wpth, *wptl;
    cudaGetSymbolAddress((void**)&xa, g_xa);
    cudaGetSymbolAddress((void**)&xn, g_xn);
    cudaGetSymbolAddress((void**)&qh, g_qh);   cudaGetSymbolAddress((void**)&ql, g_ql);
    cudaGetSymbolAddress((void**)&x1h, g_x1h); cudaGetSymbolAddress((void**)&x1l, g_x1l);
    cudaGetSymbolAddress((void**)&x2h, g_x2h); cudaGetSymbolAddress((void**)&x2l, g_x2l);
    cudaGetSymbolAddress((void**)&xnh, g_xnh); cudaGetSymbolAddress((void**)&xnl, g_xnl);
    cudaGetSymbolAddress((void**)&hh, g_hh);
    cudaGetSymbolAddress((void**)&wqh, g_wq_hi);   cudaGetSymbolAddress((void**)&wql, g_wq_lo);
    cudaGetSymbolAddress((void**)&wkvh, g_wkv_hi); cudaGetSymbolAddress((void**)&wkvl, g_wkv_lo);
    cudaGetSymbolAddress((void**)&w1h, g_w1_hi);   cudaGetSymbolAddress((void**)&w1l, g_w1_lo);
    cudaGetSymbolAddress((void**)&w2h, g_w2_hi);   cudaGetSymbolAddress((void**)&w2l, g_w2_lo);
    cudaGetSymbolAddress((void**)&wpth, g_wpth);   cudaGetSymbolAddress((void**)&wptl, g_wptl);

    cudaFuncSetAttribute(attn_mma, cudaFuncAttributeMaxDynamicSharedMemorySize, ATT_SMEM);
    cudaFuncSetAttribute(kvp_mma,  cudaFuncAttributeMaxDynamicSharedMemorySize, KVP_SMEM);
    cudaFuncSetAttribute((const void*)tgemm<0,3>, cudaFuncAttributeMaxDynamicSharedMemorySize, TG_SMEM);
    cudaFuncSetAttribute((const void*)tgemm<1,3>, cudaFuncAttributeMaxDynamicSharedMemorySize, TG_SMEM);
    cudaFuncSetAttribute((const void*)tgemm<2,2>, cudaFuncAttributeMaxDynamicSharedMemorySize, TG_SMEM);
    cudaFuncSetAttribute((const void*)tgemm<3,1>, cudaFuncAttributeMaxDynamicSharedMemorySize, TG_SMEM);

    cudaStream_t s2;
    cudaStreamCreateWithFlags(&s2, cudaStreamNonBlocking);
    cudaEvent_t eF, eKV, eJ, eW;
    cudaEventCreateWithFlags(&eF,  cudaEventDisableTiming);
    cudaEventCreateWithFlags(&eKV, cudaEventDisableTiming);
    cudaEventCreateWithFlags(&eJ,  cudaEventDisableTiming);
    cudaEventCreateWithFlags(&eW,  cudaEventDisableTiming);

    cudaEventRecord(eF, 0);
    cudaStreamWaitEvent(s2, eF, 0);

    // s2: Q-chain prep
    wsplit_k<<<dim3(C_ / 32, C_ / 32), 256, 0, s2>>>(Wq, wqh, wql, C_, C_);
    asplit_k<<<(M_ * C_) / 1024, 256, 0, s2>>>(x1, x1h, x1l);

    // legacy: KV chain
    wsplit_k<<<dim3(2 * C_ / 32, C_ / 32), 256>>>(Wkv, wkvh, wkvl, C_, 2 * C_);
    wsplit_k<<<dim3(P_ / 32, N2_ / 32), 256>>>(Wp, wpth, wptl, N2_, P_);
    asplit_k<<<(M_ * C_) / 1024, 256>>>(x2, x2h, x2l);
    tgemm<1,3><<<dim3(2 * C_ / 128, M_ / 128), 256, TG_SMEM>>>(
        x2h, x2l, wkvh, wkvl, bkv, pos_k, nullptr, nullptr, M_, 2 * C_, C_);
    cudaEventRecord(eKV, 0);

    // s2: tgemm<0> + W1/W2 splits fill kvp's idle SMs
    cudaStreamWaitEvent(s2, eKV, 0);
    tgemm<0,3><<<dim3(C_ / 128, M_ / 128), 256, TG_SMEM, s2>>>(
        x1h, x1l, wqh, wql, bq, pos_q, nullptr, nullptr, M_, C_, C_);
    cudaEventRecord(eJ, s2);
    wsplit_k<<<dim3(MLP_ / 32, C_ / 32), 256, 0, s2>>>(W1, w1h, w1l, C_, MLP_);
    wsplit_k<<<dim3(C_ / 32, MLP_ / 32), 256, 0, s2>>>(W2, w2h, w2l, MLP_, C_);
    cudaEventRecord(eW, s2);

    // legacy: kvp co-runs with s2
    kvp_mma<<<dim3(B_ * H_, 2), 256, KVP_SMEM>>>(bp);

    cudaStreamWaitEvent(0, eJ, 0);
    attn_mma<<<dim3(B_ * H_, N1_ / 64), 256, ATT_SMEM>>>(temp, xa);
    l2nq_k<<<M_ / 8, 256>>>(xa, qh, ql, xn, xnh, xnl);
    cudaStreamWaitEvent(0, eW, 0);
    // MLP1: 2-term (B-lo dropped), writes h-hi only
    tgemm<2,2><<<dim3(MLP_ / 128, M_ / 128), 256, TG_SMEM>>>(
        xnh, xnl, w1h, w1l, b1, nullptr, hh, nullptr, M_, MLP_, C_);
    // MLP2: 2-term (A-lo dropped; A = h-hi only)
    tgemm<3,1><<<dim3(C_ / 128, M_ / 128), 256, TG_SMEM>>>(
        hh, nullptr, w2h, w2l, b2, xn, xa, nullptr, M_, C_, MLP_);
    l2n_k<<<M_ / 8, 256>>>(xa, (float*)d_out);
}

// round 14
// speedup vs baseline: 2.9459x; 1.0736x over previous
#include <cuda_runtime.h>
#include <math.h>
#include <stdint.h>

#define B_   8
#define N1_  4096
#define N2_  4096
#define C_   512
#define P_   256
#define H_   8
#define HD_  64
#define MLP_ 2048
#define M_   (B_*N1_)

typedef unsigned short u16;

__device__ float g_xa[M_*C_];
__device__ float g_xn[M_*C_];
__device__ u16 g_qh [M_*C_],  g_ql [M_*C_];
__device__ u16 g_x1h[M_*C_],  g_x1l[M_*C_];
__device__ u16 g_x2h[M_*C_],  g_x2l[M_*C_];
__device__ u16 g_xnh[M_*C_];
__device__ u16 g_hh [M_*MLP_];
__device__ u16 g_kTh[B_*C_*N2_], g_kTl[B_*C_*N2_];
__device__ u16 g_vTh[B_*C_*N2_], g_vTl[B_*C_*N2_];
__device__ u16 g_kpth[B_*H_*P_*HD_], g_kptl[B_*H_*P_*HD_];
__device__ u16 g_vph [B_*H_*HD_*P_], g_vpl [B_*H_*HD_*P_];
__device__ u16 g_wq_hi [C_*C_],   g_wq_lo [C_*C_];
__device__ u16 g_wkv_hi[2*C_*C_], g_wkv_lo[2*C_*C_];
__device__ u16 g_w1_hi [MLP_*C_];
__device__ u16 g_w2_hi [C_*MLP_], g_w2_lo [C_*MLP_];
__device__ u16 g_wpth  [P_*N2_],  g_wptl  [P_*N2_];

__device__ __forceinline__ uint32_t smem_u32(const void* p) {
    uint32_t a;
    asm("{ .reg .u64 t; cvta.to.shared.u64 t, %1; cvt.u32.u64 %0, t; }" : "=r"(a) : "l"(p));
    return a;
}
#define SWZ(b) ((b) ^ (((b) >> 3) & 0x70))
#define CPA16(dst, src) asm volatile("cp.async.cg.shared.global [%0], [%1], 16;" :: "r"(dst), "l"(src))
#define CPA_COMMIT() asm volatile("cp.async.commit_group;" ::: "memory")
#define CPA_WAIT1()  asm volatile("cp.async.wait_group 1;" ::: "memory")
#define CPA_WAIT0()  asm volatile("cp.async.wait_group 0;" ::: "memory")

__device__ __forceinline__ void ldsm4(uint32_t* r, uint32_t a) {
    asm volatile("ldmatrix.sync.aligned.m8n8.x4.shared.b16 {%0,%1,%2,%3}, [%4];"
                 : "=r"(r[0]), "=r"(r[1]), "=r"(r[2]), "=r"(r[3]) : "r"(a));
}
__device__ __forceinline__ void mma_bf16(float* c, const uint32_t* a, uint32_t b0, uint32_t b1) {
    asm volatile("mma.sync.aligned.m16n8k16.row.col.f32.bf16.bf16.f32 "
        "{%0,%1,%2,%3}, {%4,%5,%6,%7}, {%8,%9}, {%0,%1,%2,%3};"
        : "+f"(c[0]), "+f"(c[1]), "+f"(c[2]), "+f"(c[3])
        : "r"(a[0]), "r"(a[1]), "r"(a[2]), "r"(a[3]), "r"(b0), "r"(b1));
}
__device__ __forceinline__ void bsplit(float a, uint32_t& hi, uint32_t& lo) {
    uint32_t u = __float_as_uint(a);
    uint32_t hr = (u + 0x7fffu + ((u >> 16) & 1u)) & 0xffff0000u;
    hi = hr >> 16;
    float l = a - __uint_as_float(hr);
    uint32_t ul = __float_as_uint(l);
    lo = (ul + 0x7fffu + ((ul >> 16) & 1u)) >> 16;
}
__device__ __forceinline__ void bsplit2(float a, float b, uint32_t& hi, uint32_t& lo) {
    uint32_t h0, l0, h1, l1;
    bsplit(a, h0, l0); bsplit(b, h1, l1);
    hi = h0 | (h1 << 16); lo = l0 | (l1 << 16);
}

__global__ __launch_bounds__(256)
void wsplit_k(const float* __restrict__ W, u16* __restrict__ hi, u16* __restrict__ lo, int K, int N)
{
    __shared__ float tile[32][33];
    const int n0 = blockIdx.x * 32, k0 = blockIdx.y * 32;
    const int tx = threadIdx.x & 31, ty = threadIdx.x >> 5;
#pragma unroll
    for (int r = 0; r < 4; r++)
        tile[ty + 8 * r][tx] = W[(size_t)(k0 + ty + 8 * r) * N + n0 + tx];
    __syncthreads();
#pragma unroll
    for (int r = 0; r < 4; r++) {
        const int n = n0 + ty + 8 * r, k = k0 + tx;
        uint32_t h, l;
        bsplit(tile[tx][ty + 8 * r], h, l);
        hi[(size_t)n * K + k] = (u16)h;
        if (lo) lo[(size_t)n * K + k] = (u16)l;
    }
}

__global__ __launch_bounds__(256)
void asplit_k(const float* __restrict__ A, u16* __restrict__ hi, u16* __restrict__ lo)
{
    const size_t i4 = ((size_t)blockIdx.x * 256 + threadIdx.x) * 4;
    float4 f = *(const float4*)(A + i4);
    uint32_t a, b, c, d;
    bsplit2(f.x, f.y, a, c); bsplit2(f.z, f.w, b, d);
    *(uint2*)(hi + i4) = make_uint2(a, b);
    *(uint2*)(lo + i4) = make_uint2(c, d);
}

// ---- bf16 HMMA GEMM, 128x128 tile, 3-stage cp.async ----
// NT 3: Ah*Bh + Al*Bh + Ah*Bl
// NT 2: Ah*Bh + Al*Bh     (B-lo dropped)
// NT 1: Ah*Bh + Ah*Bl     (A-lo dropped; MLP2)
// NT 0: Ah*Bh             (pure hi; MLP1)
// EPI 0: q -> qh/ql split (+bias+pos_q)
// EPI 1: k/v -> transposed bf16 split kT/vT (k gets +pos_k)
// EPI 2: gelu -> bf16 HI only
// EPI 3: fp32 out = acc + bias + extra
#define TG_SMEM (3 * 65536)
template<int EPI, int NT>
__global__ __launch_bounds__(256, 1)
void tgemm(const u16* __restrict__ Ahi, const u16* __restrict__ Alo,
           const u16* __restrict__ Bhi, const u16* __restrict__ Blo,
           const float* __restrict__ bias, const float* __restrict__ extra,
           void* __restrict__ out, void* __restrict__ out2, int M, int N, int K)
{
    constexpr bool UA = (NT == 3 || NT == 2);   // use A-lo
    constexpr bool UB = (NT == 3 || NT == 1);   // use B-lo
    extern __shared__ __align__(1024) char sm_raw[];
    const uint32_t sb = smem_u32(sm_raw);
    const int tid = threadIdx.x, wid = tid >> 5, lane = tid & 31;
    const int bm = blockIdx.y * 128, bn = blockIdx.x * 128;
    const int wm = (wid & 1) * 64, wn = (wid >> 1) * 32;
    const int nck = K >> 6;

    float acc[4][4][4];
#pragma unroll
    for (int i = 0; i < 4; i++)
#pragma unroll
        for (int j = 0; j < 4; j++)
#pragma unroll
            for (int r = 0; r < 4; r++) acc[i][j][r] = 0.0f;

    const int a_row = ((lane >> 3) & 1) * 8 + (lane & 7);
    const int a_col = (lane >> 4) * 8;
    const int b_row = (lane >> 4) * 8 + (lane & 7);
    const int b_col = ((lane >> 3) & 1) * 8;

    auto load_stage = [&](int ck, int stage) {
        if (ck < nck) {
            const int k0 = ck * 64;
            const uint32_t sbase = sb + stage * 65536;
#pragma unroll
            for (int i = 0; i < 4; i++) {
                const int id = tid + i * 256;
                const int row = id >> 3, c16 = id & 7;
                const uint32_t dsw = SWZ((uint32_t)(row * 128 + c16 * 16));
                const size_t asrc = (size_t)(bm + row) * K + k0 + c16 * 8;
                const size_t bsrc = (size_t)(bn + row) * K + k0 + c16 * 8;
                CPA16(sbase + dsw, Ahi + asrc);
                if (UA) CPA16(sbase + 16384 + dsw, Alo + asrc);
                CPA16(sbase + 32768 + dsw, Bhi + bsrc);
                if (UB) CPA16(sbase + 49152 + dsw, Blo + bsrc);
            }
        }
        CPA_COMMIT();
    };

    load_stage(0, 0);
    load_stage(1, 1);

    for (int ck = 0; ck < nck; ck++) {
        CPA_WAIT1();
        __syncthreads();
        load_stage(ck + 2, (ck + 2) % 3);
        const uint32_t base = sb + (ck % 3) * 65536;
#pragma unroll
        for (int ks = 0; ks < 4; ks++) {
            const int kk = ks * 16;
            uint32_t ah[4][4], al[4][4], bh[2][4], bl[2][4];
#pragma unroll
            for (int mf = 0; mf < 4; mf++) {
                const uint32_t ao = SWZ((uint32_t)((wm + mf * 16 + a_row) * 128 + (kk + a_col) * 2));
                ldsm4(ah[mf], base + ao);
                if (UA) ldsm4(al[mf], base + 16384 + ao);
            }
#pragma unroll
            for (int p = 0; p < 2; p++) {
                const uint32_t bo = SWZ((uint32_t)((wn + p * 16 + b_row) * 128 + (kk + b_col) * 2));
                ldsm4(bh[p], base + 32768 + bo);
                if (UB) ldsm4(bl[p], base + 49152 + bo);
            }
#pragma unroll
            for (int mf = 0; mf < 4; mf++)
#pragma unroll
                for (int p = 0; p < 2; p++)
#pragma unroll
                    for (int s = 0; s < 2; s++) {
                        float* c = acc[mf][p * 2 + s];
                        mma_bf16(c, ah[mf], bh[p][s * 2], bh[p][s * 2 + 1]);
                        if (UA) mma_bf16(c, al[mf], bh[p][s * 2], bh[p][s * 2 + 1]);
                        if (UB) mma_bf16(c, ah[mf], bl[p][s * 2], bl[p][s * 2 + 1]);
                    }
        }
    }

    const int l4 = lane >> 2, l2 = (lane & 3) * 2;

    if (EPI == 1) {
        CPA_WAIT0();
        __syncthreads();
        float* T = (float*)sm_raw;                       // 128 x 132 floats
        const bool is_k = (bn < C_);
#pragma unroll
        for (int mf = 0; mf < 4; mf++)
#pragma unroll
            for (int nf = 0; nf < 4; nf++) {
                const int colL = wn + nf * 8 + l2;
                const int col = bn + colL;
                const float bia0 = bias[col], bia1 = bias[col + 1];
#pragma unroll
                for (int half = 0; half < 2; half++) {
                    const int mL = wm + mf * 16 + l4 + half * 8;
                    float v0 = acc[mf][nf][half * 2]     + bia0;
                    float v1 = acc[mf][nf][half * 2 + 1] + bia1;
                    if (is_k) {
                        const int n = (bm + mL) & (N2_ - 1);
                        v0 += extra[(size_t)n * C_ + col];
                        v1 += extra[(size_t)n * C_ + col + 1];
                    }
                    T[colL * 132 + mL]       = v0;
                    T[(colL + 1) * 132 + mL] = v1;
                }
            }
        __syncthreads();
        u16* __restrict__ dh = is_k ? g_kTh : g_vTh;
        u16* __restrict__ dl = is_k ? g_kTl : g_vTl;
        const int bb = bm >> 12, n0 = bm & (N2_ - 1);
        const int r = tid >> 1, hh2 = (tid & 1) * 64;
        const int c = (bn + r) - (is_k ? 0 : C_);
        const size_t gbase = ((size_t)bb * C_ + c) * N2_ + n0 + hh2;
        const float* Tr = T + r * 132 + hh2;
#pragma unroll
        for (int j = 0; j < 64; j += 8) {
            uint32_t h0, l0, h1, l1, h2, l2x, h3, l3;
            bsplit2(Tr[j],     Tr[j + 1], h0, l0);
            bsplit2(Tr[j + 2], Tr[j + 3], h1, l1);
            bsplit2(Tr[j + 4], Tr[j + 5], h2, l2x);
            bsplit2(Tr[j + 6], Tr[j + 7], h3, l3);
            *(uint4*)(dh + gbase + j) = make_uint4(h0, h1, h2, h3);
            *(uint4*)(dl + gbase + j) = make_uint4(l0, l1, l2x, l3);
        }
        return;
    }

#pragma unroll
    for (int mf = 0; mf < 4; mf++)
#pragma unroll
        for (int nf = 0; nf < 4; nf++) {
            const int col = bn + wn + nf * 8 + l2;
            const float bia0 = bias[col], bia1 = bias[col + 1];
#pragma unroll
            for (int half = 0; half < 2; half++) {
                const int m = bm + wm + mf * 16 + l4 + half * 8;
                float v0 = acc[mf][nf][half * 2]     + bia0;
                float v1 = acc[mf][nf][half * 2 + 1] + bia1;
                if (EPI == 0) {
                    v0 += extra[(size_t)(m & (N1_ - 1)) * C_ + col];
                    v1 += extra[(size_t)(m & (N1_ - 1)) * C_ + col + 1];
                    uint32_t hi, lo;
                    bsplit2(v0, v1, hi, lo);
                    *(uint32_t*)(g_qh + (size_t)m * N + col) = hi;
                    *(uint32_t*)(g_ql + (size_t)m * N + col) = lo;
                } else if (EPI == 2) {
                    v0 = 0.5f * v0 * (1.0f + erff(v0 * 0.70710678118654752f));
                    v1 = 0.5f * v1 * (1.0f + erff(v1 * 0.70710678118654752f));
                    uint32_t hi, lo;
                    bsplit2(v0, v1, hi, lo);
                    *(uint32_t*)((u16*)out + (size_t)m * N + col) = hi;
                } else {
                    v0 += extra[(size_t)m * N + col];
                    v1 += extra[(size_t)m * N + col + 1];
                    *(float2*)((float*)out + (size_t)m * N + col) = make_float2(v0, v1);
                }
            }
        }
}

// ---- kvp via bf16x3 HMMA ----
#define KVP_STG  81920
#define KVP_SMEM (2 * KVP_STG)
__global__ __launch_bounds__(256, 1)
void kvp_mma(const float* __restrict__ bp)
{
    extern __shared__ __align__(1024) char sm_raw[];
    const uint32_t sb = smem_u32(sm_raw);
    const int tid = threadIdx.x, wid = tid >> 5, lane = tid & 31;
    const int g = lane >> 2, t4 = lane & 3;
    const int bh = blockIdx.x, b = bh >> 3, h = bh & 7;
    const int mode = blockIdx.y;
    const u16* __restrict__ Dh = mode ? g_vTh : g_kTh;
    const u16* __restrict__ Dl = mode ? g_vTl : g_kTl;

    const int a_row = ((lane >> 3) & 1) * 8 + (lane & 7);
    const int a_col = (lane >> 4) * 8;
    const int b_row = (lane >> 4) * 8 + (lane & 7);
    const int b_col = ((lane >> 3) & 1) * 8;

    auto load_stage = [&](int ck) {
        if (ck < 64) {
            const uint32_t base = sb + (ck & 1) * KVP_STG;
            const int k0 = ck * 64;
#pragma unroll
            for (int t = 0; t < 8; t++) {
                const int i = tid + t * 256;
                const int row = i >> 3, c16 = i & 7;
                const uint32_t dsw = SWZ((uint32_t)(row * 128 + c16 * 16));
                const size_t src = (size_t)row * N2_ + k0 + c16 * 8;
                CPA16(base + dsw,         g_wpth + src);
                CPA16(base + 32768 + dsw, g_wptl + src);
            }
#pragma unroll
            for (int t = 0; t < 2; t++) {
                const int i = tid + t * 256;
                const int row = i >> 3, c16 = i & 7;
                const uint32_t dsw = SWZ((uint32_t)(row * 128 + c16 * 16));
                const size_t src = ((size_t)b * C_ + h * 64 + row) * N2_ + k0 + c16 * 8;
                CPA16(base + 65536 + dsw, Dh + src);
                CPA16(base + 73728 + dsw, Dl + src);
            }
        }
        CPA_COMMIT();
    };

    load_stage(0);
    load_stage(1);

    if (mode == 0) {
        const int wm = (wid & 3) * 64, wn = (wid >> 2) * 32;
        float acc[4][4][4];
#pragma unroll
        for (int i = 0; i < 4; i++)
#pragma unroll
            for (int j = 0; j < 4; j++)
#pragma unroll
                for (int r = 0; r < 4; r++) acc[i][j][r] = 0.0f;

        for (int ck = 0; ck < 64; ck++) {
            CPA_WAIT1();
            __syncthreads();
            const uint32_t base = sb + (ck & 1) * KVP_STG;
#pragma unroll
            for (int ks = 0; ks < 4; ks++) {
                const int kk = ks * 16;
                uint32_t ah[4][4], al[4][4], bhr[2][4], blr[2][4];
#pragma unroll
                for (int mf = 0; mf < 4; mf++) {
                    const uint32_t ao = SWZ((uint32_t)((wm + mf * 16 + a_row) * 128 + (kk + a_col) * 2));
                    ldsm4(ah[mf], base + ao);
                    ldsm4(al[mf], base + 32768 + ao);
                }
#pragma unroll
                for (int p = 0; p < 2; p++) {
                    const uint32_t bo = SWZ((uint32_t)((wn + p * 16 + b_row) * 128 + (kk + b_col) * 2));
                    ldsm4(bhr[p], base + 65536 + bo);
                    ldsm4(blr[p], base + 73728 + bo);
                }
#pragma unroll
                for (int mf = 0; mf < 4; mf++)
#pragma unroll
                    for (int p = 0; p < 2; p++)
#pragma unroll
                        for (int s = 0; s < 2; s++) {
                            float* c = acc[mf][p * 2 + s];
                            mma_bf16(c, ah[mf], bhr[p][s * 2], bhr[p][s * 2 + 1]);
                            mma_bf16(c, al[mf], bhr[p][s * 2], bhr[p][s * 2 + 1]);
                            mma_bf16(c, ah[mf], blr[p][s * 2], blr[p][s * 2 + 1]);
                        }
            }
            __syncthreads();
            load_stage(ck + 2);
        }
#pragma unroll
        for (int mf = 0; mf < 4; mf++)
#pragma unroll
            for (int hf = 0; hf < 2; hf++) {
                const int p = wm + mf * 16 + hf * 8 + g;
                const float bv = bp[p];
#pragma unroll
                for (int nf = 0; nf < 4; nf++) {
                    const int d = wn + nf * 8 + t4 * 2;
                    uint32_t hi, lo;
                    bsplit2(acc[mf][nf][hf * 2] + bv, acc[mf][nf][hf * 2 + 1] + bv, hi, lo);
                    *(uint32_t*)(g_kpth + (size_t)bh * (P_ * HD_) + p * 64 + d) = hi;
                    *(uint32_t*)(g_kptl + (size_t)bh * (P_ * HD_) + p * 64 + d) = lo;
                }
            }
    } else {
        const int wm = (wid & 1) * 32, wn = (wid >> 1) * 64;
        float acc[2][8][4];
#pragma unroll
        for (int i = 0; i < 2; i++)
#pragma unroll
            for (int j = 0; j < 8; j++)
#pragma unroll
                for (int r = 0; r < 4; r++) acc[i][j][r] = 0.0f;

        for (int ck = 0; ck < 64; ck++) {
            CPA_WAIT1();
            __syncthreads();
            const uint32_t base = sb + (ck & 1) * KVP_STG;
#pragma unroll
            for (int ks = 0; ks < 4; ks++) {
                const int kk = ks * 16;
                uint32_t ah[2][4], al[2][4];
#pragma unroll
                for (int mf = 0; mf < 2; mf++) {
                    const uint32_t ao = SWZ((uint32_t)((wm + mf * 16 + a_row) * 128 + (kk + a_col) * 2));
                    ldsm4(ah[mf], base + 65536 + ao);
                    ldsm4(al[mf], base + 73728 + ao);
                }
#pragma unroll
                for (int p = 0; p < 4; p++) {
                    uint32_t bhr[4], blr[4];
                    const uint32_t bo = SWZ((uint32_t)((wn + p * 16 + b_row) * 128 + (kk + b_col) * 2));
                    ldsm4(bhr, base + bo);
                    ldsm4(blr, base + 32768 + bo);
#pragma unroll
                    for (int mf = 0; mf < 2; mf++)
#pragma unroll
                        for (int s = 0; s < 2; s++) {
                            float* c = acc[mf][p * 2 + s];
                            mma_bf16(c, ah[mf], bhr[s * 2], bhr[s * 2 + 1]);
                            mma_bf16(c, al[mf], bhr[s * 2], bhr[s * 2 + 1]);
                            mma_bf16(c, ah[mf], blr[s * 2], blr[s * 2 + 1]);
                        }
                }
            }
            __syncthreads();
            load_stage(ck + 2);
        }
#pragma unroll
        for (int mf = 0; mf < 2; mf++)
#pragma unroll
            for (int hf = 0; hf < 2; hf++) {
                const int d = wm + mf * 16 + hf * 8 + g;
#pragma unroll
                for (int nf = 0; nf < 8; nf++) {
                    const int p = wn + nf * 8 + t4 * 2;
                    uint32_t hi, lo;
                    bsplit2(acc[mf][nf][hf * 2] + bp[p], acc[mf][nf][hf * 2 + 1] + bp[p + 1], hi, lo);
                    *(uint32_t*)(g_vph + (size_t)bh * (HD_ * P_) + d * 256 + p) = hi;
                    *(uint32_t*)(g_vpl + (size_t)bh * (HD_ * P_) + d * 256 + p) = lo;
                }
            }
    }
}

// ---- attention via bf16x3 HMMA ----
#define A_QH   0
#define A_QL   8192
#define A_KH   16384
#define A_KL   49152
#define A_VH   81920
#define A_VL   114688
#define A_ST   147456
#define A_ZN   149504
#define ATT_SMEM (149504 + 4*64*66*4)

__global__ __launch_bounds__(256, 1)
void attn_mma(const float* __restrict__ temp, float* __restrict__ xa)
{
    extern __shared__ __align__(1024) char sm_raw[];
    const uint32_t sb = smem_u32(sm_raw);
    const int tid = threadIdx.x, wid = tid >> 5, lane = tid & 31;
    const int g = lane >> 2, t4 = lane & 3;
    const int bh = blockIdx.x, b = bh >> 3, h = bh & 7;
    const int q0 = blockIdx.y * 64;
    const int wm = (wid & 1) * 32, zn = wid >> 1, wn = zn * 64;

#pragma unroll
    for (int t = 0; t < 2; t++) {
        const int i = tid + t * 256;
        const int row = i >> 3, c16 = i & 7;
        const uint32_t dsw = SWZ((uint32_t)(row * 128 + c16 * 16));
        const size_t src = (size_t)(b * N1_ + q0 + row) * C_ + h * 64 + c16 * 8;
        CPA16(sb + A_QH + dsw, g_qh + src);
        CPA16(sb + A_QL + dsw, g_ql + src);
    }
#pragma unroll
    for (int t = 0; t < 8; t++) {
        const int i = tid + t * 256;
        const int row = i >> 3, c16 = i & 7;
        const uint32_t dsw = SWZ((uint32_t)(row * 128 + c16 * 16));
        const size_t src = (size_t)bh * (P_ * HD_) + row * 64 + c16 * 8;
        CPA16(sb + A_KH + dsw, g_kpth + src);
        CPA16(sb + A_KL + dsw, g_kptl + src);
    }
#pragma unroll
    for (int t = 0; t < 8; t++) {
        const int i = tid + t * 256;
        const int c16 = i & 7, d = (i >> 3) & 63, ch = i >> 9;
        const uint32_t dsw = (uint32_t)(ch * 8192) + SWZ((uint32_t)(d * 128 + c16 * 16));
        const size_t src = (size_t)bh * (HD_ * P_) + d * 256 + ch * 64 + c16 * 8;
        CPA16(sb + A_VH + dsw, g_vph + src);
        CPA16(sb + A_VL + dsw, g_vpl + src);
    }
    CPA_COMMIT();
    CPA_WAIT0();
    __syncthreads();

    const int a_row = ((lane >> 3) & 1) * 8 + (lane & 7);
    const int a_col = (lane >> 4) * 8;
    const int b_row = (lane >> 4) * 8 + (lane & 7);
    const int b_col = ((lane >> 3) & 1) * 8;

    float acc[2][8][4];
#pragma unroll
    for (int i = 0; i < 2; i++)
#pragma unroll
        for (int j = 0; j < 8; j++)
#pragma unroll
            for (int r = 0; r < 4; r++) acc[i][j][r] = 0.0f;

#pragma unroll
    for (int ks = 0; ks < 4; ks++) {
        const int kk = ks * 16;
        uint32_t ah[2][4], al[2][4];
#pragma unroll
        for (int mf = 0; mf < 2; mf++) {
            const uint32_t ao = SWZ((uint32_t)((wm + mf * 16 + a_row) * 128 + (kk + a_col) * 2));
            ldsm4(ah[mf], sb + A_QH + ao);
            ldsm4(al[mf], sb + A_QL + ao);
        }
#pragma unroll
        for (int p = 0; p < 4; p++) {
            uint32_t bhr[4], blr[4];
            const uint32_t bo = SWZ((uint32_t)((wn + p * 16 + b_row) * 128 + (kk + b_col) * 2));
            ldsm4(bhr, sb + A_KH + bo);
            ldsm4(blr, sb + A_KL + bo);
#pragma unroll
            for (int mf = 0; mf < 2; mf++)
#pragma unroll
                for (int s = 0; s < 2; s++) {
                    float* c = acc[mf][p * 2 + s];
                    mma_bf16(c, ah[mf], bhr[s * 2], bhr[s * 2 + 1]);
                    mma_bf16(c, al[mf], bhr[s * 2], bhr[s * 2 + 1]);
                    mma_bf16(c, ah[mf], blr[s * 2], blr[s * 2 + 1]);
                }
        }
    }

    const float tscale = temp[h];
    float* smax = (float*)(sm_raw + A_ST);
    float* ssum = smax + 256;
#pragma unroll
    for (int mf = 0; mf < 2; mf++)
#pragma unroll
        for (int nf = 0; nf < 8; nf++)
#pragma unroll
            for (int r = 0; r < 4; r++) acc[mf][nf][r] *= tscale;

    float rmx[2][2] = {{-1e30f, -1e30f}, {-1e30f, -1e30f}};
#pragma unroll
    for (int mf = 0; mf < 2; mf++)
#pragma unroll
        for (int nf = 0; nf < 8; nf++) {
            rmx[mf][0] = fmaxf(rmx[mf][0], fmaxf(acc[mf][nf][0], acc[mf][nf][1]));
            rmx[mf][1] = fmaxf(rmx[mf][1], fmaxf(acc[mf][nf][2], acc[mf][nf][3]));
        }
#pragma unroll
    for (int mf = 0; mf < 2; mf++)
#pragma unroll
        for (int hf = 0; hf < 2; hf++) {
            rmx[mf][hf] = fmaxf(rmx[mf][hf], __shfl_xor_sync(~0u, rmx[mf][hf], 1));
            rmx[mf][hf] = fmaxf(rmx[mf][hf], __shfl_xor_sync(~0u, rmx[mf][hf], 2));
        }
    if (t4 == 0)
#pragma unroll
        for (int mf = 0; mf < 2; mf++)
#pragma unroll
            for (int hf = 0; hf < 2; hf++)
                smax[(wm + mf * 16 + hf * 8 + g) * 4 + zn] = rmx[mf][hf];
    __syncthreads();
    float gmx[2][2], rsm[2][2] = {{0, 0}, {0, 0}};
#pragma unroll
    for (int mf = 0; mf < 2; mf++)
#pragma unroll
        for (int hf = 0; hf < 2; hf++) {
            const int r = wm + mf * 16 + hf * 8 + g;
            gmx[mf][hf] = fmaxf(fmaxf(smax[r * 4], smax[r * 4 + 1]),
                                fmaxf(smax[r * 4 + 2], smax[r * 4 + 3]));
        }
#pragma unroll
    for (int mf = 0; mf < 2; mf++)
#pragma unroll
        for (int nf = 0; nf < 8; nf++)
#pragma unroll
            for (int r = 0; r < 4; r++) {
                const int hf = r >> 1;
                const float e = __expf(acc[mf][nf][r] - gmx[mf][hf]);
                acc[mf][nf][r] = e;
                rsm[mf][hf] += e;
            }
#pragma unroll
    for (int mf = 0; mf < 2; mf++)
#pragma unroll
        for (int hf = 0; hf < 2; hf++) {
            rsm[mf][hf] += __shfl_xor_sync(~0u, rsm[mf][hf], 1);
            rsm[mf][hf] += __shfl_xor_sync(~0u, rsm[mf][hf], 2);
        }
    if (t4 == 0)
#pragma unroll
        for (int mf = 0; mf < 2; mf++)
#pragma unroll
            for (int hf = 0; hf < 2; hf++)
                ssum[(wm + mf * 16 + hf * 8 + g) * 4 + zn] = rsm[mf][hf];
    __syncthreads();
#pragma unroll
    for (int mf = 0; mf < 2; mf++)
#pragma unroll
        for (int hf = 0; hf < 2; hf++) {
            const int r = wm + mf * 16 + hf * 8 + g;
            const float inv = 1.0f / (ssum[r * 4] + ssum[r * 4 + 1] + ssum[r * 4 + 2] + ssum[r * 4 + 3]);
#pragma unroll
            for (int nf = 0; nf < 8; nf++) {
                acc[mf][nf][hf * 2]     *= inv;
                acc[mf][nf][hf * 2 + 1] *= inv;
            }
        }

    float acc2[2][8][4];
#pragma unroll
    for (int i = 0; i < 2; i++)
#pragma unroll
        for (int j = 0; j < 8; j++)
#pragma unroll
            for (int r = 0; r < 4; r++) acc2[i][j][r] = 0.0f;

#pragma unroll
    for (int kf = 0; kf < 4; kf++) {
        uint32_t pah[2][4], pal[2][4];
#pragma unroll
        for (int mf = 0; mf < 2; mf++) {
            bsplit2(acc[mf][2*kf][0],   acc[mf][2*kf][1],   pah[mf][0], pal[mf][0]);
            bsplit2(acc[mf][2*kf][2],   acc[mf][2*kf][3],   pah[mf][1], pal[mf][1]);
            bsplit2(acc[mf][2*kf+1][0], acc[mf][2*kf+1][1], pah[mf][2], pal[mf][2]);
            bsplit2(acc[mf][2*kf+1][2], acc[mf][2*kf+1][3], pah[mf][3], pal[mf][3]);
        }
#pragma unroll
        for (int df = 0; df < 4; df++) {
            uint32_t bhr[4], blr[4];
            const uint32_t bo = (uint32_t)(zn * 8192) +
                SWZ((uint32_t)((df * 16 + b_row) * 128 + (kf * 16 + b_col) * 2));
            ldsm4(bhr, sb + A_VH + bo);
            ldsm4(blr, sb + A_VL + bo);
#pragma unroll
            for (int mf = 0; mf < 2; mf++)
#pragma unroll
                for (int s = 0; s < 2; s++) {
                    float* c = acc2[mf][df * 2 + s];
                    mma_bf16(c, pah[mf], bhr[s * 2], bhr[s * 2 + 1]);
                    mma_bf16(c, pal[mf], bhr[s * 2], bhr[s * 2 + 1]);
                    mma_bf16(c, pah[mf], blr[s * 2], blr[s * 2 + 1]);
                }
        }
    }

    float* zone = (float*)(sm_raw + A_ZN) + zn * (64 * 66);
#pragma unroll
    for (int mf = 0; mf < 2; mf++)
#pragma unroll
        for (int nf = 0; nf < 8; nf++)
#pragma unroll
            for (int hf = 0; hf < 2; hf++) {
                const int row = wm + mf * 16 + hf * 8 + g;
                const int dc = nf * 8 + t4 * 2;
                *(float2*)&zone[row * 66 + dc] =
                    make_float2(acc2[mf][nf][hf * 2], acc2[mf][nf][hf * 2 + 1]);
            }
    __syncthreads();

    const int tx = tid & 15, ty = tid >> 4;
    float* z0 = (float*)(sm_raw + A_ZN);
    const size_t base = (size_t)b * (N1_ * C_) + (size_t)h * N1_ + q0 + tx * 4;
#pragma unroll
    for (int j = 0; j < 4; j++) {
        const int d = ty * 4 + j;
        float o[4];
#pragma unroll
        for (int qi = 0; qi < 4; qi++) {
            const int idx = (tx * 4 + qi) * 66 + d;
            o[qi] = z0[idx] + z0[64*66 + idx] + z0[2*64*66 + idx] + z0[3*64*66 + idx];
        }
        *(float4*)&xa[base + (size_t)d * (H_ * N1_)] = make_float4(o[0], o[1], o[2], o[3]);
    }
}

// ---- L2 norm with bf16-split residual input; writes xn fp32 + xnh (hi only) ----
__global__ __launch_bounds__(256)
void l2nq_k(const float* __restrict__ a, const u16* __restrict__ qh,
            const u16* __restrict__ ql, float* __restrict__ out,
            u16* __restrict__ oh)
{
    const int row = blockIdx.x * 8 + (threadIdx.x >> 5);
    const int lane = threadIdx.x & 31;
    const float4* pa = (const float4*)(a + (size_t)row * C_);
    float4 v[4];
    float ss = 0.0f;
#pragma unroll
    for (int i = 0; i < 4; i++) {
        float4 t = pa[lane + 32 * i];
        const size_t off = (size_t)row * C_ + (lane + 32 * i) * 4;
        const uint2 hq = *(const uint2*)(qh + off);
        const uint2 lq = *(const uint2*)(ql + off);
        t.x += __uint_as_float(hq.x << 16)          + __uint_as_float(lq.x << 16);
        t.y += __uint_as_float(hq.x & 0xffff0000u)  + __uint_as_float(lq.x & 0xffff0000u);
        t.z += __uint_as_float(hq.y << 16)          + __uint_as_float(lq.y << 16);
        t.w += __uint_as_float(hq.y & 0xffff0000u)  + __uint_as_float(lq.y & 0xffff0000u);
        v[i] = t;
        ss += t.x * t.x + t.y * t.y + t.z * t.z + t.w * t.w;
    }
#pragma unroll
    for (int o = 16; o > 0; o >>= 1) ss += __shfl_xor_sync(~0u, ss, o);
    const float inv = 1.0f / fmaxf(sqrtf(ss), 1e-12f);
    float4* po = (float4*)(out + (size_t)row * C_);
#pragma unroll
    for (int i = 0; i < 4; i++) {
        v[i].x *= inv; v[i].y *= inv; v[i].z *= inv; v[i].w *= inv;
        po[lane + 32 * i] = v[i];
        uint32_t a0, b0, c0, d0;
        bsplit2(v[i].x, v[i].y, a0, c0); bsplit2(v[i].z, v[i].w, b0, d0);
        const size_t off = (size_t)row * C_ + (lane + 32 * i) * 4;
        *(uint2*)(oh + off) = make_uint2(a0, b0);
    }
}

__global__ __launch_bounds__(256)
void l2n_k(const float* __restrict__ a, float* __restrict__ out)
{
    const int row = blockIdx.x * 8 + (threadIdx.x >> 5);
    const int lane = threadIdx.x & 31;
    const float4* pa = (const float4*)(a + (size_t)row * C_);
    float4 v[4];
    float ss = 0.0f;
#pragma unroll
    for (int i = 0; i < 4; i++) {
        float4 t = pa[lane + 32 * i];
        v[i] = t;
        ss += t.x * t.x + t.y * t.y + t.z * t.z + t.w * t.w;
    }
#pragma unroll
    for (int o = 16; o > 0; o >>= 1) ss += __shfl_xor_sync(~0u, ss, o);
    const float inv = 1.0f / fmaxf(sqrtf(ss), 1e-12f);
    float4* po = (float4*)(out + (size_t)row * C_);
#pragma unroll
    for (int i = 0; i < 4; i++) {
        v[i].x *= inv; v[i].y *= inv; v[i].z *= inv; v[i].w *= inv;
        po[lane + 32 * i] = v[i];
    }
}

extern "C" void kernel_launch(void* const* d_in, const int* in_sizes, int n_in,
                              void* d_out, int out_size)
{
    const float* x1    = (const float*)d_in[0];
    const float* x2    = (const float*)d_in[1];
    const float* Wq    = (const float*)d_in[2];
    const float* bq    = (const float*)d_in[3];
    const float* Wkv   = (const float*)d_in[4];
    const float* bkv   = (const float*)d_in[5];
    const float* Wp    = (const float*)d_in[6];
    const float* bp    = (const float*)d_in[7];
    const float* pos_q = (const float*)d_in[8];
    const float* pos_k = (const float*)d_in[9];
    const float* temp  = (const float*)d_in[10];
    const float* W1    = (const float*)d_in[11];
    const float* b1    = (const float*)d_in[12];
    const float* W2    = (const float*)d_in[13];
    const float* b2    = (const float*)d_in[14];

    float *xa, *xn;
    u16 *qh, *ql, *x1h, *x1l, *x2h, *x2l, *xnh, *hh;
    u16 *wqh, *wql, *wkvh, *wkvl, *w1h, *w2h, *w2l, *wpth, *wptl;
    cudaGetSymbolAddress((void**)&xa, g_xa);
    cudaGetSymbolAddress((void**)&xn, g_xn);
    cudaGetSymbolAddress((void**)&qh, g_qh);   cudaGetSymbolAddress((void**)&ql, g_ql);
    cudaGetSymbolAddress((void**)&x1h, g_x1h); cudaGetSymbolAddress((void**)&x1l, g_x1l);
    cudaGetSymbolAddress((void**)&x2h, g_x2h); cudaGetSymbolAddress((void**)&x2l, g_x2l);
    cudaGetSymbolAddress((void**)&xnh, g_xnh);
    cudaGetSymbolAddress((void**)&hh, g_hh);
    cudaGetSymbolAddress((void**)&wqh, g_wq_hi);   cudaGetSymbolAddress((void**)&wql, g_wq_lo);
    cudaGetSymbolAddress((void**)&wkvh, g_wkv_hi); cudaGetSymbolAddress((void**)&wkvl, g_wkv_lo);
    cudaGetSymbolAddress((void**)&w1h, g_w1_hi);
    cudaGetSymbolAddress((void**)&w2h, g_w2_hi);   cudaGetSymbolAddress((void**)&w2l, g_w2_lo);
    cudaGetSymbolAddress((void**)&wpth, g_wpth);   cudaGetSymbolAddress((void**)&wptl, g_wptl);

    cudaFuncSetAttribute(attn_mma, cudaFuncAttributeMaxDynamicSharedMemorySize, ATT_SMEM);
    cudaFuncSetAttribute(kvp_mma,  cudaFuncAttributeMaxDynamicSharedMemorySize, KVP_SMEM);
    cudaFuncSetAttribute((const void*)tgemm<0,3>, cudaFuncAttributeMaxDynamicSharedMemorySize, TG_SMEM);
    cudaFuncSetAttribute((const void*)tgemm<1,3>, cudaFuncAttributeMaxDynamicSharedMemorySize, TG_SMEM);
    cudaFuncSetAttribute((const void*)tgemm<2,0>, cudaFuncAttributeMaxDynamicSharedMemorySize, TG_SMEM);
    cudaFuncSetAttribute((const void*)tgemm<3,1>, cudaFuncAttributeMaxDynamicSharedMemorySize, TG_SMEM);

    cudaStream_t s2;
    cudaStreamCreateWithFlags(&s2, cudaStreamNonBlocking);
    cudaEvent_t eF, eKV, eJ, eW;
    cudaEventCreateWithFlags(&eF,  cudaEventDisableTiming);
    cudaEventCreateWithFlags(&eKV, cudaEventDisableTiming);
    cudaEventCreateWithFlags(&eJ,  cudaEventDisableTiming);
    cudaEventCreateWithFlags(&eW,  cudaEventDisableTiming);

    cudaEventRecord(eF, 0);
    cudaStreamWaitEvent(s2, eF, 0);

    // s2: Q-chain prep
    wsplit_k<<<dim3(C_ / 32, C_ / 32), 256, 0, s2>>>(Wq, wqh, wql, C_, C_);
    asplit_k<<<(M_ * C_) / 1024, 256, 0, s2>>>(x1, x1h, x1l);

    // legacy: KV chain
    wsplit_k<<<dim3(2 * C_ / 32, C_ / 32), 256>>>(Wkv, wkvh, wkvl, C_, 2 * C_);
    wsplit_k<<<dim3(P_ / 32, N2_ / 32), 256>>>(Wp, wpth, wptl, N2_, P_);
    asplit_k<<<(M_ * C_) / 1024, 256>>>(x2, x2h, x2l);
    tgemm<1,3><<<dim3(2 * C_ / 128, M_ / 128), 256, TG_SMEM>>>(
        x2h, x2l, wkvh, wkvl, bkv, pos_k, nullptr, nullptr, M_, 2 * C_, C_);
    cudaEventRecord(eKV, 0);

    // s2: tgemm<0> + W1/W2 splits fill kvp's idle SMs
    cudaStreamWaitEvent(s2, eKV, 0);
    tgemm<0,3><<<dim3(C_ / 128, M_ / 128), 256, TG_SMEM, s2>>>(
        x1h, x1l, wqh, wql, bq, pos_q, nullptr, nullptr, M_, C_, C_);
    cudaEventRecord(eJ, s2);
    wsplit_k<<<dim3(MLP_ / 32, C_ / 32), 256, 0, s2>>>(W1, w1h, nullptr, C_, MLP_);
    wsplit_k<<<dim3(C_ / 32, MLP_ / 32), 256, 0, s2>>>(W2, w2h, w2l, MLP_, C_);
    cudaEventRecord(eW, s2);

    // legacy: kvp co-runs with s2
    kvp_mma<<<dim3(B_ * H_, 2), 256, KVP_SMEM>>>(bp);

    cudaStreamWaitEvent(0, eJ, 0);
    attn_mma<<<dim3(B_ * H_, N1_ / 64), 256, ATT_SMEM>>>(temp, xa);
    l2nq_k<<<M_ / 8, 256>>>(xa, qh, ql, xn, xnh);
    cudaStreamWaitEvent(0, eW, 0);
    // MLP1: pure hi*hi (1-term)
    tgemm<2,0><<<dim3(MLP_ / 128, M_ / 128), 256, TG_SMEM>>>(
        xnh, nullptr, w1h, nullptr, b1, nullptr, hh, nullptr, M_, MLP_, C_);
    // MLP2: 2-term (A = h-hi; B = W2 hi+lo)
    tgemm<3,1><<<dim3(C_ / 128, M_ / 128), 256, TG_SMEM>>>(
        hh, nullptr, w2h, w2l, b2, xn, xa, nullptr, M_, C_, MLP_);
    l2n_k<<<M_ / 8, 256>>>(xa, (float*)d_out);
}

// round 15
// speedup vs baseline: 3.0258x; 1.0271x over previous
#include <cuda_runtime.h>
#include <math.h>
#include <stdint.h>

#define B_   8
#define N1_  4096
#define N2_  4096
#define C_   512
#define P_   256
#define H_   8
#define HD_  64
#define MLP_ 2048
#define M_   (B_*N1_)

typedef unsigned short u16;

__device__ float g_xa[M_*C_];
__device__ float g_xn[M_*C_];
__device__ u16 g_qh [M_*C_],  g_ql [M_*C_];
__device__ u16 g_x1h[M_*C_],  g_x1l[M_*C_];
__device__ u16 g_x2h[M_*C_],  g_x2l[M_*C_];
__device__ u16 g_xnh[M_*C_];
__device__ u16 g_hh [M_*MLP_];
__device__ u16 g_kTh[B_*C_*N2_], g_kTl[B_*C_*N2_];
__device__ u16 g_vTh[B_*C_*N2_], g_vTl[B_*C_*N2_];
__device__ u16 g_kpth[B_*H_*P_*HD_], g_kptl[B_*H_*P_*HD_];
__device__ u16 g_vph [B_*H_*HD_*P_], g_vpl [B_*H_*HD_*P_];
__device__ u16 g_wq_hi [C_*C_],   g_wq_lo [C_*C_];
__device__ u16 g_wkv_hi[2*C_*C_], g_wkv_lo[2*C_*C_];
__device__ u16 g_w1_hi [MLP_*C_];
__device__ u16 g_w2_hi [C_*MLP_], g_w2_lo [C_*MLP_];
__device__ u16 g_wpth  [P_*N2_],  g_wptl  [P_*N2_];

__device__ __forceinline__ uint32_t smem_u32(const void* p) {
    uint32_t a;
    asm("{ .reg .u64 t; cvta.to.shared.u64 t, %1; cvt.u32.u64 %0, t; }" : "=r"(a) : "l"(p));
    return a;
}
#define SWZ(b) ((b) ^ (((b) >> 3) & 0x70))
#define CPA16(dst, src) asm volatile("cp.async.cg.shared.global [%0], [%1], 16;" :: "r"(dst), "l"(src))
#define CPA_COMMIT() asm volatile("cp.async.commit_group;" ::: "memory")
#define CPA_WAIT1()  asm volatile("cp.async.wait_group 1;" ::: "memory")
#define CPA_WAIT0()  asm volatile("cp.async.wait_group 0;" ::: "memory")

__device__ __forceinline__ void ldsm4(uint32_t* r, uint32_t a) {
    asm volatile("ldmatrix.sync.aligned.m8n8.x4.shared.b16 {%0,%1,%2,%3}, [%4];"
                 : "=r"(r[0]), "=r"(r[1]), "=r"(r[2]), "=r"(r[3]) : "r"(a));
}
__device__ __forceinline__ void mma_bf16(float* c, const uint32_t* a, uint32_t b0, uint32_t b1) {
    asm volatile("mma.sync.aligned.m16n8k16.row.col.f32.bf16.bf16.f32 "
        "{%0,%1,%2,%3}, {%4,%5,%6,%7}, {%8,%9}, {%0,%1,%2,%3};"
        : "+f"(c[0]), "+f"(c[1]), "+f"(c[2]), "+f"(c[3])
        : "r"(a[0]), "r"(a[1]), "r"(a[2]), "r"(a[3]), "r"(b0), "r"(b1));
}
__device__ __forceinline__ void bsplit(float a, uint32_t& hi, uint32_t& lo) {
    uint32_t u = __float_as_uint(a);
    uint32_t hr = (u + 0x7fffu + ((u >> 16) & 1u)) & 0xffff0000u;
    hi = hr >> 16;
    float l = a - __uint_as_float(hr);
    uint32_t ul = __float_as_uint(l);
    lo = (ul + 0x7fffu + ((ul >> 16) & 1u)) >> 16;
}
__device__ __forceinline__ void bsplit2(float a, float b, uint32_t& hi, uint32_t& lo) {
    uint32_t h0, l0, h1, l1;
    bsplit(a, h0, l0); bsplit(b, h1, l1);
    hi = h0 | (h1 << 16); lo = l0 | (l1 << 16);
}

__global__ __launch_bounds__(256)
void wsplit_k(const float* __restrict__ W, u16* __restrict__ hi, u16* __restrict__ lo, int K, int N)
{
    __shared__ float tile[32][33];
    const int n0 = blockIdx.x * 32, k0 = blockIdx.y * 32;
    const int tx = threadIdx.x & 31, ty = threadIdx.x >> 5;
#pragma unroll
    for (int r = 0; r < 4; r++)
        tile[ty + 8 * r][tx] = W[(size_t)(k0 + ty + 8 * r) * N + n0 + tx];
    __syncthreads();
#pragma unroll
    for (int r = 0; r < 4; r++) {
        const int n = n0 + ty + 8 * r, k = k0 + tx;
        uint32_t h, l;
        bsplit(tile[tx][ty + 8 * r], h, l);
        hi[(size_t)n * K + k] = (u16)h;
        if (lo) lo[(size_t)n * K + k] = (u16)l;
    }
}

__global__ __launch_bounds__(256)
void asplit_k(const float* __restrict__ A, u16* __restrict__ hi, u16* __restrict__ lo)
{
    const size_t i4 = ((size_t)blockIdx.x * 256 + threadIdx.x) * 4;
    float4 f = *(const float4*)(A + i4);
    uint32_t a, b, c, d;
    bsplit2(f.x, f.y, a, c); bsplit2(f.z, f.w, b, d);
    *(uint2*)(hi + i4) = make_uint2(a, b);
    *(uint2*)(lo + i4) = make_uint2(c, d);
}

// ---- bf16 HMMA GEMM, 128x128 tile, 3-stage cp.async, packed smem per NT ----
// NT 3: Ah*Bh + Al*Bh + Ah*Bl   | NT 2: drop B-lo | NT 1: drop A-lo | NT 0: hi only
#define TG_NBUF(NT) (2 + (((NT)==3||(NT)==2)?1:0) + (((NT)==3||(NT)==1)?1:0))
#define TG_SMEM_OF(NT) (3 * TG_NBUF(NT) * 16384)
template<int EPI, int NT>
__global__ __launch_bounds__(256, (NT == 0) ? 2 : 1)
void tgemm(const u16* __restrict__ Ahi, const u16* __restrict__ Alo,
           const u16* __restrict__ Bhi, const u16* __restrict__ Blo,
           const float* __restrict__ bias, const float* __restrict__ extra,
           void* __restrict__ out, void* __restrict__ out2, int M, int N, int K)
{
    constexpr bool UA = (NT == 3 || NT == 2);
    constexpr bool UB = (NT == 3 || NT == 1);
    constexpr uint32_t OAL = 16384;
    constexpr uint32_t OBH = (UA ? 2u : 1u) * 16384u;
    constexpr uint32_t OBL = OBH + 16384u;
    constexpr uint32_t STG = (uint32_t)TG_NBUF(NT) * 16384u;
    extern __shared__ __align__(1024) char sm_raw[];
    const uint32_t sb = smem_u32(sm_raw);
    const int tid = threadIdx.x, wid = tid >> 5, lane = tid & 31;
    const int bm = blockIdx.y * 128, bn = blockIdx.x * 128;
    const int wm = (wid & 1) * 64, wn = (wid >> 1) * 32;
    const int nck = K >> 6;

    float acc[4][4][4];
#pragma unroll
    for (int i = 0; i < 4; i++)
#pragma unroll
        for (int j = 0; j < 4; j++)
#pragma unroll
            for (int r = 0; r < 4; r++) acc[i][j][r] = 0.0f;

    const int a_row = ((lane >> 3) & 1) * 8 + (lane & 7);
    const int a_col = (lane >> 4) * 8;
    const int b_row = (lane >> 4) * 8 + (lane & 7);
    const int b_col = ((lane >> 3) & 1) * 8;

    auto load_stage = [&](int ck, int stage) {
        if (ck < nck) {
            const int k0 = ck * 64;
            const uint32_t sbase = sb + stage * STG;
#pragma unroll
            for (int i = 0; i < 4; i++) {
                const int id = tid + i * 256;
                const int row = id >> 3, c16 = id & 7;
                const uint32_t dsw = SWZ((uint32_t)(row * 128 + c16 * 16));
                const size_t asrc = (size_t)(bm + row) * K + k0 + c16 * 8;
                const size_t bsrc = (size_t)(bn + row) * K + k0 + c16 * 8;
                CPA16(sbase + dsw, Ahi + asrc);
                if (UA) CPA16(sbase + OAL + dsw, Alo + asrc);
                CPA16(sbase + OBH + dsw, Bhi + bsrc);
                if (UB) CPA16(sbase + OBL + dsw, Blo + bsrc);
            }
        }
        CPA_COMMIT();
    };

    load_stage(0, 0);
    load_stage(1, 1);

    for (int ck = 0; ck < nck; ck++) {
        CPA_WAIT1();
        __syncthreads();
        load_stage(ck + 2, (ck + 2) % 3);
        const uint32_t base = sb + (ck % 3) * STG;
#pragma unroll
        for (int ks = 0; ks < 4; ks++) {
            const int kk = ks * 16;
            uint32_t ah[4][4], al[4][4], bh[2][4], bl[2][4];
#pragma unroll
            for (int mf = 0; mf < 4; mf++) {
                const uint32_t ao = SWZ((uint32_t)((wm + mf * 16 + a_row) * 128 + (kk + a_col) * 2));
                ldsm4(ah[mf], base + ao);
                if (UA) ldsm4(al[mf], base + OAL + ao);
            }
#pragma unroll
            for (int p = 0; p < 2; p++) {
                const uint32_t bo = SWZ((uint32_t)((wn + p * 16 + b_row) * 128 + (kk + b_col) * 2));
                ldsm4(bh[p], base + OBH + bo);
                if (UB) ldsm4(bl[p], base + OBL + bo);
            }
#pragma unroll
            for (int mf = 0; mf < 4; mf++)
#pragma unroll
                for (int p = 0; p < 2; p++)
#pragma unroll
                    for (int s = 0; s < 2; s++) {
                        float* c = acc[mf][p * 2 + s];
                        mma_bf16(c, ah[mf], bh[p][s * 2], bh[p][s * 2 + 1]);
                        if (UA) mma_bf16(c, al[mf], bh[p][s * 2], bh[p][s * 2 + 1]);
                        if (UB) mma_bf16(c, ah[mf], bl[p][s * 2], bl[p][s * 2 + 1]);
                    }
        }
    }

    const int l4 = lane >> 2, l2 = (lane & 3) * 2;

    if (EPI == 1) {
        CPA_WAIT0();
        __syncthreads();
        float* T = (float*)sm_raw;                       // 128 x 132 floats
        const bool is_k = (bn < C_);
#pragma unroll
        for (int mf = 0; mf < 4; mf++)
#pragma unroll
            for (int nf = 0; nf < 4; nf++) {
                const int colL = wn + nf * 8 + l2;
                const int col = bn + colL;
                const float bia0 = bias[col], bia1 = bias[col + 1];
#pragma unroll
                for (int half = 0; half < 2; half++) {
                    const int mL = wm + mf * 16 + l4 + half * 8;
                    float v0 = acc[mf][nf][half * 2]     + bia0;
                    float v1 = acc[mf][nf][half * 2 + 1] + bia1;
                    if (is_k) {
                        const int n = (bm + mL) & (N2_ - 1);
                        v0 += extra[(size_t)n * C_ + col];
                        v1 += extra[(size_t)n * C_ + col + 1];
                    }
                    T[colL * 132 + mL]       = v0;
                    T[(colL + 1) * 132 + mL] = v1;
                }
            }
        __syncthreads();
        u16* __restrict__ dh = is_k ? g_kTh : g_vTh;
        u16* __restrict__ dl = is_k ? g_kTl : g_vTl;
        const int bb = bm >> 12, n0 = bm & (N2_ - 1);
        const int r = tid >> 1, hh2 = (tid & 1) * 64;
        const int c = (bn + r) - (is_k ? 0 : C_);
        const size_t gbase = ((size_t)bb * C_ + c) * N2_ + n0 + hh2;
        const float* Tr = T + r * 132 + hh2;
#pragma unroll
        for (int j = 0; j < 64; j += 8) {
            uint32_t h0, l0, h1, l1, h2, l2x, h3, l3;
            bsplit2(Tr[j],     Tr[j + 1], h0, l0);
            bsplit2(Tr[j + 2], Tr[j + 3], h1, l1);
            bsplit2(Tr[j + 4], Tr[j + 5], h2, l2x);
            bsplit2(Tr[j + 6], Tr[j + 7], h3, l3);
            *(uint4*)(dh + gbase + j) = make_uint4(h0, h1, h2, h3);
            *(uint4*)(dl + gbase + j) = make_uint4(l0, l1, l2x, l3);
        }
        return;
    }

#pragma unroll
    for (int mf = 0; mf < 4; mf++)
#pragma unroll
        for (int nf = 0; nf < 4; nf++) {
            const int col = bn + wn + nf * 8 + l2;
            const float bia0 = bias[col], bia1 = bias[col + 1];
#pragma unroll
            for (int half = 0; half < 2; half++) {
                const int m = bm + wm + mf * 16 + l4 + half * 8;
                float v0 = acc[mf][nf][half * 2]     + bia0;
                float v1 = acc[mf][nf][half * 2 + 1] + bia1;
                if (EPI == 0) {
                    v0 += extra[(size_t)(m & (N1_ - 1)) * C_ + col];
                    v1 += extra[(size_t)(m & (N1_ - 1)) * C_ + col + 1];
                    uint32_t hi, lo;
                    bsplit2(v0, v1, hi, lo);
                    *(uint32_t*)(g_qh + (size_t)m * N + col) = hi;
                    *(uint32_t*)(g_ql + (size_t)m * N + col) = lo;
                } else if (EPI == 2) {
                    v0 = 0.5f * v0 * (1.0f + erff(v0 * 0.70710678118654752f));
                    v1 = 0.5f * v1 * (1.0f + erff(v1 * 0.70710678118654752f));
                    uint32_t hi, lo;
                    bsplit2(v0, v1, hi, lo);
                    *(uint32_t*)((u16*)out + (size_t)m * N + col) = hi;
                } else {
                    v0 += extra[(size_t)m * N + col];
                    v1 += extra[(size_t)m * N + col + 1];
                    *(float2*)((float*)out + (size_t)m * N + col) = make_float2(v0, v1);
                }
            }
        }
}

// ---- kvp via bf16x3 HMMA ----
#define KVP_STG  81920
#define KVP_SMEM (2 * KVP_STG)
__global__ __launch_bounds__(256, 1)
void kvp_mma(const float* __restrict__ bp)
{
    extern __shared__ __align__(1024) char sm_raw[];
    const uint32_t sb = smem_u32(sm_raw);
    const int tid = threadIdx.x, wid = tid >> 5, lane = tid & 31;
    const int g = lane >> 2, t4 = lane & 3;
    const int bh = blockIdx.x, b = bh >> 3, h = bh & 7;
    const int mode = blockIdx.y;
    const u16* __restrict__ Dh = mode ? g_vTh : g_kTh;
    const u16* __restrict__ Dl = mode ? g_vTl : g_kTl;

    const int a_row = ((lane >> 3) & 1) * 8 + (lane & 7);
    const int a_col = (lane >> 4) * 8;
    const int b_row = (lane >> 4) * 8 + (lane & 7);
    const int b_col = ((lane >> 3) & 1) * 8;

    auto load_stage = [&](int ck) {
        if (ck < 64) {
            const uint32_t base = sb + (ck & 1) * KVP_STG;
            const int k0 = ck * 64;
#pragma unroll
            for (int t = 0; t < 8; t++) {
                const int i = tid + t * 256;
                const int row = i >> 3, c16 = i & 7;
                const uint32_t dsw = SWZ((uint32_t)(row * 128 + c16 * 16));
                const size_t src = (size_t)row * N2_ + k0 + c16 * 8;
                CPA16(base + dsw,         g_wpth + src);
                CPA16(base + 32768 + dsw, g_wptl + src);
            }
#pragma unroll
            for (int t = 0; t < 2; t++) {
                const int i = tid + t * 256;
                const int row = i >> 3, c16 = i & 7;
                const uint32_t dsw = SWZ((uint32_t)(row * 128 + c16 * 16));
                const size_t src = ((size_t)b * C_ + h * 64 + row) * N2_ + k0 + c16 * 8;
                CPA16(base + 65536 + dsw, Dh + src);
                CPA16(base + 73728 + dsw, Dl + src);
            }
        }
        CPA_COMMIT();
    };

    load_stage(0);
    load_stage(1);

    if (mode == 0) {
        const int wm = (wid & 3) * 64, wn = (wid >> 2) * 32;
        float acc[4][4][4];
#pragma unroll
        for (int i = 0; i < 4; i++)
#pragma unroll
            for (int j = 0; j < 4; j++)
#pragma unroll
                for (int r = 0; r < 4; r++) acc[i][j][r] = 0.0f;

        for (int ck = 0; ck < 64; ck++) {
            CPA_WAIT1();
            __syncthreads();
            const uint32_t base = sb + (ck & 1) * KVP_STG;
#pragma unroll
            for (int ks = 0; ks < 4; ks++) {
                const int kk = ks * 16;
                uint32_t ah[4][4], al[4][4], bhr[2][4], blr[2][4];
#pragma unroll
                for (int mf = 0; mf < 4; mf++) {
                    const uint32_t ao = SWZ((uint32_t)((wm + mf * 16 + a_row) * 128 + (kk + a_col) * 2));
                    ldsm4(ah[mf], base + ao);
                    ldsm4(al[mf], base + 32768 + ao);
                }
#pragma unroll
                for (int p = 0; p < 2; p++) {
                    const uint32_t bo = SWZ((uint32_t)((wn + p * 16 + b_row) * 128 + (kk + b_col) * 2));
                    ldsm4(bhr[p], base + 65536 + bo);
                    ldsm4(blr[p], base + 73728 + bo);
                }
#pragma unroll
                for (int mf = 0; mf < 4; mf++)
#pragma unroll
                    for (int p = 0; p < 2; p++)
#pragma unroll
                        for (int s = 0; s < 2; s++) {
                            float* c = acc[mf][p * 2 + s];
                            mma_bf16(c, ah[mf], bhr[p][s * 2], bhr[p][s * 2 + 1]);
                            mma_bf16(c, al[mf], bhr[p][s * 2], bhr[p][s * 2 + 1]);
                            mma_bf16(c, ah[mf], blr[p][s * 2], blr[p][s * 2 + 1]);
                        }
            }
            __syncthreads();
            load_stage(ck + 2);
        }
#pragma unroll
        for (int mf = 0; mf < 4; mf++)
#pragma unroll
            for (int hf = 0; hf < 2; hf++) {
                const int p = wm + mf * 16 + hf * 8 + g;
                const float bv = bp[p];
#pragma unroll
                for (int nf = 0; nf < 4; nf++) {
                    const int d = wn + nf * 8 + t4 * 2;
                    uint32_t hi, lo;
                    bsplit2(acc[mf][nf][hf * 2] + bv, acc[mf][nf][hf * 2 + 1] + bv, hi, lo);
                    *(uint32_t*)(g_kpth + (size_t)bh * (P_ * HD_) + p * 64 + d) = hi;
                    *(uint32_t*)(g_kptl + (size_t)bh * (P_ * HD_) + p * 64 + d) = lo;
                }
            }
    } else {
        const int wm = (wid & 1) * 32, wn = (wid >> 1) * 64;
        float acc[2][8][4];
#pragma unroll
        for (int i = 0; i < 2; i++)
#pragma unroll
            for (int j = 0; j < 8; j++)
#pragma unroll
                for (int r = 0; r < 4; r++) acc[i][j][r] = 0.0f;

        for (int ck = 0; ck < 64; ck++) {
            CPA_WAIT1();
            __syncthreads();
            const uint32_t base = sb + (ck & 1) * KVP_STG;
#pragma unroll
            for (int ks = 0; ks < 4; ks++) {
                const int kk = ks * 16;
                uint32_t ah[2][4], al[2][4];
#pragma unroll
                for (int mf = 0; mf < 2; mf++) {
                    const uint32_t ao = SWZ((uint32_t)((wm + mf * 16 + a_row) * 128 + (kk + a_col) * 2));
                    ldsm4(ah[mf], base + 65536 + ao);
                    ldsm4(al[mf], base + 73728 + ao);
                }
#pragma unroll
                for (int p = 0; p < 4; p++) {
                    uint32_t bhr[4], blr[4];
                    const uint32_t bo = SWZ((uint32_t)((wn + p * 16 + b_row) * 128 + (kk + b_col) * 2));
                    ldsm4(bhr, base + bo);
                    ldsm4(blr, base + 32768 + bo);
#pragma unroll
                    for (int mf = 0; mf < 2; mf++)
#pragma unroll
                        for (int s = 0; s < 2; s++) {
                            float* c = acc[mf][p * 2 + s];
                            mma_bf16(c, ah[mf], bhr[s * 2], bhr[s * 2 + 1]);
                            mma_bf16(c, al[mf], bhr[s * 2], bhr[s * 2 + 1]);
                            mma_bf16(c, ah[mf], blr[s * 2], blr[s * 2 + 1]);
                        }
                }
            }
            __syncthreads();
            load_stage(ck + 2);
        }
#pragma unroll
        for (int mf = 0; mf < 2; mf++)
#pragma unroll
            for (int hf = 0; hf < 2; hf++) {
                const int d = wm + mf * 16 + hf * 8 + g;
#pragma unroll
                for (int nf = 0; nf < 8; nf++) {
                    const int p = wn + nf * 8 + t4 * 2;
                    uint32_t hi, lo;
                    bsplit2(acc[mf][nf][hf * 2] + bp[p], acc[mf][nf][hf * 2 + 1] + bp[p + 1], hi, lo);
                    *(uint32_t*)(g_vph + (size_t)bh * (HD_ * P_) + d * 256 + p) = hi;
                    *(uint32_t*)(g_vpl + (size_t)bh * (HD_ * P_) + d * 256 + p) = lo;
                }
            }
    }
}

// ---- attention via bf16x3 HMMA; 2 q-blocks per CTA (kp/vp loaded once) ----
#define A_QH   0
#define A_QL   8192
#define A_KH   16384
#define A_KL   49152
#define A_VH   81920
#define A_VL   114688
#define A_ST   147456
#define A_ZN   149504
#define ATT_SMEM (149504 + 4*64*66*4)

__global__ __launch_bounds__(256, 1)
void attn_mma(const float* __restrict__ temp, float* __restrict__ xa)
{
    extern __shared__ __align__(1024) char sm_raw[];
    const uint32_t sb = smem_u32(sm_raw);
    const int tid = threadIdx.x, wid = tid >> 5, lane = tid & 31;
    const int g = lane >> 2, t4 = lane & 3;
    const int bh = blockIdx.x, b = bh >> 3, h = bh & 7;
    const int wm = (wid & 1) * 32, zn = wid >> 1, wn = zn * 64;

    // kp/vp: loaded ONCE for both q-blocks
#pragma unroll
    for (int t = 0; t < 8; t++) {
        const int i = tid + t * 256;
        const int row = i >> 3, c16 = i & 7;
        const uint32_t dsw = SWZ((uint32_t)(row * 128 + c16 * 16));
        const size_t src = (size_t)bh * (P_ * HD_) + row * 64 + c16 * 8;
        CPA16(sb + A_KH + dsw, g_kpth + src);
        CPA16(sb + A_KL + dsw, g_kptl + src);
    }
#pragma unroll
    for (int t = 0; t < 8; t++) {
        const int i = tid + t * 256;
        const int c16 = i & 7, d = (i >> 3) & 63, ch = i >> 9;
        const uint32_t dsw = (uint32_t)(ch * 8192) + SWZ((uint32_t)(d * 128 + c16 * 16));
        const size_t src = (size_t)bh * (HD_ * P_) + d * 256 + ch * 64 + c16 * 8;
        CPA16(sb + A_VH + dsw, g_vph + src);
        CPA16(sb + A_VL + dsw, g_vpl + src);
    }
    CPA_COMMIT();

    const int a_row = ((lane >> 3) & 1) * 8 + (lane & 7);
    const int a_col = (lane >> 4) * 8;
    const int b_row = (lane >> 4) * 8 + (lane & 7);
    const int b_col = ((lane >> 3) & 1) * 8;
    const float tscale = temp[h];
    float* smax = (float*)(sm_raw + A_ST);
    float* ssum = smax + 256;

    for (int qi = 0; qi < 2; qi++) {
        const int q0 = (blockIdx.y * 2 + qi) * 64;
        // load Q tile for this q-block
#pragma unroll
        for (int t = 0; t < 2; t++) {
            const int i = tid + t * 256;
            const int row = i >> 3, c16 = i & 7;
            const uint32_t dsw = SWZ((uint32_t)(row * 128 + c16 * 16));
            const size_t src = (size_t)(b * N1_ + q0 + row) * C_ + h * 64 + c16 * 8;
            CPA16(sb + A_QH + dsw, g_qh + src);
            CPA16(sb + A_QL + dsw, g_ql + src);
        }
        CPA_COMMIT();
        CPA_WAIT0();
        __syncthreads();

        float acc[2][8][4];
#pragma unroll
        for (int i = 0; i < 2; i++)
#pragma unroll
            for (int j = 0; j < 8; j++)
#pragma unroll
                for (int r = 0; r < 4; r++) acc[i][j][r] = 0.0f;

#pragma unroll
        for (int ks = 0; ks < 4; ks++) {
            const int kk = ks * 16;
            uint32_t ah[2][4], al[2][4];
#pragma unroll
            for (int mf = 0; mf < 2; mf++) {
                const uint32_t ao = SWZ((uint32_t)((wm + mf * 16 + a_row) * 128 + (kk + a_col) * 2));
                ldsm4(ah[mf], sb + A_QH + ao);
                ldsm4(al[mf], sb + A_QL + ao);
            }
#pragma unroll
            for (int p = 0; p < 4; p++) {
                uint32_t bhr[4], blr[4];
                const uint32_t bo = SWZ((uint32_t)((wn + p * 16 + b_row) * 128 + (kk + b_col) * 2));
                ldsm4(bhr, sb + A_KH + bo);
                ldsm4(blr, sb + A_KL + bo);
#pragma unroll
                for (int mf = 0; mf < 2; mf++)
#pragma unroll
                    for (int s = 0; s < 2; s++) {
                        float* c = acc[mf][p * 2 + s];
                        mma_bf16(c, ah[mf], bhr[s * 2], bhr[s * 2 + 1]);
                        mma_bf16(c, al[mf], bhr[s * 2], bhr[s * 2 + 1]);
                        mma_bf16(c, ah[mf], blr[s * 2], blr[s * 2 + 1]);
                    }
            }
        }

#pragma unroll
        for (int mf = 0; mf < 2; mf++)
#pragma unroll
            for (int nf = 0; nf < 8; nf++)
#pragma unroll
                for (int r = 0; r < 4; r++) acc[mf][nf][r] *= tscale;

        float rmx[2][2] = {{-1e30f, -1e30f}, {-1e30f, -1e30f}};
#pragma unroll
        for (int mf = 0; mf < 2; mf++)
#pragma unroll
            for (int nf = 0; nf < 8; nf++) {
                rmx[mf][0] = fmaxf(rmx[mf][0], fmaxf(acc[mf][nf][0], acc[mf][nf][1]));
                rmx[mf][1] = fmaxf(rmx[mf][1], fmaxf(acc[mf][nf][2], acc[mf][nf][3]));
            }
#pragma unroll
        for (int mf = 0; mf < 2; mf++)
#pragma unroll
            for (int hf = 0; hf < 2; hf++) {
                rmx[mf][hf] = fmaxf(rmx[mf][hf], __shfl_xor_sync(~0u, rmx[mf][hf], 1));
                rmx[mf][hf] = fmaxf(rmx[mf][hf], __shfl_xor_sync(~0u, rmx[mf][hf], 2));
            }
        if (t4 == 0)
#pragma unroll
            for (int mf = 0; mf < 2; mf++)
#pragma unroll
                for (int hf = 0; hf < 2; hf++)
                    smax[(wm + mf * 16 + hf * 8 + g) * 4 + zn] = rmx[mf][hf];
        __syncthreads();
        float gmx[2][2], rsm[2][2] = {{0, 0}, {0, 0}};
#pragma unroll
        for (int mf = 0; mf < 2; mf++)
#pragma unroll
            for (int hf = 0; hf < 2; hf++) {
                const int r = wm + mf * 16 + hf * 8 + g;
                gmx[mf][hf] = fmaxf(fmaxf(smax[r * 4], smax[r * 4 + 1]),
                                    fmaxf(smax[r * 4 + 2], smax[r * 4 + 3]));
            }
#pragma unroll
        for (int mf = 0; mf < 2; mf++)
#pragma unroll
            for (int nf = 0; nf < 8; nf++)
#pragma unroll
                for (int r = 0; r < 4; r++) {
                    const int hf = r >> 1;
                    const float e = __expf(acc[mf][nf][r] - gmx[mf][hf]);
                    acc[mf][nf][r] = e;
                    rsm[mf][hf] += e;
                }
#pragma unroll
        for (int mf = 0; mf < 2; mf++)
#pragma unroll
            for (int hf = 0; hf < 2; hf++) {
                rsm[mf][hf] += __shfl_xor_sync(~0u, rsm[mf][hf], 1);
                rsm[mf][hf] += __shfl_xor_sync(~0u, rsm[mf][hf], 2);
            }
        if (t4 == 0)
#pragma unroll
            for (int mf = 0; mf < 2; mf++)
#pragma unroll
                for (int hf = 0; hf < 2; hf++)
                    ssum[(wm + mf * 16 + hf * 8 + g) * 4 + zn] = rsm[mf][hf];
        __syncthreads();
#pragma unroll
        for (int mf = 0; mf < 2; mf++)
#pragma unroll
            for (int hf = 0; hf < 2; hf++) {
                const int r = wm + mf * 16 + hf * 8 + g;
                const float inv = 1.0f / (ssum[r * 4] + ssum[r * 4 + 1] + ssum[r * 4 + 2] + ssum[r * 4 + 3]);
#pragma unroll
                for (int nf = 0; nf < 8; nf++) {
                    acc[mf][nf][hf * 2]     *= inv;
                    acc[mf][nf][hf * 2 + 1] *= inv;
                }
            }

        float acc2[2][8][4];
#pragma unroll
        for (int i = 0; i < 2; i++)
#pragma unroll
            for (int j = 0; j < 8; j++)
#pragma unroll
                for (int r = 0; r < 4; r++) acc2[i][j][r] = 0.0f;

#pragma unroll
        for (int kf = 0; kf < 4; kf++) {
            uint32_t pah[2][4], pal[2][4];
#pragma unroll
            for (int mf = 0; mf < 2; mf++) {
                bsplit2(acc[mf][2*kf][0],   acc[mf][2*kf][1],   pah[mf][0], pal[mf][0]);
                bsplit2(acc[mf][2*kf][2],   acc[mf][2*kf][3],   pah[mf][1], pal[mf][1]);
                bsplit2(acc[mf][2*kf+1][0], acc[mf][2*kf+1][1], pah[mf][2], pal[mf][2]);
                bsplit2(acc[mf][2*kf+1][2], acc[mf][2*kf+1][3], pah[mf][3], pal[mf][3]);
            }
#pragma unroll
            for (int df = 0; df < 4; df++) {
                uint32_t bhr[4], blr[4];
                const uint32_t bo = (uint32_t)(zn * 8192) +
                    SWZ((uint32_t)((df * 16 + b_row) * 128 + (kf * 16 + b_col) * 2));
                ldsm4(bhr, sb + A_VH + bo);
                ldsm4(blr, sb + A_VL + bo);
#pragma unroll
                for (int mf = 0; mf < 2; mf++)
#pragma unroll
                    for (int s = 0; s < 2; s++) {
                        float* c = acc2[mf][df * 2 + s];
                        mma_bf16(c, pah[mf], bhr[s * 2], bhr[s * 2 + 1]);
                        mma_bf16(c, pal[mf], bhr[s * 2], bhr[s * 2 + 1]);
                        mma_bf16(c, pah[mf], blr[s * 2], blr[s * 2 + 1]);
                    }
            }
        }

        float* zone = (float*)(sm_raw + A_ZN) + zn * (64 * 66);
#pragma unroll
        for (int mf = 0; mf < 2; mf++)
#pragma unroll
            for (int nf = 0; nf < 8; nf++)
#pragma unroll
                for (int hf = 0; hf < 2; hf++) {
                    const int row = wm + mf * 16 + hf * 8 + g;
                    const int dc = nf * 8 + t4 * 2;
                    *(float2*)&zone[row * 66 + dc] =
                        make_float2(acc2[mf][nf][hf * 2], acc2[mf][nf][hf * 2 + 1]);
                }
        __syncthreads();

        const int tx = tid & 15, ty = tid >> 4;
        float* z0 = (float*)(sm_raw + A_ZN);
        const size_t base = (size_t)b * (N1_ * C_) + (size_t)h * N1_ + q0 + tx * 4;
#pragma unroll
        for (int j = 0; j < 4; j++) {
            const int d = ty * 4 + j;
            float o[4];
#pragma unroll
            for (int qq = 0; qq < 4; qq++) {
                const int idx = (tx * 4 + qq) * 66 + d;
                o[qq] = z0[idx] + z0[64*66 + idx] + z0[2*64*66 + idx] + z0[3*64*66 + idx];
            }
            *(float4*)&xa[base + (size_t)d * (H_ * N1_)] = make_float4(o[0], o[1], o[2], o[3]);
        }
        __syncthreads();   // protect Q/stat/zone before next q-block overwrites
    }
}

// ---- L2 norm with bf16-split residual input; writes xn fp32 + xnh (hi only) ----
__global__ __launch_bounds__(256)
void l2nq_k(const float* __restrict__ a, const u16* __restrict__ qh,
            const u16* __restrict__ ql, float* __restrict__ out,
            u16* __restrict__ oh)
{
    const int row = blockIdx.x * 8 + (threadIdx.x >> 5);
    const int lane = threadIdx.x & 31;
    const float4* pa = (const float4*)(a + (size_t)row * C_);
    float4 v[4];
    float ss = 0.0f;
#pragma unroll
    for (int i = 0; i < 4; i++) {
        float4 t = pa[lane + 32 * i];
        const size_t off = (size_t)row * C_ + (lane + 32 * i) * 4;
        const uint2 hq = *(const uint2*)(qh + off);
        const uint2 lq = *(const uint2*)(ql + off);
        t.x += __uint_as_float(hq.x << 16)          + __uint_as_float(lq.x << 16);
        t.y += __uint_as_float(hq.x & 0xffff0000u)  + __uint_as_float(lq.x & 0xffff0000u);
        t.z += __uint_as_float(hq.y << 16)          + __uint_as_float(lq.y << 16);
        t.w += __uint_as_float(hq.y & 0xffff0000u)  + __uint_as_float(lq.y & 0xffff0000u);
        v[i] = t;
        ss += t.x * t.x + t.y * t.y + t.z * t.z + t.w * t.w;
    }
#pragma unroll
    for (int o = 16; o > 0; o >>= 1) ss += __shfl_xor_sync(~0u, ss, o);
    const float inv = 1.0f / fmaxf(sqrtf(ss), 1e-12f);
    float4* po = (float4*)(out + (size_t)row * C_);
#pragma unroll
    for (int i = 0; i < 4; i++) {
        v[i].x *= inv; v[i].y *= inv; v[i].z *= inv; v[i].w *= inv;
        po[lane + 32 * i] = v[i];
        uint32_t a0, b0, c0, d0;
        bsplit2(v[i].x, v[i].y, a0, c0); bsplit2(v[i].z, v[i].w, b0, d0);
        const size_t off = (size_t)row * C_ + (lane + 32 * i) * 4;
        *(uint2*)(oh + off) = make_uint2(a0, b0);
    }
}

__global__ __launch_bounds__(256)
void l2n_k(const float* __restrict__ a, float* __restrict__ out)
{
    const int row = blockIdx.x * 8 + (threadIdx.x >> 5);
    const int lane = threadIdx.x & 31;
    const float4* pa = (const float4*)(a + (size_t)row * C_);
    float4 v[4];
    float ss = 0.0f;
#pragma unroll
    for (int i = 0; i < 4; i++) {
        float4 t = pa[lane + 32 * i];
        v[i] = t;
        ss += t.x * t.x + t.y * t.y + t.z * t.z + t.w * t.w;
    }
#pragma unroll
    for (int o = 16; o > 0; o >>= 1) ss += __shfl_xor_sync(~0u, ss, o);
    const float inv = 1.0f / fmaxf(sqrtf(ss), 1e-12f);
    float4* po = (float4*)(out + (size_t)row * C_);
#pragma unroll
    for (int i = 0; i < 4; i++) {
        v[i].x *= inv; v[i].y *= inv; v[i].z *= inv; v[i].w *= inv;
        po[lane + 32 * i] = v[i];
    }
}

extern "C" void kernel_launch(void* const* d_in, const int* in_sizes, int n_in,
                              void* d_out, int out_size)
{
    const float* x1    = (const float*)d_in[0];
    const float* x2    = (const float*)d_in[1];
    const float* Wq    = (const float*)d_in[2];
    const float* bq    = (const float*)d_in[3];
    const float* Wkv   = (const float*)d_in[4];
    const float* bkv   = (const float*)d_in[5];
    const float* Wp    = (const float*)d_in[6];
    const float* bp    = (const float*)d_in[7];
    const float* pos_q = (const float*)d_in[8];
    const float* pos_k = (const float*)d_in[9];
    const float* temp  = (const float*)d_in[10];
    const float* W1    = (const float*)d_in[11];
    const float* b1    = (const float*)d_in[12];
    const float* W2    = (const float*)d_in[13];
    const float* b2    = (const float*)d_in[14];

    float *xa, *xn;
    u16 *qh, *ql, *x1h, *x1l, *x2h, *x2l, *xnh, *hh;
    u16 *wqh, *wql, *wkvh, *wkvl, *w1h, *w2h, *w2l, *wpth, *wptl;
    cudaGetSymbolAddress((void**)&xa, g_xa);
    cudaGetSymbolAddress((void**)&xn, g_xn);
    cudaGetSymbolAddress((void**)&qh, g_qh);   cudaGetSymbolAddress((void**)&ql, g_ql);
    cudaGetSymbolAddress((void**)&x1h, g_x1h); cudaGetSymbolAddress((void**)&x1l, g_x1l);
    cudaGetSymbolAddress((void**)&x2h, g_x2h); cudaGetSymbolAddress((void**)&x2l, g_x2l);
    cudaGetSymbolAddress((void**)&xnh, g_xnh);
    cudaGetSymbolAddress((void**)&hh, g_hh);
    cudaGetSymbolAddress((void**)&wqh, g_wq_hi);   cudaGetSymbolAddress((void**)&wql, g_wq_lo);
    cudaGetSymbolAddress((void**)&wkvh, g_wkv_hi); cudaGetSymbolAddress((void**)&wkvl, g_wkv_lo);
    cudaGetSymbolAddress((void**)&w1h, g_w1_hi);
    cudaGetSymbolAddress((void**)&w2h, g_w2_hi);   cudaGetSymbolAddress((void**)&w2l, g_w2_lo);
    cudaGetSymbolAddress((void**)&wpth, g_wpth);   cudaGetSymbolAddress((void**)&wptl, g_wptl);

    cudaFuncSetAttribute(attn_mma, cudaFuncAttributeMaxDynamicSharedMemorySize, ATT_SMEM);
    cudaFuncSetAttribute(kvp_mma,  cudaFuncAttributeMaxDynamicSharedMemorySize, KVP_SMEM);
    cudaFuncSetAttribute((const void*)tgemm<0,3>, cudaFuncAttributeMaxDynamicSharedMemorySize, TG_SMEM_OF(3));
    cudaFuncSetAttribute((const void*)tgemm<1,3>, cudaFuncAttributeMaxDynamicSharedMemorySize, TG_SMEM_OF(3));
    cudaFuncSetAttribute((const void*)tgemm<2,0>, cudaFuncAttributeMaxDynamicSharedMemorySize, TG_SMEM_OF(0));
    cudaFuncSetAttribute((const void*)tgemm<3,1>, cudaFuncAttributeMaxDynamicSharedMemorySize, TG_SMEM_OF(1));

    cudaStream_t s2;
    cudaStreamCreateWithFlags(&s2, cudaStreamNonBlocking);
    cudaEvent_t eF, eKV, eJ, eW;
    cudaEventCreateWithFlags(&eF,  cudaEventDisableTiming);
    cudaEventCreateWithFlags(&eKV, cudaEventDisableTiming);
    cudaEventCreateWithFlags(&eJ,  cudaEventDisableTiming);
    cudaEventCreateWithFlags(&eW,  cudaEventDisableTiming);

    cudaEventRecord(eF, 0);
    cudaStreamWaitEvent(s2, eF, 0);

    // s2: Q-chain prep
    wsplit_k<<<dim3(C_ / 32, C_ / 32), 256, 0, s2>>>(Wq, wqh, wql, C_, C_);
    asplit_k<<<(M_ * C_) / 1024, 256, 0, s2>>>(x1, x1h, x1l);

    // legacy: KV chain
    wsplit_k<<<dim3(2 * C_ / 32, C_ / 32), 256>>>(Wkv, wkvh, wkvl, C_, 2 * C_);
    wsplit_k<<<dim3(P_ / 32, N2_ / 32), 256>>>(Wp, wpth, wptl, N2_, P_);
    asplit_k<<<(M_ * C_) / 1024, 256>>>(x2, x2h, x2l);
    tgemm<1,3><<<dim3(2 * C_ / 128, M_ / 128), 256, TG_SMEM_OF(3)>>>(
        x2h, x2l, wkvh, wkvl, bkv, pos_k, nullptr, nullptr, M_, 2 * C_, C_);
    cudaEventRecord(eKV, 0);

    // s2: tgemm<0> + W1/W2 splits fill kvp's idle SMs
    cudaStreamWaitEvent(s2, eKV, 0);
    tgemm<0,3><<<dim3(C_ / 128, M_ / 128), 256, TG_SMEM_OF(3), s2>>>(
        x1h, x1l, wqh, wql, bq, pos_q, nullptr, nullptr, M_, C_, C_);
    cudaEventRecord(eJ, s2);
    wsplit_k<<<dim3(MLP_ / 32, C_ / 32), 256, 0, s2>>>(W1, w1h, nullptr, C_, MLP_);
    wsplit_k<<<dim3(C_ / 32, MLP_ / 32), 256, 0, s2>>>(W2, w2h, w2l, MLP_, C_);
    cudaEventRecord(eW, s2);

    // legacy: kvp co-runs with s2
    kvp_mma<<<dim3(B_ * H_, 2), 256, KVP_SMEM>>>(bp);

    cudaStreamWaitEvent(0, eJ, 0);
    attn_mma<<<dim3(B_ * H_, N1_ / 128), 256, ATT_SMEM>>>(temp, xa);
    l2nq_k<<<M_ / 8, 256>>>(xa, qh, ql, xn, xnh);
    cudaStreamWaitEvent(0, eW, 0);
    // MLP1: pure hi*hi (1-term), 2 CTAs/SM
    tgemm<2,0><<<dim3(MLP_ / 128, M_ / 128), 256, TG_SMEM_OF(0)>>>(
        xnh, nullptr, w1h, nullptr, b1, nullptr, hh, nullptr, M_, MLP_, C_);
    // MLP2: 2-term (A = h-hi; B = W2 hi+lo)
    tgemm<3,1><<<dim3(C_ / 128, M_ / 128), 256, TG_SMEM_OF(1)>>>(
        hh, nullptr, w2h, w2l, b2, xn, xa, nullptr, M_, C_, MLP_);
    l2n_k<<<M_ / 8, 256>>>(xa, (float*)d_out);
}

// round 17
// speedup vs baseline: 3.1310x; 1.0348x over previous
#include <cuda_runtime.h>
#include <math.h>
#include <stdint.h>

#define B_   8
#define N1_  4096
#define N2_  4096
#define C_   512
#define P_   256
#define H_   8
#define HD_  64
#define MLP_ 2048
#define M_   (B_*N1_)

typedef unsigned short u16;

__device__ float g_xa[M_*C_];
__device__ float g_xn[M_*C_];
__device__ u16 g_qh [M_*C_],  g_ql [M_*C_];
__device__ u16 g_x1h[M_*C_],  g_x1l[M_*C_];
__device__ u16 g_x2h[M_*C_],  g_x2l[M_*C_];
__device__ u16 g_xnh[M_*C_];
__device__ u16 g_hh [M_*MLP_];
__device__ u16 g_kTh[B_*C_*N2_], g_kTl[B_*C_*N2_];
__device__ u16 g_vTh[B_*C_*N2_], g_vTl[B_*C_*N2_];
__device__ u16 g_kpth[B_*H_*P_*HD_], g_kptl[B_*H_*P_*HD_];
__device__ u16 g_vph [B_*H_*HD_*P_], g_vpl [B_*H_*HD_*P_];
__device__ u16 g_wq_hi [C_*C_],   g_wq_lo [C_*C_];
__device__ u16 g_wkv_hi[2*C_*C_], g_wkv_lo[2*C_*C_];
__device__ u16 g_w1_hi [MLP_*C_];
__device__ u16 g_w2_hi [C_*MLP_], g_w2_lo [C_*MLP_];
__device__ u16 g_wpth  [P_*N2_],  g_wptl  [P_*N2_];

__device__ __forceinline__ uint32_t smem_u32(const void* p) {
    uint32_t a;
    asm("{ .reg .u64 t; cvta.to.shared.u64 t, %1; cvt.u32.u64 %0, t; }" : "=r"(a) : "l"(p));
    return a;
}
#define SWZ(b) ((b) ^ (((b) >> 3) & 0x70))
#define CPA16(dst, src) asm volatile("cp.async.cg.shared.global [%0], [%1], 16;" :: "r"(dst), "l"(src))
#define CPA_COMMIT() asm volatile("cp.async.commit_group;" ::: "memory")
#define CPA_WAIT1()  asm volatile("cp.async.wait_group 1;" ::: "memory")
#define CPA_WAIT0()  asm volatile("cp.async.wait_group 0;" ::: "memory")

__device__ __forceinline__ void ldsm4(uint32_t* r, uint32_t a) {
    asm volatile("ldmatrix.sync.aligned.m8n8.x4.shared.b16 {%0,%1,%2,%3}, [%4];"
                 : "=r"(r[0]), "=r"(r[1]), "=r"(r[2]), "=r"(r[3]) : "r"(a));
}
__device__ __forceinline__ void mma_bf16(float* c, const uint32_t* a, uint32_t b0, uint32_t b1) {
    asm volatile("mma.sync.aligned.m16n8k16.row.col.f32.bf16.bf16.f32 "
        "{%0,%1,%2,%3}, {%4,%5,%6,%7}, {%8,%9}, {%0,%1,%2,%3};"
        : "+f"(c[0]), "+f"(c[1]), "+f"(c[2]), "+f"(c[3])
        : "r"(a[0]), "r"(a[1]), "r"(a[2]), "r"(a[3]), "r"(b0), "r"(b1));
}
__device__ __forceinline__ void bsplit(float a, uint32_t& hi, uint32_t& lo) {
    uint32_t u = __float_as_uint(a);
    uint32_t hr = (u + 0x7fffu + ((u >> 16) & 1u)) & 0xffff0000u;
    hi = hr >> 16;
    float l = a - __uint_as_float(hr);
    uint32_t ul = __float_as_uint(l);
    lo = (ul + 0x7fffu + ((ul >> 16) & 1u)) >> 16;
}
__device__ __forceinline__ void bsplit2(float a, float b, uint32_t& hi, uint32_t& lo) {
    uint32_t h0, l0, h1, l1;
    bsplit(a, h0, l0); bsplit(b, h1, l1);
    hi = h0 | (h1 << 16); lo = l0 | (l1 << 16);
}

__global__ __launch_bounds__(256)
void wsplit_k(const float* __restrict__ W, u16* __restrict__ hi, u16* __restrict__ lo, int K, int N)
{
    __shared__ float tile[32][33];
    const int n0 = blockIdx.x * 32, k0 = blockIdx.y * 32;
    const int tx = threadIdx.x & 31, ty = threadIdx.x >> 5;
#pragma unroll
    for (int r = 0; r < 4; r++)
        tile[ty + 8 * r][tx] = W[(size_t)(k0 + ty + 8 * r) * N + n0 + tx];
    __syncthreads();
#pragma unroll
    for (int r = 0; r < 4; r++) {
        const int n = n0 + ty + 8 * r, k = k0 + tx;
        uint32_t h, l;
        bsplit(tile[tx][ty + 8 * r], h, l);
        hi[(size_t)n * K + k] = (u16)h;
        if (lo) lo[(size_t)n * K + k] = (u16)l;
    }
}

__global__ __launch_bounds__(256)
void asplit_k(const float* __restrict__ A, u16* __restrict__ hi, u16* __restrict__ lo)
{
    const size_t i4 = ((size_t)blockIdx.x * 256 + threadIdx.x) * 4;
    float4 f = *(const float4*)(A + i4);
    uint32_t a, b, c, d;
    bsplit2(f.x, f.y, a, c); bsplit2(f.z, f.w, b, d);
    *(uint2*)(hi + i4) = make_uint2(a, b);
    *(uint2*)(lo + i4) = make_uint2(c, d);
}

// ---- bf16 HMMA GEMM, 128x128 tile, packed smem per NT ----
// NT 3: Ah*Bh + Al*Bh + Ah*Bl | NT 2: drop B-lo | NT 1: drop A-lo | NT 0: hi only
// NT 3/2/0: 3-stage pipeline.  NT 1: 2-stage (compute-then-load) -> 2 CTAs/SM.
#define TG_NBUF(NT) (2 + (((NT)==3||(NT)==2)?1:0) + (((NT)==3||(NT)==1)?1:0))
#define TG_NSTG(NT) (((NT)==1) ? 2 : 3)
#define TG_SMEM_OF(NT) (TG_NSTG(NT) * TG_NBUF(NT) * 16384)
template<int EPI, int NT>
__global__ __launch_bounds__(256, (NT == 0 || NT == 1) ? 2 : 1)
void tgemm(const u16* __restrict__ Ahi, const u16* __restrict__ Alo,
           const u16* __restrict__ Bhi, const u16* __restrict__ Blo,
           const float* __restrict__ bias, const float* __restrict__ extra,
           void* __restrict__ out, void* __restrict__ out2, int M, int N, int K)
{
    constexpr bool UA = (NT == 3 || NT == 2);
    constexpr bool UB = (NT == 3 || NT == 1);
    constexpr int  NS = TG_NSTG(NT);
    constexpr uint32_t OAL = 16384;
    constexpr uint32_t OBH = (UA ? 2u : 1u) * 16384u;
    constexpr uint32_t OBL = OBH + 16384u;
    constexpr uint32_t STG = (uint32_t)TG_NBUF(NT) * 16384u;
    extern __shared__ __align__(1024) char sm_raw[];
    const uint32_t sb = smem_u32(sm_raw);
    const int tid = threadIdx.x, wid = tid >> 5, lane = tid & 31;
    const int bm = blockIdx.y * 128, bn = blockIdx.x * 128;
    const int wm = (wid & 1) * 64, wn = (wid >> 1) * 32;
    const int nck = K >> 6;

    float acc[4][4][4];
#pragma unroll
    for (int i = 0; i < 4; i++)
#pragma unroll
        for (int j = 0; j < 4; j++)
#pragma unroll
            for (int r = 0; r < 4; r++) acc[i][j][r] = 0.0f;

    const int a_row = ((lane >> 3) & 1) * 8 + (lane & 7);
    const int a_col = (lane >> 4) * 8;
    const int b_row = (lane >> 4) * 8 + (lane & 7);
    const int b_col = ((lane >> 3) & 1) * 8;

    auto load_stage = [&](int ck, int stage) {
        if (ck < nck) {
            const int k0 = ck * 64;
            const uint32_t sbase = sb + stage * STG;
#pragma unroll
            for (int i = 0; i < 4; i++) {
                const int id = tid + i * 256;
                const int row = id >> 3, c16 = id & 7;
                const uint32_t dsw = SWZ((uint32_t)(row * 128 + c16 * 16));
                const size_t asrc = (size_t)(bm + row) * K + k0 + c16 * 8;
                const size_t bsrc = (size_t)(bn + row) * K + k0 + c16 * 8;
                CPA16(sbase + dsw, Ahi + asrc);
                if (UA) CPA16(sbase + OAL + dsw, Alo + asrc);
                CPA16(sbase + OBH + dsw, Bhi + bsrc);
                if (UB) CPA16(sbase + OBL + dsw, Blo + bsrc);
            }
        }
        CPA_COMMIT();
    };

    auto compute_chunk = [&](uint32_t base) {
#pragma unroll
        for (int ks = 0; ks < 4; ks++) {
            const int kk = ks * 16;
            uint32_t ah[4][4], al[4][4], bh[2][4], bl[2][4];
#pragma unroll
            for (int mf = 0; mf < 4; mf++) {
                const uint32_t ao = SWZ((uint32_t)((wm + mf * 16 + a_row) * 128 + (kk + a_col) * 2));
                ldsm4(ah[mf], base + ao);
                if (UA) ldsm4(al[mf], base + OAL + ao);
            }
#pragma unroll
            for (int p = 0; p < 2; p++) {
                const uint32_t bo = SWZ((uint32_t)((wn + p * 16 + b_row) * 128 + (kk + b_col) * 2));
                ldsm4(bh[p], base + OBH + bo);
                if (UB) ldsm4(bl[p], base + OBL + bo);
            }
#pragma unroll
            for (int mf = 0; mf < 4; mf++)
#pragma unroll
                for (int p = 0; p < 2; p++)
#pragma unroll
                    for (int s = 0; s < 2; s++) {
                        float* c = acc[mf][p * 2 + s];
                        mma_bf16(c, ah[mf], bh[p][s * 2], bh[p][s * 2 + 1]);
                        if (UA) mma_bf16(c, al[mf], bh[p][s * 2], bh[p][s * 2 + 1]);
                        if (UB) mma_bf16(c, ah[mf], bl[p][s * 2], bl[p][s * 2 + 1]);
                    }
        }
    };

    load_stage(0, 0);
    load_stage(1, 1);

    if (NS == 3) {
        for (int ck = 0; ck < nck; ck++) {
            CPA_WAIT1();
            __syncthreads();
            load_stage(ck + 2, (ck + 2) % 3);
            compute_chunk(sb + (ck % 3) * STG);
        }
    } else {
        for (int ck = 0; ck < nck; ck++) {
            CPA_WAIT1();
            __syncthreads();
            compute_chunk(sb + (ck & 1) * STG);
            __syncthreads();
            load_stage(ck + 2, (ck & 1));
        }
    }

    const int l4 = lane >> 2, l2 = (lane & 3) * 2;

    if (EPI == 1) {
        CPA_WAIT0();
        __syncthreads();
        float* T = (float*)sm_raw;                       // 128 x 132 floats
        const bool is_k = (bn < C_);
#pragma unroll
        for (int mf = 0; mf < 4; mf++)
#pragma unroll
            for (int nf = 0; nf < 4; nf++) {
                const int colL = wn + nf * 8 + l2;
                const int col = bn + colL;
                const float bia0 = bias[col], bia1 = bias[col + 1];
#pragma unroll
                for (int half = 0; half < 2; half++) {
                    const int mL = wm + mf * 16 + l4 + half * 8;
                    float v0 = acc[mf][nf][half * 2]     + bia0;
                    float v1 = acc[mf][nf][half * 2 + 1] + bia1;
                    if (is_k) {
                        const int n = (bm + mL) & (N2_ - 1);
                        v0 += extra[(size_t)n * C_ + col];
                        v1 += extra[(size_t)n * C_ + col + 1];
                    }
                    T[colL * 132 + mL]       = v0;
                    T[(colL + 1) * 132 + mL] = v1;
                }
            }
        __syncthreads();
        u16* __restrict__ dh = is_k ? g_kTh : g_vTh;
        u16* __restrict__ dl = is_k ? g_kTl : g_vTl;
        const int bb = bm >> 12, n0 = bm & (N2_ - 1);
        const int r = tid >> 1, hh2 = (tid & 1) * 64;
        const int c = (bn + r) - (is_k ? 0 : C_);
        const size_t gbase = ((size_t)bb * C_ + c) * N2_ + n0 + hh2;
        const float* Tr = T + r * 132 + hh2;
#pragma unroll
        for (int j = 0; j < 64; j += 8) {
            uint32_t h0, l0, h1, l1, h2, l2x, h3, l3;
            bsplit2(Tr[j],     Tr[j + 1], h0, l0);
            bsplit2(Tr[j + 2], Tr[j + 3], h1, l1);
            bsplit2(Tr[j + 4], Tr[j + 5], h2, l2x);
            bsplit2(Tr[j + 6], Tr[j + 7], h3, l3);
            *(uint4*)(dh + gbase + j) = make_uint4(h0, h1, h2, h3);
            *(uint4*)(dl + gbase + j) = make_uint4(l0, l1, l2x, l3);
        }
        return;
    }

#pragma unroll
    for (int mf = 0; mf < 4; mf++)
#pragma unroll
        for (int nf = 0; nf < 4; nf++) {
            const int col = bn + wn + nf * 8 + l2;
            const float bia0 = bias[col], bia1 = bias[col + 1];
#pragma unroll
            for (int half = 0; half < 2; half++) {
                const int m = bm + wm + mf * 16 + l4 + half * 8;
                float v0 = acc[mf][nf][half * 2]     + bia0;
                float v1 = acc[mf][nf][half * 2 + 1] + bia1;
                if (EPI == 0) {
                    v0 += extra[(size_t)(m & (N1_ - 1)) * C_ + col];
                    v1 += extra[(size_t)(m & (N1_ - 1)) * C_ + col + 1];
                    uint32_t hi, lo;
                    bsplit2(v0, v1, hi, lo);
                    *(uint32_t*)(g_qh + (size_t)m * N + col) = hi;
                    *(uint32_t*)(g_ql + (size_t)m * N + col) = lo;
                } else if (EPI == 2) {
                    v0 = 0.5f * v0 * (1.0f + erff(v0 * 0.70710678118654752f));
                    v1 = 0.5f * v1 * (1.0f + erff(v1 * 0.70710678118654752f));
                    uint32_t hi, lo;
                    bsplit2(v0, v1, hi, lo);
                    *(uint32_t*)((u16*)out + (size_t)m * N + col) = hi;
                } else {
                    v0 += extra[(size_t)m * N + col];
                    v1 += extra[(size_t)m * N + col + 1];
                    *(float2*)((float*)out + (size_t)m * N + col) = make_float2(v0, v1);
                }
            }
        }
}

// ---- kvp via bf16x3 HMMA ----
#define KVP_STG  81920
#define KVP_SMEM (2 * KVP_STG)
__global__ __launch_bounds__(256, 1)
void kvp_mma(const float* __restrict__ bp)
{
    extern __shared__ __align__(1024) char sm_raw[];
    const uint32_t sb = smem_u32(sm_raw);
    const int tid = threadIdx.x, wid = tid >> 5, lane = tid & 31;
    const int g = lane >> 2, t4 = lane & 3;
    const int bh = blockIdx.x, b = bh >> 3, h = bh & 7;
    const int mode = blockIdx.y;
    const u16* __restrict__ Dh = mode ? g_vTh : g_kTh;
    const u16* __restrict__ Dl = mode ? g_vTl : g_kTl;

    const int a_row = ((lane >> 3) & 1) * 8 + (lane & 7);
    const int a_col = (lane >> 4) * 8;
    const int b_row = (lane >> 4) * 8 + (lane & 7);
    const int b_col = ((lane >> 3) & 1) * 8;

    auto load_stage = [&](int ck) {
        if (ck < 64) {
            const uint32_t base = sb + (ck & 1) * KVP_STG;
            const int k0 = ck * 64;
#pragma unroll
            for (int t = 0; t < 8; t++) {
                const int i = tid + t * 256;
                const int row = i >> 3, c16 = i & 7;
                const uint32_t dsw = SWZ((uint32_t)(row * 128 + c16 * 16));
                const size_t src = (size_t)row * N2_ + k0 + c16 * 8;
                CPA16(base + dsw,         g_wpth + src);
                CPA16(base + 32768 + dsw, g_wptl + src);
            }
#pragma unroll
            for (int t = 0; t < 2; t++) {
                const int i = tid + t * 256;
                const int row = i >> 3, c16 = i & 7;
                const uint32_t dsw = SWZ((uint32_t)(row * 128 + c16 * 16));
                const size_t src = ((size_t)b * C_ + h * 64 + row) * N2_ + k0 + c16 * 8;
                CPA16(base + 65536 + dsw, Dh + src);
                CPA16(base + 73728 + dsw, Dl + src);
            }
        }
        CPA_COMMIT();
    };

    load_stage(0);
    load_stage(1);

    if (mode == 0) {
        const int wm = (wid & 3) * 64, wn = (wid >> 2) * 32;
        float acc[4][4][4];
#pragma unroll
        for (int i = 0; i < 4; i++)
#pragma unroll
            for (int j = 0; j < 4; j++)
#pragma unroll
                for (int r = 0; r < 4; r++) acc[i][j][r] = 0.0f;

        for (int ck = 0; ck < 64; ck++) {
            CPA_WAIT1();
            __syncthreads();
            const uint32_t base = sb + (ck & 1) * KVP_STG;
#pragma unroll
            for (int ks = 0; ks < 4; ks++) {
                const int kk = ks * 16;
                uint32_t ah[4][4], al[4][4], bhr[2][4], blr[2][4];
#pragma unroll
                for (int mf = 0; mf < 4; mf++) {
                    const uint32_t ao = SWZ((uint32_t)((wm + mf * 16 + a_row) * 128 + (kk + a_col) * 2));
                    ldsm4(ah[mf], base + ao);
                    ldsm4(al[mf], base + 32768 + ao);
                }
#pragma unroll
                for (int p = 0; p < 2; p++) {
                    const uint32_t bo = SWZ((uint32_t)((wn + p * 16 + b_row) * 128 + (kk + b_col) * 2));
                    ldsm4(bhr[p], base + 65536 + bo);
                    ldsm4(blr[p], base + 73728 + bo);
                }
#pragma unroll
                for (int mf = 0; mf < 4; mf++)
#pragma unroll
                    for (int p = 0; p < 2; p++)
#pragma unroll
                        for (int s = 0; s < 2; s++) {
                            float* c = acc[mf][p * 2 + s];
                            mma_bf16(c, ah[mf], bhr[p][s * 2], bhr[p][s * 2 + 1]);
                            mma_bf16(c, al[mf], bhr[p][s * 2], bhr[p][s * 2 + 1]);
                            mma_bf16(c, ah[mf], blr[p][s * 2], blr[p][s * 2 + 1]);
                        }
            }
            __syncthreads();
            load_stage(ck + 2);
        }
#pragma unroll
        for (int mf = 0; mf < 4; mf++)
#pragma unroll
            for (int hf = 0; hf < 2; hf++) {
                const int p = wm + mf * 16 + hf * 8 + g;
                const float bv = bp[p];
#pragma unroll
                for (int nf = 0; nf < 4; nf++) {
                    const int d = wn + nf * 8 + t4 * 2;
                    uint32_t hi, lo;
                    bsplit2(acc[mf][nf][hf * 2] + bv, acc[mf][nf][hf * 2 + 1] + bv, hi, lo);
                    *(uint32_t*)(g_kpth + (size_t)bh * (P_ * HD_) + p * 64 + d) = hi;
                    *(uint32_t*)(g_kptl + (size_t)bh * (P_ * HD_) + p * 64 + d) = lo;
                }
            }
    } else {
        const int wm = (wid & 1) * 32, wn = (wid >> 1) * 64;
        float acc[2][8][4];
#pragma unroll
        for (int i = 0; i < 2; i++)
#pragma unroll
            for (int j = 0; j < 8; j++)
#pragma unroll
                for (int r = 0; r < 4; r++) acc[i][j][r] = 0.0f;

        for (int ck = 0; ck < 64; ck++) {
            CPA_WAIT1();
            __syncthreads();
            const uint32_t base = sb + (ck & 1) * KVP_STG;
#pragma unroll
            for (int ks = 0; ks < 4; ks++) {
                const int kk = ks * 16;
                uint32_t ah[2][4], al[2][4];
#pragma unroll
                for (int mf = 0; mf < 2; mf++) {
                    const uint32_t ao = SWZ((uint32_t)((wm + mf * 16 + a_row) * 128 + (kk + a_col) * 2));
                    ldsm4(ah[mf], base + 65536 + ao);
                    ldsm4(al[mf], base + 73728 + ao);
                }
#pragma unroll
                for (int p = 0; p < 4; p++) {
                    uint32_t bhr[4], blr[4];
                    const uint32_t bo = SWZ((uint32_t)((wn + p * 16 + b_row) * 128 + (kk + b_col) * 2));
                    ldsm4(bhr, base + bo);
                    ldsm4(blr, base + 32768 + bo);
#pragma unroll
                    for (int mf = 0; mf < 2; mf++)
#pragma unroll
                        for (int s = 0; s < 2; s++) {
                            float* c = acc[mf][p * 2 + s];
                            mma_bf16(c, ah[mf], bhr[s * 2], bhr[s * 2 + 1]);
                            mma_bf16(c, al[mf], bhr[s * 2], bhr[s * 2 + 1]);
                            mma_bf16(c, ah[mf], blr[s * 2], blr[s * 2 + 1]);
                        }
                }
            }
            __syncthreads();
            load_stage(ck + 2);
        }
#pragma unroll
        for (int mf = 0; mf < 2; mf++)
#pragma unroll
            for (int hf = 0; hf < 2; hf++) {
                const int d = wm + mf * 16 + hf * 8 + g;
#pragma unroll
                for (int nf = 0; nf < 8; nf++) {
                    const int p = wn + nf * 8 + t4 * 2;
                    uint32_t hi, lo;
                    bsplit2(acc[mf][nf][hf * 2] + bp[p], acc[mf][nf][hf * 2 + 1] + bp[p + 1], hi, lo);
                    *(uint32_t*)(g_vph + (size_t)bh * (HD_ * P_) + d * 256 + p) = hi;
                    *(uint32_t*)(g_vpl + (size_t)bh * (HD_ * P_) + d * 256 + p) = lo;
                }
            }
    }
}

// ---- attention via bf16x3 HMMA; 2 q-blocks per CTA (kp/vp loaded once) ----
#define A_QH   0
#define A_QL   8192
#define A_KH   16384
#define A_KL   49152
#define A_VH   81920
#define A_VL   114688
#define A_ST   147456
#define A_ZN   149504
#define ATT_SMEM (149504 + 4*64*66*4)

__global__ __launch_bounds__(256, 1)
void attn_mma(const float* __restrict__ temp, float* __restrict__ xa)
{
    extern __shared__ __align__(1024) char sm_raw[];
    const uint32_t sb = smem_u32(sm_raw);
    const int tid = threadIdx.x, wid = tid >> 5, lane = tid & 31;
    const int g = lane >> 2, t4 = lane & 3;
    const int bh = blockIdx.x, b = bh >> 3, h = bh & 7;
    const int wm = (wid & 1) * 32, zn = wid >> 1, wn = zn * 64;

#pragma unroll
    for (int t = 0; t < 8; t++) {
        const int i = tid + t * 256;
        const int row = i >> 3, c16 = i & 7;
        const uint32_t dsw = SWZ((uint32_t)(row * 128 + c16 * 16));
        const size_t src = (size_t)bh * (P_ * HD_) + row * 64 + c16 * 8;
        CPA16(sb + A_KH + dsw, g_kpth + src);
        CPA16(sb + A_KL + dsw, g_kptl + src);
    }
#pragma unroll
    for (int t = 0; t < 8; t++) {
        const int i = tid + t * 256;
        const int c16 = i & 7, d = (i >> 3) & 63, ch = i >> 9;
        const uint32_t dsw = (uint32_t)(ch * 8192) + SWZ((uint32_t)(d * 128 + c16 * 16));
        const size_t src = (size_t)bh * (HD_ * P_) + d * 256 + ch * 64 + c16 * 8;
        CPA16(sb + A_VH + dsw, g_vph + src);
        CPA16(sb + A_VL + dsw, g_vpl + src);
    }
    CPA_COMMIT();

    const int a_row = ((lane >> 3) & 1) * 8 + (lane & 7);
    const int a_col = (lane >> 4) * 8;
    const int b_row = (lane >> 4) * 8 + (lane & 7);
    const int b_col = ((lane >> 3) & 1) * 8;
    const float tscale = temp[h];
    float* smax = (float*)(sm_raw + A_ST);
    float* ssum = smax + 256;

    for (int qi = 0; qi < 2; qi++) {
        const int q0 = (blockIdx.y * 2 + qi) * 64;
#pragma unroll
        for (int t = 0; t < 2; t++) {
            const int i = tid + t * 256;
            const int row = i >> 3, c16 = i & 7;
            const uint32_t dsw = SWZ((uint32_t)(row * 128 + c16 * 16));
            const size_t src = (size_t)(b * N1_ + q0 + row) * C_ + h * 64 + c16 * 8;
            CPA16(sb + A_QH + dsw, g_qh + src);
            CPA16(sb + A_QL + dsw, g_ql + src);
        }
        CPA_COMMIT();
        CPA_WAIT0();
        __syncthreads();

        float acc[2][8][4];
#pragma unroll
        for (int i = 0; i < 2; i++)
#pragma unroll
            for (int j = 0; j < 8; j++)
#pragma unroll
                for (int r = 0; r < 4; r++) acc[i][j][r] = 0.0f;

#pragma unroll
        for (int ks = 0; ks < 4; ks++) {
            const int kk = ks * 16;
            uint32_t ah[2][4], al[2][4];
#pragma unroll
            for (int mf = 0; mf < 2; mf++) {
                const uint32_t ao = SWZ((uint32_t)((wm + mf * 16 + a_row) * 128 + (kk + a_col) * 2));
                ldsm4(ah[mf], sb + A_QH + ao);
                ldsm4(al[mf], sb + A_QL + ao);
            }
#pragma unroll
            for (int p = 0; p < 4; p++) {
                uint32_t bhr[4], blr[4];
                const uint32_t bo = SWZ((uint32_t)((wn + p * 16 + b_row) * 128 + (kk + b_col) * 2));
                ldsm4(bhr, sb + A_KH + bo);
                ldsm4(blr, sb + A_KL + bo);
#pragma unroll
                for (int mf = 0; mf < 2; mf++)
#pragma unroll
                    for (int s = 0; s < 2; s++) {
                        float* c = acc[mf][p * 2 + s];
                        mma_bf16(c, ah[mf], bhr[s * 2], bhr[s * 2 + 1]);
                        mma_bf16(c, al[mf], bhr[s * 2], bhr[s * 2 + 1]);
                        mma_bf16(c, ah[mf], blr[s * 2], blr[s * 2 + 1]);
                    }
            }
        }

#pragma unroll
        for (int mf = 0; mf < 2; mf++)
#pragma unroll
            for (int nf = 0; nf < 8; nf++)
#pragma unroll
                for (int r = 0; r < 4; r++) acc[mf][nf][r] *= tscale;

        float rmx[2][2] = {{-1e30f, -1e30f}, {-1e30f, -1e30f}};
#pragma unroll
        for (int mf = 0; mf < 2; mf++)
#pragma unroll
            for (int nf = 0; nf < 8; nf++) {
                rmx[mf][0] = fmaxf(rmx[mf][0], fmaxf(acc[mf][nf][0], acc[mf][nf][1]));
                rmx[mf][1] = fmaxf(rmx[mf][1], fmaxf(acc[mf][nf][2], acc[mf][nf][3]));
            }
#pragma unroll
        for (int mf = 0; mf < 2; mf++)
#pragma unroll
            for (int hf = 0; hf < 2; hf++) {
                rmx[mf][hf] = fmaxf(rmx[mf][hf], __shfl_xor_sync(~0u, rmx[mf][hf], 1));
                rmx[mf][hf] = fmaxf(rmx[mf][hf], __shfl_xor_sync(~0u, rmx[mf][hf], 2));
            }
        if (t4 == 0)
#pragma unroll
            for (int mf = 0; mf < 2; mf++)
#pragma unroll
                for (int hf = 0; hf < 2; hf++)
                    smax[(wm + mf * 16 + hf * 8 + g) * 4 + zn] = rmx[mf][hf];
        __syncthreads();
        float gmx[2][2], rsm[2][2] = {{0, 0}, {0, 0}};
#pragma unroll
        for (int mf = 0; mf < 2; mf++)
#pragma unroll
            for (int hf = 0; hf < 2; hf++) {
                const int r = wm + mf * 16 + hf * 8 + g;
                gmx[mf][hf] = fmaxf(fmaxf(smax[r * 4], smax[r * 4 + 1]),
                                    fmaxf(smax[r * 4 + 2], smax[r * 4 + 3]));
            }
#pragma unroll
        for (int mf = 0; mf < 2; mf++)
#pragma unroll
            for (int nf = 0; nf < 8; nf++)
#pragma unroll
                for (int r = 0; r < 4; r++) {
                    const int hf = r >> 1;
                    const float e = __expf(acc[mf][nf][r] - gmx[mf][hf]);
                    acc[mf][nf][r] = e;
                    rsm[mf][hf] += e;
                }
#pragma unroll
        for (int mf = 0; mf < 2; mf++)
#pragma unroll
            for (int hf = 0; hf < 2; hf++) {
                rsm[mf][hf] += __shfl_xor_sync(~0u, rsm[mf][hf], 1);
                rsm[mf][hf] += __shfl_xor_sync(~0u, rsm[mf][hf], 2);
            }
        if (t4 == 0)
#pragma unroll
            for (int mf = 0; mf < 2; mf++)
#pragma unroll
                for (int hf = 0; hf < 2; hf++)
                    ssum[(wm + mf * 16 + hf * 8 + g) * 4 + zn] = rsm[mf][hf];
        __syncthreads();
#pragma unroll
        for (int mf = 0; mf < 2; mf++)
#pragma unroll
            for (int hf = 0; hf < 2; hf++) {
                const int r = wm + mf * 16 + hf * 8 + g;
                const float inv = 1.0f / (ssum[r * 4] + ssum[r * 4 + 1] + ssum[r * 4 + 2] + ssum[r * 4 + 3]);
#pragma unroll
                for (int nf = 0; nf < 8; nf++) {
                    acc[mf][nf][hf * 2]     *= inv;
                    acc[mf][nf][hf * 2 + 1] *= inv;
                }
            }

        float acc2[2][8][4];
#pragma unroll
        for (int i = 0; i < 2; i++)
#pragma unroll
            for (int j = 0; j < 8; j++)
#pragma unroll
                for (int r = 0; r < 4; r++) acc2[i][j][r] = 0.0f;

#pragma unroll
        for (int kf = 0; kf < 4; kf++) {
            uint32_t pah[2][4], pal[2][4];
#pragma unroll
            for (int mf = 0; mf < 2; mf++) {
                bsplit2(acc[mf][2*kf][0],   acc[mf][2*kf][1],   pah[mf][0], pal[mf][0]);
                bsplit2(acc[mf][2*kf][2],   acc[mf][2*kf][3],   pah[mf][1], pal[mf][1]);
                bsplit2(acc[mf][2*kf+1][0], acc[mf][2*kf+1][1], pah[mf][2], pal[mf][2]);
                bsplit2(acc[mf][2*kf+1][2], acc[mf][2*kf+1][3], pah[mf][3], pal[mf][3]);
            }
#pragma unroll
            for (int df = 0; df < 4; df++) {
                uint32_t bhr[4], blr[4];
                const uint32_t bo = (uint32_t)(zn * 8192) +
                    SWZ((uint32_t)((df * 16 + b_row) * 128 + (kf * 16 + b_col) * 2));
                ldsm4(bhr, sb + A_VH + bo);
                ldsm4(blr, sb + A_VL + bo);
#pragma unroll
                for (int mf = 0; mf < 2; mf++)
#pragma unroll
                    for (int s = 0; s < 2; s++) {
                        float* c = acc2[mf][df * 2 + s];
                        mma_bf16(c, pah[mf], bhr[s * 2], bhr[s * 2 + 1]);
                        mma_bf16(c, pal[mf], bhr[s * 2], bhr[s * 2 + 1]);
                        mma_bf16(c, pah[mf], blr[s * 2], blr[s * 2 + 1]);
                    }
            }
        }

        float* zone = (float*)(sm_raw + A_ZN) + zn * (64 * 66);
#pragma unroll
        for (int mf = 0; mf < 2; mf++)
#pragma unroll
            for (int nf = 0; nf < 8; nf++)
#pragma unroll
                for (int hf = 0; hf < 2; hf++) {
                    const int row = wm + mf * 16 + hf * 8 + g;
                    const int dc = nf * 8 + t4 * 2;
                    *(float2*)&zone[row * 66 + dc] =
                        make_float2(acc2[mf][nf][hf * 2], acc2[mf][nf][hf * 2 + 1]);
                }
        __syncthreads();

        const int tx = tid & 15, ty = tid >> 4;
        float* z0 = (float*)(sm_raw + A_ZN);
        const size_t base = (size_t)b * (N1_ * C_) + (size_t)h * N1_ + q0 + tx * 4;
#pragma unroll
        for (int j = 0; j < 4; j++) {
            const int d = ty * 4 + j;
            float o[4];
#pragma unroll
            for (int qq = 0; qq < 4; qq++) {
                const int idx = (tx * 4 + qq) * 66 + d;
                o[qq] = z0[idx] + z0[64*66 + idx] + z0[2*64*66 + idx] + z0[3*64*66 + idx];
            }
            *(float4*)&xa[base + (size_t)d * (H_ * N1_)] = make_float4(o[0], o[1], o[2], o[3]);
        }
        __syncthreads();
    }
}

// ---- L2 norm with bf16-split residual input; writes xn fp32 + xnh (hi only) ----
__global__ __launch_bounds__(256)
void l2nq_k(const float* __restrict__ a, const u16* __restrict__ qh,
            const u16* __restrict__ ql, float* __restrict__ out,
            u16* __restrict__ oh)
{
    const int row = blockIdx.x * 8 + (threadIdx.x >> 5);
    const int lane = threadIdx.x & 31;
    const float4* pa = (const float4*)(a + (size_t)row * C_);
    float4 v[4];
    float ss = 0.0f;
#pragma unroll
    for (int i = 0; i < 4; i++) {
        float4 t = pa[lane + 32 * i];
        const size_t off = (size_t)row * C_ + (lane + 32 * i) * 4;
        const uint2 hq = *(const uint2*)(qh + off);
        const uint2 lq = *(const uint2*)(ql + off);
        t.x += __uint_as_float(hq.x << 16)          + __uint_as_float(lq.x << 16);
        t.y += __uint_as_float(hq.x & 0xffff0000u)  + __uint_as_float(lq.x & 0xffff0000u);
        t.z += __uint_as_float(hq.y << 16)          + __uint_as_float(lq.y << 16);
        t.w += __uint_as_float(hq.y & 0xffff0000u)  + __uint_as_float(lq.y & 0xffff0000u);
        v[i] = t;
        ss += t.x * t.x + t.y * t.y + t.z * t.z + t.w * t.w;
    }
#pragma unroll
    for (int o = 16; o > 0; o >>= 1) ss += __shfl_xor_sync(~0u, ss, o);
    const float inv = 1.0f / fmaxf(sqrtf(ss), 1e-12f);
    float4* po = (float4*)(out + (size_t)row * C_);
#pragma unroll
    for (int i = 0; i < 4; i++) {
        v[i].x *= inv; v[i].y *= inv; v[i].z *= inv; v[i].w *= inv;
        po[lane + 32 * i] = v[i];
        uint32_t a0, b0, c0, d0;
        bsplit2(v[i].x, v[i].y, a0, c0); bsplit2(v[i].z, v[i].w, b0, d0);
        const size_t off = (size_t)row * C_ + (lane + 32 * i) * 4;
        *(uint2*)(oh + off) = make_uint2(a0, b0);
    }
}

__global__ __launch_bounds__(256)
void l2n_k(const float* __restrict__ a, float* __restrict__ out)
{
    const int row = blockIdx.x * 8 + (threadIdx.x >> 5);
    const int lane = threadIdx.x & 31;
    const float4* pa = (const float4*)(a + (size_t)row * C_);
    float4 v[4];
    float ss = 0.0f;
#pragma unroll
    for (int i = 0; i < 4; i++) {
        float4 t = pa[lane + 32 * i];
        v[i] = t;
        ss += t.x * t.x + t.y * t.y + t.z * t.z + t.w * t.w;
    }
#pragma unroll
    for (int o = 16; o > 0; o >>= 1) ss += __shfl_xor_sync(~0u, ss, o);
    const float inv = 1.0f / fmaxf(sqrtf(ss), 1e-12f);
    float4* po = (float4*)(out + (size_t)row * C_);
#pragma unroll
    for (int i = 0; i < 4; i++) {
        v[i].x *= inv; v[i].y *= inv; v[i].z *= inv; v[i].w *= inv;
        po[lane + 32 * i] = v[i];
    }
}

extern "C" void kernel_launch(void* const* d_in, const int* in_sizes, int n_in,
                              void* d_out, int out_size)
{
    const float* x1    = (const float*)d_in[0];
    const float* x2    = (const float*)d_in[1];
    const float* Wq    = (const float*)d_in[2];
    const float* bq    = (const float*)d_in[3];
    const float* Wkv   = (const float*)d_in[4];
    const float* bkv   = (const float*)d_in[5];
    const float* Wp    = (const float*)d_in[6];
    const float* bp    = (const float*)d_in[7];
    const float* pos_q = (const float*)d_in[8];
    const float* pos_k = (const float*)d_in[9];
    const float* temp  = (const float*)d_in[10];
    const float* W1    = (const float*)d_in[11];
    const float* b1    = (const float*)d_in[12];
    const float* W2    = (const float*)d_in[13];
    const float* b2    = (const float*)d_in[14];

    float *xa, *xn;
    u16 *qh, *ql, *x1h, *x1l, *x2h, *x2l, *xnh, *hh;
    u16 *wqh, *wql, *wkvh, *wkvl, *w1h, *w2h, *w2l, *wpth, *wptl;
    cudaGetSymbolAddress((void**)&xa, g_xa);
    cudaGetSymbolAddress((void**)&xn, g_xn);
    cudaGetSymbolAddress((void**)&qh, g_qh);   cudaGetSymbolAddress((void**)&ql, g_ql);
    cudaGetSymbolAddress((void**)&x1h, g_x1h); cudaGetSymbolAddress((void**)&x1l, g_x1l);
    cudaGetSymbolAddress((void**)&x2h, g_x2h); cudaGetSymbolAddress((void**)&x2l, g_x2l);
    cudaGetSymbolAddress((void**)&xnh, g_xnh);
    cudaGetSymbolAddress((void**)&hh, g_hh);
    cudaGetSymbolAddress((void**)&wqh, g_wq_hi);   cudaGetSymbolAddress((void**)&wql, g_wq_lo);
    cudaGetSymbolAddress((void**)&wkvh, g_wkv_hi); cudaGetSymbolAddress((void**)&wkvl, g_wkv_lo);
    cudaGetSymbolAddress((void**)&w1h, g_w1_hi);
    cudaGetSymbolAddress((void**)&w2h, g_w2_hi);   cudaGetSymbolAddress((void**)&w2l, g_w2_lo);
    cudaGetSymbolAddress((void**)&wpth, g_wpth);   cudaGetSymbolAddress((void**)&wptl, g_wptl);

    cudaFuncSetAttribute(attn_mma, cudaFuncAttributeMaxDynamicSharedMemorySize, ATT_SMEM);
    cudaFuncSetAttribute(kvp_mma,  cudaFuncAttributeMaxDynamicSharedMemorySize, KVP_SMEM);
    cudaFuncSetAttribute((const void*)tgemm<0,3>, cudaFuncAttributeMaxDynamicSharedMemorySize, TG_SMEM_OF(3));
    cudaFuncSetAttribute((const void*)tgemm<1,3>, cudaFuncAttributeMaxDynamicSharedMemorySize, TG_SMEM_OF(3));
    cudaFuncSetAttribute((const void*)tgemm<2,0>, cudaFuncAttributeMaxDynamicSharedMemorySize, TG_SMEM_OF(0));
    cudaFuncSetAttribute((const void*)tgemm<3,1>, cudaFuncAttributeMaxDynamicSharedMemorySize, TG_SMEM_OF(1));

    cudaStream_t s2;
    cudaStreamCreateWithFlags(&s2, cudaStreamNonBlocking);
    cudaEvent_t eF, eKV, eJ, eW;
    cudaEventCreateWithFlags(&eF,  cudaEventDisableTiming);
    cudaEventCreateWithFlags(&eKV, cudaEventDisableTiming);
    cudaEventCreateWithFlags(&eJ,  cudaEventDisableTiming);
    cudaEventCreateWithFlags(&eW,  cudaEventDisableTiming);

    cudaEventRecord(eF, 0);
    cudaStreamWaitEvent(s2, eF, 0);

    // s2: Q-chain prep
    wsplit_k<<<dim3(C_ / 32, C_ / 32), 256, 0, s2>>>(Wq, wqh, wql, C_, C_);
    asplit_k<<<(M_ * C_) / 1024, 256, 0, s2>>>(x1, x1h, x1l);

    // legacy: KV chain
    wsplit_k<<<dim3(2 * C_ / 32, C_ / 32), 256>>>(Wkv, wkvh, wkvl, C_, 2 * C_);
    wsplit_k<<<dim3(P_ / 32, N2_ / 32), 256>>>(Wp, wpth, wptl, N2_, P_);
    asplit_k<<<(M_ * C_) / 1024, 256>>>(x2, x2h, x2l);
    tgemm<1,3><<<dim3(2 * C_ / 128, M_ / 128), 256, TG_SMEM_OF(3)>>>(
        x2h, x2l, wkvh, wkvl, bkv, pos_k, nullptr, nullptr, M_, 2 * C_, C_);
    cudaEventRecord(eKV, 0);

    // s2: tgemm<0> + W1/W2 splits fill kvp's idle SMs
    cudaStreamWaitEvent(s2, eKV, 0);
    tgemm<0,3><<<dim3(C_ / 128, M_ / 128), 256, TG_SMEM_OF(3), s2>>>(
        x1h, x1l, wqh, wql, bq, pos_q, nullptr, nullptr, M_, C_, C_);
    cudaEventRecord(eJ, s2);
    wsplit_k<<<dim3(MLP_ / 32, C_ / 32), 256, 0, s2>>>(W1, w1h, nullptr, C_, MLP_);
    wsplit_k<<<dim3(C_ / 32, MLP_ / 32), 256, 0, s2>>>(W2, w2h, w2l, MLP_, C_);
    cudaEventRecord(eW, s2);

    // legacy: kvp co-runs with s2
    kvp_mma<<<dim3(B_ * H_, 2), 256, KVP_SMEM>>>(bp);

    cudaStreamWaitEvent(0, eJ, 0);
    attn_mma<<<dim3(B_ * H_, N1_ / 128), 256, ATT_SMEM>>>(temp, xa);
    l2nq_k<<<M_ / 8, 256>>>(xa, qh, ql, xn, xnh);
    cudaStreamWaitEvent(0, eW, 0);
    // MLP1: pure hi*hi (1-term), 2 CTAs/SM
    tgemm<2,0><<<dim3(MLP_ / 128, M_ / 128), 256, TG_SMEM_OF(0)>>>(
        xnh, nullptr, w1h, nullptr, b1, nullptr, hh, nullptr, M_, MLP_, C_);
    // MLP2: 2-term, 2-stage double buffer -> 2 CTAs/SM
    tgemm<3,1><<<dim3(C_ / 128, M_ / 128), 256, TG_SMEM_OF(1)>>>(
        hh, nullptr, w2h, w2l, b2, xn, xa, nullptr, M_, C_, MLP_);
    l2n_k<<<M_ / 8, 256>>>(xa, (float*)d_out);
}